// round 1
// baseline (speedup 1.0000x reference)
#include <cuda_runtime.h>
#include <math.h>

#define BATCH 16
#define SEQ 1024
#define NTOK (BATCH*SEQ)
#define DMODEL 512
#define NH 8
#define HD 64
#define NF 256
#define NFH 128
#define NLAYERS 4
#define FFNH 1024

// ---------------- scratch (device globals; no allocation allowed) ----------------
__device__ float g_h  [NTOK*DMODEL];      // running hidden state
__device__ float g_t0 [NTOK*256];         // encoder hidden
__device__ float g_qk [NTOK*DMODEL];      // q / k / attn-out scratch
__device__ float g_v  [NTOK*DMODEL];      // v / generic 512-wide scratch
__device__ float g_ffn[NTOK*FFNH];        // ffn hidden
__device__ float g_Qf [BATCH*NH*SEQ*NF];  // FAVOR Q features [b,h,s,f]
__device__ float g_Kf [BATCH*NH*SEQ*NF];  // FAVOR K features [b,h,s,f]
__device__ float g_kv [BATCH*NH*NF*HD];   // kv accumulators [b,h,f,d]
__device__ float g_ks [BATCH*NH*NF];      // K feature sums  [b,h,f]
__device__ float g_z  [BATCH*NH*SEQ];     // normalizers     [b,h,s]

// ---------------- generic batched-strided SGEMM ----------------
// C[m,n] = sum_k A(m,k)*B(k,n)  (+bias[n]) (relu) (*rowscale[m])
// A(m,k) at Ap[m*sAm + k*sAk]; B(k,n) at Bp[k*sBk + n]; C(m,n) at Cp[m*sCm + n]
// batch z: two-level offsets via Hdiv: off = (z/Hdiv)*o1 + (z%Hdiv)*o2
__global__ void __launch_bounds__(256) sgemm_kernel(
    const float* __restrict__ A, const float* __restrict__ B,
    const float* __restrict__ bias, const float* __restrict__ rscale,
    float* __restrict__ C,
    int M, int Nn, int K,
    long long sAm, long long sAk, long long sBk, long long sCm,
    long long oA1, long long oA2, long long oB1, long long oB2,
    long long oC1, long long oC2, long long oS1, long long oS2,
    int Hdiv, int relu)
{
    int z  = blockIdx.z;
    int z1 = z / Hdiv, z2 = z - z1 * Hdiv;
    const float* Ap = A + z1 * oA1 + z2 * oA2;
    const float* Bp = B + z1 * oB1 + z2 * oB2;
    float*       Cp = C + z1 * oC1 + z2 * oC2;
    long long    oS = z1 * oS1 + z2 * oS2;

    int m0 = blockIdx.y * 64;
    int n0 = blockIdx.x * 64;
    int tid = threadIdx.x;
    int tx = tid & 15, ty = tid >> 4;

    __shared__ float As[16][64];
    __shared__ float Bs[16][64];

    float acc[4][4];
#pragma unroll
    for (int i = 0; i < 4; i++)
#pragma unroll
        for (int j = 0; j < 4; j++) acc[i][j] = 0.f;

    for (int kt = 0; kt < K; kt += 16) {
        if (sAk == 1) {
#pragma unroll
            for (int i = 0; i < 4; i++) {
                int e = tid + i * 256; int kk = e & 15; int mm = e >> 4;
                As[kk][mm] = Ap[(long long)(m0 + mm) * sAm + (kt + kk)];
            }
        } else { // sAm == 1 path (transposed-A, m contiguous)
#pragma unroll
            for (int i = 0; i < 4; i++) {
                int e = tid + i * 256; int mm = e & 63; int kk = e >> 6;
                As[kk][mm] = Ap[(long long)(m0 + mm) * sAm + (long long)(kt + kk) * sAk];
            }
        }
#pragma unroll
        for (int i = 0; i < 4; i++) {
            int e = tid + i * 256; int nn = e & 63; int kk = e >> 6;
            Bs[kk][nn] = Bp[(long long)(kt + kk) * sBk + (n0 + nn)];
        }
        __syncthreads();
#pragma unroll
        for (int kk = 0; kk < 16; kk++) {
            float4 a4 = *(const float4*)&As[kk][ty * 4];
            float4 b4 = *(const float4*)&Bs[kk][tx * 4];
            float av[4] = {a4.x, a4.y, a4.z, a4.w};
            float bv[4] = {b4.x, b4.y, b4.z, b4.w};
#pragma unroll
            for (int i = 0; i < 4; i++)
#pragma unroll
                for (int j = 0; j < 4; j++)
                    acc[i][j] = fmaf(av[i], bv[j], acc[i][j]);
        }
        __syncthreads();
    }

#pragma unroll
    for (int i = 0; i < 4; i++) {
        int m = m0 + ty * 4 + i;
        float rs = rscale ? rscale[oS + m] : 1.f;
        float* crow = Cp + (long long)m * sCm + n0 + tx * 4;
#pragma unroll
        for (int j = 0; j < 4; j++) {
            float v = acc[i][j];
            if (bias) v += bias[n0 + tx * 4 + j];
            if (relu) v = fmaxf(v, 0.f);
            crow[j] = v * rs;
        }
    }
}

// ---------------- encoder first layer: relu([x,pos] @ w + b), K=6 ----------------
__global__ void __launch_bounds__(256) enc1_kernel(
    const float* __restrict__ x, const float* __restrict__ pos,
    const float* __restrict__ w, const float* __restrict__ b,
    float* __restrict__ out)
{
    int idx = blockIdx.x * 256 + threadIdx.x;      // over NTOK*256
    int row = idx >> 8, col = idx & 255;
    const float* xr = x + row * 3;
    const float* pr = pos + row * 3;
    float a = b[col];
#pragma unroll
    for (int d = 0; d < 3; d++) a = fmaf(xr[d], w[d * 256 + col], a);
#pragma unroll
    for (int d = 0; d < 3; d++) a = fmaf(pr[d], w[(3 + d) * 256 + col], a);
    out[idx] = fmaxf(a, 0.f);
}

// ---------------- LayerNorm (optional residual), width 512 ----------------
__global__ void __launch_bounds__(512) ln_kernel(
    float* __restrict__ out, const float* __restrict__ resid,
    const float* __restrict__ y,
    const float* __restrict__ g, const float* __restrict__ b)
{
    int row = blockIdx.x, t = threadIdx.x;
    long long base = (long long)row * 512;
    float v = y[base + t];
    if (resid) v += resid[base + t];
    float s = v, s2 = v * v;
#pragma unroll
    for (int o = 16; o; o >>= 1) {
        s  += __shfl_xor_sync(0xffffffffu, s,  o);
        s2 += __shfl_xor_sync(0xffffffffu, s2, o);
    }
    __shared__ float rs[16], rs2[16];
    int w = t >> 5, lane = t & 31;
    if (!lane) { rs[w] = s; rs2[w] = s2; }
    __syncthreads();
    if (t < 32) {
        float a  = (t < 16) ? rs[t]  : 0.f;
        float a2 = (t < 16) ? rs2[t] : 0.f;
#pragma unroll
        for (int o = 8; o; o >>= 1) {
            a  += __shfl_xor_sync(0xffffffffu, a,  o);
            a2 += __shfl_xor_sync(0xffffffffu, a2, o);
        }
        if (!t) { rs[0] = a; rs2[0] = a2; }
    }
    __syncthreads();
    float mean = rs[0] * (1.f / 512.f);
    float var  = rs2[0] * (1.f / 512.f) - mean * mean;
    out[base + t] = (v - mean) * rsqrtf(var + 1e-5f) * g[t] + b[t];
}

// ---------------- FAVOR+ feature map ----------------
// in: q/k rows [NTOK x 512]; omega [64 x 128]; out [b,h,s,f] with f in 0..255
__global__ void __launch_bounds__(128) favor_kernel(
    const float* __restrict__ qk, const float* __restrict__ omega,
    float* __restrict__ outF)
{
    int row = blockIdx.x, hh_ = blockIdx.y, t = threadIdx.x;
    __shared__ float xv[64];
    if (t < 64) xv[t] = qk[(long long)row * 512 + hh_ * 64 + t] * 0.3535533905932738f; // 64^-0.25
    __syncthreads();
    float u = 0.f, hv = 0.f;
#pragma unroll 16
    for (int d = 0; d < 64; d++) {
        float xd = xv[d];
        u  = fmaf(xd, omega[d * 128 + t], u);
        hv = fmaf(xd, xd, hv);
    }
    hv *= 0.5f;
    long long o = ((long long)((row >> 10) * NH + hh_) * SEQ + (row & 1023)) * NF;
    outF[o + t]       = expf( u - hv) * 0.0625f;   // 256^-0.5
    outF[o + 128 + t] = expf(-u - hv) * 0.0625f;
}

// ---------------- K feature sums over sequence ----------------
__global__ void __launch_bounds__(256) ksum_kernel(
    const float* __restrict__ Kf, float* __restrict__ ks)
{
    int bh = blockIdx.x; int f = threadIdx.x;
    const float* base = Kf + (long long)bh * SEQ * NF + f;
    float s = 0.f;
#pragma unroll 8
    for (int i = 0; i < SEQ; i++) s += base[(long long)i * NF];
    ks[bh * NF + f] = s;
}

// ---------------- z = 1 / (Q . ksum + eps) ----------------
__global__ void __launch_bounds__(256) z_kernel(
    const float* __restrict__ Qf, const float* __restrict__ ks,
    float* __restrict__ z)
{
    int bh = blockIdx.x;
    int s  = blockIdx.y * 8 + (threadIdx.x >> 5);
    int lane = threadIdx.x & 31;
    __shared__ float kss[NF];
    kss[threadIdx.x] = ks[bh * NF + threadIdx.x];
    __syncthreads();
    const float* q = Qf + ((long long)bh * SEQ + s) * NF;
    float acc = 0.f;
#pragma unroll
    for (int i = lane; i < NF; i += 32) acc = fmaf(q[i], kss[i], acc);
#pragma unroll
    for (int o = 16; o; o >>= 1) acc += __shfl_xor_sync(0xffffffffu, acc, o);
    if (!lane) z[bh * SEQ + s] = 1.f / (acc + 1e-6f);
}

// ---------------- mean pool + classifier ----------------
__global__ void __launch_bounds__(512) pool_cls_kernel(
    const float* __restrict__ h, const float* __restrict__ cw,
    const float* __restrict__ cb, float* __restrict__ out)
{
    int b = blockIdx.x, t = threadIdx.x;
    const float* base = h + (long long)b * SEQ * DMODEL + t;
    float s = 0.f;
#pragma unroll 8
    for (int i = 0; i < SEQ; i++) s += base[(long long)i * DMODEL];
    __shared__ float pooled[DMODEL];
    pooled[t] = s * (1.f / (float)SEQ);
    __syncthreads();
    if (t < 16) {
        float acc = cb[t];
        for (int d = 0; d < DMODEL; d++) acc = fmaf(pooled[d], cw[d * 16 + t], acc);
        out[b * 16 + t] = acc;
    }
}

// ---------------- host driver ----------------
extern "C" void kernel_launch(void* const* d_in, const int* in_sizes, int n_in,
                              void* d_out, int out_size)
{
    const float* x      = (const float*)d_in[0];
    const float* pos    = (const float*)d_in[1];
    const float* enc_w1 = (const float*)d_in[2];
    const float* enc_b1 = (const float*)d_in[3];
    const float* enc_w2 = (const float*)d_in[4];
    const float* enc_b2 = (const float*)d_in[5];
    const float* enc_g  = (const float*)d_in[6];
    const float* enc_bb = (const float*)d_in[7];
    const float* wq     = (const float*)d_in[8];
    const float* bq     = (const float*)d_in[9];
    const float* wk     = (const float*)d_in[10];
    const float* bk     = (const float*)d_in[11];
    const float* wv     = (const float*)d_in[12];
    const float* bv     = (const float*)d_in[13];
    const float* wo     = (const float*)d_in[14];
    const float* bo     = (const float*)d_in[15];
    const float* ln1_g  = (const float*)d_in[16];
    const float* ln1_b  = (const float*)d_in[17];
    const float* w1     = (const float*)d_in[18];
    const float* b1     = (const float*)d_in[19];
    const float* w2     = (const float*)d_in[20];
    const float* b2     = (const float*)d_in[21];
    const float* ln2_g  = (const float*)d_in[22];
    const float* ln2_b  = (const float*)d_in[23];
    const float* omega  = (const float*)d_in[24];
    const float* cls_w  = (const float*)d_in[25];
    const float* cls_b  = (const float*)d_in[26];

    float *p_h, *p_t0, *p_qk, *p_v, *p_ffn, *p_Qf, *p_Kf, *p_kv, *p_ks, *p_z;
    cudaGetSymbolAddress((void**)&p_h,  g_h);
    cudaGetSymbolAddress((void**)&p_t0, g_t0);
    cudaGetSymbolAddress((void**)&p_qk, g_qk);
    cudaGetSymbolAddress((void**)&p_v,  g_v);
    cudaGetSymbolAddress((void**)&p_ffn,g_ffn);
    cudaGetSymbolAddress((void**)&p_Qf, g_Qf);
    cudaGetSymbolAddress((void**)&p_Kf, g_Kf);
    cudaGetSymbolAddress((void**)&p_kv, g_kv);
    cudaGetSymbolAddress((void**)&p_ks, g_ks);
    cudaGetSymbolAddress((void**)&p_z,  g_z);

    // dense GEMM launcher: C[M x Nn] = A[M x K] @ W + bias (opt relu)
    auto dense = [&](const float* A, const float* W, const float* bias,
                     float* C, int M, int Nn, int K, int relu) {
        dim3 grid(Nn / 64, M / 64, 1);
        sgemm_kernel<<<grid, 256>>>(A, W, bias, nullptr, C, M, Nn, K,
                                    (long long)K, 1LL, (long long)Nn, (long long)Nn,
                                    0, 0, 0, 0, 0, 0, 0, 0, 1, relu);
    };

    // ---- encoder ----
    enc1_kernel<<<NTOK, 256>>>(x, pos, enc_w1, enc_b1, p_t0);
    dense(p_t0, enc_w2, enc_b2, p_v, NTOK, DMODEL, 256, 0);
    ln_kernel<<<NTOK, 512>>>(p_h, nullptr, p_v, enc_g, enc_bb);

    for (int l = 0; l < NLAYERS; l++) {
        const float* Wq = wq + (long long)l * DMODEL * DMODEL;
        const float* Wk = wk + (long long)l * DMODEL * DMODEL;
        const float* Wv = wv + (long long)l * DMODEL * DMODEL;
        const float* Wo = wo + (long long)l * DMODEL * DMODEL;
        const float* Bq = bq + l * DMODEL;
        const float* Bk = bk + l * DMODEL;
        const float* Bv = bv + l * DMODEL;
        const float* Bo = bo + l * DMODEL;
        const float* W1 = w1 + (long long)l * DMODEL * FFNH;
        const float* B1 = b1 + l * FFNH;
        const float* W2 = w2 + (long long)l * FFNH * DMODEL;
        const float* B2 = b2 + l * DMODEL;
        const float* Om = omega + (long long)l * HD * NFH;

        // Q -> FAVOR(Q)
        dense(p_h, Wq, Bq, p_qk, NTOK, DMODEL, DMODEL, 0);
        favor_kernel<<<dim3(NTOK, NH), 128>>>(p_qk, Om, p_Qf);
        // K -> FAVOR(K)
        dense(p_h, Wk, Bk, p_qk, NTOK, DMODEL, DMODEL, 0);
        favor_kernel<<<dim3(NTOK, NH), 128>>>(p_qk, Om, p_Kf);
        // V
        dense(p_h, Wv, Bv, p_v, NTOK, DMODEL, DMODEL, 0);

        // kv[b,h,f,d] = sum_s Kf[b,h,s,f] * v[b,s,h,d]   (batched, A-transposed)
        {
            dim3 grid(HD / 64, NF / 64, BATCH * NH);
            sgemm_kernel<<<grid, 256>>>(p_Kf, p_v, nullptr, nullptr, p_kv,
                NF, HD, SEQ,
                1LL, (long long)NF,            // A strides (sAm, sAk)
                (long long)DMODEL,             // sBk
                (long long)HD,                 // sCm
                (long long)NH * SEQ * NF, (long long)SEQ * NF,   // A batch offsets
                (long long)SEQ * DMODEL, (long long)HD,          // B batch offsets
                (long long)NH * NF * HD, (long long)NF * HD,     // C batch offsets
                0, 0, NH, 0);
        }
        ksum_kernel<<<BATCH * NH, 256>>>(p_Kf, p_ks);
        z_kernel<<<dim3(BATCH * NH, SEQ / 8), 256>>>(p_Qf, p_ks, p_z);

        // attn[b,s,h,d] = z * Qf[b,h,s,:] @ kv[b,h,:,:]   (batched, rowscale z)
        {
            dim3 grid(HD / 64, SEQ / 64, BATCH * NH);
            sgemm_kernel<<<grid, 256>>>(p_Qf, p_kv, nullptr, p_z, p_qk,
                SEQ, HD, NF,
                (long long)NF, 1LL,            // A strides
                (long long)HD,                 // sBk
                (long long)DMODEL,             // sCm (head slice within 512-wide row)
                (long long)NH * SEQ * NF, (long long)SEQ * NF,   // A batch offsets
                (long long)NH * NF * HD, (long long)NF * HD,     // B batch offsets
                (long long)SEQ * DMODEL, (long long)HD,          // C batch offsets
                (long long)NH * SEQ, (long long)SEQ,             // rowscale offsets
                NH, 0);
        }

        // output projection + residual LN
        dense(p_qk, Wo, Bo, p_v, NTOK, DMODEL, DMODEL, 0);
        ln_kernel<<<NTOK, 512>>>(p_h, p_h, p_v, ln1_g + l * DMODEL, ln1_b + l * DMODEL);

        // FFN + residual LN
        dense(p_h, W1, B1, p_ffn, NTOK, FFNH, DMODEL, 1);
        dense(p_ffn, W2, B2, p_v, NTOK, DMODEL, FFNH, 0);
        ln_kernel<<<NTOK, 512>>>(p_h, p_h, p_v, ln2_g + l * DMODEL, ln2_b + l * DMODEL);
    }

    pool_cls_kernel<<<BATCH, 512>>>(p_h, cls_w, cls_b, (float*)d_out);
}

// round 2
// speedup vs baseline: 1.1827x; 1.1827x over previous
#include <cuda_runtime.h>
#include <math.h>

#define BATCH 16
#define SEQ 1024
#define NTOK (BATCH*SEQ)
#define DMODEL 512
#define NH 8
#define HD 64
#define NF 256
#define NFH 128
#define NLAYERS 4
#define FFNH 1024

// ---------------- scratch (device globals; no allocation allowed) ----------------
__device__ float g_h  [NTOK*DMODEL];
__device__ float g_t0 [NTOK*256];
__device__ float g_qk [NTOK*DMODEL];
__device__ float g_v  [NTOK*DMODEL];
__device__ float g_ffn[NTOK*FFNH];
__device__ float g_Qf [BATCH*NH*SEQ*NF];
__device__ float g_Kf [BATCH*NH*SEQ*NF];
__device__ float g_kv [BATCH*NH*NF*HD];
__device__ float g_ks [BATCH*NH*NF];
__device__ float g_z  [BATCH*NH*SEQ];

__device__ __forceinline__ float f2tf32(float x) {
    unsigned u;
    asm("cvt.rna.tf32.f32 %0, %1;" : "=r"(u) : "f"(x));
    return __uint_as_float(u);
}

__device__ __forceinline__ void mma_tf32(float* d, const float* a, const float* b) {
    asm volatile(
        "mma.sync.aligned.m16n8k8.row.col.f32.tf32.tf32.f32 "
        "{%0,%1,%2,%3},{%4,%5,%6,%7},{%8,%9},{%0,%1,%2,%3};\n"
        : "+f"(d[0]), "+f"(d[1]), "+f"(d[2]), "+f"(d[3])
        : "r"(__float_as_uint(a[0])), "r"(__float_as_uint(a[1])),
          "r"(__float_as_uint(a[2])), "r"(__float_as_uint(a[3])),
          "r"(__float_as_uint(b[0])), "r"(__float_as_uint(b[1])));
}

// ---------------- tf32 tensor-core batched-strided GEMM ----------------
// C[m,n] = sum_k A(m,k)*B(k,n)  (+bias[n]) (relu) (*rowscale[m])
// A(m,k) at Ap[m*sAm + k*sAk]; B(k,n) at Bp[k*sBk + n]; C(m,n) at Cp[m*sCm + n]
// batch z: off = (z/Hdiv)*o1 + (z%Hdiv)*o2
template<int BM, int BN, int WY, int WX>
__global__ void __launch_bounds__(256) mma_gemm(
    const float* __restrict__ A, const float* __restrict__ B,
    const float* __restrict__ bias, const float* __restrict__ rscale,
    float* __restrict__ C,
    int M, int Nn, int K,
    long long sAm, long long sAk, long long sBk, long long sCm,
    long long oA1, long long oA2, long long oB1, long long oB2,
    long long oC1, long long oC2, long long oS1, long long oS2,
    int Hdiv, int relu)
{
    constexpr int MT = BM / WY / 16;   // m16 tiles per warp
    constexpr int NT = BN / WX / 8;    // n8 tiles per warp
    constexpr int ALD = BM * 16 / 256; // A elems per thread per tile
    constexpr int BLD = BN * 16 / 256;

    int z  = blockIdx.z;
    int z1 = z / Hdiv, z2 = z - z1 * Hdiv;
    const float* Ap = A + z1 * oA1 + z2 * oA2;
    const float* Bp = B + z1 * oB1 + z2 * oB2;
    float*       Cp = C + z1 * oC1 + z2 * oC2;
    long long    oS = z1 * oS1 + z2 * oS2;

    int m0 = blockIdx.y * BM;
    int n0 = blockIdx.x * BN;
    int tid = threadIdx.x;
    int warp = tid >> 5, lane = tid & 31;
    int wy = warp % WY, wx = warp / WY;
    int wm = wy * (BM / WY), wn = wx * (BN / WX);

    __shared__ float As[16][BM + 8];
    __shared__ float Bs[16][BN + 8];

    float acc[MT][NT][4];
#pragma unroll
    for (int i = 0; i < MT; i++)
#pragma unroll
        for (int j = 0; j < NT; j++)
#pragma unroll
            for (int c = 0; c < 4; c++) acc[i][j][c] = 0.f;

    float ra[ALD], rb[BLD];
    int a_mm[ALD], a_kk[ALD], b_nn[BLD], b_kk[BLD];
#pragma unroll
    for (int i = 0; i < ALD; i++) {
        int e = tid + i * 256;
        if (sAk == 1) { a_kk[i] = e & 15;      a_mm[i] = e >> 4; }
        else          { a_mm[i] = e & (BM-1);  a_kk[i] = e / BM; }
    }
#pragma unroll
    for (int i = 0; i < BLD; i++) {
        int e = tid + i * 256;
        b_nn[i] = e & (BN - 1);
        b_kk[i] = e / BN;
    }

    auto gldA = [&](int kt) {
#pragma unroll
        for (int i = 0; i < ALD; i++)
            ra[i] = f2tf32(Ap[(long long)(m0 + a_mm[i]) * sAm + (long long)(kt + a_kk[i]) * sAk]);
    };
    auto gldB = [&](int kt) {
#pragma unroll
        for (int i = 0; i < BLD; i++)
            rb[i] = f2tf32(Bp[(long long)(kt + b_kk[i]) * sBk + (n0 + b_nn[i])]);
    };

    gldA(0); gldB(0);

    for (int kt = 0; kt < K; kt += 16) {
#pragma unroll
        for (int i = 0; i < ALD; i++) As[a_kk[i]][a_mm[i]] = ra[i];
#pragma unroll
        for (int i = 0; i < BLD; i++) Bs[b_kk[i]][b_nn[i]] = rb[i];
        __syncthreads();

        if (kt + 16 < K) { gldA(kt + 16); gldB(kt + 16); }

#pragma unroll
        for (int k0 = 0; k0 < 16; k0 += 8) {
            float afr[MT][4], bfr[NT][2];
#pragma unroll
            for (int i = 0; i < MT; i++) {
                int row = wm + i * 16 + (lane >> 2);
                int kc = k0 + (lane & 3);
                afr[i][0] = As[kc][row];
                afr[i][1] = As[kc][row + 8];
                afr[i][2] = As[kc + 4][row];
                afr[i][3] = As[kc + 4][row + 8];
            }
#pragma unroll
            for (int j = 0; j < NT; j++) {
                int col = wn + j * 8 + (lane >> 2);
                int kc = k0 + (lane & 3);
                bfr[j][0] = Bs[kc][col];
                bfr[j][1] = Bs[kc + 4][col];
            }
#pragma unroll
            for (int i = 0; i < MT; i++)
#pragma unroll
                for (int j = 0; j < NT; j++)
                    mma_tf32(acc[i][j], afr[i], bfr[j]);
        }
        __syncthreads();
    }

    // epilogue
#pragma unroll
    for (int i = 0; i < MT; i++) {
        int mA = m0 + wm + i * 16 + (lane >> 2);
        int mB = mA + 8;
        float rsA = rscale ? rscale[oS + mA] : 1.f;
        float rsB = rscale ? rscale[oS + mB] : 1.f;
#pragma unroll
        for (int j = 0; j < NT; j++) {
            int n = n0 + wn + j * 8 + (lane & 3) * 2;
            float b0 = 0.f, b1 = 0.f;
            if (bias) { b0 = bias[n]; b1 = bias[n + 1]; }
            float2 v0, v1;
            v0.x = acc[i][j][0] + b0; v0.y = acc[i][j][1] + b1;
            v1.x = acc[i][j][2] + b0; v1.y = acc[i][j][3] + b1;
            if (relu) {
                v0.x = fmaxf(v0.x, 0.f); v0.y = fmaxf(v0.y, 0.f);
                v1.x = fmaxf(v1.x, 0.f); v1.y = fmaxf(v1.y, 0.f);
            }
            v0.x *= rsA; v0.y *= rsA; v1.x *= rsB; v1.y *= rsB;
            *(float2*)(Cp + (long long)mA * sCm + n) = v0;
            *(float2*)(Cp + (long long)mB * sCm + n) = v1;
        }
    }
}

// ---------------- encoder first layer: relu([x,pos] @ w + b), K=6 ----------------
__global__ void __launch_bounds__(256) enc1_kernel(
    const float* __restrict__ x, const float* __restrict__ pos,
    const float* __restrict__ w, const float* __restrict__ b,
    float* __restrict__ out)
{
    int idx = blockIdx.x * 256 + threadIdx.x;
    int row = idx >> 8, col = idx & 255;
    const float* xr = x + row * 3;
    const float* pr = pos + row * 3;
    float a = b[col];
#pragma unroll
    for (int d = 0; d < 3; d++) a = fmaf(xr[d], w[d * 256 + col], a);
#pragma unroll
    for (int d = 0; d < 3; d++) a = fmaf(pr[d], w[(3 + d) * 256 + col], a);
    out[idx] = fmaxf(a, 0.f);
}

// ---------------- LayerNorm (optional residual), width 512 ----------------
__global__ void __launch_bounds__(512) ln_kernel(
    float* __restrict__ out, const float* __restrict__ resid,
    const float* __restrict__ y,
    const float* __restrict__ g, const float* __restrict__ b)
{
    int row = blockIdx.x, t = threadIdx.x;
    long long base = (long long)row * 512;
    float v = y[base + t];
    if (resid) v += resid[base + t];
    float s = v, s2 = v * v;
#pragma unroll
    for (int o = 16; o; o >>= 1) {
        s  += __shfl_xor_sync(0xffffffffu, s,  o);
        s2 += __shfl_xor_sync(0xffffffffu, s2, o);
    }
    __shared__ float rs[16], rs2[16];
    int w = t >> 5, lane = t & 31;
    if (!lane) { rs[w] = s; rs2[w] = s2; }
    __syncthreads();
    if (t < 32) {
        float a  = (t < 16) ? rs[t]  : 0.f;
        float a2 = (t < 16) ? rs2[t] : 0.f;
#pragma unroll
        for (int o = 8; o; o >>= 1) {
            a  += __shfl_xor_sync(0xffffffffu, a,  o);
            a2 += __shfl_xor_sync(0xffffffffu, a2, o);
        }
        if (!t) { rs[0] = a; rs2[0] = a2; }
    }
    __syncthreads();
    float mean = rs[0] * (1.f / 512.f);
    float var  = rs2[0] * (1.f / 512.f) - mean * mean;
    out[base + t] = (v - mean) * rsqrtf(var + 1e-5f) * g[t] + b[t];
}

// ---------------- FAVOR+ feature map ----------------
__global__ void __launch_bounds__(128) favor_kernel(
    const float* __restrict__ qk, const float* __restrict__ omega,
    float* __restrict__ outF)
{
    int row = blockIdx.x, hh_ = blockIdx.y, t = threadIdx.x;
    __shared__ float xv[64];
    if (t < 64) xv[t] = qk[(long long)row * 512 + hh_ * 64 + t] * 0.3535533905932738f;
    __syncthreads();
    float u = 0.f, hv = 0.f;
#pragma unroll 16
    for (int d = 0; d < 64; d++) {
        float xd = xv[d];
        u  = fmaf(xd, omega[d * 128 + t], u);
        hv = fmaf(xd, xd, hv);
    }
    hv *= 0.5f;
    long long o = ((long long)((row >> 10) * NH + hh_) * SEQ + (row & 1023)) * NF;
    outF[o + t]       = expf( u - hv) * 0.0625f;
    outF[o + 128 + t] = expf(-u - hv) * 0.0625f;
}

// ---------------- K feature sums over sequence ----------------
__global__ void __launch_bounds__(256) ksum_kernel(
    const float* __restrict__ Kf, float* __restrict__ ks)
{
    int bh = blockIdx.x; int f = threadIdx.x;
    const float* base = Kf + (long long)bh * SEQ * NF + f;
    float s = 0.f;
#pragma unroll 8
    for (int i = 0; i < SEQ; i++) s += base[(long long)i * NF];
    ks[bh * NF + f] = s;
}

// ---------------- z = 1 / (Q . ksum + eps) ----------------
__global__ void __launch_bounds__(256) z_kernel(
    const float* __restrict__ Qf, const float* __restrict__ ks,
    float* __restrict__ z)
{
    int bh = blockIdx.x;
    int s  = blockIdx.y * 8 + (threadIdx.x >> 5);
    int lane = threadIdx.x & 31;
    __shared__ float kss[NF];
    kss[threadIdx.x] = ks[bh * NF + threadIdx.x];
    __syncthreads();
    const float* q = Qf + ((long long)bh * SEQ + s) * NF;
    float acc = 0.f;
#pragma unroll
    for (int i = lane; i < NF; i += 32) acc = fmaf(q[i], kss[i], acc);
#pragma unroll
    for (int o = 16; o; o >>= 1) acc += __shfl_xor_sync(0xffffffffu, acc, o);
    if (!lane) z[bh * SEQ + s] = 1.f / (acc + 1e-6f);
}

// ---------------- mean pool + classifier ----------------
__global__ void __launch_bounds__(512) pool_cls_kernel(
    const float* __restrict__ h, const float* __restrict__ cw,
    const float* __restrict__ cb, float* __restrict__ out)
{
    int b = blockIdx.x, t = threadIdx.x;
    const float* base = h + (long long)b * SEQ * DMODEL + t;
    float s = 0.f;
#pragma unroll 8
    for (int i = 0; i < SEQ; i++) s += base[(long long)i * DMODEL];
    __shared__ float pooled[DMODEL];
    pooled[t] = s * (1.f / (float)SEQ);
    __syncthreads();
    if (t < 16) {
        float acc = cb[t];
        for (int d = 0; d < DMODEL; d++) acc = fmaf(pooled[d], cw[d * 16 + t], acc);
        out[b * 16 + t] = acc;
    }
}

// ---------------- host driver ----------------
extern "C" void kernel_launch(void* const* d_in, const int* in_sizes, int n_in,
                              void* d_out, int out_size)
{
    const float* x      = (const float*)d_in[0];
    const float* pos    = (const float*)d_in[1];
    const float* enc_w1 = (const float*)d_in[2];
    const float* enc_b1 = (const float*)d_in[3];
    const float* enc_w2 = (const float*)d_in[4];
    const float* enc_b2 = (const float*)d_in[5];
    const float* enc_g  = (const float*)d_in[6];
    const float* enc_bb = (const float*)d_in[7];
    const float* wq     = (const float*)d_in[8];
    const float* bq     = (const float*)d_in[9];
    const float* wk     = (const float*)d_in[10];
    const float* bk     = (const float*)d_in[11];
    const float* wv     = (const float*)d_in[12];
    const float* bv     = (const float*)d_in[13];
    const float* wo     = (const float*)d_in[14];
    const float* bo     = (const float*)d_in[15];
    const float* ln1_g  = (const float*)d_in[16];
    const float* ln1_b  = (const float*)d_in[17];
    const float* w1     = (const float*)d_in[18];
    const float* b1     = (const float*)d_in[19];
    const float* w2     = (const float*)d_in[20];
    const float* b2     = (const float*)d_in[21];
    const float* ln2_g  = (const float*)d_in[22];
    const float* ln2_b  = (const float*)d_in[23];
    const float* omega  = (const float*)d_in[24];
    const float* cls_w  = (const float*)d_in[25];
    const float* cls_b  = (const float*)d_in[26];

    float *p_h, *p_t0, *p_qk, *p_v, *p_ffn, *p_Qf, *p_Kf, *p_kv, *p_ks, *p_z;
    cudaGetSymbolAddress((void**)&p_h,  g_h);
    cudaGetSymbolAddress((void**)&p_t0, g_t0);
    cudaGetSymbolAddress((void**)&p_qk, g_qk);
    cudaGetSymbolAddress((void**)&p_v,  g_v);
    cudaGetSymbolAddress((void**)&p_ffn,g_ffn);
    cudaGetSymbolAddress((void**)&p_Qf, g_Qf);
    cudaGetSymbolAddress((void**)&p_Kf, g_Kf);
    cudaGetSymbolAddress((void**)&p_kv, g_kv);
    cudaGetSymbolAddress((void**)&p_ks, g_ks);
    cudaGetSymbolAddress((void**)&p_z,  g_z);

    // dense GEMM: C[M x Nn] = A[M x K] @ W + bias (opt relu), row-major
    auto dense = [&](const float* A, const float* W, const float* bias,
                     float* C, int M, int Nn, int K, int relu) {
        dim3 grid(Nn / 128, M / 128, 1);
        mma_gemm<128,128,2,4><<<grid, 256>>>(A, W, bias, nullptr, C, M, Nn, K,
                                    (long long)K, 1LL, (long long)Nn, (long long)Nn,
                                    0, 0, 0, 0, 0, 0, 0, 0, 1, relu);
    };

    // ---- encoder ----
    enc1_kernel<<<NTOK, 256>>>(x, pos, enc_w1, enc_b1, p_t0);
    dense(p_t0, enc_w2, enc_b2, p_v, NTOK, DMODEL, 256, 0);
    ln_kernel<<<NTOK, 512>>>(p_h, nullptr, p_v, enc_g, enc_bb);

    for (int l = 0; l < NLAYERS; l++) {
        const float* Wq = wq + (long long)l * DMODEL * DMODEL;
        const float* Wk = wk + (long long)l * DMODEL * DMODEL;
        const float* Wv = wv + (long long)l * DMODEL * DMODEL;
        const float* Wo = wo + (long long)l * DMODEL * DMODEL;
        const float* Bq = bq + l * DMODEL;
        const float* Bk = bk + l * DMODEL;
        const float* Bv = bv + l * DMODEL;
        const float* Bo = bo + l * DMODEL;
        const float* W1 = w1 + (long long)l * DMODEL * FFNH;
        const float* B1 = b1 + l * FFNH;
        const float* W2 = w2 + (long long)l * FFNH * DMODEL;
        const float* B2 = b2 + l * DMODEL;
        const float* Om = omega + (long long)l * HD * NFH;

        // Q -> FAVOR(Q)
        dense(p_h, Wq, Bq, p_qk, NTOK, DMODEL, DMODEL, 0);
        favor_kernel<<<dim3(NTOK, NH), 128>>>(p_qk, Om, p_Qf);
        // K -> FAVOR(K)
        dense(p_h, Wk, Bk, p_qk, NTOK, DMODEL, DMODEL, 0);
        favor_kernel<<<dim3(NTOK, NH), 128>>>(p_qk, Om, p_Kf);
        // V
        dense(p_h, Wv, Bv, p_v, NTOK, DMODEL, DMODEL, 0);

        // kv[b,h,f,d] = sum_s Kf[b,h,s,f] * v[b,s,h,d]   (batched, A-transposed)
        {
            dim3 grid(HD / 64, NF / 128, BATCH * NH);
            mma_gemm<128,64,4,2><<<grid, 256>>>(p_Kf, p_v, nullptr, nullptr, p_kv,
                NF, HD, SEQ,
                1LL, (long long)NF,
                (long long)DMODEL,
                (long long)HD,
                (long long)NH * SEQ * NF, (long long)SEQ * NF,
                (long long)SEQ * DMODEL, (long long)HD,
                (long long)NH * NF * HD, (long long)NF * HD,
                0, 0, NH, 0);
        }
        ksum_kernel<<<BATCH * NH, 256>>>(p_Kf, p_ks);
        z_kernel<<<dim3(BATCH * NH, SEQ / 8), 256>>>(p_Qf, p_ks, p_z);

        // attn[b,s,h,d] = z * Qf[b,h,s,:] @ kv[b,h,:,:]   (batched, rowscale z)
        {
            dim3 grid(HD / 64, SEQ / 128, BATCH * NH);
            mma_gemm<128,64,4,2><<<grid, 256>>>(p_Qf, p_kv, nullptr, p_z, p_qk,
                SEQ, HD, NF,
                (long long)NF, 1LL,
                (long long)HD,
                (long long)DMODEL,
                (long long)NH * SEQ * NF, (long long)SEQ * NF,
                (long long)NH * NF * HD, (long long)NF * HD,
                (long long)SEQ * DMODEL, (long long)HD,
                (long long)NH * SEQ, (long long)SEQ,
                NH, 0);
        }

        // output projection + residual LN
        dense(p_qk, Wo, Bo, p_v, NTOK, DMODEL, DMODEL, 0);
        ln_kernel<<<NTOK, 512>>>(p_h, p_h, p_v, ln1_g + l * DMODEL, ln1_b + l * DMODEL);

        // FFN + residual LN
        dense(p_h, W1, B1, p_ffn, NTOK, FFNH, DMODEL, 1);
        dense(p_ffn, W2, B2, p_v, NTOK, DMODEL, FFNH, 0);
        ln_kernel<<<NTOK, 512>>>(p_h, p_h, p_v, ln2_g + l * DMODEL, ln2_b + l * DMODEL);
    }

    pool_cls_kernel<<<BATCH, 512>>>(p_h, cls_w, cls_b, (float*)d_out);
}

// round 4
// speedup vs baseline: 2.2402x; 1.8941x over previous
#include <cuda_runtime.h>
#include <math.h>

#define BATCH 16
#define SEQ 1024
#define NTOK (BATCH*SEQ)
#define DMODEL 512
#define NH 8
#define HD 64
#define NF 256
#define NFH 128
#define NLAYERS 4
#define FFNH 1024

// ---------------- scratch (device globals; no allocation allowed) ----------------
__device__ float g_h  [NTOK*DMODEL];
__device__ float g_t0 [NTOK*256];
__device__ float g_qk [NTOK*DMODEL];
__device__ float g_v  [NTOK*DMODEL];
__device__ float g_ffn[NTOK*FFNH];
__device__ float g_Qf [BATCH*NH*SEQ*NF];
__device__ float g_Kf [BATCH*NH*SEQ*NF];
__device__ float g_kv [BATCH*NH*NF*HD];
__device__ float g_ks [BATCH*NH*NF];
__device__ float g_z  [BATCH*NH*SEQ];

__device__ __forceinline__ float f2tf32(float x) {
    unsigned u;
    asm("cvt.rna.tf32.f32 %0, %1;" : "=r"(u) : "f"(x));
    return __uint_as_float(u);
}

__device__ __forceinline__ void mma_tf32(float* d, const float* a, const float* b) {
    asm volatile(
        "mma.sync.aligned.m16n8k8.row.col.f32.tf32.tf32.f32 "
        "{%0,%1,%2,%3},{%4,%5,%6,%7},{%8,%9},{%0,%1,%2,%3};\n"
        : "+f"(d[0]), "+f"(d[1]), "+f"(d[2]), "+f"(d[3])
        : "r"(__float_as_uint(a[0])), "r"(__float_as_uint(a[1])),
          "r"(__float_as_uint(a[2])), "r"(__float_as_uint(a[3])),
          "r"(__float_as_uint(b[0])), "r"(__float_as_uint(b[1])));
}

__device__ __forceinline__ void cpa16(void* dst, const void* src) {
    unsigned s = (unsigned)__cvta_generic_to_shared(dst);
    asm volatile("cp.async.ca.shared.global [%0], [%1], 16;\n" :: "r"(s), "l"(src));
}
#define CP_COMMIT  asm volatile("cp.async.commit_group;\n")

// ---------------- tf32 tensor-core batched-strided GEMM, cp.async 2-stage ----------------
// C[m,n] = sum_k A(m,k)*B(k,n)  (+bias[n]) (relu) (*rowscale[m])
// AT=0: A row-major (sAk==1). AT=1: A trans (sAm==1, m contiguous).
// B(k,n) at Bp[k*sBk + n] (n contiguous). batch z: off = (z/Hdiv)*o1 + (z%Hdiv)*o2
template<int BM, int BN, int WY, int WX, int AT>
__global__ void __launch_bounds__(256, 2) mma_gemm(
    const float* __restrict__ A, const float* __restrict__ B,
    const float* __restrict__ bias, const float* __restrict__ rscale,
    float* __restrict__ C,
    int M, int Nn, int K,
    long long sAm, long long sAk, long long sBk, long long sCm,
    long long oA1, long long oA2, long long oB1, long long oB2,
    long long oC1, long long oC2, long long oS1, long long oS2,
    int Hdiv, int relu)
{
    constexpr int BK  = 16;
    constexpr int MT  = BM / WY / 16;
    constexpr int NT  = BN / WX / 8;
    constexpr int APITCH = (AT == 0) ? 20 : (BM + 8);
    constexpr int BPITCH = BN + 8;
    constexpr int ASZ = (AT == 0) ? BM * 20 : BK * (BM + 8);
    constexpr int BSZ = BK * BPITCH;
    constexpr int AQ  = BM * BK / 4 / 256;
    constexpr int BQ  = BK * BN / 4 / 256;

    int z  = blockIdx.z;
    int z1 = z / Hdiv, z2 = z - z1 * Hdiv;
    const float* Ap = A + z1 * oA1 + z2 * oA2;
    const float* Bp = B + z1 * oB1 + z2 * oB2;
    float*       Cp = C + z1 * oC1 + z2 * oC2;
    long long    oS = z1 * oS1 + z2 * oS2;

    int m0 = blockIdx.y * BM;
    int n0 = blockIdx.x * BN;
    int tid = threadIdx.x;
    int warp = tid >> 5, lane = tid & 31;
    int wy = warp % WY, wx = warp / WY;
    int wm = wy * (BM / WY), wn = wx * (BN / WX);

    __shared__ float As[2][ASZ];
    __shared__ float Bs[2][BSZ];

    float acc[MT][NT][4];
#pragma unroll
    for (int i = 0; i < MT; i++)
#pragma unroll
        for (int j = 0; j < NT; j++)
#pragma unroll
            for (int c = 0; c < 4; c++) acc[i][j][c] = 0.f;

    auto loadA = [&](int st, int kt) {
#pragma unroll
        for (int i = 0; i < AQ; i++) {
            int e = tid + i * 256;
            if (AT == 0) {
                int row = e >> 2, q = (e & 3) * 4;
                cpa16(&As[st][row * 20 + q],
                      Ap + (long long)(m0 + row) * sAm + (kt + q));
            } else {
                constexpr int QPR = BM / 4;
                int kk = e / QPR, q = (e % QPR) * 4;
                cpa16(&As[st][kk * APITCH + q],
                      Ap + (long long)(kt + kk) * sAk + (m0 + q));
            }
        }
    };
    auto loadB = [&](int st, int kt) {
#pragma unroll
        for (int i = 0; i < BQ; i++) {
            int e = tid + i * 256;
            constexpr int QPR = BN / 4;
            int kk = e / QPR, q = (e % QPR) * 4;
            cpa16(&Bs[st][kk * BPITCH + q],
                  Bp + (long long)(kt + kk) * sBk + (n0 + q));
        }
    };

    loadA(0, 0); loadB(0, 0); CP_COMMIT;

    int T = K / BK;
    for (int t = 0; t < T; t++) {
        int st = t & 1;
        if (t + 1 < T) {
            loadA(st ^ 1, (t + 1) * BK);
            loadB(st ^ 1, (t + 1) * BK);
            CP_COMMIT;
            asm volatile("cp.async.wait_group 1;\n");
        } else {
            asm volatile("cp.async.wait_group 0;\n");
        }
        __syncthreads();

#pragma unroll
        for (int k0 = 0; k0 < BK; k0 += 8) {
            float afr[MT][4], bfr[NT][2];
            int kc = k0 + (lane & 3);
#pragma unroll
            for (int i = 0; i < MT; i++) {
                int row = wm + i * 16 + (lane >> 2);
                if (AT == 0) {
                    afr[i][0] = f2tf32(As[st][row * 20 + kc]);
                    afr[i][1] = f2tf32(As[st][(row + 8) * 20 + kc]);
                    afr[i][2] = f2tf32(As[st][row * 20 + kc + 4]);
                    afr[i][3] = f2tf32(As[st][(row + 8) * 20 + kc + 4]);
                } else {
                    afr[i][0] = f2tf32(As[st][kc * APITCH + row]);
                    afr[i][1] = f2tf32(As[st][kc * APITCH + row + 8]);
                    afr[i][2] = f2tf32(As[st][(kc + 4) * APITCH + row]);
                    afr[i][3] = f2tf32(As[st][(kc + 4) * APITCH + row + 8]);
                }
            }
#pragma unroll
            for (int j = 0; j < NT; j++) {
                int col = wn + j * 8 + (lane >> 2);
                bfr[j][0] = f2tf32(Bs[st][kc * BPITCH + col]);
                bfr[j][1] = f2tf32(Bs[st][(kc + 4) * BPITCH + col]);
            }
#pragma unroll
            for (int i = 0; i < MT; i++)
#pragma unroll
                for (int j = 0; j < NT; j++)
                    mma_tf32(acc[i][j], afr[i], bfr[j]);
        }
        __syncthreads();
    }

    // epilogue
#pragma unroll
    for (int i = 0; i < MT; i++) {
        int mA = m0 + wm + i * 16 + (lane >> 2);
        int mB = mA + 8;
        float rsA = rscale ? rscale[oS + mA] : 1.f;
        float rsB = rscale ? rscale[oS + mB] : 1.f;
#pragma unroll
        for (int j = 0; j < NT; j++) {
            int n = n0 + wn + j * 8 + (lane & 3) * 2;
            float b0 = 0.f, b1 = 0.f;
            if (bias) { b0 = bias[n]; b1 = bias[n + 1]; }
            float2 v0, v1;
            v0.x = acc[i][j][0] + b0; v0.y = acc[i][j][1] + b1;
            v1.x = acc[i][j][2] + b0; v1.y = acc[i][j][3] + b1;
            if (relu) {
                v0.x = fmaxf(v0.x, 0.f); v0.y = fmaxf(v0.y, 0.f);
                v1.x = fmaxf(v1.x, 0.f); v1.y = fmaxf(v1.y, 0.f);
            }
            v0.x *= rsA; v0.y *= rsA; v1.x *= rsB; v1.y *= rsB;
            *(float2*)(Cp + (long long)mA * sCm + n) = v0;
            *(float2*)(Cp + (long long)mB * sCm + n) = v1;
        }
    }
}

// ---------------- encoder first layer: relu([x,pos] @ w + b), K=6 ----------------
__global__ void __launch_bounds__(256) enc1_kernel(
    const float* __restrict__ x, const float* __restrict__ pos,
    const float* __restrict__ w, const float* __restrict__ b,
    float* __restrict__ out)
{
    int idx = blockIdx.x * 256 + threadIdx.x;
    int row = idx >> 8, col = idx & 255;
    const float* xr = x + row * 3;
    const float* pr = pos + row * 3;
    float a = b[col];
#pragma unroll
    for (int d = 0; d < 3; d++) a = fmaf(xr[d], w[d * 256 + col], a);
#pragma unroll
    for (int d = 0; d < 3; d++) a = fmaf(pr[d], w[(3 + d) * 256 + col], a);
    out[idx] = fmaxf(a, 0.f);
}

// ---------------- LayerNorm (optional residual), width 512 ----------------
__global__ void __launch_bounds__(512) ln_kernel(
    float* __restrict__ out, const float* __restrict__ resid,
    const float* __restrict__ y,
    const float* __restrict__ g, const float* __restrict__ b)
{
    int row = blockIdx.x, t = threadIdx.x;
    long long base = (long long)row * 512;
    float v = y[base + t];
    if (resid) v += resid[base + t];
    float s = v, s2 = v * v;
#pragma unroll
    for (int o = 16; o; o >>= 1) {
        s  += __shfl_xor_sync(0xffffffffu, s,  o);
        s2 += __shfl_xor_sync(0xffffffffu, s2, o);
    }
    __shared__ float rs[16], rs2[16];
    int w = t >> 5, lane = t & 31;
    if (!lane) { rs[w] = s; rs2[w] = s2; }
    __syncthreads();
    if (t < 32) {
        float a  = (t < 16) ? rs[t]  : 0.f;
        float a2 = (t < 16) ? rs2[t] : 0.f;
#pragma unroll
        for (int o = 8; o; o >>= 1) {
            a  += __shfl_xor_sync(0xffffffffu, a,  o);
            a2 += __shfl_xor_sync(0xffffffffu, a2, o);
        }
        if (!t) { rs[0] = a; rs2[0] = a2; }
    }
    __syncthreads();
    float mean = rs[0] * (1.f / 512.f);
    float var  = rs2[0] * (1.f / 512.f) - mean * mean;
    out[base + t] = (v - mean) * rsqrtf(var + 1e-5f) * g[t] + b[t];
}

// ---------------- FAVOR+ feature map (4 rows per block) ----------------
__global__ void __launch_bounds__(128) favor_kernel(
    const float* __restrict__ qk, const float* __restrict__ omega,
    float* __restrict__ outF)
{
    int r0 = blockIdx.x * 4;
    int hh_ = blockIdx.y, t = threadIdx.x;
    __shared__ float xv[4][64];
    __shared__ float hvs[4];
#pragma unroll
    for (int i = 0; i < 2; i++) {
        int e = t + i * 128;
        int r = e >> 6, d = e & 63;
        xv[r][d] = qk[(long long)(r0 + r) * 512 + hh_ * 64 + d] * 0.3535533905932738f;
    }
    __syncthreads();
    {
        int w = t >> 5, lane = t & 31;
        float a = xv[w][lane], bb = xv[w][lane + 32];
        float s = a * a + bb * bb;
#pragma unroll
        for (int o = 16; o; o >>= 1) s += __shfl_xor_sync(0xffffffffu, s, o);
        if (!lane) hvs[w] = s * 0.5f;
    }
    __syncthreads();
    float u0 = 0.f, u1 = 0.f, u2 = 0.f, u3 = 0.f;
#pragma unroll 8
    for (int d = 0; d < 64; d++) {
        float om = omega[d * 128 + t];
        u0 = fmaf(xv[0][d], om, u0);
        u1 = fmaf(xv[1][d], om, u1);
        u2 = fmaf(xv[2][d], om, u2);
        u3 = fmaf(xv[3][d], om, u3);
    }
    int b = r0 >> 10;
    long long ob = ((long long)(b * NH + hh_) * SEQ + (r0 & 1023)) * NF;
    float uu[4] = {u0, u1, u2, u3};
#pragma unroll
    for (int r = 0; r < 4; r++) {
        float hv = hvs[r];
        long long o = ob + (long long)r * NF;
        outF[o + t]       = expf( uu[r] - hv) * 0.0625f;
        outF[o + 128 + t] = expf(-uu[r] - hv) * 0.0625f;
    }
}

// ---------------- K feature sums over sequence ----------------
__global__ void __launch_bounds__(256) ksum_kernel(
    const float* __restrict__ Kf, float* __restrict__ ks)
{
    int bh = blockIdx.x; int f = threadIdx.x;
    const float* base = Kf + (long long)bh * SEQ * NF + f;
    float s = 0.f;
#pragma unroll 8
    for (int i = 0; i < SEQ; i++) s += base[(long long)i * NF];
    ks[bh * NF + f] = s;
}

// ---------------- z = 1 / (Q . ksum + eps) ----------------
__global__ void __launch_bounds__(256) z_kernel(
    const float* __restrict__ Qf, const float* __restrict__ ks,
    float* __restrict__ z)
{
    int bh = blockIdx.x;
    int s  = blockIdx.y * 8 + (threadIdx.x >> 5);
    int lane = threadIdx.x & 31;
    __shared__ float kss[NF];
    kss[threadIdx.x] = ks[bh * NF + threadIdx.x];
    __syncthreads();
    const float* q = Qf + ((long long)bh * SEQ + s) * NF;
    float acc = 0.f;
#pragma unroll
    for (int i = lane; i < NF; i += 32) acc = fmaf(q[i], kss[i], acc);
#pragma unroll
    for (int o = 16; o; o >>= 1) acc += __shfl_xor_sync(0xffffffffu, acc, o);
    if (!lane) z[bh * SEQ + s] = 1.f / (acc + 1e-6f);
}

// ---------------- mean pool + classifier ----------------
__global__ void __launch_bounds__(512) pool_cls_kernel(
    const float* __restrict__ h, const float* __restrict__ cw,
    const float* __restrict__ cb, float* __restrict__ out)
{
    int b = blockIdx.x, t = threadIdx.x;
    const float* base = h + (long long)b * SEQ * DMODEL + t;
    float s = 0.f;
#pragma unroll 8
    for (int i = 0; i < SEQ; i++) s += base[(long long)i * DMODEL];
    __shared__ float pooled[DMODEL];
    pooled[t] = s * (1.f / (float)SEQ);
    __syncthreads();
    if (t < 16) {
        float acc = cb[t];
        for (int d = 0; d < DMODEL; d++) acc = fmaf(pooled[d], cw[d * 16 + t], acc);
        out[b * 16 + t] = acc;
    }
}

// ---------------- host driver ----------------
extern "C" void kernel_launch(void* const* d_in, const int* in_sizes, int n_in,
                              void* d_out, int out_size)
{
    const float* x      = (const float*)d_in[0];
    const float* pos    = (const float*)d_in[1];
    const float* enc_w1 = (const float*)d_in[2];
    const float* enc_b1 = (const float*)d_in[3];
    const float* enc_w2 = (const float*)d_in[4];
    const float* enc_b2 = (const float*)d_in[5];
    const float* enc_g  = (const float*)d_in[6];
    const float* enc_bb = (const float*)d_in[7];
    const float* wq     = (const float*)d_in[8];
    const float* bq     = (const float*)d_in[9];
    const float* wk     = (const float*)d_in[10];
    const float* bk     = (const float*)d_in[11];
    const float* wv     = (const float*)d_in[12];
    const float* bv     = (const float*)d_in[13];
    const float* wo     = (const float*)d_in[14];
    const float* bo     = (const float*)d_in[15];
    const float* ln1_g  = (const float*)d_in[16];
    const float* ln1_b  = (const float*)d_in[17];
    const float* w1     = (const float*)d_in[18];
    const float* b1     = (const float*)d_in[19];
    const float* w2     = (const float*)d_in[20];
    const float* b2     = (const float*)d_in[21];
    const float* ln2_g  = (const float*)d_in[22];
    const float* ln2_b  = (const float*)d_in[23];
    const float* omega  = (const float*)d_in[24];
    const float* cls_w  = (const float*)d_in[25];
    const float* cls_b  = (const float*)d_in[26];

    float *p_h, *p_t0, *p_qk, *p_v, *p_ffn, *p_Qf, *p_Kf, *p_kv, *p_ks, *p_z;
    cudaGetSymbolAddress((void**)&p_h,  g_h);
    cudaGetSymbolAddress((void**)&p_t0, g_t0);
    cudaGetSymbolAddress((void**)&p_qk, g_qk);
    cudaGetSymbolAddress((void**)&p_v,  g_v);
    cudaGetSymbolAddress((void**)&p_ffn,g_ffn);
    cudaGetSymbolAddress((void**)&p_Qf, g_Qf);
    cudaGetSymbolAddress((void**)&p_Kf, g_Kf);
    cudaGetSymbolAddress((void**)&p_kv, g_kv);
    cudaGetSymbolAddress((void**)&p_ks, g_ks);
    cudaGetSymbolAddress((void**)&p_z,  g_z);

    auto dense = [&](const float* A, const float* W, const float* bias,
                     float* C, int M, int Nn, int K, int relu) {
        dim3 grid(Nn / 128, M / 128, 1);
        mma_gemm<128,128,2,4,0><<<grid, 256>>>(A, W, bias, nullptr, C, M, Nn, K,
                                    (long long)K, 1LL, (long long)Nn, (long long)Nn,
                                    0, 0, 0, 0, 0, 0, 0, 0, 1, relu);
    };

    // ---- encoder ----
    enc1_kernel<<<NTOK, 256>>>(x, pos, enc_w1, enc_b1, p_t0);
    dense(p_t0, enc_w2, enc_b2, p_v, NTOK, DMODEL, 256, 0);
    ln_kernel<<<NTOK, 512>>>(p_h, nullptr, p_v, enc_g, enc_bb);

    for (int l = 0; l < NLAYERS; l++) {
        const float* Wq = wq + (long long)l * DMODEL * DMODEL;
        const float* Wk = wk + (long long)l * DMODEL * DMODEL;
        const float* Wv = wv + (long long)l * DMODEL * DMODEL;
        const float* Wo = wo + (long long)l * DMODEL * DMODEL;
        const float* Bq = bq + l * DMODEL;
        const float* Bk = bk + l * DMODEL;
        const float* Bv = bv + l * DMODEL;
        const float* Bo = bo + l * DMODEL;
        const float* W1 = w1 + (long long)l * DMODEL * FFNH;
        const float* B1 = b1 + l * FFNH;
        const float* W2 = w2 + (long long)l * FFNH * DMODEL;
        const float* B2 = b2 + l * DMODEL;
        const float* Om = omega + (long long)l * HD * NFH;

        // Q -> FAVOR(Q)
        dense(p_h, Wq, Bq, p_qk, NTOK, DMODEL, DMODEL, 0);
        favor_kernel<<<dim3(NTOK / 4, NH), 128>>>(p_qk, Om, p_Qf);
        // K -> FAVOR(K)
        dense(p_h, Wk, Bk, p_qk, NTOK, DMODEL, DMODEL, 0);
        favor_kernel<<<dim3(NTOK / 4, NH), 128>>>(p_qk, Om, p_Kf);
        // V
        dense(p_h, Wv, Bv, p_v, NTOK, DMODEL, DMODEL, 0);

        // kv[b,h,f,d] = sum_s Kf[b,h,s,f] * v[b,s,h,d]   (batched, A-transposed)
        {
            dim3 grid(1, NF / 128, BATCH * NH);
            mma_gemm<128,64,4,2,1><<<grid, 256>>>(p_Kf, p_v, nullptr, nullptr, p_kv,
                NF, HD, SEQ,
                1LL, (long long)NF,
                (long long)DMODEL,
                (long long)HD,
                (long long)NH * SEQ * NF, (long long)SEQ * NF,
                (long long)SEQ * DMODEL, (long long)HD,
                (long long)NH * NF * HD, (long long)NF * HD,
                0, 0, NH, 0);
        }
        ksum_kernel<<<BATCH * NH, 256>>>(p_Kf, p_ks);
        z_kernel<<<dim3(BATCH * NH, SEQ / 8), 256>>>(p_Qf, p_ks, p_z);

        // attn[b,s,h,d] = z * Qf[b,h,s,:] @ kv[b,h,:,:]   (batched, rowscale z)
        {
            dim3 grid(1, SEQ / 128, BATCH * NH);
            mma_gemm<128,64,4,2,0><<<grid, 256>>>(p_Qf, p_kv, nullptr, p_z, p_qk,
                SEQ, HD, NF,
                (long long)NF, 1LL,
                (long long)HD,
                (long long)DMODEL,
                (long long)NH * SEQ * NF, (long long)SEQ * NF,
                (long long)NH * NF * HD, (long long)NF * HD,
                (long long)SEQ * DMODEL, (long long)HD,
                (long long)NH * SEQ, (long long)SEQ,
                NH, 0);
        }

        // output projection + residual LN
        dense(p_qk, Wo, Bo, p_v, NTOK, DMODEL, DMODEL, 0);
        ln_kernel<<<NTOK, 512>>>(p_h, p_h, p_v, ln1_g + l * DMODEL, ln1_b + l * DMODEL);

        // FFN + residual LN
        dense(p_h, W1, B1, p_ffn, NTOK, FFNH, DMODEL, 1);
        dense(p_ffn, W2, B2, p_v, NTOK, DMODEL, FFNH, 0);
        ln_kernel<<<NTOK, 512>>>(p_h, p_h, p_v, ln2_g + l * DMODEL, ln2_b + l * DMODEL);
    }

    pool_cls_kernel<<<BATCH, 512>>>(p_h, cls_w, cls_b, (float*)d_out);
}

// round 5
// speedup vs baseline: 3.7009x; 1.6521x over previous
#include <cuda_runtime.h>
#include <math.h>

#define BATCH 16
#define SEQ 1024
#define NTOK (BATCH*SEQ)
#define DMODEL 512
#define NH 8
#define HD 64
#define NF 256
#define NFH 128
#define NLAYERS 4
#define FFNH 1024
#define QKVW 1536

// ---------------- scratch (device globals; no allocation allowed) ----------------
__device__ float g_h   [NTOK*DMODEL];
__device__ float g_t0  [NTOK*256];
__device__ float g_qk  [NTOK*DMODEL];      // attn output
__device__ float g_v   [NTOK*DMODEL];      // generic 512-wide temp
__device__ float g_ffn [NTOK*FFNH];
__device__ float g_qkv [NTOK*QKVW];        // merged q|k|v
__device__ float g_Qf  [BATCH*NH*SEQ*NF];
__device__ float g_Kf  [BATCH*NH*SEQ*NF];
__device__ float g_kv  [BATCH*NH*NF*HD];
__device__ float g_ks  [BATCH*NH*NF];
__device__ float g_kp  [BATCH*NH*8*NF];    // ksum partials
__device__ float g_z   [BATCH*NH*SEQ];
// pre-rounded weights
__device__ float g_wqkv[NLAYERS*DMODEL*QKVW];
__device__ float g_bqkv[NLAYERS*QKVW];
__device__ float g_w1r [NLAYERS*DMODEL*FFNH];
__device__ float g_w2r [NLAYERS*FFNH*DMODEL];
__device__ float g_ew2r[256*DMODEL];

__device__ __forceinline__ float f2tf32(float x) {
    unsigned u;
    asm("cvt.rna.tf32.f32 %0, %1;" : "=r"(u) : "f"(x));
    return __uint_as_float(u);
}

__device__ __forceinline__ void mma_tf32(float* d, const float* a, const float* b) {
    asm volatile(
        "mma.sync.aligned.m16n8k8.row.col.f32.tf32.tf32.f32 "
        "{%0,%1,%2,%3},{%4,%5,%6,%7},{%8,%9},{%0,%1,%2,%3};\n"
        : "+f"(d[0]), "+f"(d[1]), "+f"(d[2]), "+f"(d[3])
        : "r"(__float_as_uint(a[0])), "r"(__float_as_uint(a[1])),
          "r"(__float_as_uint(a[2])), "r"(__float_as_uint(a[3])),
          "r"(__float_as_uint(b[0])), "r"(__float_as_uint(b[1])));
}

__device__ __forceinline__ void cpa16(void* dst, const void* src) {
    unsigned s = (unsigned)__cvta_generic_to_shared(dst);
    asm volatile("cp.async.ca.shared.global [%0], [%1], 16;\n" :: "r"(s), "l"(src));
}
#define CP_COMMIT  asm volatile("cp.async.commit_group;\n")

// ---------------- tf32 tensor-core batched-strided GEMM, cp.async 2-stage ----------------
// Inputs are assumed ALREADY tf32-rounded (producers round). Epilogue rounds outputs.
template<int BM, int BN, int WY, int WX, int AT>
__global__ void __launch_bounds__(256, 2) mma_gemm(
    const float* __restrict__ A, const float* __restrict__ B,
    const float* __restrict__ bias, const float* __restrict__ rscale,
    float* __restrict__ C,
    int M, int Nn, int K,
    long long sAm, long long sAk, long long sBk, long long sCm,
    long long oA1, long long oA2, long long oB1, long long oB2,
    long long oC1, long long oC2, long long oS1, long long oS2,
    int Hdiv, int relu)
{
    constexpr int BK  = 16;
    constexpr int MT  = BM / WY / 16;
    constexpr int NT  = BN / WX / 8;
    constexpr int APITCH = (AT == 0) ? 20 : (BM + 8);
    constexpr int BPITCH = BN + 8;
    constexpr int ASZ = (AT == 0) ? BM * 20 : BK * (BM + 8);
    constexpr int BSZ = BK * BPITCH;
    constexpr int AQ  = BM * BK / 4 / 256;
    constexpr int BQ  = BK * BN / 4 / 256;

    int z  = blockIdx.z;
    int z1 = z / Hdiv, z2 = z - z1 * Hdiv;
    const float* Ap = A + z1 * oA1 + z2 * oA2;
    const float* Bp = B + z1 * oB1 + z2 * oB2;
    float*       Cp = C + z1 * oC1 + z2 * oC2;
    long long    oS = z1 * oS1 + z2 * oS2;

    int m0 = blockIdx.y * BM;
    int n0 = blockIdx.x * BN;
    int tid = threadIdx.x;
    int warp = tid >> 5, lane = tid & 31;
    int wy = warp % WY, wx = warp / WY;
    int wm = wy * (BM / WY), wn = wx * (BN / WX);

    __shared__ float As[2][ASZ];
    __shared__ float Bs[2][BSZ];

    float acc[MT][NT][4];
#pragma unroll
    for (int i = 0; i < MT; i++)
#pragma unroll
        for (int j = 0; j < NT; j++)
#pragma unroll
            for (int c = 0; c < 4; c++) acc[i][j][c] = 0.f;

    auto loadA = [&](int st, int kt) {
#pragma unroll
        for (int i = 0; i < AQ; i++) {
            int e = tid + i * 256;
            if (AT == 0) {
                int row = e >> 2, q = (e & 3) * 4;
                cpa16(&As[st][row * 20 + q],
                      Ap + (long long)(m0 + row) * sAm + (kt + q));
            } else {
                constexpr int QPR = BM / 4;
                int kk = e / QPR, q = (e % QPR) * 4;
                cpa16(&As[st][kk * APITCH + q],
                      Ap + (long long)(kt + kk) * sAk + (m0 + q));
            }
        }
    };
    auto loadB = [&](int st, int kt) {
#pragma unroll
        for (int i = 0; i < BQ; i++) {
            int e = tid + i * 256;
            constexpr int QPR = BN / 4;
            int kk = e / QPR, q = (e % QPR) * 4;
            cpa16(&Bs[st][kk * BPITCH + q],
                  Bp + (long long)(kt + kk) * sBk + (n0 + q));
        }
    };

    loadA(0, 0); loadB(0, 0); CP_COMMIT;

    int T = K / BK;
    for (int t = 0; t < T; t++) {
        int st = t & 1;
        if (t + 1 < T) {
            loadA(st ^ 1, (t + 1) * BK);
            loadB(st ^ 1, (t + 1) * BK);
            CP_COMMIT;
            asm volatile("cp.async.wait_group 1;\n");
        } else {
            asm volatile("cp.async.wait_group 0;\n");
        }
        __syncthreads();

#pragma unroll
        for (int k0 = 0; k0 < BK; k0 += 8) {
            float afr[MT][4], bfr[NT][2];
            int kc = k0 + (lane & 3);
#pragma unroll
            for (int i = 0; i < MT; i++) {
                int row = wm + i * 16 + (lane >> 2);
                if (AT == 0) {
                    afr[i][0] = As[st][row * 20 + kc];
                    afr[i][1] = As[st][(row + 8) * 20 + kc];
                    afr[i][2] = As[st][row * 20 + kc + 4];
                    afr[i][3] = As[st][(row + 8) * 20 + kc + 4];
                } else {
                    afr[i][0] = As[st][kc * APITCH + row];
                    afr[i][1] = As[st][kc * APITCH + row + 8];
                    afr[i][2] = As[st][(kc + 4) * APITCH + row];
                    afr[i][3] = As[st][(kc + 4) * APITCH + row + 8];
                }
            }
#pragma unroll
            for (int j = 0; j < NT; j++) {
                int col = wn + j * 8 + (lane >> 2);
                bfr[j][0] = Bs[st][kc * BPITCH + col];
                bfr[j][1] = Bs[st][(kc + 4) * BPITCH + col];
            }
#pragma unroll
            for (int i = 0; i < MT; i++)
#pragma unroll
                for (int j = 0; j < NT; j++)
                    mma_tf32(acc[i][j], afr[i], bfr[j]);
        }
        __syncthreads();
    }

    // epilogue (round outputs to tf32 so consumers' MMA truncation is exact)
#pragma unroll
    for (int i = 0; i < MT; i++) {
        int mA = m0 + wm + i * 16 + (lane >> 2);
        int mB = mA + 8;
        float rsA = rscale ? rscale[oS + mA] : 1.f;
        float rsB = rscale ? rscale[oS + mB] : 1.f;
#pragma unroll
        for (int j = 0; j < NT; j++) {
            int n = n0 + wn + j * 8 + (lane & 3) * 2;
            float b0 = 0.f, b1 = 0.f;
            if (bias) { b0 = bias[n]; b1 = bias[n + 1]; }
            float2 v0, v1;
            v0.x = acc[i][j][0] + b0; v0.y = acc[i][j][1] + b1;
            v1.x = acc[i][j][2] + b0; v1.y = acc[i][j][3] + b1;
            if (relu) {
                v0.x = fmaxf(v0.x, 0.f); v0.y = fmaxf(v0.y, 0.f);
                v1.x = fmaxf(v1.x, 0.f); v1.y = fmaxf(v1.y, 0.f);
            }
            v0.x = f2tf32(v0.x * rsA); v0.y = f2tf32(v0.y * rsA);
            v1.x = f2tf32(v1.x * rsB); v1.y = f2tf32(v1.y * rsB);
            *(float2*)(Cp + (long long)mA * sCm + n) = v0;
            *(float2*)(Cp + (long long)mB * sCm + n) = v1;
        }
    }
}

// ---------------- weight prep: concat + tf32-round ----------------
__global__ void __launch_bounds__(256) prep_qkv_kernel(
    const float* __restrict__ wq, const float* __restrict__ wk, const float* __restrict__ wv,
    const float* __restrict__ bq, const float* __restrict__ bk, const float* __restrict__ bv,
    float* __restrict__ wqkv, float* __restrict__ bqkv)
{
    long long idx = (long long)blockIdx.x * 256 + threadIdx.x;
    if (idx < (long long)NLAYERS * DMODEL * QKVW) {
        int l = (int)(idx / (DMODEL * QKVW));
        int rem = (int)(idx % (DMODEL * QKVW));
        int r = rem / QKVW, c = rem % QKVW;
        const float* src = c < 512 ? wq : (c < 1024 ? wk : wv);
        wqkv[idx] = f2tf32(src[(long long)l * DMODEL * DMODEL + r * DMODEL + (c & 511)]);
    }
    if (idx < NLAYERS * QKVW) {
        int l = (int)(idx / QKVW), c = (int)(idx % QKVW);
        const float* src = c < 512 ? bq : (c < 1024 ? bk : bv);
        bqkv[idx] = src[l * DMODEL + (c & 511)];
    }
}

__global__ void __launch_bounds__(256) round_copy_kernel(
    const float* __restrict__ src, float* __restrict__ dst, long long n)
{
    long long idx = (long long)blockIdx.x * 256 + threadIdx.x;
    if (idx < n) dst[idx] = f2tf32(src[idx]);
}

// ---------------- encoder first layer ----------------
__global__ void __launch_bounds__(256) enc1_kernel(
    const float* __restrict__ x, const float* __restrict__ pos,
    const float* __restrict__ w, const float* __restrict__ b,
    float* __restrict__ out)
{
    int idx = blockIdx.x * 256 + threadIdx.x;
    int row = idx >> 8, col = idx & 255;
    const float* xr = x + row * 3;
    const float* pr = pos + row * 3;
    float a = b[col];
#pragma unroll
    for (int d = 0; d < 3; d++) a = fmaf(xr[d], w[d * 256 + col], a);
#pragma unroll
    for (int d = 0; d < 3; d++) a = fmaf(pr[d], w[(3 + d) * 256 + col], a);
    out[idx] = f2tf32(fmaxf(a, 0.f));
}

// ---------------- LayerNorm (optional residual), width 512; tf32-rounded out ----------------
__global__ void __launch_bounds__(512) ln_kernel(
    float* __restrict__ out, const float* __restrict__ resid,
    const float* __restrict__ y,
    const float* __restrict__ g, const float* __restrict__ b)
{
    int row = blockIdx.x, t = threadIdx.x;
    long long base = (long long)row * 512;
    float v = y[base + t];
    if (resid) v += resid[base + t];
    float s = v, s2 = v * v;
#pragma unroll
    for (int o = 16; o; o >>= 1) {
        s  += __shfl_xor_sync(0xffffffffu, s,  o);
        s2 += __shfl_xor_sync(0xffffffffu, s2, o);
    }
    __shared__ float rs[16], rs2[16];
    int w = t >> 5, lane = t & 31;
    if (!lane) { rs[w] = s; rs2[w] = s2; }
    __syncthreads();
    if (t < 32) {
        float a  = (t < 16) ? rs[t]  : 0.f;
        float a2 = (t < 16) ? rs2[t] : 0.f;
#pragma unroll
        for (int o = 8; o; o >>= 1) {
            a  += __shfl_xor_sync(0xffffffffu, a,  o);
            a2 += __shfl_xor_sync(0xffffffffu, a2, o);
        }
        if (!t) { rs[0] = a; rs2[0] = a2; }
    }
    __syncthreads();
    float mean = rs[0] * (1.f / 512.f);
    float var  = rs2[0] * (1.f / 512.f) - mean * mean;
    out[base + t] = f2tf32((v - mean) * rsqrtf(var + 1e-5f) * g[t] + b[t]);
}

// ---------------- FAVOR+ feature map (4 rows/block), reads merged qkv ----------------
// colOff selects q (0) or k (512) slice. If zOut != null, also computes
// z[bh][row] = 1/(Qf_row . ks[bh] + eps) via block reduction.
__global__ void __launch_bounds__(128) favor_kernel(
    const float* __restrict__ qkv, const float* __restrict__ omega,
    float* __restrict__ outF, float* __restrict__ zOut,
    const float* __restrict__ ks, int colOff)
{
    int r0 = blockIdx.x * 4;
    int hh_ = blockIdx.y, t = threadIdx.x;
    __shared__ float xv[4][64];
    __shared__ float hvs[4];
#pragma unroll
    for (int i = 0; i < 2; i++) {
        int e = t + i * 128;
        int r = e >> 6, d = e & 63;
        xv[r][d] = qkv[(long long)(r0 + r) * QKVW + colOff + hh_ * 64 + d] * 0.3535533905932738f;
    }
    __syncthreads();
    {
        int w = t >> 5, lane = t & 31;
        float a = xv[w][lane], bb = xv[w][lane + 32];
        float s = a * a + bb * bb;
#pragma unroll
        for (int o = 16; o; o >>= 1) s += __shfl_xor_sync(0xffffffffu, s, o);
        if (!lane) hvs[w] = s * 0.5f;
    }
    __syncthreads();
    float u0 = 0.f, u1 = 0.f, u2 = 0.f, u3 = 0.f;
#pragma unroll 8
    for (int d = 0; d < 64; d++) {
        float om = omega[d * 128 + t];
        u0 = fmaf(xv[0][d], om, u0);
        u1 = fmaf(xv[1][d], om, u1);
        u2 = fmaf(xv[2][d], om, u2);
        u3 = fmaf(xv[3][d], om, u3);
    }
    int b = r0 >> 10;
    int bh = b * NH + hh_;
    long long ob = ((long long)bh * SEQ + (r0 & 1023)) * NF;
    float uu[4] = {u0, u1, u2, u3};
    float fa[4], fb[4];
#pragma unroll
    for (int r = 0; r < 4; r++) {
        float hv = hvs[r];
        fa[r] = f2tf32(expf( uu[r] - hv) * 0.0625f);
        fb[r] = f2tf32(expf(-uu[r] - hv) * 0.0625f);
        long long o = ob + (long long)r * NF;
        outF[o + t]       = fa[r];
        outF[o + 128 + t] = fb[r];
    }
    if (zOut) {
        float ka = ks[bh * NF + t];
        float kb = ks[bh * NF + 128 + t];
        float p[4];
#pragma unroll
        for (int r = 0; r < 4; r++) p[r] = fa[r] * ka + fb[r] * kb;
#pragma unroll
        for (int o = 16; o; o >>= 1)
#pragma unroll
            for (int r = 0; r < 4; r++) p[r] += __shfl_xor_sync(0xffffffffu, p[r], o);
        __shared__ float pr[4][4];
        int w = t >> 5, lane = t & 31;
        if (!lane) {
#pragma unroll
            for (int r = 0; r < 4; r++) pr[w][r] = p[r];
        }
        __syncthreads();
        if (t < 4) {
            float s = pr[0][t] + pr[1][t] + pr[2][t] + pr[3][t];
            zOut[bh * SEQ + (r0 & 1023) + t] = 1.f / (s + 1e-6f);
        }
    }
}

// ---------------- K feature sums: 2-stage deterministic ----------------
__global__ void __launch_bounds__(256) ksum1_kernel(
    const float* __restrict__ Kf, float* __restrict__ part)
{
    int bh = blockIdx.x, ch = blockIdx.y, f = threadIdx.x;
    const float* base = Kf + ((long long)bh * SEQ + ch * 128) * NF + f;
    float s = 0.f;
#pragma unroll 8
    for (int i = 0; i < 128; i++) s += base[(long long)i * NF];
    part[(bh * 8 + ch) * NF + f] = s;
}
__global__ void __launch_bounds__(256) ksum2_kernel(
    const float* __restrict__ part, float* __restrict__ ks)
{
    int bh = blockIdx.x, f = threadIdx.x;
    float s = 0.f;
#pragma unroll
    for (int c = 0; c < 8; c++) s += part[(bh * 8 + c) * NF + f];
    ks[bh * NF + f] = s;
}

// ---------------- mean pool + classifier ----------------
__global__ void __launch_bounds__(512) pool_cls_kernel(
    const float* __restrict__ h, const float* __restrict__ cw,
    const float* __restrict__ cb, float* __restrict__ out)
{
    int b = blockIdx.x, t = threadIdx.x;
    const float* base = h + (long long)b * SEQ * DMODEL + t;
    float s = 0.f;
#pragma unroll 8
    for (int i = 0; i < SEQ; i++) s += base[(long long)i * DMODEL];
    __shared__ float pooled[DMODEL];
    pooled[t] = s * (1.f / (float)SEQ);
    __syncthreads();
    if (t < 16) {
        float acc = cb[t];
        for (int d = 0; d < DMODEL; d++) acc = fmaf(pooled[d], cw[d * 16 + t], acc);
        out[b * 16 + t] = acc;
    }
}

// ---------------- host driver ----------------
extern "C" void kernel_launch(void* const* d_in, const int* in_sizes, int n_in,
                              void* d_out, int out_size)
{
    const float* x      = (const float*)d_in[0];
    const float* pos    = (const float*)d_in[1];
    const float* enc_w1 = (const float*)d_in[2];
    const float* enc_b1 = (const float*)d_in[3];
    const float* enc_w2 = (const float*)d_in[4];
    const float* enc_b2 = (const float*)d_in[5];
    const float* enc_g  = (const float*)d_in[6];
    const float* enc_bb = (const float*)d_in[7];
    const float* wq     = (const float*)d_in[8];
    const float* bq     = (const float*)d_in[9];
    const float* wk     = (const float*)d_in[10];
    const float* bk     = (const float*)d_in[11];
    const float* wv     = (const float*)d_in[12];
    const float* bv     = (const float*)d_in[13];
    const float* wo     = (const float*)d_in[14];
    const float* bo     = (const float*)d_in[15];
    const float* ln1_g  = (const float*)d_in[16];
    const float* ln1_b  = (const float*)d_in[17];
    const float* w1     = (const float*)d_in[18];
    const float* b1     = (const float*)d_in[19];
    const float* w2     = (const float*)d_in[20];
    const float* b2     = (const float*)d_in[21];
    const float* ln2_g  = (const float*)d_in[22];
    const float* ln2_b  = (const float*)d_in[23];
    const float* omega  = (const float*)d_in[24];
    const float* cls_w  = (const float*)d_in[25];
    const float* cls_b  = (const float*)d_in[26];

    float *p_h, *p_t0, *p_qk, *p_v, *p_ffn, *p_qkv, *p_Qf, *p_Kf, *p_kv, *p_ks, *p_kp, *p_z;
    float *p_wqkv, *p_bqkv, *p_w1r, *p_w2r, *p_ew2r;
    cudaGetSymbolAddress((void**)&p_h,   g_h);
    cudaGetSymbolAddress((void**)&p_t0,  g_t0);
    cudaGetSymbolAddress((void**)&p_qk,  g_qk);
    cudaGetSymbolAddress((void**)&p_v,   g_v);
    cudaGetSymbolAddress((void**)&p_ffn, g_ffn);
    cudaGetSymbolAddress((void**)&p_qkv, g_qkv);
    cudaGetSymbolAddress((void**)&p_Qf,  g_Qf);
    cudaGetSymbolAddress((void**)&p_Kf,  g_Kf);
    cudaGetSymbolAddress((void**)&p_kv,  g_kv);
    cudaGetSymbolAddress((void**)&p_ks,  g_ks);
    cudaGetSymbolAddress((void**)&p_kp,  g_kp);
    cudaGetSymbolAddress((void**)&p_z,   g_z);
    cudaGetSymbolAddress((void**)&p_wqkv,g_wqkv);
    cudaGetSymbolAddress((void**)&p_bqkv,g_bqkv);
    cudaGetSymbolAddress((void**)&p_w1r, g_w1r);
    cudaGetSymbolAddress((void**)&p_w2r, g_w2r);
    cudaGetSymbolAddress((void**)&p_ew2r,g_ew2r);

    // ---- weight prep (inside graph; cheap) ----
    {
        long long nqkv = (long long)NLAYERS * DMODEL * QKVW;
        prep_qkv_kernel<<<(unsigned)((nqkv + 255) / 256), 256>>>(
            wq, wk, wv, bq, bk, bv, p_wqkv, p_bqkv);
        long long n1 = (long long)NLAYERS * DMODEL * FFNH;
        round_copy_kernel<<<(unsigned)((n1 + 255) / 256), 256>>>(w1, p_w1r, n1);
        round_copy_kernel<<<(unsigned)((n1 + 255) / 256), 256>>>(w2, p_w2r, n1);
        long long ne = 256LL * DMODEL;
        round_copy_kernel<<<(unsigned)((ne + 255) / 256), 256>>>(enc_w2, p_ew2r, ne);
    }

    // dense GEMM: C[M x Nn] = A[M x K] @ W + bias (opt relu), row-major
    auto dense = [&](const float* A, const float* W, const float* bias,
                     float* C, int M, int Nn, int K, int relu) {
        dim3 grid(Nn / 128, M / 128, 1);
        mma_gemm<128,128,2,4,0><<<grid, 256>>>(A, W, bias, nullptr, C, M, Nn, K,
                                    (long long)K, 1LL, (long long)Nn, (long long)Nn,
                                    0, 0, 0, 0, 0, 0, 0, 0, 1, relu);
    };

    // ---- encoder ----
    enc1_kernel<<<NTOK, 256>>>(x, pos, enc_w1, enc_b1, p_t0);
    dense(p_t0, p_ew2r, enc_b2, p_v, NTOK, DMODEL, 256, 0);
    ln_kernel<<<NTOK, 512>>>(p_h, nullptr, p_v, enc_g, enc_bb);

    for (int l = 0; l < NLAYERS; l++) {
        const float* Wqkv = p_wqkv + (long long)l * DMODEL * QKVW;
        const float* Bqkv = p_bqkv + l * QKVW;
        const float* Wo = wo + (long long)l * DMODEL * DMODEL;
        const float* Bo = bo + l * DMODEL;
        const float* W1 = p_w1r + (long long)l * DMODEL * FFNH;
        const float* B1 = b1 + l * FFNH;
        const float* W2 = p_w2r + (long long)l * FFNH * DMODEL;
        const float* B2 = b2 + l * DMODEL;
        const float* Om = omega + (long long)l * HD * NFH;

        // merged QKV projection -> g_qkv [NTOK x 1536]
        dense(p_h, Wqkv, Bqkv, p_qkv, NTOK, QKVW, DMODEL, 0);

        // FAVOR(K) first, then ksum, then FAVOR(Q) with fused z
        favor_kernel<<<dim3(NTOK / 4, NH), 128>>>(p_qkv, Om, p_Kf, nullptr, nullptr, 512);
        ksum1_kernel<<<dim3(BATCH * NH, 8), 256>>>(p_Kf, p_kp);
        ksum2_kernel<<<BATCH * NH, 256>>>(p_kp, p_ks);
        favor_kernel<<<dim3(NTOK / 4, NH), 128>>>(p_qkv, Om, p_Qf, p_z, p_ks, 0);

        // kv[b,h,f,d] = sum_s Kf[b,h,s,f] * v[b,s,h,d]  (v = qkv slice at 1024)
        {
            dim3 grid(1, NF / 128, BATCH * NH);
            mma_gemm<128,64,4,2,1><<<grid, 256>>>(p_Kf, p_qkv + 1024, nullptr, nullptr, p_kv,
                NF, HD, SEQ,
                1LL, (long long)NF,
                (long long)QKVW,
                (long long)HD,
                (long long)NH * SEQ * NF, (long long)SEQ * NF,
                (long long)SEQ * QKVW, (long long)HD,
                (long long)NH * NF * HD, (long long)NF * HD,
                0, 0, NH, 0);
        }

        // attn[b,s,h,d] = z * Qf[b,h,s,:] @ kv[b,h,:,:]
        {
            dim3 grid(1, SEQ / 128, BATCH * NH);
            mma_gemm<128,64,4,2,0><<<grid, 256>>>(p_Qf, p_kv, nullptr, p_z, p_qk,
                SEQ, HD, NF,
                (long long)NF, 1LL,
                (long long)HD,
                (long long)DMODEL,
                (long long)NH * SEQ * NF, (long long)SEQ * NF,
                (long long)NH * NF * HD, (long long)NF * HD,
                (long long)SEQ * DMODEL, (long long)HD,
                (long long)NH * SEQ, (long long)SEQ,
                NH, 0);
        }

        // output projection + residual LN (Wo rounded at fragment? no - Wo raw fp32!)
        // Wo is consumed directly as B operand; pre-round it via per-layer view of g_v?
        // -> Wo is small; round it on the fly into g_kp? Instead we round Wo into a
        //    dedicated slice reusing g_ew2r is too small. Use extra scratch:
        dense(p_qk, Wo, Bo, p_v, NTOK, DMODEL, DMODEL, 0);
        ln_kernel<<<NTOK, 512>>>(p_h, p_h, p_v, ln1_g + l * DMODEL, ln1_b + l * DMODEL);

        // FFN + residual LN
        dense(p_h, W1, B1, p_ffn, NTOK, FFNH, DMODEL, 1);
        dense(p_ffn, W2, B2, p_v, NTOK, DMODEL, FFNH, 0);
        ln_kernel<<<NTOK, 512>>>(p_h, p_h, p_v, ln2_g + l * DMODEL, ln2_b + l * DMODEL);
    }

    pool_cls_kernel<<<BATCH, 512>>>(p_h, cls_w, cls_b, (float*)d_out);
}

// NOTE on Wo: it is passed unrounded (raw fp32) as the B operand of its GEMM.
// The MMA will truncate it (RZ instead of RNA) for that single GEMM. This is one
// biased rounding among 9 chained GEMMs; expected added error well under budget.
// If rel_err regresses, round Wo into scratch like the other weights.

// round 6
// speedup vs baseline: 3.7603x; 1.0161x over previous
#include <cuda_runtime.h>
#include <math.h>

#define BATCH 16
#define SEQ 1024
#define NTOK (BATCH*SEQ)
#define DMODEL 512
#define NH 8
#define HD 64
#define NF 256
#define NFH 128
#define NLAYERS 4
#define FFNH 1024
#define QKVW 1536

// ---------------- scratch (device globals; no allocation allowed) ----------------
__device__ float g_h   [NTOK*DMODEL];
__device__ float g_t0  [NTOK*256];
__device__ float g_qk  [NTOK*DMODEL];
__device__ float g_v   [NTOK*DMODEL];
__device__ float g_ffn [NTOK*FFNH];
__device__ float g_qkv [NTOK*QKVW];
__device__ float g_Qf  [BATCH*NH*SEQ*NF];
__device__ float g_Kf  [BATCH*NH*SEQ*NF];
__device__ float g_kv  [BATCH*NH*NF*HD];
__device__ float g_ks  [BATCH*NH*NF];
__device__ float g_kp  [BATCH*NH*256*NF];   // ksum partials (per favor block)
__device__ float g_z   [BATCH*NH*SEQ];
// pre-rounded weights
__device__ float g_wqkv[NLAYERS*DMODEL*QKVW];
__device__ float g_bqkv[NLAYERS*QKVW];
__device__ float g_w1r [NLAYERS*DMODEL*FFNH];
__device__ float g_w2r [NLAYERS*FFNH*DMODEL];
__device__ float g_ew2r[256*DMODEL];

__device__ __forceinline__ float f2tf32(float x) {
    unsigned u;
    asm("cvt.rna.tf32.f32 %0, %1;" : "=r"(u) : "f"(x));
    return __uint_as_float(u);
}

__device__ __forceinline__ void mma_tf32(float* d, const float* a, const float* b) {
    asm volatile(
        "mma.sync.aligned.m16n8k8.row.col.f32.tf32.tf32.f32 "
        "{%0,%1,%2,%3},{%4,%5,%6,%7},{%8,%9},{%0,%1,%2,%3};\n"
        : "+f"(d[0]), "+f"(d[1]), "+f"(d[2]), "+f"(d[3])
        : "r"(__float_as_uint(a[0])), "r"(__float_as_uint(a[1])),
          "r"(__float_as_uint(a[2])), "r"(__float_as_uint(a[3])),
          "r"(__float_as_uint(b[0])), "r"(__float_as_uint(b[1])));
}

__device__ __forceinline__ void cpa16(void* dst, const void* src) {
    unsigned s = (unsigned)__cvta_generic_to_shared(dst);
    asm volatile("cp.async.ca.shared.global [%0], [%1], 16;\n" :: "r"(s), "l"(src));
}
#define CP_COMMIT  asm volatile("cp.async.commit_group;\n")

// ---------------- tf32 tensor-core batched-strided GEMM, 3-stage cp.async ----------------
// Inputs assumed ALREADY tf32-rounded. Epilogue rounds outputs.
// One __syncthreads per k-tile: wait -> barrier -> prefetch freed buffer -> compute.
template<int BM, int BN, int WY, int WX, int AT, int NS>
__global__ void __launch_bounds__(256, 2) mma_gemm(
    const float* __restrict__ A, const float* __restrict__ B,
    const float* __restrict__ bias, const float* __restrict__ rscale,
    float* __restrict__ C,
    int M, int Nn, int K,
    long long sAm, long long sAk, long long sBk, long long sCm,
    long long oA1, long long oA2, long long oB1, long long oB2,
    long long oC1, long long oC2, long long oS1, long long oS2,
    int Hdiv, int relu)
{
    constexpr int BK  = 16;
    constexpr int MT  = BM / WY / 16;
    constexpr int NT  = BN / WX / 8;
    constexpr int APITCH = (AT == 0) ? 20 : (BM + 8);
    constexpr int BPITCH = BN + 8;
    constexpr int ASZ = (AT == 0) ? BM * 20 : BK * (BM + 8);
    constexpr int BSZ = BK * BPITCH;
    constexpr int AQ  = BM * BK / 4 / 256;
    constexpr int BQ  = BK * BN / 4 / 256;

    extern __shared__ float dsm[];
    float* AsB = dsm;
    float* BsB = dsm + NS * ASZ;

    int z  = blockIdx.z;
    int z1 = z / Hdiv, z2 = z - z1 * Hdiv;
    const float* Ap = A + z1 * oA1 + z2 * oA2;
    const float* Bp = B + z1 * oB1 + z2 * oB2;
    float*       Cp = C + z1 * oC1 + z2 * oC2;
    long long    oS = z1 * oS1 + z2 * oS2;

    int m0 = blockIdx.y * BM;
    int n0 = blockIdx.x * BN;
    int tid = threadIdx.x;
    int warp = tid >> 5, lane = tid & 31;
    int wy = warp % WY, wx = warp / WY;
    int wm = wy * (BM / WY), wn = wx * (BN / WX);

    float acc[MT][NT][4];
#pragma unroll
    for (int i = 0; i < MT; i++)
#pragma unroll
        for (int j = 0; j < NT; j++)
#pragma unroll
            for (int c = 0; c < 4; c++) acc[i][j][c] = 0.f;

    auto loadA = [&](int st, int kt) {
        float* As = AsB + st * ASZ;
#pragma unroll
        for (int i = 0; i < AQ; i++) {
            int e = tid + i * 256;
            if (AT == 0) {
                int row = e >> 2, q = (e & 3) * 4;
                cpa16(&As[row * 20 + q],
                      Ap + (long long)(m0 + row) * sAm + (kt + q));
            } else {
                constexpr int QPR = BM / 4;
                int kk = e / QPR, q = (e % QPR) * 4;
                cpa16(&As[kk * APITCH + q],
                      Ap + (long long)(kt + kk) * sAk + (m0 + q));
            }
        }
    };
    auto loadB = [&](int st, int kt) {
        float* Bs = BsB + st * BSZ;
#pragma unroll
        for (int i = 0; i < BQ; i++) {
            int e = tid + i * 256;
            constexpr int QPR = BN / 4;
            int kk = e / QPR, q = (e % QPR) * 4;
            cpa16(&Bs[kk * BPITCH + q],
                  Bp + (long long)(kt + kk) * sBk + (n0 + q));
        }
    };

    int T = K / BK;
    // prologue: stages 0..NS-2
#pragma unroll
    for (int s = 0; s < NS - 1; s++) {
        loadA(s, s * BK); loadB(s, s * BK); CP_COMMIT;
    }

    int st = 0, ps = NS - 1;
    for (int t = 0; t < T; t++) {
        asm volatile("cp.async.wait_group %0;\n" :: "n"(NS - 2));
        __syncthreads();

        int pf = t + NS - 1;
        if (pf < T) { loadA(ps, pf * BK); loadB(ps, pf * BK); }
        CP_COMMIT;

        float* As = AsB + st * ASZ;
        float* Bs = BsB + st * BSZ;
#pragma unroll
        for (int k0 = 0; k0 < BK; k0 += 8) {
            float afr[MT][4], bfr[NT][2];
            int kc = k0 + (lane & 3);
#pragma unroll
            for (int i = 0; i < MT; i++) {
                int row = wm + i * 16 + (lane >> 2);
                if (AT == 0) {
                    afr[i][0] = As[row * 20 + kc];
                    afr[i][1] = As[(row + 8) * 20 + kc];
                    afr[i][2] = As[row * 20 + kc + 4];
                    afr[i][3] = As[(row + 8) * 20 + kc + 4];
                } else {
                    afr[i][0] = As[kc * APITCH + row];
                    afr[i][1] = As[kc * APITCH + row + 8];
                    afr[i][2] = As[(kc + 4) * APITCH + row];
                    afr[i][3] = As[(kc + 4) * APITCH + row + 8];
                }
            }
#pragma unroll
            for (int j = 0; j < NT; j++) {
                int col = wn + j * 8 + (lane >> 2);
                bfr[j][0] = Bs[kc * BPITCH + col];
                bfr[j][1] = Bs[(kc + 4) * BPITCH + col];
            }
#pragma unroll
            for (int i = 0; i < MT; i++)
#pragma unroll
                for (int j = 0; j < NT; j++)
                    mma_tf32(acc[i][j], afr[i], bfr[j]);
        }
        st = (st + 1 == NS) ? 0 : st + 1;
        ps = (ps + 1 == NS) ? 0 : ps + 1;
    }

    // epilogue (round outputs to tf32)
#pragma unroll
    for (int i = 0; i < MT; i++) {
        int mA = m0 + wm + i * 16 + (lane >> 2);
        int mB = mA + 8;
        float rsA = rscale ? rscale[oS + mA] : 1.f;
        float rsB = rscale ? rscale[oS + mB] : 1.f;
#pragma unroll
        for (int j = 0; j < NT; j++) {
            int n = n0 + wn + j * 8 + (lane & 3) * 2;
            float b0 = 0.f, b1 = 0.f;
            if (bias) { b0 = bias[n]; b1 = bias[n + 1]; }
            float2 v0, v1;
            v0.x = acc[i][j][0] + b0; v0.y = acc[i][j][1] + b1;
            v1.x = acc[i][j][2] + b0; v1.y = acc[i][j][3] + b1;
            if (relu) {
                v0.x = fmaxf(v0.x, 0.f); v0.y = fmaxf(v0.y, 0.f);
                v1.x = fmaxf(v1.x, 0.f); v1.y = fmaxf(v1.y, 0.f);
            }
            v0.x = f2tf32(v0.x * rsA); v0.y = f2tf32(v0.y * rsA);
            v1.x = f2tf32(v1.x * rsB); v1.y = f2tf32(v1.y * rsB);
            *(float2*)(Cp + (long long)mA * sCm + n) = v0;
            *(float2*)(Cp + (long long)mB * sCm + n) = v1;
        }
    }
}

// ---------------- weight prep ----------------
__global__ void __launch_bounds__(256) prep_qkv_kernel(
    const float* __restrict__ wq, const float* __restrict__ wk, const float* __restrict__ wv,
    const float* __restrict__ bq, const float* __restrict__ bk, const float* __restrict__ bv,
    float* __restrict__ wqkv, float* __restrict__ bqkv)
{
    long long idx = (long long)blockIdx.x * 256 + threadIdx.x;
    if (idx < (long long)NLAYERS * DMODEL * QKVW) {
        int l = (int)(idx / (DMODEL * QKVW));
        int rem = (int)(idx % (DMODEL * QKVW));
        int r = rem / QKVW, c = rem % QKVW;
        const float* src = c < 512 ? wq : (c < 1024 ? wk : wv);
        wqkv[idx] = f2tf32(src[(long long)l * DMODEL * DMODEL + r * DMODEL + (c & 511)]);
    }
    if (idx < NLAYERS * QKVW) {
        int l = (int)(idx / QKVW), c = (int)(idx % QKVW);
        const float* src = c < 512 ? bq : (c < 1024 ? bk : bv);
        bqkv[idx] = src[l * DMODEL + (c & 511)];
    }
}

__global__ void __launch_bounds__(256) round_copy_kernel(
    const float* __restrict__ src, float* __restrict__ dst, long long n)
{
    long long idx = (long long)blockIdx.x * 256 + threadIdx.x;
    if (idx < n) dst[idx] = f2tf32(src[idx]);
}

// ---------------- encoder first layer ----------------
__global__ void __launch_bounds__(256) enc1_kernel(
    const float* __restrict__ x, const float* __restrict__ pos,
    const float* __restrict__ w, const float* __restrict__ b,
    float* __restrict__ out)
{
    int idx = blockIdx.x * 256 + threadIdx.x;
    int row = idx >> 8, col = idx & 255;
    const float* xr = x + row * 3;
    const float* pr = pos + row * 3;
    float a = b[col];
#pragma unroll
    for (int d = 0; d < 3; d++) a = fmaf(xr[d], w[d * 256 + col], a);
#pragma unroll
    for (int d = 0; d < 3; d++) a = fmaf(pr[d], w[(3 + d) * 256 + col], a);
    out[idx] = f2tf32(fmaxf(a, 0.f));
}

// ---------------- LayerNorm (optional residual), width 512 ----------------
__global__ void __launch_bounds__(512) ln_kernel(
    float* __restrict__ out, const float* __restrict__ resid,
    const float* __restrict__ y,
    const float* __restrict__ g, const float* __restrict__ b)
{
    int row = blockIdx.x, t = threadIdx.x;
    long long base = (long long)row * 512;
    float v = y[base + t];
    if (resid) v += resid[base + t];
    float s = v, s2 = v * v;
#pragma unroll
    for (int o = 16; o; o >>= 1) {
        s  += __shfl_xor_sync(0xffffffffu, s,  o);
        s2 += __shfl_xor_sync(0xffffffffu, s2, o);
    }
    __shared__ float rs[16], rs2[16];
    int w = t >> 5, lane = t & 31;
    if (!lane) { rs[w] = s; rs2[w] = s2; }
    __syncthreads();
    if (t < 32) {
        float a  = (t < 16) ? rs[t]  : 0.f;
        float a2 = (t < 16) ? rs2[t] : 0.f;
#pragma unroll
        for (int o = 8; o; o >>= 1) {
            a  += __shfl_xor_sync(0xffffffffu, a,  o);
            a2 += __shfl_xor_sync(0xffffffffu, a2, o);
        }
        if (!t) { rs[0] = a; rs2[0] = a2; }
    }
    __syncthreads();
    float mean = rs[0] * (1.f / 512.f);
    float var  = rs2[0] * (1.f / 512.f) - mean * mean;
    out[base + t] = f2tf32((v - mean) * rsqrtf(var + 1e-5f) * g[t] + b[t]);
}

// ---------------- FAVOR+ feature map (4 rows/block) ----------------
// colOff: q (0) or k (512). part!=null: write per-block feature partial sums.
// zOut!=null: fused z = 1/(Qf . ks + eps).
__global__ void __launch_bounds__(128) favor_kernel(
    const float* __restrict__ qkv, const float* __restrict__ omega,
    float* __restrict__ outF, float* __restrict__ zOut,
    const float* __restrict__ ks, float* __restrict__ part, int colOff)
{
    int r0 = blockIdx.x * 4;
    int hh_ = blockIdx.y, t = threadIdx.x;
    __shared__ float xv[4][64];
    __shared__ float hvs[4];
#pragma unroll
    for (int i = 0; i < 2; i++) {
        int e = t + i * 128;
        int r = e >> 6, d = e & 63;
        xv[r][d] = qkv[(long long)(r0 + r) * QKVW + colOff + hh_ * 64 + d] * 0.3535533905932738f;
    }
    __syncthreads();
    {
        int w = t >> 5, lane = t & 31;
        float a = xv[w][lane], bb = xv[w][lane + 32];
        float s = a * a + bb * bb;
#pragma unroll
        for (int o = 16; o; o >>= 1) s += __shfl_xor_sync(0xffffffffu, s, o);
        if (!lane) hvs[w] = s * 0.5f;
    }
    __syncthreads();
    float u0 = 0.f, u1 = 0.f, u2 = 0.f, u3 = 0.f;
#pragma unroll 8
    for (int d = 0; d < 64; d++) {
        float om = omega[d * 128 + t];
        u0 = fmaf(xv[0][d], om, u0);
        u1 = fmaf(xv[1][d], om, u1);
        u2 = fmaf(xv[2][d], om, u2);
        u3 = fmaf(xv[3][d], om, u3);
    }
    int b = r0 >> 10;
    int bh = b * NH + hh_;
    long long ob = ((long long)bh * SEQ + (r0 & 1023)) * NF;
    float uu[4] = {u0, u1, u2, u3};
    float fa[4], fb[4];
#pragma unroll
    for (int r = 0; r < 4; r++) {
        float hv = hvs[r];
        fa[r] = f2tf32(expf( uu[r] - hv) * 0.0625f);
        fb[r] = f2tf32(expf(-uu[r] - hv) * 0.0625f);
        long long o = ob + (long long)r * NF;
        outF[o + t]       = fa[r];
        outF[o + 128 + t] = fb[r];
    }
    if (part) {
        int blk = (r0 & 1023) >> 2;   // 0..255 within this bh
        long long po = ((long long)bh * 256 + blk) * NF;
        part[po + t]       = fa[0] + fa[1] + fa[2] + fa[3];
        part[po + 128 + t] = fb[0] + fb[1] + fb[2] + fb[3];
    }
    if (zOut) {
        float ka = ks[bh * NF + t];
        float kb = ks[bh * NF + 128 + t];
        float p[4];
#pragma unroll
        for (int r = 0; r < 4; r++) p[r] = fa[r] * ka + fb[r] * kb;
#pragma unroll
        for (int o = 16; o; o >>= 1)
#pragma unroll
            for (int r = 0; r < 4; r++) p[r] += __shfl_xor_sync(0xffffffffu, p[r], o);
        __shared__ float pr[4][4];
        int w = t >> 5, lane = t & 31;
        if (!lane) {
#pragma unroll
            for (int r = 0; r < 4; r++) pr[w][r] = p[r];
        }
        __syncthreads();
        if (t < 4) {
            float s = pr[0][t] + pr[1][t] + pr[2][t] + pr[3][t];
            zOut[bh * SEQ + (r0 & 1023) + t] = 1.f / (s + 1e-6f);
        }
    }
}

// ---------------- ksum final reduce over 256 partials ----------------
__global__ void __launch_bounds__(256) ksum2_kernel(
    const float* __restrict__ part, float* __restrict__ ks)
{
    int bh = blockIdx.x, f = threadIdx.x;
    const float* p = part + (long long)bh * 256 * NF + f;
    float s = 0.f;
#pragma unroll 8
    for (int c = 0; c < 256; c++) s += p[(long long)c * NF];
    ks[bh * NF + f] = s;
}

// ---------------- mean pool + classifier ----------------
__global__ void __launch_bounds__(512) pool_cls_kernel(
    const float* __restrict__ h, const float* __restrict__ cw,
    const float* __restrict__ cb, float* __restrict__ out)
{
    int b = blockIdx.x, t = threadIdx.x;
    const float* base = h + (long long)b * SEQ * DMODEL + t;
    float s = 0.f;
#pragma unroll 8
    for (int i = 0; i < SEQ; i++) s += base[(long long)i * DMODEL];
    __shared__ float pooled[DMODEL];
    pooled[t] = s * (1.f / (float)SEQ);
    __syncthreads();
    if (t < 16) {
        float acc = cb[t];
        for (int d = 0; d < DMODEL; d++) acc = fmaf(pooled[d], cw[d * 16 + t], acc);
        out[b * 16 + t] = acc;
    }
}

// ---------------- host driver ----------------
extern "C" void kernel_launch(void* const* d_in, const int* in_sizes, int n_in,
                              void* d_out, int out_size)
{
    const float* x      = (const float*)d_in[0];
    const float* pos    = (const float*)d_in[1];
    const float* enc_w1 = (const float*)d_in[2];
    const float* enc_b1 = (const float*)d_in[3];
    const float* enc_w2 = (const float*)d_in[4];
    const float* enc_b2 = (const float*)d_in[5];
    const float* enc_g  = (const float*)d_in[6];
    const float* enc_bb = (const float*)d_in[7];
    const float* wq     = (const float*)d_in[8];
    const float* bq     = (const float*)d_in[9];
    const float* wk     = (const float*)d_in[10];
    const float* bk     = (const float*)d_in[11];
    const float* wv     = (const float*)d_in[12];
    const float* bv     = (const float*)d_in[13];
    const float* wo     = (const float*)d_in[14];
    const float* bo     = (const float*)d_in[15];
    const float* ln1_g  = (const float*)d_in[16];
    const float* ln1_b  = (const float*)d_in[17];
    const float* w1     = (const float*)d_in[18];
    const float* b1     = (const float*)d_in[19];
    const float* w2     = (const float*)d_in[20];
    const float* b2     = (const float*)d_in[21];
    const float* ln2_g  = (const float*)d_in[22];
    const float* ln2_b  = (const float*)d_in[23];
    const float* omega  = (const float*)d_in[24];
    const float* cls_w  = (const float*)d_in[25];
    const float* cls_b  = (const float*)d_in[26];

    float *p_h, *p_t0, *p_qk, *p_v, *p_ffn, *p_qkv, *p_Qf, *p_Kf, *p_kv, *p_ks, *p_kp, *p_z;
    float *p_wqkv, *p_bqkv, *p_w1r, *p_w2r, *p_ew2r;
    cudaGetSymbolAddress((void**)&p_h,   g_h);
    cudaGetSymbolAddress((void**)&p_t0,  g_t0);
    cudaGetSymbolAddress((void**)&p_qk,  g_qk);
    cudaGetSymbolAddress((void**)&p_v,   g_v);
    cudaGetSymbolAddress((void**)&p_ffn, g_ffn);
    cudaGetSymbolAddress((void**)&p_qkv, g_qkv);
    cudaGetSymbolAddress((void**)&p_Qf,  g_Qf);
    cudaGetSymbolAddress((void**)&p_Kf,  g_Kf);
    cudaGetSymbolAddress((void**)&p_kv,  g_kv);
    cudaGetSymbolAddress((void**)&p_ks,  g_ks);
    cudaGetSymbolAddress((void**)&p_kp,  g_kp);
    cudaGetSymbolAddress((void**)&p_z,   g_z);
    cudaGetSymbolAddress((void**)&p_wqkv,g_wqkv);
    cudaGetSymbolAddress((void**)&p_bqkv,g_bqkv);
    cudaGetSymbolAddress((void**)&p_w1r, g_w1r);
    cudaGetSymbolAddress((void**)&p_w2r, g_w2r);
    cudaGetSymbolAddress((void**)&p_ew2r,g_ew2r);

    // dynamic smem sizes (NS=3)
    const int SM_DENSE = 3 * (128 * 20 + 16 * 136) * 4;   // 56832
    const int SM_KV    = 3 * (16 * 136 + 16 * 72) * 4;    // 39936
    const int SM_ATTN  = 3 * (128 * 20 + 16 * 72) * 4;    // 44544
    cudaFuncSetAttribute(mma_gemm<128,128,2,4,0,3>,
        cudaFuncAttributeMaxDynamicSharedMemorySize, SM_DENSE);
    cudaFuncSetAttribute(mma_gemm<128,64,4,2,1,3>,
        cudaFuncAttributeMaxDynamicSharedMemorySize, SM_KV);
    cudaFuncSetAttribute(mma_gemm<128,64,4,2,0,3>,
        cudaFuncAttributeMaxDynamicSharedMemorySize, SM_ATTN);

    // ---- weight prep (inside graph; cheap) ----
    {
        long long nqkv = (long long)NLAYERS * DMODEL * QKVW;
        prep_qkv_kernel<<<(unsigned)((nqkv + 255) / 256), 256>>>(
            wq, wk, wv, bq, bk, bv, p_wqkv, p_bqkv);
        long long n1 = (long long)NLAYERS * DMODEL * FFNH;
        round_copy_kernel<<<(unsigned)((n1 + 255) / 256), 256>>>(w1, p_w1r, n1);
        round_copy_kernel<<<(unsigned)((n1 + 255) / 256), 256>>>(w2, p_w2r, n1);
        long long ne = 256LL * DMODEL;
        round_copy_kernel<<<(unsigned)((ne + 255) / 256), 256>>>(enc_w2, p_ew2r, ne);
    }

    auto dense = [&](const float* A, const float* W, const float* bias,
                     float* C, int M, int Nn, int K, int relu) {
        dim3 grid(Nn / 128, M / 128, 1);
        mma_gemm<128,128,2,4,0,3><<<grid, 256, SM_DENSE>>>(A, W, bias, nullptr, C, M, Nn, K,
                                    (long long)K, 1LL, (long long)Nn, (long long)Nn,
                                    0, 0, 0, 0, 0, 0, 0, 0, 1, relu);
    };

    // ---- encoder ----
    enc1_kernel<<<NTOK, 256>>>(x, pos, enc_w1, enc_b1, p_t0);
    dense(p_t0, p_ew2r, enc_b2, p_v, NTOK, DMODEL, 256, 0);
    ln_kernel<<<NTOK, 512>>>(p_h, nullptr, p_v, enc_g, enc_bb);

    for (int l = 0; l < NLAYERS; l++) {
        const float* Wqkv = p_wqkv + (long long)l * DMODEL * QKVW;
        const float* Bqkv = p_bqkv + l * QKVW;
        const float* Wo = wo + (long long)l * DMODEL * DMODEL;
        const float* Bo = bo + l * DMODEL;
        const float* W1 = p_w1r + (long long)l * DMODEL * FFNH;
        const float* B1 = b1 + l * FFNH;
        const float* W2 = p_w2r + (long long)l * FFNH * DMODEL;
        const float* B2 = b2 + l * DMODEL;
        const float* Om = omega + (long long)l * HD * NFH;

        // merged QKV projection
        dense(p_h, Wqkv, Bqkv, p_qkv, NTOK, QKVW, DMODEL, 0);

        // FAVOR(K) with fused partial ksum, reduce, FAVOR(Q) with fused z
        favor_kernel<<<dim3(NTOK / 4, NH), 128>>>(p_qkv, Om, p_Kf, nullptr, nullptr, p_kp, 512);
        ksum2_kernel<<<BATCH * NH, 256>>>(p_kp, p_ks);
        favor_kernel<<<dim3(NTOK / 4, NH), 128>>>(p_qkv, Om, p_Qf, p_z, p_ks, nullptr, 0);

        // kv[b,h,f,d] = sum_s Kf[b,h,s,f] * v[b,s,h,d]
        {
            dim3 grid(1, NF / 128, BATCH * NH);
            mma_gemm<128,64,4,2,1,3><<<grid, 256, SM_KV>>>(p_Kf, p_qkv + 1024, nullptr, nullptr, p_kv,
                NF, HD, SEQ,
                1LL, (long long)NF,
                (long long)QKVW,
                (long long)HD,
                (long long)NH * SEQ * NF, (long long)SEQ * NF,
                (long long)SEQ * QKVW, (long long)HD,
                (long long)NH * NF * HD, (long long)NF * HD,
                0, 0, NH, 0);
        }

        // attn[b,s,h,d] = z * Qf[b,h,s,:] @ kv[b,h,:,:]
        {
            dim3 grid(1, SEQ / 128, BATCH * NH);
            mma_gemm<128,64,4,2,0,3><<<grid, 256, SM_ATTN>>>(p_Qf, p_kv, nullptr, p_z, p_qk,
                SEQ, HD, NF,
                (long long)NF, 1LL,
                (long long)HD,
                (long long)DMODEL,
                (long long)NH * SEQ * NF, (long long)SEQ * NF,
                (long long)NH * NF * HD, (long long)NF * HD,
                (long long)SEQ * DMODEL, (long long)HD,
                (long long)NH * SEQ, (long long)SEQ,
                NH, 0);
        }

        // output projection + residual LN
        dense(p_qk, Wo, Bo, p_v, NTOK, DMODEL, DMODEL, 0);
        ln_kernel<<<NTOK, 512>>>(p_h, p_h, p_v, ln1_g + l * DMODEL, ln1_b + l * DMODEL);

        // FFN + residual LN
        dense(p_h, W1, B1, p_ffn, NTOK, FFNH, DMODEL, 1);
        dense(p_ffn, W2, B2, p_v, NTOK, DMODEL, FFNH, 0);
        ln_kernel<<<NTOK, 512>>>(p_h, p_h, p_v, ln2_g + l * DMODEL, ln2_b + l * DMODEL);
    }

    pool_cls_kernel<<<BATCH, 512>>>(p_h, cls_w, cls_b, (float*)d_out);
}

// round 8
// speedup vs baseline: 4.8703x; 1.2952x over previous
#include <cuda_runtime.h>
#include <cuda_fp16.h>
#include <math.h>

#define BATCH 16
#define SEQ 1024
#define NTOK (BATCH*SEQ)
#define DMODEL 512
#define NH 8
#define HD 64
#define NF 256
#define NLAYERS 4
#define FFNH 1024
#define QKVW 1536

// ---------------- scratch ----------------
__device__ float  g_h   [NTOK*DMODEL];          // fp32 hidden (residual/pool)
__device__ __half g_h16 [NTOK*DMODEL];          // half hidden (GEMM A)
__device__ __half g_t016[NTOK*256];
__device__ __half g_qkv16[NTOK*QKVW];
__device__ __half g_ffn16[NTOK*FFNH];
__device__ __half g_attn16[NTOK*DMODEL];
__device__ float  g_v   [NTOK*DMODEL];          // fp32 temp (pre-LN)
__device__ float  g_Qf  [BATCH*NH*SEQ*NF];
__device__ float  g_Kf  [BATCH*NH*SEQ*NF];
__device__ float  g_kv  [BATCH*NH*NF*HD];
__device__ float  g_ks  [BATCH*NH*NF];
__device__ float  g_kp  [BATCH*NH*256*NF];
__device__ float  g_z   [BATCH*NH*SEQ];
// pre-transposed half weights [n][k]
__device__ __half g_wqkvT[NLAYERS*QKVW*DMODEL];
__device__ float  g_bqkv [NLAYERS*QKVW];
__device__ __half g_w1T  [NLAYERS*FFNH*DMODEL];
__device__ __half g_w2T  [NLAYERS*DMODEL*FFNH];
__device__ __half g_woT  [NLAYERS*DMODEL*DMODEL];
__device__ __half g_ew2T [DMODEL*256];

__device__ __forceinline__ float f2tf32(float x) {
    unsigned u;
    asm("cvt.rna.tf32.f32 %0, %1;" : "=r"(u) : "f"(x));
    return __uint_as_float(u);
}

__device__ __forceinline__ void mma_tf32(float* d, const float* a, const float* b) {
    asm volatile(
        "mma.sync.aligned.m16n8k8.row.col.f32.tf32.tf32.f32 "
        "{%0,%1,%2,%3},{%4,%5,%6,%7},{%8,%9},{%0,%1,%2,%3};\n"
        : "+f"(d[0]), "+f"(d[1]), "+f"(d[2]), "+f"(d[3])
        : "r"(__float_as_uint(a[0])), "r"(__float_as_uint(a[1])),
          "r"(__float_as_uint(a[2])), "r"(__float_as_uint(a[3])),
          "r"(__float_as_uint(b[0])), "r"(__float_as_uint(b[1])));
}

__device__ __forceinline__ void mma_f16(float* d, const unsigned* a, const unsigned* b) {
    asm volatile(
        "mma.sync.aligned.m16n8k16.row.col.f32.f16.f16.f32 "
        "{%0,%1,%2,%3},{%4,%5,%6,%7},{%8,%9},{%0,%1,%2,%3};\n"
        : "+f"(d[0]), "+f"(d[1]), "+f"(d[2]), "+f"(d[3])
        : "r"(a[0]), "r"(a[1]), "r"(a[2]), "r"(a[3]),
          "r"(b[0]), "r"(b[1]));
}

__device__ __forceinline__ void cpa16(void* dst, const void* src) {
    unsigned s = (unsigned)__cvta_generic_to_shared(dst);
    asm volatile("cp.async.ca.shared.global [%0], [%1], 16;\n" :: "r"(s), "l"(src));
}
#define CP_COMMIT  asm volatile("cp.async.commit_group;\n")

// ================= fp16 dense GEMM: C = A[M][K] @ B^T (B stored [N][K]) =================
// OUTH=0: fp32 out; OUTH=1: half out. bias fp32, optional relu.
template<int OUTH>
__global__ void __launch_bounds__(256, 2) hgemm(
    const __half* __restrict__ A, const __half* __restrict__ B,
    const float* __restrict__ bias, void* __restrict__ Cout,
    int M, int N, int K, int relu)
{
    constexpr int BM = 128, BN = 128, BK = 32, NS = 3;
    constexpr int PITCH = BK + 8;            // 40 halves, 80B rows (16B aligned)
    constexpr int TSZ = BM * PITCH;          // halves per stage per operand

    extern __shared__ __half hsm[];
    __half* AsB = hsm;
    __half* BsB = hsm + NS * TSZ;

    int m0 = blockIdx.y * BM;
    int n0 = blockIdx.x * BN;
    int tid = threadIdx.x;
    int warp = tid >> 5, lane = tid & 31;
    int wy = warp & 1, wx = warp >> 1;       // 2 x 4 warp grid
    int wm = wy * 64, wn = wx * 32;          // MT=4 (m16), NT=4 (n8)

    float acc[4][4][4];
#pragma unroll
    for (int i = 0; i < 4; i++)
#pragma unroll
        for (int j = 0; j < 4; j++)
#pragma unroll
            for (int c = 0; c < 4; c++) acc[i][j][c] = 0.f;

    auto loadT = [&](__half* S, const __half* G, int row0, int ld, int kt) {
#pragma unroll
        for (int i = 0; i < 2; i++) {
            int e = tid + i * 256;
            int row = e >> 2, q = (e & 3) * 8;
            cpa16(&S[row * PITCH + q], G + (long long)(row0 + row) * ld + kt + q);
        }
    };

    int T = K / BK;
#pragma unroll
    for (int s = 0; s < NS - 1; s++) {
        loadT(AsB + s * TSZ, A, m0, K, s * BK);
        loadT(BsB + s * TSZ, B, n0, K, s * BK);
        CP_COMMIT;
    }

    int st = 0, ps = NS - 1;
    for (int t = 0; t < T; t++) {
        asm volatile("cp.async.wait_group %0;\n" :: "n"(NS - 2));
        __syncthreads();
        int pf = t + NS - 1;
        if (pf < T) {
            loadT(AsB + ps * TSZ, A, m0, K, pf * BK);
            loadT(BsB + ps * TSZ, B, n0, K, pf * BK);
        }
        CP_COMMIT;

        const __half* As = AsB + st * TSZ;
        const __half* Bs = BsB + st * TSZ;
#pragma unroll
        for (int ks = 0; ks < BK; ks += 16) {
            int kp = ks + (lane & 3) * 2;
            unsigned a[4][4], b[4][2];
#pragma unroll
            for (int i = 0; i < 4; i++) {
                int row = wm + i * 16 + (lane >> 2);
                a[i][0] = *(const unsigned*)&As[row * PITCH + kp];
                a[i][1] = *(const unsigned*)&As[(row + 8) * PITCH + kp];
                a[i][2] = *(const unsigned*)&As[row * PITCH + kp + 8];
                a[i][3] = *(const unsigned*)&As[(row + 8) * PITCH + kp + 8];
            }
#pragma unroll
            for (int j = 0; j < 4; j++) {
                int col = wn + j * 8 + (lane >> 2);
                b[j][0] = *(const unsigned*)&Bs[col * PITCH + kp];
                b[j][1] = *(const unsigned*)&Bs[col * PITCH + kp + 8];
            }
#pragma unroll
            for (int i = 0; i < 4; i++)
#pragma unroll
                for (int j = 0; j < 4; j++)
                    mma_f16(acc[i][j], a[i], b[j]);
        }
        st = (st + 1 == NS) ? 0 : st + 1;
        ps = (ps + 1 == NS) ? 0 : ps + 1;
    }

#pragma unroll
    for (int i = 0; i < 4; i++) {
        int mA = m0 + wm + i * 16 + (lane >> 2);
        int mB = mA + 8;
#pragma unroll
        for (int j = 0; j < 4; j++) {
            int n = n0 + wn + j * 8 + (lane & 3) * 2;
            float b0 = bias ? bias[n] : 0.f;
            float b1 = bias ? bias[n + 1] : 0.f;
            float v00 = acc[i][j][0] + b0, v01 = acc[i][j][1] + b1;
            float v10 = acc[i][j][2] + b0, v11 = acc[i][j][3] + b1;
            if (relu) {
                v00 = fmaxf(v00, 0.f); v01 = fmaxf(v01, 0.f);
                v10 = fmaxf(v10, 0.f); v11 = fmaxf(v11, 0.f);
            }
            if (OUTH) {
                __half* C = (__half*)Cout;
                __half2 h0; h0.x = __float2half(v00); h0.y = __float2half(v01);
                __half2 h1; h1.x = __float2half(v10); h1.y = __float2half(v11);
                *(__half2*)(C + (long long)mA * N + n) = h0;
                *(__half2*)(C + (long long)mB * N + n) = h1;
            } else {
                float* C = (float*)Cout;
                *(float2*)(C + (long long)mA * N + n) = make_float2(v00, v01);
                *(float2*)(C + (long long)mB * N + n) = make_float2(v10, v11);
            }
        }
    }
}

// ================= tf32 batched GEMM (attention) =================
// AT=1: A trans (sAm==1). HB=1: B is half. OUTH=1: half out.
template<int BM, int BN, int WY, int WX, int AT, int NS, int HB, int OUTH>
__global__ void __launch_bounds__(256, 2) mma_gemm(
    const float* __restrict__ A, const void* __restrict__ B,
    const float* __restrict__ rscale, void* __restrict__ Cv,
    int K,
    long long sAm, long long sAk, long long sBk, long long sCm,
    long long oA1, long long oA2, long long oB1, long long oB2,
    long long oC1, long long oC2, long long oS1, long long oS2,
    int Hdiv)
{
    constexpr int BK  = 16;
    constexpr int MT  = BM / WY / 16;
    constexpr int NT  = BN / WX / 8;
    constexpr int APITCH = (AT == 0) ? 20 : (BM + 8);
    constexpr int BPITCH = BN + 8;
    constexpr int ASZB = ((AT == 0) ? BM * 20 : BK * (BM + 8)) * 4;
    constexpr int BSZB = HB ? BK * BPITCH * 2 : BK * BPITCH * 4;
    constexpr int AQ  = BM * BK / 4 / 256;

    extern __shared__ char smraw[];
    char* AsBase = smraw;
    char* BsBase = smraw + NS * ASZB;

    int z  = blockIdx.z;
    int z1 = z / Hdiv, z2 = z - z1 * Hdiv;
    const float* Ap = A + z1 * oA1 + z2 * oA2;
    const float* Bpf = HB ? nullptr : (const float*)B + z1 * oB1 + z2 * oB2;
    const __half* Bph = HB ? (const __half*)B + z1 * oB1 + z2 * oB2 : nullptr;
    long long    oS = z1 * oS1 + z2 * oS2;

    int m0 = blockIdx.y * BM;
    int n0 = blockIdx.x * BN;
    int tid = threadIdx.x;
    int warp = tid >> 5, lane = tid & 31;
    int wy = warp % WY, wx = warp / WY;
    int wm = wy * (BM / WY), wn = wx * (BN / WX);

    float acc[MT][NT][4];
#pragma unroll
    for (int i = 0; i < MT; i++)
#pragma unroll
        for (int j = 0; j < NT; j++)
#pragma unroll
            for (int c = 0; c < 4; c++) acc[i][j][c] = 0.f;

    auto loadA = [&](int st, int kt) {
        float* As = (float*)(AsBase + st * ASZB);
#pragma unroll
        for (int i = 0; i < AQ; i++) {
            int e = tid + i * 256;
            if (AT == 0) {
                int row = e >> 2, q = (e & 3) * 4;
                cpa16(&As[row * 20 + q],
                      Ap + (long long)(m0 + row) * sAm + (kt + q));
            } else {
                constexpr int QPR = BM / 4;
                int kk = e / QPR, q = (e % QPR) * 4;
                cpa16(&As[kk * APITCH + q],
                      Ap + (long long)(kt + kk) * sAk + (m0 + q));
            }
        }
    };
    auto loadB = [&](int st, int kt) {
        if (HB) {
            __half* Bs = (__half*)(BsBase + st * BSZB);
            // BK*BN/8 = 128 chunks of 8 halves
            if (tid < BK * BN / 8) {
                int kk = tid >> 3, q = (tid & 7) * 8;
                cpa16(&Bs[kk * BPITCH + q],
                      Bph + (long long)(kt + kk) * sBk + (n0 + q));
            }
        } else {
            float* Bs = (float*)(BsBase + st * BSZB);
            constexpr int BQ = BK * BN / 4 / 256;
#pragma unroll
            for (int i = 0; i < BQ; i++) {
                int e = tid + i * 256;
                constexpr int QPR = BN / 4;
                int kk = e / QPR, q = (e % QPR) * 4;
                cpa16(&Bs[kk * BPITCH + q],
                      Bpf + (long long)(kt + kk) * sBk + (n0 + q));
            }
        }
    };

    int T = K / BK;
#pragma unroll
    for (int s = 0; s < NS - 1; s++) { loadA(s, s * BK); loadB(s, s * BK); CP_COMMIT; }

    int st = 0, ps = NS - 1;
    for (int t = 0; t < T; t++) {
        asm volatile("cp.async.wait_group %0;\n" :: "n"(NS - 2));
        __syncthreads();
        int pf = t + NS - 1;
        if (pf < T) { loadA(ps, pf * BK); loadB(ps, pf * BK); }
        CP_COMMIT;

        const float* As = (const float*)(AsBase + st * ASZB);
        const float* Bsf = (const float*)(BsBase + st * BSZB);
        const __half* Bsh = (const __half*)(BsBase + st * BSZB);
#pragma unroll
        for (int k0 = 0; k0 < BK; k0 += 8) {
            float afr[MT][4], bfr[NT][2];
            int kc = k0 + (lane & 3);
#pragma unroll
            for (int i = 0; i < MT; i++) {
                int row = wm + i * 16 + (lane >> 2);
                if (AT == 0) {
                    afr[i][0] = As[row * 20 + kc];
                    afr[i][1] = As[(row + 8) * 20 + kc];
                    afr[i][2] = As[row * 20 + kc + 4];
                    afr[i][3] = As[(row + 8) * 20 + kc + 4];
                } else {
                    afr[i][0] = As[kc * APITCH + row];
                    afr[i][1] = As[kc * APITCH + row + 8];
                    afr[i][2] = As[(kc + 4) * APITCH + row];
                    afr[i][3] = As[(kc + 4) * APITCH + row + 8];
                }
            }
#pragma unroll
            for (int j = 0; j < NT; j++) {
                int col = wn + j * 8 + (lane >> 2);
                if (HB) {
                    bfr[j][0] = __half2float(Bsh[kc * BPITCH + col]);
                    bfr[j][1] = __half2float(Bsh[(kc + 4) * BPITCH + col]);
                } else {
                    bfr[j][0] = Bsf[kc * BPITCH + col];
                    bfr[j][1] = Bsf[(kc + 4) * BPITCH + col];
                }
            }
#pragma unroll
            for (int i = 0; i < MT; i++)
#pragma unroll
                for (int j = 0; j < NT; j++)
                    mma_tf32(acc[i][j], afr[i], bfr[j]);
        }
        st = (st + 1 == NS) ? 0 : st + 1;
        ps = (ps + 1 == NS) ? 0 : ps + 1;
    }

#pragma unroll
    for (int i = 0; i < MT; i++) {
        int mA = m0 + wm + i * 16 + (lane >> 2);
        int mB = mA + 8;
        float rsA = rscale ? rscale[oS + mA] : 1.f;
        float rsB = rscale ? rscale[oS + mB] : 1.f;
#pragma unroll
        for (int j = 0; j < NT; j++) {
            int n = n0 + wn + j * 8 + (lane & 3) * 2;
            float v00 = acc[i][j][0] * rsA, v01 = acc[i][j][1] * rsA;
            float v10 = acc[i][j][2] * rsB, v11 = acc[i][j][3] * rsB;
            if (OUTH) {
                __half* Cp = (__half*)Cv + z1 * oC1 + z2 * oC2;
                __half2 h0; h0.x = __float2half(v00); h0.y = __float2half(v01);
                __half2 h1; h1.x = __float2half(v10); h1.y = __float2half(v11);
                *(__half2*)(Cp + (long long)mA * sCm + n) = h0;
                *(__half2*)(Cp + (long long)mB * sCm + n) = h1;
            } else {
                float* Cp = (float*)Cv + z1 * oC1 + z2 * oC2;
                *(float2*)(Cp + (long long)mA * sCm + n) =
                    make_float2(f2tf32(v00), f2tf32(v01));
                *(float2*)(Cp + (long long)mB * sCm + n) =
                    make_float2(f2tf32(v10), f2tf32(v11));
            }
        }
    }
}

// ---------------- prep: tiled transpose fp32[K][N] -> half[N][K] ----------------
__global__ void __launch_bounds__(256) transpose_h(
    const float* __restrict__ in, __half* __restrict__ out, int K, int N,
    long long inL, long long outL)
{
    __shared__ float tile[32][33];
    const float* ip = in + blockIdx.z * inL;
    __half* op = out + blockIdx.z * outL;
    int n0 = blockIdx.x * 32, k0 = blockIdx.y * 32;
    int tx = threadIdx.x & 31, ty = threadIdx.x >> 5;   // 32 x 8
#pragma unroll
    for (int r = 0; r < 4; r++)
        tile[ty + r * 8][tx] = ip[(long long)(k0 + ty + r * 8) * N + n0 + tx];
    __syncthreads();
#pragma unroll
    for (int r = 0; r < 4; r++)
        op[(long long)(n0 + ty + r * 8) * K + k0 + tx] = __float2half(tile[tx][ty + r * 8]);
}

__global__ void __launch_bounds__(256) prep_bias_kernel(
    const float* __restrict__ bq, const float* __restrict__ bk,
    const float* __restrict__ bv, float* __restrict__ bqkv)
{
    int idx = blockIdx.x * 256 + threadIdx.x;
    if (idx < NLAYERS * QKVW) {
        int l = idx / QKVW, c = idx % QKVW;
        const float* src = c < 512 ? bq : (c < 1024 ? bk : bv);
        bqkv[idx] = src[l * DMODEL + (c & 511)];
    }
}

// ---------------- encoder first layer ----------------
__global__ void __launch_bounds__(256) enc1_kernel(
    const float* __restrict__ x, const float* __restrict__ pos,
    const float* __restrict__ w, const float* __restrict__ b,
    __half* __restrict__ out)
{
    int idx = blockIdx.x * 256 + threadIdx.x;
    int row = idx >> 8, col = idx & 255;
    const float* xr = x + row * 3;
    const float* pr = pos + row * 3;
    float a = b[col];
#pragma unroll
    for (int d = 0; d < 3; d++) a = fmaf(xr[d], w[d * 256 + col], a);
#pragma unroll
    for (int d = 0; d < 3; d++) a = fmaf(pr[d], w[(3 + d) * 256 + col], a);
    out[idx] = __float2half(fmaxf(a, 0.f));
}

// ---------------- LayerNorm: writes fp32 + half ----------------
__global__ void __launch_bounds__(512) ln_kernel(
    float* __restrict__ out, __half* __restrict__ out16,
    const float* __restrict__ resid, const float* __restrict__ y,
    const float* __restrict__ g, const float* __restrict__ b)
{
    int row = blockIdx.x, t = threadIdx.x;
    long long base = (long long)row * 512;
    float v = y[base + t];
    if (resid) v += resid[base + t];
    float s = v, s2 = v * v;
#pragma unroll
    for (int o = 16; o; o >>= 1) {
        s  += __shfl_xor_sync(0xffffffffu, s,  o);
        s2 += __shfl_xor_sync(0xffffffffu, s2, o);
    }
    __shared__ float rs[16], rs2[16];
    int w = t >> 5, lane = t & 31;
    if (!lane) { rs[w] = s; rs2[w] = s2; }
    __syncthreads();
    if (t < 32) {
        float a  = (t < 16) ? rs[t]  : 0.f;
        float a2 = (t < 16) ? rs2[t] : 0.f;
#pragma unroll
        for (int o = 8; o; o >>= 1) {
            a  += __shfl_xor_sync(0xffffffffu, a,  o);
            a2 += __shfl_xor_sync(0xffffffffu, a2, o);
        }
        if (!t) { rs[0] = a; rs2[0] = a2; }
    }
    __syncthreads();
    float mean = rs[0] * (1.f / 512.f);
    float var  = rs2[0] * (1.f / 512.f) - mean * mean;
    float r = (v - mean) * rsqrtf(var + 1e-5f) * g[t] + b[t];
    out[base + t] = r;
    out16[base + t] = __float2half(r);
}

// ---------------- FAVOR+ feature map (4 rows/block), reads half qkv ----------------
__global__ void __launch_bounds__(128) favor_kernel(
    const __half* __restrict__ qkv, const float* __restrict__ omega,
    float* __restrict__ outF, float* __restrict__ zOut,
    const float* __restrict__ ks, float* __restrict__ part, int colOff)
{
    int r0 = blockIdx.x * 4;
    int hh_ = blockIdx.y, t = threadIdx.x;
    __shared__ float xv[4][64];
    __shared__ float hvs[4];
#pragma unroll
    for (int i = 0; i < 2; i++) {
        int e = t + i * 128;
        int r = e >> 6, d = e & 63;
        xv[r][d] = __half2float(qkv[(long long)(r0 + r) * QKVW + colOff + hh_ * 64 + d])
                   * 0.3535533905932738f;
    }
    __syncthreads();
    {
        int w = t >> 5, lane = t & 31;
        float a = xv[w][lane], bb = xv[w][lane + 32];
        float s = a * a + bb * bb;
#pragma unroll
        for (int o = 16; o; o >>= 1) s += __shfl_xor_sync(0xffffffffu, s, o);
        if (!lane) hvs[w] = s * 0.5f;
    }
    __syncthreads();
    float u0 = 0.f, u1 = 0.f, u2 = 0.f, u3 = 0.f;
#pragma unroll 8
    for (int d = 0; d < 64; d++) {
        float om = omega[d * 128 + t];
        u0 = fmaf(xv[0][d], om, u0);
        u1 = fmaf(xv[1][d], om, u1);
        u2 = fmaf(xv[2][d], om, u2);
        u3 = fmaf(xv[3][d], om, u3);
    }
    int b = r0 >> 10;
    int bh = b * NH + hh_;
    long long ob = ((long long)bh * SEQ + (r0 & 1023)) * NF;
    float uu[4] = {u0, u1, u2, u3};
    float fa[4], fb[4];
#pragma unroll
    for (int r = 0; r < 4; r++) {
        float hv = hvs[r];
        fa[r] = f2tf32(expf( uu[r] - hv) * 0.0625f);
        fb[r] = f2tf32(expf(-uu[r] - hv) * 0.0625f);
        long long o = ob + (long long)r * NF;
        outF[o + t]       = fa[r];
        outF[o + 128 + t] = fb[r];
    }
    if (part) {
        int blk = (r0 & 1023) >> 2;
        long long po = ((long long)bh * 256 + blk) * NF;
        part[po + t]       = fa[0] + fa[1] + fa[2] + fa[3];
        part[po + 128 + t] = fb[0] + fb[1] + fb[2] + fb[3];
    }
    if (zOut) {
        float ka = ks[bh * NF + t];
        float kb = ks[bh * NF + 128 + t];
        float p[4];
#pragma unroll
        for (int r = 0; r < 4; r++) p[r] = fa[r] * ka + fb[r] * kb;
#pragma unroll
        for (int o = 16; o; o >>= 1)
#pragma unroll
            for (int r = 0; r < 4; r++) p[r] += __shfl_xor_sync(0xffffffffu, p[r], o);
        __shared__ float pr[4][4];
        int w = t >> 5, lane = t & 31;
        if (!lane) {
#pragma unroll
            for (int r = 0; r < 4; r++) pr[w][r] = p[r];
        }
        __syncthreads();
        if (t < 4) {
            float s = pr[0][t] + pr[1][t] + pr[2][t] + pr[3][t];
            zOut[bh * SEQ + (r0 & 1023) + t] = 1.f / (s + 1e-6f);
        }
    }
}

// ---------------- ksum final reduce ----------------
__global__ void __launch_bounds__(256) ksum2_kernel(
    const float* __restrict__ part, float* __restrict__ ks)
{
    int bh = blockIdx.x, f = threadIdx.x;
    const float* p = part + (long long)bh * 256 * NF + f;
    float s = 0.f;
#pragma unroll 8
    for (int c = 0; c < 256; c++) s += p[(long long)c * NF];
    ks[bh * NF + f] = s;
}

// ---------------- mean pool + classifier ----------------
__global__ void __launch_bounds__(512) pool_cls_kernel(
    const float* __restrict__ h, const float* __restrict__ cw,
    const float* __restrict__ cb, float* __restrict__ out)
{
    int b = blockIdx.x, t = threadIdx.x;
    const float* base = h + (long long)b * SEQ * DMODEL + t;
    float s = 0.f;
#pragma unroll 8
    for (int i = 0; i < SEQ; i++) s += base[(long long)i * DMODEL];
    __shared__ float pooled[DMODEL];
    pooled[t] = s * (1.f / (float)SEQ);
    __syncthreads();
    if (t < 16) {
        float acc = cb[t];
        for (int d = 0; d < DMODEL; d++) acc = fmaf(pooled[d], cw[d * 16 + t], acc);
        out[b * 16 + t] = acc;
    }
}

// ---------------- host driver ----------------
extern "C" void kernel_launch(void* const* d_in, const int* in_sizes, int n_in,
                              void* d_out, int out_size)
{
    const float* x      = (const float*)d_in[0];
    const float* pos    = (const float*)d_in[1];
    const float* enc_w1 = (const float*)d_in[2];
    const float* enc_b1 = (const float*)d_in[3];
    const float* enc_w2 = (const float*)d_in[4];
    const float* enc_b2 = (const float*)d_in[5];
    const float* enc_g  = (const float*)d_in[6];
    const float* enc_bb = (const float*)d_in[7];
    const float* wq     = (const float*)d_in[8];
    const float* bq     = (const float*)d_in[9];
    const float* wk     = (const float*)d_in[10];
    const float* bk     = (const float*)d_in[11];
    const float* wv     = (const float*)d_in[12];
    const float* bv     = (const float*)d_in[13];
    const float* wo     = (const float*)d_in[14];
    const float* bo     = (const float*)d_in[15];
    const float* ln1_g  = (const float*)d_in[16];
    const float* ln1_b  = (const float*)d_in[17];
    const float* w1     = (const float*)d_in[18];
    const float* b1     = (const float*)d_in[19];
    const float* w2     = (const float*)d_in[20];
    const float* b2     = (const float*)d_in[21];
    const float* ln2_g  = (const float*)d_in[22];
    const float* ln2_b  = (const float*)d_in[23];
    const float* omega  = (const float*)d_in[24];
    const float* cls_w  = (const float*)d_in[25];
    const float* cls_b  = (const float*)d_in[26];

    float *p_h, *p_v, *p_Qf, *p_Kf, *p_kv, *p_ks, *p_kp, *p_z, *p_bqkv;
    __half *p_h16, *p_t016, *p_qkv16, *p_ffn16, *p_attn16;
    __half *p_wqkvT, *p_w1T, *p_w2T, *p_woT, *p_ew2T;
    cudaGetSymbolAddress((void**)&p_h,    g_h);
    cudaGetSymbolAddress((void**)&p_v,    g_v);
    cudaGetSymbolAddress((void**)&p_Qf,   g_Qf);
    cudaGetSymbolAddress((void**)&p_Kf,   g_Kf);
    cudaGetSymbolAddress((void**)&p_kv,   g_kv);
    cudaGetSymbolAddress((void**)&p_ks,   g_ks);
    cudaGetSymbolAddress((void**)&p_kp,   g_kp);
    cudaGetSymbolAddress((void**)&p_z,    g_z);
    cudaGetSymbolAddress((void**)&p_bqkv, g_bqkv);
    cudaGetSymbolAddress((void**)&p_h16,  g_h16);
    cudaGetSymbolAddress((void**)&p_t016, g_t016);
    cudaGetSymbolAddress((void**)&p_qkv16,g_qkv16);
    cudaGetSymbolAddress((void**)&p_ffn16,g_ffn16);
    cudaGetSymbolAddress((void**)&p_attn16,g_attn16);
    cudaGetSymbolAddress((void**)&p_wqkvT,g_wqkvT);
    cudaGetSymbolAddress((void**)&p_w1T,  g_w1T);
    cudaGetSymbolAddress((void**)&p_w2T,  g_w2T);
    cudaGetSymbolAddress((void**)&p_woT,  g_woT);
    cudaGetSymbolAddress((void**)&p_ew2T, g_ew2T);

    // smem sizes
    const int SM_H    = 3 * 2 * 128 * 40 * 2;                 // 61440 (hgemm)
    const int SM_KV   = 3 * (16 * 136 * 4 + 16 * 72 * 2);     // 33024 (AT=1, HB=1)
    const int SM_ATTN = 3 * (128 * 20 * 4 + 16 * 72 * 4);     // 44544 (AT=0, HB=0)
    cudaFuncSetAttribute(hgemm<0>, cudaFuncAttributeMaxDynamicSharedMemorySize, SM_H);
    cudaFuncSetAttribute(hgemm<1>, cudaFuncAttributeMaxDynamicSharedMemorySize, SM_H);
    cudaFuncSetAttribute(mma_gemm<128,64,4,2,1,3,1,0>,
        cudaFuncAttributeMaxDynamicSharedMemorySize, SM_KV);
    cudaFuncSetAttribute(mma_gemm<128,64,4,2,0,3,0,1>,
        cudaFuncAttributeMaxDynamicSharedMemorySize, SM_ATTN);

    // ---- weight prep: transpose+convert ----
    transpose_h<<<dim3(16,16,4), 256>>>(wq, p_wqkvT,            DMODEL, DMODEL, 512*512, (long long)QKVW*DMODEL);
    transpose_h<<<dim3(16,16,4), 256>>>(wk, p_wqkvT + 512*512,  DMODEL, DMODEL, 512*512, (long long)QKVW*DMODEL);
    transpose_h<<<dim3(16,16,4), 256>>>(wv, p_wqkvT + 1024*512, DMODEL, DMODEL, 512*512, (long long)QKVW*DMODEL);
    transpose_h<<<dim3(32,16,4), 256>>>(w1, p_w1T, DMODEL, FFNH, (long long)512*1024, (long long)FFNH*DMODEL);
    transpose_h<<<dim3(16,32,4), 256>>>(w2, p_w2T, FFNH, DMODEL, (long long)1024*512, (long long)DMODEL*FFNH);
    transpose_h<<<dim3(16,16,4), 256>>>(wo, p_woT, DMODEL, DMODEL, 512*512, 512*512);
    transpose_h<<<dim3(16,8,1),  256>>>(enc_w2, p_ew2T, 256, DMODEL, 0, 0);
    prep_bias_kernel<<<(NLAYERS*QKVW + 255)/256, 256>>>(bq, bk, bv, p_bqkv);

    auto dense = [&](const __half* A, const __half* Bt, const float* bias,
                     void* C, int M, int Nn, int K, int relu, int outh) {
        dim3 grid(Nn / 128, M / 128, 1);
        if (outh) hgemm<1><<<grid, 256, SM_H>>>(A, Bt, bias, C, M, Nn, K, relu);
        else      hgemm<0><<<grid, 256, SM_H>>>(A, Bt, bias, C, M, Nn, K, relu);
    };

    // ---- encoder ----
    enc1_kernel<<<NTOK, 256>>>(x, pos, enc_w1, enc_b1, p_t016);
    dense(p_t016, p_ew2T, enc_b2, p_v, NTOK, DMODEL, 256, 0, 0);
    ln_kernel<<<NTOK, 512>>>(p_h, p_h16, nullptr, p_v, enc_g, enc_bb);

    for (int l = 0; l < NLAYERS; l++) {
        const __half* WqkvT = p_wqkvT + (long long)l * QKVW * DMODEL;
        const float*  Bqkv  = p_bqkv + l * QKVW;
        const __half* WoT   = p_woT + (long long)l * DMODEL * DMODEL;
        const float*  Bo    = bo + l * DMODEL;
        const __half* W1T   = p_w1T + (long long)l * FFNH * DMODEL;
        const float*  B1    = b1 + l * FFNH;
        const __half* W2T   = p_w2T + (long long)l * DMODEL * FFNH;
        const float*  B2    = b2 + l * DMODEL;
        const float*  Om    = omega + (long long)l * HD * 128;

        // merged QKV projection (half out)
        dense(p_h16, WqkvT, Bqkv, p_qkv16, NTOK, QKVW, DMODEL, 0, 1);

        // FAVOR(K) + partial ksum; reduce; FAVOR(Q) + fused z
        favor_kernel<<<dim3(NTOK/4, NH), 128>>>(p_qkv16, Om, p_Kf, nullptr, nullptr, p_kp, 512);
        ksum2_kernel<<<BATCH*NH, 256>>>(p_kp, p_ks);
        favor_kernel<<<dim3(NTOK/4, NH), 128>>>(p_qkv16, Om, p_Qf, p_z, p_ks, nullptr, 0);

        // kv[b,h,f,d] = sum_s Kf[s][f] * v[s][d]   (A trans fp32, B half)
        {
            dim3 grid(1, NF / 128, BATCH * NH);
            mma_gemm<128,64,4,2,1,3,1,0><<<grid, 256, SM_KV>>>(
                p_Kf, p_qkv16 + 1024, nullptr, p_kv,
                SEQ,
                1LL, (long long)NF, (long long)QKVW, (long long)HD,
                (long long)NH * SEQ * NF, (long long)SEQ * NF,
                (long long)SEQ * QKVW, (long long)HD,
                (long long)NH * NF * HD, (long long)NF * HD,
                0, 0, NH);
        }

        // attn[s][h*64+d] = z * Qf[s][:] @ kv  (half out)
        {
            dim3 grid(1, SEQ / 128, BATCH * NH);
            mma_gemm<128,64,4,2,0,3,0,1><<<grid, 256, SM_ATTN>>>(
                p_Qf, p_kv, p_z, p_attn16,
                NF,
                (long long)NF, 1LL, (long long)HD, (long long)DMODEL,
                (long long)NH * SEQ * NF, (long long)SEQ * NF,
                (long long)NH * NF * HD, (long long)NF * HD,
                (long long)SEQ * DMODEL, (long long)HD,
                (long long)NH * SEQ, (long long)SEQ,
                NH);
        }

        // output projection + residual LN
        dense(p_attn16, WoT, Bo, p_v, NTOK, DMODEL, DMODEL, 0, 0);
        ln_kernel<<<NTOK, 512>>>(p_h, p_h16, p_h, p_v, ln1_g + l*DMODEL, ln1_b + l*DMODEL);

        // FFN + residual LN
        dense(p_h16, W1T, B1, p_ffn16, NTOK, FFNH, DMODEL, 1, 1);
        dense(p_ffn16, W2T, B2, p_v, NTOK, DMODEL, FFNH, 0, 0);
        ln_kernel<<<NTOK, 512>>>(p_h, p_h16, p_h, p_v, ln2_g + l*DMODEL, ln2_b + l*DMODEL);
    }

    pool_cls_kernel<<<BATCH, 512>>>(p_h, cls_w, cls_b, (float*)d_out);
}

// round 10
// speedup vs baseline: 5.0909x; 1.0453x over previous
#include <cuda_runtime.h>
#include <cuda_fp16.h>
#include <math.h>

#define BATCH 16
#define SEQ 1024
#define NTOK (BATCH*SEQ)
#define DMODEL 512
#define NH 8
#define HD 64
#define NF 256
#define NLAYERS 4
#define FFNH 1024
#define QKVW 1536

// ---------------- scratch ----------------
__device__ float  g_h   [NTOK*DMODEL];
__device__ __half g_h16 [NTOK*DMODEL];
__device__ __half g_t016[NTOK*256];
__device__ __half g_qkv16[NTOK*QKVW];
__device__ __half g_ffn16[NTOK*FFNH];
__device__ __half g_attn16[NTOK*DMODEL];
__device__ float  g_v   [NTOK*DMODEL];
__device__ float  g_Qf  [BATCH*NH*SEQ*NF];
__device__ float  g_Kf  [BATCH*NH*SEQ*NF];
__device__ float  g_kv  [BATCH*NH*NF*HD];
__device__ float  g_ks  [BATCH*NH*NF];
__device__ float  g_kp  [BATCH*NH*256*NF];
__device__ float  g_z   [BATCH*NH*SEQ];
__device__ __half g_wqkvT[NLAYERS*QKVW*DMODEL];
__device__ float  g_bqkv [NLAYERS*QKVW];
__device__ __half g_w1T  [NLAYERS*FFNH*DMODEL];
__device__ __half g_w2T  [NLAYERS*DMODEL*FFNH];
__device__ __half g_woT  [NLAYERS*DMODEL*DMODEL];
__device__ __half g_ew2T [DMODEL*256];

__device__ __forceinline__ float f2tf32(float x) {
    unsigned u;
    asm("cvt.rna.tf32.f32 %0, %1;" : "=r"(u) : "f"(x));
    return __uint_as_float(u);
}

__device__ __forceinline__ void mma_tf32(float* d, const float* a, const float* b) {
    asm volatile(
        "mma.sync.aligned.m16n8k8.row.col.f32.tf32.tf32.f32 "
        "{%0,%1,%2,%3},{%4,%5,%6,%7},{%8,%9},{%0,%1,%2,%3};\n"
        : "+f"(d[0]), "+f"(d[1]), "+f"(d[2]), "+f"(d[3])
        : "r"(__float_as_uint(a[0])), "r"(__float_as_uint(a[1])),
          "r"(__float_as_uint(a[2])), "r"(__float_as_uint(a[3])),
          "r"(__float_as_uint(b[0])), "r"(__float_as_uint(b[1])));
}

__device__ __forceinline__ void mma_f16(float* d, const unsigned* a, const unsigned* b) {
    asm volatile(
        "mma.sync.aligned.m16n8k16.row.col.f32.f16.f16.f32 "
        "{%0,%1,%2,%3},{%4,%5,%6,%7},{%8,%9},{%0,%1,%2,%3};\n"
        : "+f"(d[0]), "+f"(d[1]), "+f"(d[2]), "+f"(d[3])
        : "r"(a[0]), "r"(a[1]), "r"(a[2]), "r"(a[3]),
          "r"(b[0]), "r"(b[1]));
}

__device__ __forceinline__ void ldsm_x4(unsigned& r0, unsigned& r1,
                                        unsigned& r2, unsigned& r3, unsigned addr) {
    asm volatile("ldmatrix.sync.aligned.m8n8.x4.shared.b16 {%0,%1,%2,%3}, [%4];"
        : "=r"(r0), "=r"(r1), "=r"(r2), "=r"(r3) : "r"(addr));
}

__device__ __forceinline__ void cpa16(void* dst, const void* src) {
    unsigned s = (unsigned)__cvta_generic_to_shared(dst);
    asm volatile("cp.async.ca.shared.global [%0], [%1], 16;\n" :: "r"(s), "l"(src));
}
#define CP_COMMIT  asm volatile("cp.async.commit_group;\n")

// ================= fp16 dense GEMM: C = A[M][K] @ B^T (B stored [N][K]) =================
// ldmatrix fragment loads; 128x128x32 tile, 8 warps, 3-stage cp.async.
template<int OUTH>
__global__ void __launch_bounds__(256, 2) hgemm(
    const __half* __restrict__ A, const __half* __restrict__ B,
    const float* __restrict__ bias, void* __restrict__ Cout,
    int M, int N, int K, int relu)
{
    constexpr int BM = 128, BN = 128, BK = 32, NS = 3;
    constexpr int PITCH = BK + 8;            // 40 halves = 80B rows
    constexpr int TSZ = BM * PITCH;

    extern __shared__ __half hsm[];
    unsigned sb = (unsigned)__cvta_generic_to_shared(hsm);

    int m0 = blockIdx.y * BM;
    int n0 = blockIdx.x * BN;
    int tid = threadIdx.x;
    int warp = tid >> 5, lane = tid & 31;
    int wy = warp & 1, wx = warp >> 1;
    int wm = wy * 64, wn = wx * 32;

    int lrow = lane & 15, lk = lane >> 4;

    float acc[4][4][4];
#pragma unroll
    for (int i = 0; i < 4; i++)
#pragma unroll
        for (int j = 0; j < 4; j++)
#pragma unroll
            for (int c = 0; c < 4; c++) acc[i][j][c] = 0.f;

    auto loadT = [&](__half* S, const __half* G, int row0, int ld, int kt) {
#pragma unroll
        for (int i = 0; i < 2; i++) {
            int e = tid + i * 256;
            int row = e >> 2, q = (e & 3) * 8;
            cpa16(&S[row * PITCH + q], G + (long long)(row0 + row) * ld + kt + q);
        }
    };

    int T = K / BK;
#pragma unroll
    for (int s = 0; s < NS - 1; s++) {
        loadT(hsm + s * TSZ, A, m0, K, s * BK);
        loadT(hsm + (NS + s) * TSZ, B, n0, K, s * BK);
        CP_COMMIT;
    }

    int st = 0, ps = NS - 1;
    for (int t = 0; t < T; t++) {
        asm volatile("cp.async.wait_group %0;\n" :: "n"(NS - 2));
        __syncthreads();
        int pf = t + NS - 1;
        if (pf < T) {
            loadT(hsm + ps * TSZ, A, m0, K, pf * BK);
            loadT(hsm + (NS + ps) * TSZ, B, n0, K, pf * BK);
        }
        CP_COMMIT;

        unsigned sA = sb + st * (TSZ * 2);
        unsigned sB = sb + (NS + st) * (TSZ * 2);
        unsigned aB = sA + (wm + lrow) * (PITCH * 2) + lk * 16;
        unsigned bB = sB + (wn + lrow) * (PITCH * 2) + lk * 16;

#pragma unroll
        for (int ks = 0; ks < 2; ks++) {
            unsigned kb = ks * 32;           // 16 halves * 2B
            unsigned a[4][4], b0q[4], b1q[4];
#pragma unroll
            for (int i = 0; i < 4; i++)
                ldsm_x4(a[i][0], a[i][1], a[i][2], a[i][3],
                        aB + i * (16 * PITCH * 2) + kb);
            ldsm_x4(b0q[0], b0q[1], b0q[2], b0q[3], bB + kb);
            ldsm_x4(b1q[0], b1q[1], b1q[2], b1q[3], bB + 16 * (PITCH * 2) + kb);
            unsigned bfr[4][2] = {
                {b0q[0], b0q[2]}, {b0q[1], b0q[3]},
                {b1q[0], b1q[2]}, {b1q[1], b1q[3]}};
#pragma unroll
            for (int i = 0; i < 4; i++)
#pragma unroll
                for (int j = 0; j < 4; j++)
                    mma_f16(acc[i][j], a[i], bfr[j]);
        }
        st = (st + 1 == NS) ? 0 : st + 1;
        ps = (ps + 1 == NS) ? 0 : ps + 1;
    }

#pragma unroll
    for (int i = 0; i < 4; i++) {
        int mA = m0 + wm + i * 16 + (lane >> 2);
        int mB = mA + 8;
#pragma unroll
        for (int j = 0; j < 4; j++) {
            int n = n0 + wn + j * 8 + (lane & 3) * 2;
            float b0 = bias ? bias[n] : 0.f;
            float b1 = bias ? bias[n + 1] : 0.f;
            float v00 = acc[i][j][0] + b0, v01 = acc[i][j][1] + b1;
            float v10 = acc[i][j][2] + b0, v11 = acc[i][j][3] + b1;
            if (relu) {
                v00 = fmaxf(v00, 0.f); v01 = fmaxf(v01, 0.f);
                v10 = fmaxf(v10, 0.f); v11 = fmaxf(v11, 0.f);
            }
            if (OUTH) {
                __half* C = (__half*)Cout;
                __half2 h0; h0.x = __float2half(v00); h0.y = __float2half(v01);
                __half2 h1; h1.x = __float2half(v10); h1.y = __float2half(v11);
                *(__half2*)(C + (long long)mA * N + n) = h0;
                *(__half2*)(C + (long long)mB * N + n) = h1;
            } else {
                float* C = (float*)Cout;
                *(float2*)(C + (long long)mA * N + n) = make_float2(v00, v01);
                *(float2*)(C + (long long)mB * N + n) = make_float2(v10, v11);
            }
        }
    }
}

// ================= tf32 batched GEMM (attention) =================
template<int BM, int BN, int WY, int WX, int AT, int NS, int HB, int OUTH>
__global__ void __launch_bounds__(256, 2) mma_gemm(
    const float* __restrict__ A, const void* __restrict__ B,
    const float* __restrict__ rscale, void* __restrict__ Cv,
    int K,
    long long sAm, long long sAk, long long sBk, long long sCm,
    long long oA1, long long oA2, long long oB1, long long oB2,
    long long oC1, long long oC2, long long oS1, long long oS2,
    int Hdiv)
{
    constexpr int BK  = 16;
    constexpr int MT  = BM / WY / 16;
    constexpr int NT  = BN / WX / 8;
    constexpr int APITCH = (AT == 0) ? 20 : (BM + 8);
    constexpr int BPITCH = BN + 8;
    constexpr int ASZB = ((AT == 0) ? BM * 20 : BK * (BM + 8)) * 4;
    constexpr int BSZB = HB ? BK * BPITCH * 2 : BK * BPITCH * 4;
    constexpr int AQ  = BM * BK / 4 / 256;

    extern __shared__ char smraw[];
    char* AsBase = smraw;
    char* BsBase = smraw + NS * ASZB;

    int z  = blockIdx.z;
    int z1 = z / Hdiv, z2 = z - z1 * Hdiv;
    const float* Ap = A + z1 * oA1 + z2 * oA2;
    const float* Bpf = HB ? nullptr : (const float*)B + z1 * oB1 + z2 * oB2;
    const __half* Bph = HB ? (const __half*)B + z1 * oB1 + z2 * oB2 : nullptr;
    long long    oS = z1 * oS1 + z2 * oS2;

    int m0 = blockIdx.y * BM;
    int n0 = blockIdx.x * BN;
    int tid = threadIdx.x;
    int warp = tid >> 5, lane = tid & 31;
    int wy = warp % WY, wx = warp / WY;
    int wm = wy * (BM / WY), wn = wx * (BN / WX);

    float acc[MT][NT][4];
#pragma unroll
    for (int i = 0; i < MT; i++)
#pragma unroll
        for (int j = 0; j < NT; j++)
#pragma unroll
            for (int c = 0; c < 4; c++) acc[i][j][c] = 0.f;

    auto loadA = [&](int st, int kt) {
        float* As = (float*)(AsBase + st * ASZB);
#pragma unroll
        for (int i = 0; i < AQ; i++) {
            int e = tid + i * 256;
            if (AT == 0) {
                int row = e >> 2, q = (e & 3) * 4;
                cpa16(&As[row * 20 + q],
                      Ap + (long long)(m0 + row) * sAm + (kt + q));
            } else {
                constexpr int QPR = BM / 4;
                int kk = e / QPR, q = (e % QPR) * 4;
                cpa16(&As[kk * APITCH + q],
                      Ap + (long long)(kt + kk) * sAk + (m0 + q));
            }
        }
    };
    auto loadB = [&](int st, int kt) {
        if (HB) {
            __half* Bs = (__half*)(BsBase + st * BSZB);
            if (tid < BK * BN / 8) {
                int kk = tid >> 3, q = (tid & 7) * 8;
                cpa16(&Bs[kk * BPITCH + q],
                      Bph + (long long)(kt + kk) * sBk + (n0 + q));
            }
        } else {
            float* Bs = (float*)(BsBase + st * BSZB);
            constexpr int BQ = BK * BN / 4 / 256;
#pragma unroll
            for (int i = 0; i < BQ; i++) {
                int e = tid + i * 256;
                constexpr int QPR = BN / 4;
                int kk = e / QPR, q = (e % QPR) * 4;
                cpa16(&Bs[kk * BPITCH + q],
                      Bpf + (long long)(kt + kk) * sBk + (n0 + q));
            }
        }
    };

    int T = K / BK;
#pragma unroll
    for (int s = 0; s < NS - 1; s++) { loadA(s, s * BK); loadB(s, s * BK); CP_COMMIT; }

    int st = 0, ps = NS - 1;
    for (int t = 0; t < T; t++) {
        asm volatile("cp.async.wait_group %0;\n" :: "n"(NS - 2));
        __syncthreads();
        int pf = t + NS - 1;
        if (pf < T) { loadA(ps, pf * BK); loadB(ps, pf * BK); }
        CP_COMMIT;

        const float* As = (const float*)(AsBase + st * ASZB);
        const float* Bsf = (const float*)(BsBase + st * BSZB);
        const __half* Bsh = (const __half*)(BsBase + st * BSZB);
#pragma unroll
        for (int k0 = 0; k0 < BK; k0 += 8) {
            float afr[MT][4], bfr[NT][2];
            int kc = k0 + (lane & 3);
#pragma unroll
            for (int i = 0; i < MT; i++) {
                int row = wm + i * 16 + (lane >> 2);
                if (AT == 0) {
                    afr[i][0] = As[row * 20 + kc];
                    afr[i][1] = As[(row + 8) * 20 + kc];
                    afr[i][2] = As[row * 20 + kc + 4];
                    afr[i][3] = As[(row + 8) * 20 + kc + 4];
                } else {
                    afr[i][0] = As[kc * APITCH + row];
                    afr[i][1] = As[kc * APITCH + row + 8];
                    afr[i][2] = As[(kc + 4) * APITCH + row];
                    afr[i][3] = As[(kc + 4) * APITCH + row + 8];
                }
            }
#pragma unroll
            for (int j = 0; j < NT; j++) {
                int col = wn + j * 8 + (lane >> 2);
                if (HB) {
                    bfr[j][0] = __half2float(Bsh[kc * BPITCH + col]);
                    bfr[j][1] = __half2float(Bsh[(kc + 4) * BPITCH + col]);
                } else {
                    bfr[j][0] = Bsf[kc * BPITCH + col];
                    bfr[j][1] = Bsf[(kc + 4) * BPITCH + col];
                }
            }
#pragma unroll
            for (int i = 0; i < MT; i++)
#pragma unroll
                for (int j = 0; j < NT; j++)
                    mma_tf32(acc[i][j], afr[i], bfr[j]);
        }
        st = (st + 1 == NS) ? 0 : st + 1;
        ps = (ps + 1 == NS) ? 0 : ps + 1;
    }

#pragma unroll
    for (int i = 0; i < MT; i++) {
        int mA = m0 + wm + i * 16 + (lane >> 2);
        int mB = mA + 8;
        float rsA = rscale ? rscale[oS + mA] : 1.f;
        float rsB = rscale ? rscale[oS + mB] : 1.f;
#pragma unroll
        for (int j = 0; j < NT; j++) {
            int n = n0 + wn + j * 8 + (lane & 3) * 2;
            float v00 = acc[i][j][0] * rsA, v01 = acc[i][j][1] * rsA;
            float v10 = acc[i][j][2] * rsB, v11 = acc[i][j][3] * rsB;
            if (OUTH) {
                __half* Cp = (__half*)Cv + z1 * oC1 + z2 * oC2;
                __half2 h0; h0.x = __float2half(v00); h0.y = __float2half(v01);
                __half2 h1; h1.x = __float2half(v10); h1.y = __float2half(v11);
                *(__half2*)(Cp + (long long)mA * sCm + n) = h0;
                *(__half2*)(Cp + (long long)mB * sCm + n) = h1;
            } else {
                float* Cp = (float*)Cv + z1 * oC1 + z2 * oC2;
                *(float2*)(Cp + (long long)mA * sCm + n) =
                    make_float2(f2tf32(v00), f2tf32(v01));
                *(float2*)(Cp + (long long)mB * sCm + n) =
                    make_float2(f2tf32(v10), f2tf32(v11));
            }
        }
    }
}

// ---------------- prep: tiled transpose fp32[K][N] -> half[N][K] ----------------
__global__ void __launch_bounds__(256) transpose_h(
    const float* __restrict__ in, __half* __restrict__ out, int K, int N,
    long long inL, long long outL)
{
    __shared__ float tile[32][33];
    const float* ip = in + blockIdx.z * inL;
    __half* op = out + blockIdx.z * outL;
    int n0 = blockIdx.x * 32, k0 = blockIdx.y * 32;
    int tx = threadIdx.x & 31, ty = threadIdx.x >> 5;
#pragma unroll
    for (int r = 0; r < 4; r++)
        tile[ty + r * 8][tx] = ip[(long long)(k0 + ty + r * 8) * N + n0 + tx];
    __syncthreads();
#pragma unroll
    for (int r = 0; r < 4; r++)
        op[(long long)(n0 + ty + r * 8) * K + k0 + tx] = __float2half(tile[tx][ty + r * 8]);
}

__global__ void __launch_bounds__(256) prep_bias_kernel(
    const float* __restrict__ bq, const float* __restrict__ bk,
    const float* __restrict__ bv, float* __restrict__ bqkv)
{
    int idx = blockIdx.x * 256 + threadIdx.x;
    if (idx < NLAYERS * QKVW) {
        int l = idx / QKVW, c = idx % QKVW;
        const float* src = c < 512 ? bq : (c < 1024 ? bk : bv);
        bqkv[idx] = src[l * DMODEL + (c & 511)];
    }
}

// ---------------- encoder first layer ----------------
__global__ void __launch_bounds__(256) enc1_kernel(
    const float* __restrict__ x, const float* __restrict__ pos,
    const float* __restrict__ w, const float* __restrict__ b,
    __half* __restrict__ out)
{
    int idx = blockIdx.x * 256 + threadIdx.x;
    int row = idx >> 8, col = idx & 255;
    const float* xr = x + row * 3;
    const float* pr = pos + row * 3;
    float a = b[col];
#pragma unroll
    for (int d = 0; d < 3; d++) a = fmaf(xr[d], w[d * 256 + col], a);
#pragma unroll
    for (int d = 0; d < 3; d++) a = fmaf(pr[d], w[(3 + d) * 256 + col], a);
    out[idx] = __float2half(fmaxf(a, 0.f));
}

// ---------------- LayerNorm: writes fp32 + half ----------------
__global__ void __launch_bounds__(512) ln_kernel(
    float* __restrict__ out, __half* __restrict__ out16,
    const float* __restrict__ resid, const float* __restrict__ y,
    const float* __restrict__ g, const float* __restrict__ b)
{
    int row = blockIdx.x, t = threadIdx.x;
    long long base = (long long)row * 512;
    float v = y[base + t];
    if (resid) v += resid[base + t];
    float s = v, s2 = v * v;
#pragma unroll
    for (int o = 16; o; o >>= 1) {
        s  += __shfl_xor_sync(0xffffffffu, s,  o);
        s2 += __shfl_xor_sync(0xffffffffu, s2, o);
    }
    __shared__ float rs[16], rs2[16];
    int w = t >> 5, lane = t & 31;
    if (!lane) { rs[w] = s; rs2[w] = s2; }
    __syncthreads();
    if (t < 32) {
        float a  = (t < 16) ? rs[t]  : 0.f;
        float a2 = (t < 16) ? rs2[t] : 0.f;
#pragma unroll
        for (int o = 8; o; o >>= 1) {
            a  += __shfl_xor_sync(0xffffffffu, a,  o);
            a2 += __shfl_xor_sync(0xffffffffu, a2, o);
        }
        if (!t) { rs[0] = a; rs2[0] = a2; }
    }
    __syncthreads();
    float mean = rs[0] * (1.f / 512.f);
    float var  = rs2[0] * (1.f / 512.f) - mean * mean;
    float r = (v - mean) * rsqrtf(var + 1e-5f) * g[t] + b[t];
    out[base + t] = r;
    out16[base + t] = __float2half(r);
}

// ---------------- FAVOR+ feature map (4 rows/block), reads half qkv ----------------
__global__ void __launch_bounds__(128) favor_kernel(
    const __half* __restrict__ qkv, const float* __restrict__ omega,
    float* __restrict__ outF, float* __restrict__ zOut,
    const float* __restrict__ ks, float* __restrict__ part, int colOff)
{
    int r0 = blockIdx.x * 4;
    int hh_ = blockIdx.y, t = threadIdx.x;
    __shared__ float xv[4][64];
    __shared__ float hvs[4];
#pragma unroll
    for (int i = 0; i < 2; i++) {
        int e = t + i * 128;
        int r = e >> 6, d = e & 63;
        xv[r][d] = __half2float(qkv[(long long)(r0 + r) * QKVW + colOff + hh_ * 64 + d])
                   * 0.3535533905932738f;
    }
    __syncthreads();
    {
        int w = t >> 5, lane = t & 31;
        float a = xv[w][lane], bb = xv[w][lane + 32];
        float s = a * a + bb * bb;
#pragma unroll
        for (int o = 16; o; o >>= 1) s += __shfl_xor_sync(0xffffffffu, s, o);
        if (!lane) hvs[w] = s * 0.5f;
    }
    __syncthreads();
    float u0 = 0.f, u1 = 0.f, u2 = 0.f, u3 = 0.f;
#pragma unroll 8
    for (int d = 0; d < 64; d++) {
        float om = omega[d * 128 + t];
        u0 = fmaf(xv[0][d], om, u0);
        u1 = fmaf(xv[1][d], om, u1);
        u2 = fmaf(xv[2][d], om, u2);
        u3 = fmaf(xv[3][d], om, u3);
    }
    int b = r0 >> 10;
    int bh = b * NH + hh_;
    long long ob = ((long long)bh * SEQ + (r0 & 1023)) * NF;
    float uu[4] = {u0, u1, u2, u3};
    float fa[4], fb[4];
#pragma unroll
    for (int r = 0; r < 4; r++) {
        float hv = hvs[r];
        fa[r] = f2tf32(expf( uu[r] - hv) * 0.0625f);
        fb[r] = f2tf32(expf(-uu[r] - hv) * 0.0625f);
        long long o = ob + (long long)r * NF;
        outF[o + t]       = fa[r];
        outF[o + 128 + t] = fb[r];
    }
    if (part) {
        int blk = (r0 & 1023) >> 2;
        long long po = ((long long)bh * 256 + blk) * NF;
        part[po + t]       = fa[0] + fa[1] + fa[2] + fa[3];
        part[po + 128 + t] = fb[0] + fb[1] + fb[2] + fb[3];
    }
    if (zOut) {
        float ka = ks[bh * NF + t];
        float kb = ks[bh * NF + 128 + t];
        float p[4];
#pragma unroll
        for (int r = 0; r < 4; r++) p[r] = fa[r] * ka + fb[r] * kb;
#pragma unroll
        for (int o = 16; o; o >>= 1)
#pragma unroll
            for (int r = 0; r < 4; r++) p[r] += __shfl_xor_sync(0xffffffffu, p[r], o);
        __shared__ float pr[4][4];
        int w = t >> 5, lane = t & 31;
        if (!lane) {
#pragma unroll
            for (int r = 0; r < 4; r++) pr[w][r] = p[r];
        }
        __syncthreads();
        if (t < 4) {
            float s = pr[0][t] + pr[1][t] + pr[2][t] + pr[3][t];
            zOut[bh * SEQ + (r0 & 1023) + t] = 1.f / (s + 1e-6f);
        }
    }
}

// ---------------- ksum final reduce ----------------
__global__ void __launch_bounds__(256) ksum2_kernel(
    const float* __restrict__ part, float* __restrict__ ks)
{
    int bh = blockIdx.x, f = threadIdx.x;
    const float* p = part + (long long)bh * 256 * NF + f;
    float s = 0.f;
#pragma unroll 8
    for (int c = 0; c < 256; c++) s += p[(long long)c * NF];
    ks[bh * NF + f] = s;
}

// ---------------- mean pool + classifier ----------------
__global__ void __launch_bounds__(512) pool_cls_kernel(
    const float* __restrict__ h, const float* __restrict__ cw,
    const float* __restrict__ cb, float* __restrict__ out)
{
    int b = blockIdx.x, t = threadIdx.x;
    const float* base = h + (long long)b * SEQ * DMODEL + t;
    float s = 0.f;
#pragma unroll 8
    for (int i = 0; i < SEQ; i++) s += base[(long long)i * DMODEL];
    __shared__ float pooled[DMODEL];
    pooled[t] = s * (1.f / (float)SEQ);
    __syncthreads();
    if (t < 16) {
        float acc = cb[t];
        for (int d = 0; d < DMODEL; d++) acc = fmaf(pooled[d], cw[d * 16 + t], acc);
        out[b * 16 + t] = acc;
    }
}

// ---------------- host driver ----------------
extern "C" void kernel_launch(void* const* d_in, const int* in_sizes, int n_in,
                              void* d_out, int out_size)
{
    const float* x      = (const float*)d_in[0];
    const float* pos    = (const float*)d_in[1];
    const float* enc_w1 = (const float*)d_in[2];
    const float* enc_b1 = (const float*)d_in[3];
    const float* enc_w2 = (const float*)d_in[4];
    const float* enc_b2 = (const float*)d_in[5];
    const float* enc_g  = (const float*)d_in[6];
    const float* enc_bb = (const float*)d_in[7];
    const float* wq     = (const float*)d_in[8];
    const float* bq     = (const float*)d_in[9];
    const float* wk     = (const float*)d_in[10];
    const float* bk     = (const float*)d_in[11];
    const float* wv     = (const float*)d_in[12];
    const float* bv     = (const float*)d_in[13];
    const float* wo     = (const float*)d_in[14];
    const float* bo     = (const float*)d_in[15];
    const float* ln1_g  = (const float*)d_in[16];
    const float* ln1_b  = (const float*)d_in[17];
    const float* w1     = (const float*)d_in[18];
    const float* b1     = (const float*)d_in[19];
    const float* w2     = (const float*)d_in[20];
    const float* b2     = (const float*)d_in[21];
    const float* ln2_g  = (const float*)d_in[22];
    const float* ln2_b  = (const float*)d_in[23];
    const float* omega  = (const float*)d_in[24];
    const float* cls_w  = (const float*)d_in[25];
    const float* cls_b  = (const float*)d_in[26];

    float *p_h, *p_v, *p_Qf, *p_Kf, *p_kv, *p_ks, *p_kp, *p_z, *p_bqkv;
    __half *p_h16, *p_t016, *p_qkv16, *p_ffn16, *p_attn16;
    __half *p_wqkvT, *p_w1T, *p_w2T, *p_woT, *p_ew2T;
    cudaGetSymbolAddress((void**)&p_h,    g_h);
    cudaGetSymbolAddress((void**)&p_v,    g_v);
    cudaGetSymbolAddress((void**)&p_Qf,   g_Qf);
    cudaGetSymbolAddress((void**)&p_Kf,   g_Kf);
    cudaGetSymbolAddress((void**)&p_kv,   g_kv);
    cudaGetSymbolAddress((void**)&p_ks,   g_ks);
    cudaGetSymbolAddress((void**)&p_kp,   g_kp);
    cudaGetSymbolAddress((void**)&p_z,    g_z);
    cudaGetSymbolAddress((void**)&p_bqkv, g_bqkv);
    cudaGetSymbolAddress((void**)&p_h16,  g_h16);
    cudaGetSymbolAddress((void**)&p_t016, g_t016);
    cudaGetSymbolAddress((void**)&p_qkv16,g_qkv16);
    cudaGetSymbolAddress((void**)&p_ffn16,g_ffn16);
    cudaGetSymbolAddress((void**)&p_attn16,g_attn16);
    cudaGetSymbolAddress((void**)&p_wqkvT,g_wqkvT);
    cudaGetSymbolAddress((void**)&p_w1T,  g_w1T);
    cudaGetSymbolAddress((void**)&p_w2T,  g_w2T);
    cudaGetSymbolAddress((void**)&p_woT,  g_woT);
    cudaGetSymbolAddress((void**)&p_ew2T, g_ew2T);

    // smem sizes
    const int SM_H    = 3 * 2 * 128 * 40 * 2;                 // 61440 (hgemm)
    const int SM_KV   = 3 * (16 * 136 * 4 + 16 * 72 * 2);     // 33024 (AT=1, HB=1)
    const int SM_ATTN = 3 * (128 * 20 * 4 + 16 * 72 * 4);     // 44544 (AT=0, HB=0)
    cudaFuncSetAttribute(hgemm<0>, cudaFuncAttributeMaxDynamicSharedMemorySize, SM_H);
    cudaFuncSetAttribute(hgemm<1>, cudaFuncAttributeMaxDynamicSharedMemorySize, SM_H);
    cudaFuncSetAttribute(mma_gemm<128,64,4,2,1,3,1,0>,
        cudaFuncAttributeMaxDynamicSharedMemorySize, SM_KV);
    cudaFuncSetAttribute(mma_gemm<128,64,4,2,0,3,0,1>,
        cudaFuncAttributeMaxDynamicSharedMemorySize, SM_ATTN);

    // ---- weight prep: transpose+convert ----
    transpose_h<<<dim3(16,16,4), 256>>>(wq, p_wqkvT,            DMODEL, DMODEL, 512*512, (long long)QKVW*DMODEL);
    transpose_h<<<dim3(16,16,4), 256>>>(wk, p_wqkvT + 512*512,  DMODEL, DMODEL, 512*512, (long long)QKVW*DMODEL);
    transpose_h<<<dim3(16,16,4), 256>>>(wv, p_wqkvT + 1024*512, DMODEL, DMODEL, 512*512, (long long)QKVW*DMODEL);
    transpose_h<<<dim3(32,16,4), 256>>>(w1, p_w1T, DMODEL, FFNH, (long long)512*1024, (long long)FFNH*DMODEL);
    transpose_h<<<dim3(16,32,4), 256>>>(w2, p_w2T, FFNH, DMODEL, (long long)1024*512, (long long)DMODEL*FFNH);
    transpose_h<<<dim3(16,16,4), 256>>>(wo, p_woT, DMODEL, DMODEL, 512*512, 512*512);
    transpose_h<<<dim3(16,8,1),  256>>>(enc_w2, p_ew2T, 256, DMODEL, 0, 0);
    prep_bias_kernel<<<(NLAYERS*QKVW + 255)/256, 256>>>(bq, bk, bv, p_bqkv);

    auto dense = [&](const __half* A, const __half* Bt, const float* bias,
                     void* C, int M, int Nn, int K, int relu, int outh) {
        dim3 grid(Nn / 128, M / 128, 1);
        if (outh) hgemm<1><<<grid, 256, SM_H>>>(A, Bt, bias, C, M, Nn, K, relu);
        else      hgemm<0><<<grid, 256, SM_H>>>(A, Bt, bias, C, M, Nn, K, relu);
    };

    // ---- encoder ----
    enc1_kernel<<<NTOK, 256>>>(x, pos, enc_w1, enc_b1, p_t016);
    dense(p_t016, p_ew2T, enc_b2, p_v, NTOK, DMODEL, 256, 0, 0);
    ln_kernel<<<NTOK, 512>>>(p_h, p_h16, nullptr, p_v, enc_g, enc_bb);

    for (int l = 0; l < NLAYERS; l++) {
        const __half* WqkvT = p_wqkvT + (long long)l * QKVW * DMODEL;
        const float*  Bqkv  = p_bqkv + l * QKVW;
        const __half* WoT   = p_woT + (long long)l * DMODEL * DMODEL;
        const float*  Bo    = bo + l * DMODEL;
        const __half* W1T   = p_w1T + (long long)l * FFNH * DMODEL;
        const float*  B1    = b1 + l * FFNH;
        const __half* W2T   = p_w2T + (long long)l * DMODEL * FFNH;
        const float*  B2    = b2 + l * DMODEL;
        const float*  Om    = omega + (long long)l * HD * 128;

        // merged QKV projection (half out)
        dense(p_h16, WqkvT, Bqkv, p_qkv16, NTOK, QKVW, DMODEL, 0, 1);

        // FAVOR(K) + partial ksum; reduce; FAVOR(Q) + fused z
        favor_kernel<<<dim3(NTOK/4, NH), 128>>>(p_qkv16, Om, p_Kf, nullptr, nullptr, p_kp, 512);
        ksum2_kernel<<<BATCH*NH, 256>>>(p_kp, p_ks);
        favor_kernel<<<dim3(NTOK/4, NH), 128>>>(p_qkv16, Om, p_Qf, p_z, p_ks, nullptr, 0);

        // kv[b,h,f,d] = sum_s Kf[s][f] * v[s][d]   (A trans fp32, B half)
        {
            dim3 grid(1, NF / 128, BATCH * NH);
            mma_gemm<128,64,4,2,1,3,1,0><<<grid, 256, SM_KV>>>(
                p_Kf, p_qkv16 + 1024, nullptr, p_kv,
                SEQ,
                1LL, (long long)NF, (long long)QKVW, (long long)HD,
                (long long)NH * SEQ * NF, (long long)SEQ * NF,
                (long long)SEQ * QKVW, (long long)HD,
                (long long)NH * NF * HD, (long long)NF * HD,
                0, 0, NH);
        }

        // attn[s][h*64+d] = z * Qf[s][:] @ kv  (half out)
        {
            dim3 grid(1, SEQ / 128, BATCH * NH);
            mma_gemm<128,64,4,2,0,3,0,1><<<grid, 256, SM_ATTN>>>(
                p_Qf, p_kv, p_z, p_attn16,
                NF,
                (long long)NF, 1LL, (long long)HD, (long long)DMODEL,
                (long long)NH * SEQ * NF, (long long)SEQ * NF,
                (long long)NH * NF * HD, (long long)NF * HD,
                (long long)SEQ * DMODEL, (long long)HD,
                (long long)NH * SEQ, (long long)SEQ,
                NH);
        }

        // output projection + residual LN
        dense(p_attn16, WoT, Bo, p_v, NTOK, DMODEL, DMODEL, 0, 0);
        ln_kernel<<<NTOK, 512>>>(p_h, p_h16, p_h, p_v, ln1_g + l*DMODEL, ln1_b + l*DMODEL);

        // FFN + residual LN
        dense(p_h16, W1T, B1, p_ffn16, NTOK, FFNH, DMODEL, 1, 1);
        dense(p_ffn16, W2T, B2, p_v, NTOK, DMODEL, FFNH, 0, 0);
        ln_kernel<<<NTOK, 512>>>(p_h, p_h16, p_h, p_v, ln2_g + l*DMODEL, ln2_b + l*DMODEL);
    }

    pool_cls_kernel<<<BATCH, 512>>>(p_h, cls_w, cls_b, (float*)d_out);
}

// round 11
// speedup vs baseline: 5.4288x; 1.0664x over previous
#include <cuda_runtime.h>
#include <cuda_fp16.h>
#include <math.h>

#define BATCH 16
#define SEQ 1024
#define NTOK (BATCH*SEQ)
#define DMODEL 512
#define NH 8
#define HD 64
#define NF 256
#define NLAYERS 4
#define FFNH 1024
#define QKVW 1536

// ---------------- scratch ----------------
__device__ float  g_h   [NTOK*DMODEL];
__device__ __half g_h16 [NTOK*DMODEL];
__device__ __half g_t016[NTOK*256];
__device__ __half g_qkv16[NTOK*QKVW];
__device__ __half g_ffn16[NTOK*FFNH];
__device__ __half g_attn16[NTOK*DMODEL];
__device__ float  g_v   [NTOK*DMODEL];
__device__ __half g_Qf  [BATCH*NH*SEQ*NF];
__device__ __half g_Kf  [BATCH*NH*SEQ*NF];
__device__ __half g_kv  [BATCH*NH*NF*HD];
__device__ float  g_ks  [BATCH*NH*NF];
__device__ float  g_kp  [BATCH*NH*256*NF];
__device__ float  g_z   [BATCH*NH*SEQ];
__device__ __half g_wqkvT[NLAYERS*QKVW*DMODEL];
__device__ float  g_bqkv [NLAYERS*QKVW];
__device__ __half g_w1T  [NLAYERS*FFNH*DMODEL];
__device__ __half g_w2T  [NLAYERS*DMODEL*FFNH];
__device__ __half g_woT  [NLAYERS*DMODEL*DMODEL];
__device__ __half g_ew2T [DMODEL*256];

__device__ __forceinline__ void mma_f16(float* d, const unsigned* a, const unsigned* b) {
    asm volatile(
        "mma.sync.aligned.m16n8k16.row.col.f32.f16.f16.f32 "
        "{%0,%1,%2,%3},{%4,%5,%6,%7},{%8,%9},{%0,%1,%2,%3};\n"
        : "+f"(d[0]), "+f"(d[1]), "+f"(d[2]), "+f"(d[3])
        : "r"(a[0]), "r"(a[1]), "r"(a[2]), "r"(a[3]),
          "r"(b[0]), "r"(b[1]));
}

__device__ __forceinline__ void ldsm_x4(unsigned& r0, unsigned& r1,
                                        unsigned& r2, unsigned& r3, unsigned addr) {
    asm volatile("ldmatrix.sync.aligned.m8n8.x4.shared.b16 {%0,%1,%2,%3}, [%4];"
        : "=r"(r0), "=r"(r1), "=r"(r2), "=r"(r3) : "r"(addr));
}
__device__ __forceinline__ void ldsm_x4t(unsigned& r0, unsigned& r1,
                                         unsigned& r2, unsigned& r3, unsigned addr) {
    asm volatile("ldmatrix.sync.aligned.m8n8.x4.trans.shared.b16 {%0,%1,%2,%3}, [%4];"
        : "=r"(r0), "=r"(r1), "=r"(r2), "=r"(r3) : "r"(addr));
}

__device__ __forceinline__ void cpa16(void* dst, const void* src) {
    unsigned s = (unsigned)__cvta_generic_to_shared(dst);
    asm volatile("cp.async.ca.shared.global [%0], [%1], 16;\n" :: "r"(s), "l"(src));
}
#define CP_COMMIT  asm volatile("cp.async.commit_group;\n")

// ================= fp16 dense GEMM: C = A[M][K] @ B^T (B stored [N][K]) =================
template<int OUTH>
__global__ void __launch_bounds__(256, 2) hgemm(
    const __half* __restrict__ A, const __half* __restrict__ B,
    const float* __restrict__ bias, void* __restrict__ Cout,
    int M, int N, int K, int relu)
{
    constexpr int BM = 128, BN = 128, BK = 32, NS = 3;
    constexpr int PITCH = BK + 8;
    constexpr int TSZ = BM * PITCH;

    extern __shared__ __half hsm[];
    unsigned sb = (unsigned)__cvta_generic_to_shared(hsm);

    int m0 = blockIdx.y * BM;
    int n0 = blockIdx.x * BN;
    int tid = threadIdx.x;
    int warp = tid >> 5, lane = tid & 31;
    int wy = warp & 1, wx = warp >> 1;
    int wm = wy * 64, wn = wx * 32;
    int lrow = lane & 15, lk = lane >> 4;

    float acc[4][4][4];
#pragma unroll
    for (int i = 0; i < 4; i++)
#pragma unroll
        for (int j = 0; j < 4; j++)
#pragma unroll
            for (int c = 0; c < 4; c++) acc[i][j][c] = 0.f;

    auto loadT = [&](__half* S, const __half* G, int row0, int ld, int kt) {
#pragma unroll
        for (int i = 0; i < 2; i++) {
            int e = tid + i * 256;
            int row = e >> 2, q = (e & 3) * 8;
            cpa16(&S[row * PITCH + q], G + (long long)(row0 + row) * ld + kt + q);
        }
    };

    int T = K / BK;
#pragma unroll
    for (int s = 0; s < NS - 1; s++) {
        loadT(hsm + s * TSZ, A, m0, K, s * BK);
        loadT(hsm + (NS + s) * TSZ, B, n0, K, s * BK);
        CP_COMMIT;
    }

    int st = 0, ps = NS - 1;
    for (int t = 0; t < T; t++) {
        asm volatile("cp.async.wait_group %0;\n" :: "n"(NS - 2));
        __syncthreads();
        int pf = t + NS - 1;
        if (pf < T) {
            loadT(hsm + ps * TSZ, A, m0, K, pf * BK);
            loadT(hsm + (NS + ps) * TSZ, B, n0, K, pf * BK);
        }
        CP_COMMIT;

        unsigned sA = sb + st * (TSZ * 2);
        unsigned sB = sb + (NS + st) * (TSZ * 2);
        unsigned aB = sA + (wm + lrow) * (PITCH * 2) + lk * 16;
        unsigned bB = sB + (wn + lrow) * (PITCH * 2) + lk * 16;

#pragma unroll
        for (int ks = 0; ks < 2; ks++) {
            unsigned kb = ks * 32;
            unsigned a[4][4], b0q[4], b1q[4];
#pragma unroll
            for (int i = 0; i < 4; i++)
                ldsm_x4(a[i][0], a[i][1], a[i][2], a[i][3],
                        aB + i * (16 * PITCH * 2) + kb);
            ldsm_x4(b0q[0], b0q[1], b0q[2], b0q[3], bB + kb);
            ldsm_x4(b1q[0], b1q[1], b1q[2], b1q[3], bB + 16 * (PITCH * 2) + kb);
            unsigned bfr[4][2] = {
                {b0q[0], b0q[2]}, {b0q[1], b0q[3]},
                {b1q[0], b1q[2]}, {b1q[1], b1q[3]}};
#pragma unroll
            for (int i = 0; i < 4; i++)
#pragma unroll
                for (int j = 0; j < 4; j++)
                    mma_f16(acc[i][j], a[i], bfr[j]);
        }
        st = (st + 1 == NS) ? 0 : st + 1;
        ps = (ps + 1 == NS) ? 0 : ps + 1;
    }

#pragma unroll
    for (int i = 0; i < 4; i++) {
        int mA = m0 + wm + i * 16 + (lane >> 2);
        int mB = mA + 8;
#pragma unroll
        for (int j = 0; j < 4; j++) {
            int n = n0 + wn + j * 8 + (lane & 3) * 2;
            float b0 = bias ? bias[n] : 0.f;
            float b1 = bias ? bias[n + 1] : 0.f;
            float v00 = acc[i][j][0] + b0, v01 = acc[i][j][1] + b1;
            float v10 = acc[i][j][2] + b0, v11 = acc[i][j][3] + b1;
            if (relu) {
                v00 = fmaxf(v00, 0.f); v01 = fmaxf(v01, 0.f);
                v10 = fmaxf(v10, 0.f); v11 = fmaxf(v11, 0.f);
            }
            if (OUTH) {
                __half* C = (__half*)Cout;
                __half2 h0; h0.x = __float2half(v00); h0.y = __float2half(v01);
                __half2 h1; h1.x = __float2half(v10); h1.y = __float2half(v11);
                *(__half2*)(C + (long long)mA * N + n) = h0;
                *(__half2*)(C + (long long)mB * N + n) = h1;
            } else {
                float* C = (float*)Cout;
                *(float2*)(C + (long long)mA * N + n) = make_float2(v00, v01);
                *(float2*)(C + (long long)mB * N + n) = make_float2(v10, v11);
            }
        }
    }
}

// ================= kv GEMM: kv[f][d] = sum_s Kf[s][f] * v[s][d]  (both trans-ldsm) =================
// BM=64 (f), BN=64 (d), BK=32 (s). grid (1, NF/64, BATCH*NH).
__global__ void __launch_bounds__(256, 2) kv_gemm(
    const __half* __restrict__ Kf, const __half* __restrict__ V,
    __half* __restrict__ KV)
{
    constexpr int BK = 32, NS = 3;
    constexpr int PITCH = 72;
    constexpr int TSZ = BK * PITCH;       // 2304 halves

    extern __shared__ __half hsm[];
    unsigned sb = (unsigned)__cvta_generic_to_shared(hsm);

    int bh = blockIdx.z;
    int b = bh >> 3, h = bh & 7;
    const __half* Ap = Kf + (long long)bh * SEQ * NF;
    const __half* Vp = V + (long long)b * SEQ * QKVW + h * HD;
    __half* Cp = KV + (long long)bh * NF * HD;

    int m0 = blockIdx.y * 64;
    int tid = threadIdx.x;
    int warp = tid >> 5, lane = tid & 31;
    int wm = (warp & 1) * 32, wn = (warp >> 1) * 16;

    int trow = (lane & 7) + ((lane >> 4) << 3);
    int tcol = ((lane >> 3) & 1) << 3;

    float acc[2][2][4];
#pragma unroll
    for (int i = 0; i < 2; i++)
#pragma unroll
        for (int j = 0; j < 2; j++)
#pragma unroll
            for (int c = 0; c < 4; c++) acc[i][j][c] = 0.f;

    auto loadA = [&](__half* S, int kt) {
        int kk = tid >> 3, q = (tid & 7) * 8;
        cpa16(&S[kk * PITCH + q], Ap + (long long)(kt + kk) * NF + m0 + q);
    };
    auto loadB = [&](__half* S, int kt) {
        int kk = tid >> 3, q = (tid & 7) * 8;
        cpa16(&S[kk * PITCH + q], Vp + (long long)(kt + kk) * QKVW + q);
    };

    int T = SEQ / BK;
#pragma unroll
    for (int s = 0; s < NS - 1; s++) {
        loadA(hsm + s * TSZ, s * BK);
        loadB(hsm + (NS + s) * TSZ, s * BK);
        CP_COMMIT;
    }

    int st = 0, ps = NS - 1;
    for (int t = 0; t < T; t++) {
        asm volatile("cp.async.wait_group %0;\n" :: "n"(NS - 2));
        __syncthreads();
        int pf = t + NS - 1;
        if (pf < T) {
            loadA(hsm + ps * TSZ, pf * BK);
            loadB(hsm + (NS + ps) * TSZ, pf * BK);
        }
        CP_COMMIT;

        unsigned sA = sb + st * (TSZ * 2);
        unsigned sB = sb + (NS + st) * (TSZ * 2);
#pragma unroll
        for (int ks = 0; ks < 2; ks++) {
            int kr = ks * 16 + trow;
            unsigned a[2][4], bq[4];
#pragma unroll
            for (int i = 0; i < 2; i++)
                ldsm_x4t(a[i][0], a[i][1], a[i][2], a[i][3],
                         sA + (kr * PITCH + wm + i * 16 + tcol) * 2);
            ldsm_x4t(bq[0], bq[1], bq[2], bq[3],
                     sB + (kr * PITCH + wn + tcol) * 2);
            unsigned bfr[2][2] = {{bq[0], bq[2]}, {bq[1], bq[3]}};
#pragma unroll
            for (int i = 0; i < 2; i++)
#pragma unroll
                for (int j = 0; j < 2; j++)
                    mma_f16(acc[i][j], a[i], bfr[j]);
        }
        st = (st + 1 == NS) ? 0 : st + 1;
        ps = (ps + 1 == NS) ? 0 : ps + 1;
    }

#pragma unroll
    for (int i = 0; i < 2; i++) {
        int mA = m0 + wm + i * 16 + (lane >> 2);
        int mB = mA + 8;
#pragma unroll
        for (int j = 0; j < 2; j++) {
            int n = wn + j * 8 + (lane & 3) * 2;
            __half2 h0, h1;
            h0.x = __float2half(acc[i][j][0]); h0.y = __float2half(acc[i][j][1]);
            h1.x = __float2half(acc[i][j][2]); h1.y = __float2half(acc[i][j][3]);
            *(__half2*)(Cp + mA * HD + n) = h0;
            *(__half2*)(Cp + mB * HD + n) = h1;
        }
    }
}

// ================= attn GEMM: O[s][h*64+d] = z[s] * Qf[s][:] @ kv[:][d] =================
// BM=128 (s), BN=64 (d), BK=32 (f). grid (1, SEQ/128, BATCH*NH).
__global__ void __launch_bounds__(256, 2) attn_gemm(
    const __half* __restrict__ Qf, const __half* __restrict__ KV,
    const float* __restrict__ z, __half* __restrict__ O)
{
    constexpr int BK = 32, NS = 3;
    constexpr int APITCH = 40;
    constexpr int BPITCH = 72;
    constexpr int ATSZ = 128 * APITCH;    // 5120 halves
    constexpr int BTSZ = BK * BPITCH;     // 2304 halves

    extern __shared__ __half hsm[];
    unsigned sb = (unsigned)__cvta_generic_to_shared(hsm);
    __half* Bs0 = hsm + NS * ATSZ;

    int bh = blockIdx.z;
    int b = bh >> 3, h = bh & 7;
    int m0 = blockIdx.y * 128;
    const __half* Ap = Qf + (long long)bh * SEQ * NF;
    const __half* Bp = KV + (long long)bh * NF * HD;
    __half* Op = O + (long long)b * SEQ * DMODEL + h * HD;
    const float* zp = z + (long long)bh * SEQ;

    int tid = threadIdx.x;
    int warp = tid >> 5, lane = tid & 31;
    int wm = (warp & 1) * 64, wn = (warp >> 1) * 16;
    int lrow = lane & 15, lk = lane >> 4;
    int trow = (lane & 7) + ((lane >> 4) << 3);
    int tcol = ((lane >> 3) & 1) << 3;

    float acc[4][2][4];
#pragma unroll
    for (int i = 0; i < 4; i++)
#pragma unroll
        for (int j = 0; j < 2; j++)
#pragma unroll
            for (int c = 0; c < 4; c++) acc[i][j][c] = 0.f;

    auto loadA = [&](__half* S, int kt) {
#pragma unroll
        for (int i = 0; i < 2; i++) {
            int e = tid + i * 256;
            int row = e >> 2, q = (e & 3) * 8;
            cpa16(&S[row * APITCH + q], Ap + (long long)(m0 + row) * NF + kt + q);
        }
    };
    auto loadB = [&](__half* S, int kt) {
        int kk = tid >> 3, q = (tid & 7) * 8;
        cpa16(&S[kk * BPITCH + q], Bp + (long long)(kt + kk) * HD + q);
    };

    int T = NF / BK;       // 8
#pragma unroll
    for (int s = 0; s < NS - 1; s++) {
        loadA(hsm + s * ATSZ, s * BK);
        loadB(Bs0 + s * BTSZ, s * BK);
        CP_COMMIT;
    }

    int st = 0, ps = NS - 1;
    for (int t = 0; t < T; t++) {
        asm volatile("cp.async.wait_group %0;\n" :: "n"(NS - 2));
        __syncthreads();
        int pf = t + NS - 1;
        if (pf < T) {
            loadA(hsm + ps * ATSZ, pf * BK);
            loadB(Bs0 + ps * BTSZ, pf * BK);
        }
        CP_COMMIT;

        unsigned sA = sb + st * (ATSZ * 2);
        unsigned sB = sb + (NS * ATSZ + st * BTSZ) * 2;
        unsigned aB = sA + (wm + lrow) * (APITCH * 2) + lk * 16;
#pragma unroll
        for (int ks = 0; ks < 2; ks++) {
            unsigned kb = ks * 32;
            int kr = ks * 16 + trow;
            unsigned a[4][4], bq[4];
#pragma unroll
            for (int i = 0; i < 4; i++)
                ldsm_x4(a[i][0], a[i][1], a[i][2], a[i][3],
                        aB + i * (16 * APITCH * 2) + kb);
            ldsm_x4t(bq[0], bq[1], bq[2], bq[3],
                     sB + (kr * BPITCH + wn + tcol) * 2);
            unsigned bfr[2][2] = {{bq[0], bq[2]}, {bq[1], bq[3]}};
#pragma unroll
            for (int i = 0; i < 4; i++)
#pragma unroll
                for (int j = 0; j < 2; j++)
                    mma_f16(acc[i][j], a[i], bfr[j]);
        }
        st = (st + 1 == NS) ? 0 : st + 1;
        ps = (ps + 1 == NS) ? 0 : ps + 1;
    }

#pragma unroll
    for (int i = 0; i < 4; i++) {
        int mA = m0 + wm + i * 16 + (lane >> 2);
        int mB = mA + 8;
        float rsA = zp[mA], rsB = zp[mB];
#pragma unroll
        for (int j = 0; j < 2; j++) {
            int n = wn + j * 8 + (lane & 3) * 2;
            __half2 h0, h1;
            h0.x = __float2half(acc[i][j][0] * rsA);
            h0.y = __float2half(acc[i][j][1] * rsA);
            h1.x = __float2half(acc[i][j][2] * rsB);
            h1.y = __float2half(acc[i][j][3] * rsB);
            *(__half2*)(Op + (long long)mA * DMODEL + n) = h0;
            *(__half2*)(Op + (long long)mB * DMODEL + n) = h1;
        }
    }
}

// ---------------- prep: tiled transpose fp32[K][N] -> half[N][K] ----------------
__global__ void __launch_bounds__(256) transpose_h(
    const float* __restrict__ in, __half* __restrict__ out, int K, int N,
    long long inL, long long outL)
{
    __shared__ float tile[32][33];
    const float* ip = in + blockIdx.z * inL;
    __half* op = out + blockIdx.z * outL;
    int n0 = blockIdx.x * 32, k0 = blockIdx.y * 32;
    int tx = threadIdx.x & 31, ty = threadIdx.x >> 5;
#pragma unroll
    for (int r = 0; r < 4; r++)
        tile[ty + r * 8][tx] = ip[(long long)(k0 + ty + r * 8) * N + n0 + tx];
    __syncthreads();
#pragma unroll
    for (int r = 0; r < 4; r++)
        op[(long long)(n0 + ty + r * 8) * K + k0 + tx] = __float2half(tile[tx][ty + r * 8]);
}

__global__ void __launch_bounds__(256) prep_bias_kernel(
    const float* __restrict__ bq, const float* __restrict__ bk,
    const float* __restrict__ bv, float* __restrict__ bqkv)
{
    int idx = blockIdx.x * 256 + threadIdx.x;
    if (idx < NLAYERS * QKVW) {
        int l = idx / QKVW, c = idx % QKVW;
        const float* src = c < 512 ? bq : (c < 1024 ? bk : bv);
        bqkv[idx] = src[l * DMODEL + (c & 511)];
    }
}

// ---------------- encoder first layer ----------------
__global__ void __launch_bounds__(256) enc1_kernel(
    const float* __restrict__ x, const float* __restrict__ pos,
    const float* __restrict__ w, const float* __restrict__ b,
    __half* __restrict__ out)
{
    int idx = blockIdx.x * 256 + threadIdx.x;
    int row = idx >> 8, col = idx & 255;
    const float* xr = x + row * 3;
    const float* pr = pos + row * 3;
    float a = b[col];
#pragma unroll
    for (int d = 0; d < 3; d++) a = fmaf(xr[d], w[d * 256 + col], a);
#pragma unroll
    for (int d = 0; d < 3; d++) a = fmaf(pr[d], w[(3 + d) * 256 + col], a);
    out[idx] = __float2half(fmaxf(a, 0.f));
}

// ---------------- LayerNorm: writes fp32 + half ----------------
__global__ void __launch_bounds__(512) ln_kernel(
    float* __restrict__ out, __half* __restrict__ out16,
    const float* __restrict__ resid, const float* __restrict__ y,
    const float* __restrict__ g, const float* __restrict__ b)
{
    int row = blockIdx.x, t = threadIdx.x;
    long long base = (long long)row * 512;
    float v = y[base + t];
    if (resid) v += resid[base + t];
    float s = v, s2 = v * v;
#pragma unroll
    for (int o = 16; o; o >>= 1) {
        s  += __shfl_xor_sync(0xffffffffu, s,  o);
        s2 += __shfl_xor_sync(0xffffffffu, s2, o);
    }
    __shared__ float rs[16], rs2[16];
    int w = t >> 5, lane = t & 31;
    if (!lane) { rs[w] = s; rs2[w] = s2; }
    __syncthreads();
    if (t < 32) {
        float a  = (t < 16) ? rs[t]  : 0.f;
        float a2 = (t < 16) ? rs2[t] : 0.f;
#pragma unroll
        for (int o = 8; o; o >>= 1) {
            a  += __shfl_xor_sync(0xffffffffu, a,  o);
            a2 += __shfl_xor_sync(0xffffffffu, a2, o);
        }
        if (!t) { rs[0] = a; rs2[0] = a2; }
    }
    __syncthreads();
    float mean = rs[0] * (1.f / 512.f);
    float var  = rs2[0] * (1.f / 512.f) - mean * mean;
    float r = (v - mean) * rsqrtf(var + 1e-5f) * g[t] + b[t];
    out[base + t] = r;
    out16[base + t] = __float2half(r);
}

// ---------------- FAVOR+ feature map (4 rows/block); half features out ----------------
__global__ void __launch_bounds__(128) favor_kernel(
    const __half* __restrict__ qkv, const float* __restrict__ omega,
    __half* __restrict__ outF, float* __restrict__ zOut,
    const float* __restrict__ ks, float* __restrict__ part, int colOff)
{
    int r0 = blockIdx.x * 4;
    int hh_ = blockIdx.y, t = threadIdx.x;
    __shared__ float xv[4][64];
    __shared__ float hvs[4];
#pragma unroll
    for (int i = 0; i < 2; i++) {
        int e = t + i * 128;
        int r = e >> 6, d = e & 63;
        xv[r][d] = __half2float(qkv[(long long)(r0 + r) * QKVW + colOff + hh_ * 64 + d])
                   * 0.3535533905932738f;
    }
    __syncthreads();
    {
        int w = t >> 5, lane = t & 31;
        float a = xv[w][lane], bb = xv[w][lane + 32];
        float s = a * a + bb * bb;
#pragma unroll
        for (int o = 16; o; o >>= 1) s += __shfl_xor_sync(0xffffffffu, s, o);
        if (!lane) hvs[w] = s * 0.5f;
    }
    __syncthreads();
    float u0 = 0.f, u1 = 0.f, u2 = 0.f, u3 = 0.f;
#pragma unroll 8
    for (int d = 0; d < 64; d++) {
        float om = omega[d * 128 + t];
        u0 = fmaf(xv[0][d], om, u0);
        u1 = fmaf(xv[1][d], om, u1);
        u2 = fmaf(xv[2][d], om, u2);
        u3 = fmaf(xv[3][d], om, u3);
    }
    int b = r0 >> 10;
    int bh = b * NH + hh_;
    long long ob = ((long long)bh * SEQ + (r0 & 1023)) * NF;
    float uu[4] = {u0, u1, u2, u3};
    float fa[4], fb[4];
#pragma unroll
    for (int r = 0; r < 4; r++) {
        float hv = hvs[r];
        fa[r] = expf( uu[r] - hv) * 0.0625f;
        fb[r] = expf(-uu[r] - hv) * 0.0625f;
        long long o = ob + (long long)r * NF;
        outF[o + t]       = __float2half(fa[r]);
        outF[o + 128 + t] = __float2half(fb[r]);
    }
    if (part) {
        int blk = (r0 & 1023) >> 2;
        long long po = ((long long)bh * 256 + blk) * NF;
        part[po + t]       = fa[0] + fa[1] + fa[2] + fa[3];
        part[po + 128 + t] = fb[0] + fb[1] + fb[2] + fb[3];
    }
    if (zOut) {
        float ka = ks[bh * NF + t];
        float kb = ks[bh * NF + 128 + t];
        float p[4];
#pragma unroll
        for (int r = 0; r < 4; r++) p[r] = fa[r] * ka + fb[r] * kb;
#pragma unroll
        for (int o = 16; o; o >>= 1)
#pragma unroll
            for (int r = 0; r < 4; r++) p[r] += __shfl_xor_sync(0xffffffffu, p[r], o);
        __shared__ float pr[4][4];
        int w = t >> 5, lane = t & 31;
        if (!lane) {
#pragma unroll
            for (int r = 0; r < 4; r++) pr[w][r] = p[r];
        }
        __syncthreads();
        if (t < 4) {
            float s = pr[0][t] + pr[1][t] + pr[2][t] + pr[3][t];
            zOut[bh * SEQ + (r0 & 1023) + t] = 1.f / (s + 1e-6f);
        }
    }
}

// ---------------- ksum final reduce ----------------
__global__ void __launch_bounds__(256) ksum2_kernel(
    const float* __restrict__ part, float* __restrict__ ks)
{
    int bh = blockIdx.x, f = threadIdx.x;
    const float* p = part + (long long)bh * 256 * NF + f;
    float s = 0.f;
#pragma unroll 8
    for (int c = 0; c < 256; c++) s += p[(long long)c * NF];
    ks[bh * NF + f] = s;
}

// ---------------- mean pool + classifier ----------------
__global__ void __launch_bounds__(512) pool_cls_kernel(
    const float* __restrict__ h, const float* __restrict__ cw,
    const float* __restrict__ cb, float* __restrict__ out)
{
    int b = blockIdx.x, t = threadIdx.x;
    const float* base = h + (long long)b * SEQ * DMODEL + t;
    float s = 0.f;
#pragma unroll 8
    for (int i = 0; i < SEQ; i++) s += base[(long long)i * DMODEL];
    __shared__ float pooled[DMODEL];
    pooled[t] = s * (1.f / (float)SEQ);
    __syncthreads();
    if (t < 16) {
        float acc = cb[t];
        for (int d = 0; d < DMODEL; d++) acc = fmaf(pooled[d], cw[d * 16 + t], acc);
        out[b * 16 + t] = acc;
    }
}

// ---------------- host driver ----------------
extern "C" void kernel_launch(void* const* d_in, const int* in_sizes, int n_in,
                              void* d_out, int out_size)
{
    const float* x      = (const float*)d_in[0];
    const float* pos    = (const float*)d_in[1];
    const float* enc_w1 = (const float*)d_in[2];
    const float* enc_b1 = (const float*)d_in[3];
    const float* enc_w2 = (const float*)d_in[4];
    const float* enc_b2 = (const float*)d_in[5];
    const float* enc_g  = (const float*)d_in[6];
    const float* enc_bb = (const float*)d_in[7];
    const float* wq     = (const float*)d_in[8];
    const float* bq     = (const float*)d_in[9];
    const float* wk     = (const float*)d_in[10];
    const float* bk     = (const float*)d_in[11];
    const float* wv     = (const float*)d_in[12];
    const float* bv     = (const float*)d_in[13];
    const float* wo     = (const float*)d_in[14];
    const float* bo     = (const float*)d_in[15];
    const float* ln1_g  = (const float*)d_in[16];
    const float* ln1_b  = (const float*)d_in[17];
    const float* w1     = (const float*)d_in[18];
    const float* b1     = (const float*)d_in[19];
    const float* w2     = (const float*)d_in[20];
    const float* b2     = (const float*)d_in[21];
    const float* ln2_g  = (const float*)d_in[22];
    const float* ln2_b  = (const float*)d_in[23];
    const float* omega  = (const float*)d_in[24];
    const float* cls_w  = (const float*)d_in[25];
    const float* cls_b  = (const float*)d_in[26];

    float *p_h, *p_v, *p_ks, *p_kp, *p_z, *p_bqkv;
    __half *p_h16, *p_t016, *p_qkv16, *p_ffn16, *p_attn16, *p_Qf, *p_Kf, *p_kv;
    __half *p_wqkvT, *p_w1T, *p_w2T, *p_woT, *p_ew2T;
    cudaGetSymbolAddress((void**)&p_h,    g_h);
    cudaGetSymbolAddress((void**)&p_v,    g_v);
    cudaGetSymbolAddress((void**)&p_Qf,   g_Qf);
    cudaGetSymbolAddress((void**)&p_Kf,   g_Kf);
    cudaGetSymbolAddress((void**)&p_kv,   g_kv);
    cudaGetSymbolAddress((void**)&p_ks,   g_ks);
    cudaGetSymbolAddress((void**)&p_kp,   g_kp);
    cudaGetSymbolAddress((void**)&p_z,    g_z);
    cudaGetSymbolAddress((void**)&p_bqkv, g_bqkv);
    cudaGetSymbolAddress((void**)&p_h16,  g_h16);
    cudaGetSymbolAddress((void**)&p_t016, g_t016);
    cudaGetSymbolAddress((void**)&p_qkv16,g_qkv16);
    cudaGetSymbolAddress((void**)&p_ffn16,g_ffn16);
    cudaGetSymbolAddress((void**)&p_attn16,g_attn16);
    cudaGetSymbolAddress((void**)&p_wqkvT,g_wqkvT);
    cudaGetSymbolAddress((void**)&p_w1T,  g_w1T);
    cudaGetSymbolAddress((void**)&p_w2T,  g_w2T);
    cudaGetSymbolAddress((void**)&p_woT,  g_woT);
    cudaGetSymbolAddress((void**)&p_ew2T, g_ew2T);

    // smem sizes
    const int SM_H    = 3 * 2 * 128 * 40 * 2;                   // 61440
    const int SM_KV   = 3 * 2 * 32 * 72 * 2;                    // 27648
    const int SM_ATTN = 3 * (128 * 40 + 32 * 72) * 2;           // 44544
    cudaFuncSetAttribute(hgemm<0>, cudaFuncAttributeMaxDynamicSharedMemorySize, SM_H);
    cudaFuncSetAttribute(hgemm<1>, cudaFuncAttributeMaxDynamicSharedMemorySize, SM_H);
    cudaFuncSetAttribute(kv_gemm,  cudaFuncAttributeMaxDynamicSharedMemorySize, SM_KV);
    cudaFuncSetAttribute(attn_gemm,cudaFuncAttributeMaxDynamicSharedMemorySize, SM_ATTN);

    // ---- weight prep: transpose+convert ----
    transpose_h<<<dim3(16,16,4), 256>>>(wq, p_wqkvT,            DMODEL, DMODEL, 512*512, (long long)QKVW*DMODEL);
    transpose_h<<<dim3(16,16,4), 256>>>(wk, p_wqkvT + 512*512,  DMODEL, DMODEL, 512*512, (long long)QKVW*DMODEL);
    transpose_h<<<dim3(16,16,4), 256>>>(wv, p_wqkvT + 1024*512, DMODEL, DMODEL, 512*512, (long long)QKVW*DMODEL);
    transpose_h<<<dim3(32,16,4), 256>>>(w1, p_w1T, DMODEL, FFNH, (long long)512*1024, (long long)FFNH*DMODEL);
    transpose_h<<<dim3(16,32,4), 256>>>(w2, p_w2T, FFNH, DMODEL, (long long)1024*512, (long long)DMODEL*FFNH);
    transpose_h<<<dim3(16,16,4), 256>>>(wo, p_woT, DMODEL, DMODEL, 512*512, 512*512);
    transpose_h<<<dim3(16,8,1),  256>>>(enc_w2, p_ew2T, 256, DMODEL, 0, 0);
    prep_bias_kernel<<<(NLAYERS*QKVW + 255)/256, 256>>>(bq, bk, bv, p_bqkv);

    auto dense = [&](const __half* A, const __half* Bt, const float* bias,
                     void* C, int M, int Nn, int K, int relu, int outh) {
        dim3 grid(Nn / 128, M / 128, 1);
        if (outh) hgemm<1><<<grid, 256, SM_H>>>(A, Bt, bias, C, M, Nn, K, relu);
        else      hgemm<0><<<grid, 256, SM_H>>>(A, Bt, bias, C, M, Nn, K, relu);
    };

    // ---- encoder ----
    enc1_kernel<<<NTOK, 256>>>(x, pos, enc_w1, enc_b1, p_t016);
    dense(p_t016, p_ew2T, enc_b2, p_v, NTOK, DMODEL, 256, 0, 0);
    ln_kernel<<<NTOK, 512>>>(p_h, p_h16, nullptr, p_v, enc_g, enc_bb);

    for (int l = 0; l < NLAYERS; l++) {
        const __half* WqkvT = p_wqkvT + (long long)l * QKVW * DMODEL;
        const float*  Bqkv  = p_bqkv + l * QKVW;
        const __half* WoT   = p_woT + (long long)l * DMODEL * DMODEL;
        const float*  Bo    = bo + l * DMODEL;
        const __half* W1T   = p_w1T + (long long)l * FFNH * DMODEL;
        const float*  B1    = b1 + l * FFNH;
        const __half* W2T   = p_w2T + (long long)l * DMODEL * FFNH;
        const float*  B2    = b2 + l * DMODEL;
        const float*  Om    = omega + (long long)l * HD * 128;

        // merged QKV projection (half out)
        dense(p_h16, WqkvT, Bqkv, p_qkv16, NTOK, QKVW, DMODEL, 0, 1);

        // FAVOR(K) + partial ksum; reduce; FAVOR(Q) + fused z
        favor_kernel<<<dim3(NTOK/4, NH), 128>>>(p_qkv16, Om, p_Kf, nullptr, nullptr, p_kp, 512);
        ksum2_kernel<<<BATCH*NH, 256>>>(p_kp, p_ks);
        favor_kernel<<<dim3(NTOK/4, NH), 128>>>(p_qkv16, Om, p_Qf, p_z, p_ks, nullptr, 0);

        // kv[f][d] = sum_s Kf[s][f] v[s][d]   (fp16)
        kv_gemm<<<dim3(1, NF/64, BATCH*NH), 256, SM_KV>>>(p_Kf, p_qkv16 + 1024, p_kv);

        // attn = z * Qf @ kv  (fp16)
        attn_gemm<<<dim3(1, SEQ/128, BATCH*NH), 256, SM_ATTN>>>(p_Qf, p_kv, p_z, p_attn16);

        // output projection + residual LN
        dense(p_attn16, WoT, Bo, p_v, NTOK, DMODEL, DMODEL, 0, 0);
        ln_kernel<<<NTOK, 512>>>(p_h, p_h16, p_h, p_v, ln1_g + l*DMODEL, ln1_b + l*DMODEL);

        // FFN + residual LN
        dense(p_h16, W1T, B1, p_ffn16, NTOK, FFNH, DMODEL, 1, 1);
        dense(p_ffn16, W2T, B2, p_v, NTOK, DMODEL, FFNH, 0, 0);
        ln_kernel<<<NTOK, 512>>>(p_h, p_h16, p_h, p_v, ln2_g + l*DMODEL, ln2_b + l*DMODEL);
    }

    pool_cls_kernel<<<BATCH, 512>>>(p_h, cls_w, cls_b, (float*)d_out);
}

// round 12
// speedup vs baseline: 5.7149x; 1.0527x over previous
#include <cuda_runtime.h>
#include <cuda_fp16.h>
#include <math.h>

#define BATCH 16
#define SEQ 1024
#define NTOK (BATCH*SEQ)
#define DMODEL 512
#define NH 8
#define HD 64
#define NF 256
#define NLAYERS 4
#define FFNH 1024
#define QKVW 1536

// ---------------- scratch ----------------
__device__ float  g_h   [NTOK*DMODEL];
__device__ __half g_h16 [NTOK*DMODEL];
__device__ __half g_t016[NTOK*256];
__device__ __half g_qkv16[NTOK*QKVW];
__device__ __half g_ffn16[NTOK*FFNH];
__device__ __half g_attn16[NTOK*DMODEL];
__device__ float  g_v   [NTOK*DMODEL];
__device__ __half g_Qf  [BATCH*NH*SEQ*NF];
__device__ __half g_Kf  [BATCH*NH*SEQ*NF];
__device__ __half g_kv  [BATCH*NH*NF*HD];
__device__ float  g_ks  [BATCH*NH*NF];
__device__ float  g_kp  [BATCH*NH*8*NF];
__device__ float  g_z   [BATCH*NH*SEQ];
__device__ __half g_wqkvT[NLAYERS*QKVW*DMODEL];
__device__ float  g_bqkv [NLAYERS*QKVW];
__device__ __half g_w1T  [NLAYERS*FFNH*DMODEL];
__device__ __half g_w2T  [NLAYERS*DMODEL*FFNH];
__device__ __half g_woT  [NLAYERS*DMODEL*DMODEL];
__device__ __half g_ew2T [DMODEL*256];

__device__ __forceinline__ void mma_f16(float* d, const unsigned* a, const unsigned* b) {
    asm volatile(
        "mma.sync.aligned.m16n8k16.row.col.f32.f16.f16.f32 "
        "{%0,%1,%2,%3},{%4,%5,%6,%7},{%8,%9},{%0,%1,%2,%3};\n"
        : "+f"(d[0]), "+f"(d[1]), "+f"(d[2]), "+f"(d[3])
        : "r"(a[0]), "r"(a[1]), "r"(a[2]), "r"(a[3]),
          "r"(b[0]), "r"(b[1]));
}

__device__ __forceinline__ void ldsm_x4(unsigned& r0, unsigned& r1,
                                        unsigned& r2, unsigned& r3, unsigned addr) {
    asm volatile("ldmatrix.sync.aligned.m8n8.x4.shared.b16 {%0,%1,%2,%3}, [%4];"
        : "=r"(r0), "=r"(r1), "=r"(r2), "=r"(r3) : "r"(addr));
}
__device__ __forceinline__ void ldsm_x4t(unsigned& r0, unsigned& r1,
                                         unsigned& r2, unsigned& r3, unsigned addr) {
    asm volatile("ldmatrix.sync.aligned.m8n8.x4.trans.shared.b16 {%0,%1,%2,%3}, [%4];"
        : "=r"(r0), "=r"(r1), "=r"(r2), "=r"(r3) : "r"(addr));
}

__device__ __forceinline__ void cpa16(void* dst, const void* src) {
    unsigned s = (unsigned)__cvta_generic_to_shared(dst);
    asm volatile("cp.async.ca.shared.global [%0], [%1], 16;\n" :: "r"(s), "l"(src));
}
#define CP_COMMIT  asm volatile("cp.async.commit_group;\n")

// ================= fp16 dense GEMM: C = A[M][K] @ B^T (B stored [N][K]) =================
// BK=64, NS=2 double-buffer: 8 k-tiles, 8 barriers.
template<int OUTH>
__global__ void __launch_bounds__(256, 2) hgemm(
    const __half* __restrict__ A, const __half* __restrict__ B,
    const float* __restrict__ bias, void* __restrict__ Cout,
    int M, int N, int K, int relu)
{
    constexpr int BM = 128, BN = 128, BK = 64, NS = 2;
    constexpr int PITCH = BK + 8;          // 72 halves = 144B rows
    constexpr int TSZ = BM * PITCH;        // 9216 halves

    extern __shared__ __half hsm[];
    unsigned sb = (unsigned)__cvta_generic_to_shared(hsm);

    int m0 = blockIdx.y * BM;
    int n0 = blockIdx.x * BN;
    int tid = threadIdx.x;
    int warp = tid >> 5, lane = tid & 31;
    int wy = warp & 1, wx = warp >> 1;
    int wm = wy * 64, wn = wx * 32;
    int lrow = lane & 15, lk = lane >> 4;

    float acc[4][4][4];
#pragma unroll
    for (int i = 0; i < 4; i++)
#pragma unroll
        for (int j = 0; j < 4; j++)
#pragma unroll
            for (int c = 0; c < 4; c++) acc[i][j][c] = 0.f;

    auto loadT = [&](__half* S, const __half* G, int row0, int ld, int kt) {
#pragma unroll
        for (int i = 0; i < 4; i++) {
            int e = tid + i * 256;
            int row = e >> 3, q = (e & 7) * 8;
            cpa16(&S[row * PITCH + q], G + (long long)(row0 + row) * ld + kt + q);
        }
    };

    int T = K / BK;
    loadT(hsm, A, m0, K, 0);
    loadT(hsm + NS * TSZ, B, n0, K, 0);
    CP_COMMIT;

    int st = 0;
    for (int t = 0; t < T; t++) {
        if (t + 1 < T) {
            loadT(hsm + (st ^ 1) * TSZ, A, m0, K, (t + 1) * BK);
            loadT(hsm + (NS + (st ^ 1)) * TSZ, B, n0, K, (t + 1) * BK);
            CP_COMMIT;
            asm volatile("cp.async.wait_group 1;\n");
        } else {
            asm volatile("cp.async.wait_group 0;\n");
        }
        __syncthreads();

        unsigned sA = sb + st * (TSZ * 2);
        unsigned sB = sb + (NS + st) * (TSZ * 2);
        unsigned aB = sA + (wm + lrow) * (PITCH * 2) + lk * 16;
        unsigned bB = sB + (wn + lrow) * (PITCH * 2) + lk * 16;

#pragma unroll
        for (int ks = 0; ks < 4; ks++) {
            unsigned kb = ks * 32;
            unsigned a[4][4], b0q[4], b1q[4];
#pragma unroll
            for (int i = 0; i < 4; i++)
                ldsm_x4(a[i][0], a[i][1], a[i][2], a[i][3],
                        aB + i * (16 * PITCH * 2) + kb);
            ldsm_x4(b0q[0], b0q[1], b0q[2], b0q[3], bB + kb);
            ldsm_x4(b1q[0], b1q[1], b1q[2], b1q[3], bB + 16 * (PITCH * 2) + kb);
            unsigned bfr[4][2] = {
                {b0q[0], b0q[2]}, {b0q[1], b0q[3]},
                {b1q[0], b1q[2]}, {b1q[1], b1q[3]}};
#pragma unroll
            for (int i = 0; i < 4; i++)
#pragma unroll
                for (int j = 0; j < 4; j++)
                    mma_f16(acc[i][j], a[i], bfr[j]);
        }
        __syncthreads();
        st ^= 1;
    }

#pragma unroll
    for (int i = 0; i < 4; i++) {
        int mA = m0 + wm + i * 16 + (lane >> 2);
        int mB = mA + 8;
#pragma unroll
        for (int j = 0; j < 4; j++) {
            int n = n0 + wn + j * 8 + (lane & 3) * 2;
            float b0 = bias ? bias[n] : 0.f;
            float b1 = bias ? bias[n + 1] : 0.f;
            float v00 = acc[i][j][0] + b0, v01 = acc[i][j][1] + b1;
            float v10 = acc[i][j][2] + b0, v11 = acc[i][j][3] + b1;
            if (relu) {
                v00 = fmaxf(v00, 0.f); v01 = fmaxf(v01, 0.f);
                v10 = fmaxf(v10, 0.f); v11 = fmaxf(v11, 0.f);
            }
            if (OUTH) {
                __half* C = (__half*)Cout;
                __half2 h0; h0.x = __float2half(v00); h0.y = __float2half(v01);
                __half2 h1; h1.x = __float2half(v10); h1.y = __float2half(v11);
                *(__half2*)(C + (long long)mA * N + n) = h0;
                *(__half2*)(C + (long long)mB * N + n) = h1;
            } else {
                float* C = (float*)Cout;
                *(float2*)(C + (long long)mA * N + n) = make_float2(v00, v01);
                *(float2*)(C + (long long)mB * N + n) = make_float2(v10, v11);
            }
        }
    }
}

// ================= kv GEMM: kv[f][d] = sum_s Kf[s][f] * v[s][d] =================
__global__ void __launch_bounds__(256, 2) kv_gemm(
    const __half* __restrict__ Kf, const __half* __restrict__ V,
    __half* __restrict__ KV)
{
    constexpr int BK = 32, NS = 3;
    constexpr int PITCH = 72;
    constexpr int TSZ = BK * PITCH;

    extern __shared__ __half hsm[];
    unsigned sb = (unsigned)__cvta_generic_to_shared(hsm);

    int bh = blockIdx.z;
    int b = bh >> 3, h = bh & 7;
    const __half* Ap = Kf + (long long)bh * SEQ * NF;
    const __half* Vp = V + (long long)b * SEQ * QKVW + h * HD;
    __half* Cp = KV + (long long)bh * NF * HD;

    int m0 = blockIdx.y * 64;
    int tid = threadIdx.x;
    int warp = tid >> 5, lane = tid & 31;
    int wm = (warp & 1) * 32, wn = (warp >> 1) * 16;
    int trow = (lane & 7) + ((lane >> 4) << 3);
    int tcol = ((lane >> 3) & 1) << 3;

    float acc[2][2][4];
#pragma unroll
    for (int i = 0; i < 2; i++)
#pragma unroll
        for (int j = 0; j < 2; j++)
#pragma unroll
            for (int c = 0; c < 4; c++) acc[i][j][c] = 0.f;

    auto loadA = [&](__half* S, int kt) {
        int kk = tid >> 3, q = (tid & 7) * 8;
        cpa16(&S[kk * PITCH + q], Ap + (long long)(kt + kk) * NF + m0 + q);
    };
    auto loadB = [&](__half* S, int kt) {
        int kk = tid >> 3, q = (tid & 7) * 8;
        cpa16(&S[kk * PITCH + q], Vp + (long long)(kt + kk) * QKVW + q);
    };

    int T = SEQ / BK;
#pragma unroll
    for (int s = 0; s < NS - 1; s++) {
        loadA(hsm + s * TSZ, s * BK);
        loadB(hsm + (NS + s) * TSZ, s * BK);
        CP_COMMIT;
    }

    int st = 0, ps = NS - 1;
    for (int t = 0; t < T; t++) {
        asm volatile("cp.async.wait_group %0;\n" :: "n"(NS - 2));
        __syncthreads();
        int pf = t + NS - 1;
        if (pf < T) {
            loadA(hsm + ps * TSZ, pf * BK);
            loadB(hsm + (NS + ps) * TSZ, pf * BK);
        }
        CP_COMMIT;

        unsigned sA = sb + st * (TSZ * 2);
        unsigned sB = sb + (NS + st) * (TSZ * 2);
#pragma unroll
        for (int ks = 0; ks < 2; ks++) {
            int kr = ks * 16 + trow;
            unsigned a[2][4], bq[4];
#pragma unroll
            for (int i = 0; i < 2; i++)
                ldsm_x4t(a[i][0], a[i][1], a[i][2], a[i][3],
                         sA + (kr * PITCH + wm + i * 16 + tcol) * 2);
            ldsm_x4t(bq[0], bq[1], bq[2], bq[3],
                     sB + (kr * PITCH + wn + tcol) * 2);
            unsigned bfr[2][2] = {{bq[0], bq[2]}, {bq[1], bq[3]}};
#pragma unroll
            for (int i = 0; i < 2; i++)
#pragma unroll
                for (int j = 0; j < 2; j++)
                    mma_f16(acc[i][j], a[i], bfr[j]);
        }
        st = (st + 1 == NS) ? 0 : st + 1;
        ps = (ps + 1 == NS) ? 0 : ps + 1;
    }

#pragma unroll
    for (int i = 0; i < 2; i++) {
        int mA = m0 + wm + i * 16 + (lane >> 2);
        int mB = mA + 8;
#pragma unroll
        for (int j = 0; j < 2; j++) {
            int n = wn + j * 8 + (lane & 3) * 2;
            __half2 h0, h1;
            h0.x = __float2half(acc[i][j][0]); h0.y = __float2half(acc[i][j][1]);
            h1.x = __float2half(acc[i][j][2]); h1.y = __float2half(acc[i][j][3]);
            *(__half2*)(Cp + mA * HD + n) = h0;
            *(__half2*)(Cp + mB * HD + n) = h1;
        }
    }
}

// ================= attn GEMM: O[s][h*64+d] = z[s] * Qf[s][:] @ kv[:][d] =================
__global__ void __launch_bounds__(256, 2) attn_gemm(
    const __half* __restrict__ Qf, const __half* __restrict__ KV,
    const float* __restrict__ z, __half* __restrict__ O)
{
    constexpr int BK = 32, NS = 3;
    constexpr int APITCH = 40;
    constexpr int BPITCH = 72;
    constexpr int ATSZ = 128 * APITCH;
    constexpr int BTSZ = BK * BPITCH;

    extern __shared__ __half hsm[];
    unsigned sb = (unsigned)__cvta_generic_to_shared(hsm);
    __half* Bs0 = hsm + NS * ATSZ;

    int bh = blockIdx.z;
    int b = bh >> 3, h = bh & 7;
    int m0 = blockIdx.y * 128;
    const __half* Ap = Qf + (long long)bh * SEQ * NF;
    const __half* Bp = KV + (long long)bh * NF * HD;
    __half* Op = O + (long long)b * SEQ * DMODEL + h * HD;
    const float* zp = z + (long long)bh * SEQ;

    int tid = threadIdx.x;
    int warp = tid >> 5, lane = tid & 31;
    int wm = (warp & 1) * 64, wn = (warp >> 1) * 16;
    int lrow = lane & 15, lk = lane >> 4;
    int trow = (lane & 7) + ((lane >> 4) << 3);
    int tcol = ((lane >> 3) & 1) << 3;

    float acc[4][2][4];
#pragma unroll
    for (int i = 0; i < 4; i++)
#pragma unroll
        for (int j = 0; j < 2; j++)
#pragma unroll
            for (int c = 0; c < 4; c++) acc[i][j][c] = 0.f;

    auto loadA = [&](__half* S, int kt) {
#pragma unroll
        for (int i = 0; i < 2; i++) {
            int e = tid + i * 256;
            int row = e >> 2, q = (e & 3) * 8;
            cpa16(&S[row * APITCH + q], Ap + (long long)(m0 + row) * NF + kt + q);
        }
    };
    auto loadB = [&](__half* S, int kt) {
        int kk = tid >> 3, q = (tid & 7) * 8;
        cpa16(&S[kk * BPITCH + q], Bp + (long long)(kt + kk) * HD + q);
    };

    int T = NF / BK;
#pragma unroll
    for (int s = 0; s < NS - 1; s++) {
        loadA(hsm + s * ATSZ, s * BK);
        loadB(Bs0 + s * BTSZ, s * BK);
        CP_COMMIT;
    }

    int st = 0, ps = NS - 1;
    for (int t = 0; t < T; t++) {
        asm volatile("cp.async.wait_group %0;\n" :: "n"(NS - 2));
        __syncthreads();
        int pf = t + NS - 1;
        if (pf < T) {
            loadA(hsm + ps * ATSZ, pf * BK);
            loadB(Bs0 + ps * BTSZ, pf * BK);
        }
        CP_COMMIT;

        unsigned sA = sb + st * (ATSZ * 2);
        unsigned sB = sb + (NS * ATSZ + st * BTSZ) * 2;
        unsigned aB = sA + (wm + lrow) * (APITCH * 2) + lk * 16;
#pragma unroll
        for (int ks = 0; ks < 2; ks++) {
            unsigned kb = ks * 32;
            int kr = ks * 16 + trow;
            unsigned a[4][4], bq[4];
#pragma unroll
            for (int i = 0; i < 4; i++)
                ldsm_x4(a[i][0], a[i][1], a[i][2], a[i][3],
                        aB + i * (16 * APITCH * 2) + kb);
            ldsm_x4t(bq[0], bq[1], bq[2], bq[3],
                     sB + (kr * BPITCH + wn + tcol) * 2);
            unsigned bfr[2][2] = {{bq[0], bq[2]}, {bq[1], bq[3]}};
#pragma unroll
            for (int i = 0; i < 4; i++)
#pragma unroll
                for (int j = 0; j < 2; j++)
                    mma_f16(acc[i][j], a[i], bfr[j]);
        }
        st = (st + 1 == NS) ? 0 : st + 1;
        ps = (ps + 1 == NS) ? 0 : ps + 1;
    }

#pragma unroll
    for (int i = 0; i < 4; i++) {
        int mA = m0 + wm + i * 16 + (lane >> 2);
        int mB = mA + 8;
        float rsA = zp[mA], rsB = zp[mB];
#pragma unroll
        for (int j = 0; j < 2; j++) {
            int n = wn + j * 8 + (lane & 3) * 2;
            __half2 h0, h1;
            h0.x = __float2half(acc[i][j][0] * rsA);
            h0.y = __float2half(acc[i][j][1] * rsA);
            h1.x = __float2half(acc[i][j][2] * rsB);
            h1.y = __float2half(acc[i][j][3] * rsB);
            *(__half2*)(Op + (long long)mA * DMODEL + n) = h0;
            *(__half2*)(Op + (long long)mB * DMODEL + n) = h1;
        }
    }
}

// ---------------- prep: tiled transpose fp32[K][N] -> half[N][K] ----------------
__global__ void __launch_bounds__(256) transpose_h(
    const float* __restrict__ in, __half* __restrict__ out, int K, int N,
    long long inL, long long outL)
{
    __shared__ float tile[32][33];
    const float* ip = in + blockIdx.z * inL;
    __half* op = out + blockIdx.z * outL;
    int n0 = blockIdx.x * 32, k0 = blockIdx.y * 32;
    int tx = threadIdx.x & 31, ty = threadIdx.x >> 5;
#pragma unroll
    for (int r = 0; r < 4; r++)
        tile[ty + r * 8][tx] = ip[(long long)(k0 + ty + r * 8) * N + n0 + tx];
    __syncthreads();
#pragma unroll
    for (int r = 0; r < 4; r++)
        op[(long long)(n0 + ty + r * 8) * K + k0 + tx] = __float2half(tile[tx][ty + r * 8]);
}

__global__ void __launch_bounds__(256) prep_bias_kernel(
    const float* __restrict__ bq, const float* __restrict__ bk,
    const float* __restrict__ bv, float* __restrict__ bqkv)
{
    int idx = blockIdx.x * 256 + threadIdx.x;
    if (idx < NLAYERS * QKVW) {
        int l = idx / QKVW, c = idx % QKVW;
        const float* src = c < 512 ? bq : (c < 1024 ? bk : bv);
        bqkv[idx] = src[l * DMODEL + (c & 511)];
    }
}

// ---------------- encoder first layer ----------------
__global__ void __launch_bounds__(256) enc1_kernel(
    const float* __restrict__ x, const float* __restrict__ pos,
    const float* __restrict__ w, const float* __restrict__ b,
    __half* __restrict__ out)
{
    int idx = blockIdx.x * 256 + threadIdx.x;
    int row = idx >> 8, col = idx & 255;
    const float* xr = x + row * 3;
    const float* pr = pos + row * 3;
    float a = b[col];
#pragma unroll
    for (int d = 0; d < 3; d++) a = fmaf(xr[d], w[d * 256 + col], a);
#pragma unroll
    for (int d = 0; d < 3; d++) a = fmaf(pr[d], w[(3 + d) * 256 + col], a);
    out[idx] = __float2half(fmaxf(a, 0.f));
}

// ---------------- LayerNorm: writes fp32 + half ----------------
__global__ void __launch_bounds__(512) ln_kernel(
    float* __restrict__ out, __half* __restrict__ out16,
    const float* __restrict__ resid, const float* __restrict__ y,
    const float* __restrict__ g, const float* __restrict__ b)
{
    int row = blockIdx.x, t = threadIdx.x;
    long long base = (long long)row * 512;
    float v = y[base + t];
    if (resid) v += resid[base + t];
    float s = v, s2 = v * v;
#pragma unroll
    for (int o = 16; o; o >>= 1) {
        s  += __shfl_xor_sync(0xffffffffu, s,  o);
        s2 += __shfl_xor_sync(0xffffffffu, s2, o);
    }
    __shared__ float rs[16], rs2[16];
    int w = t >> 5, lane = t & 31;
    if (!lane) { rs[w] = s; rs2[w] = s2; }
    __syncthreads();
    if (t < 32) {
        float a  = (t < 16) ? rs[t]  : 0.f;
        float a2 = (t < 16) ? rs2[t] : 0.f;
#pragma unroll
        for (int o = 8; o; o >>= 1) {
            a  += __shfl_xor_sync(0xffffffffu, a,  o);
            a2 += __shfl_xor_sync(0xffffffffu, a2, o);
        }
        if (!t) { rs[0] = a; rs2[0] = a2; }
    }
    __syncthreads();
    float mean = rs[0] * (1.f / 512.f);
    float var  = rs2[0] * (1.f / 512.f) - mean * mean;
    float r = (v - mean) * rsqrtf(var + 1e-5f) * g[t] + b[t];
    out[base + t] = r;
    out16[base + t] = __float2half(r);
}

// ---------------- FAVOR+ feature map (4 rows/block); half features out ----------------
__global__ void __launch_bounds__(128) favor_kernel(
    const __half* __restrict__ qkv, const float* __restrict__ omega,
    __half* __restrict__ outF, float* __restrict__ zOut,
    const float* __restrict__ ks, int colOff)
{
    int r0 = blockIdx.x * 4;
    int hh_ = blockIdx.y, t = threadIdx.x;
    __shared__ float xv[4][64];
    __shared__ float hvs[4];
#pragma unroll
    for (int i = 0; i < 2; i++) {
        int e = t + i * 128;
        int r = e >> 6, d = e & 63;
        xv[r][d] = __half2float(qkv[(long long)(r0 + r) * QKVW + colOff + hh_ * 64 + d])
                   * 0.3535533905932738f;
    }
    __syncthreads();
    {
        int w = t >> 5, lane = t & 31;
        float a = xv[w][lane], bb = xv[w][lane + 32];
        float s = a * a + bb * bb;
#pragma unroll
        for (int o = 16; o; o >>= 1) s += __shfl_xor_sync(0xffffffffu, s, o);
        if (!lane) hvs[w] = s * 0.5f;
    }
    __syncthreads();
    float u0 = 0.f, u1 = 0.f, u2 = 0.f, u3 = 0.f;
#pragma unroll 8
    for (int d = 0; d < 64; d++) {
        float om = omega[d * 128 + t];
        u0 = fmaf(xv[0][d], om, u0);
        u1 = fmaf(xv[1][d], om, u1);
        u2 = fmaf(xv[2][d], om, u2);
        u3 = fmaf(xv[3][d], om, u3);
    }
    int b = r0 >> 10;
    int bh = b * NH + hh_;
    long long ob = ((long long)bh * SEQ + (r0 & 1023)) * NF;
    float uu[4] = {u0, u1, u2, u3};
    float fa[4], fb[4];
#pragma unroll
    for (int r = 0; r < 4; r++) {
        float hv = hvs[r];
        fa[r] = __expf( uu[r] - hv) * 0.0625f;
        fb[r] = __expf(-uu[r] - hv) * 0.0625f;
        long long o = ob + (long long)r * NF;
        outF[o + t]       = __float2half(fa[r]);
        outF[o + 128 + t] = __float2half(fb[r]);
    }
    if (zOut) {
        float ka = ks[bh * NF + t];
        float kb = ks[bh * NF + 128 + t];
        float p[4];
#pragma unroll
        for (int r = 0; r < 4; r++) p[r] = fa[r] * ka + fb[r] * kb;
#pragma unroll
        for (int o = 16; o; o >>= 1)
#pragma unroll
            for (int r = 0; r < 4; r++) p[r] += __shfl_xor_sync(0xffffffffu, p[r], o);
        __shared__ float pr[4][4];
        int w = t >> 5, lane = t & 31;
        if (!lane) {
#pragma unroll
            for (int r = 0; r < 4; r++) pr[w][r] = p[r];
        }
        __syncthreads();
        if (t < 4) {
            float s = pr[0][t] + pr[1][t] + pr[2][t] + pr[3][t];
            zOut[bh * SEQ + (r0 & 1023) + t] = 1.f / (s + 1e-6f);
        }
    }
}

// ---------------- ksum: read half Kf directly, 2-stage ----------------
__global__ void __launch_bounds__(256) ksum1_kernel(
    const __half* __restrict__ Kf, float* __restrict__ part)
{
    int bh = blockIdx.x, ch = blockIdx.y, f = threadIdx.x;
    const __half* base = Kf + ((long long)bh * SEQ + ch * 128) * NF + f;
    float s = 0.f;
#pragma unroll 8
    for (int i = 0; i < 128; i++) s += __half2float(base[(long long)i * NF]);
    part[(bh * 8 + ch) * NF + f] = s;
}
__global__ void __launch_bounds__(256) ksum2_kernel(
    const float* __restrict__ part, float* __restrict__ ks)
{
    int bh = blockIdx.x, f = threadIdx.x;
    float s = 0.f;
#pragma unroll
    for (int c = 0; c < 8; c++) s += part[(bh * 8 + c) * NF + f];
    ks[bh * NF + f] = s;
}

// ---------------- mean pool + classifier ----------------
__global__ void __launch_bounds__(512) pool_cls_kernel(
    const float* __restrict__ h, const float* __restrict__ cw,
    const float* __restrict__ cb, float* __restrict__ out)
{
    int b = blockIdx.x, t = threadIdx.x;
    const float* base = h + (long long)b * SEQ * DMODEL + t;
    float s = 0.f;
#pragma unroll 8
    for (int i = 0; i < SEQ; i++) s += base[(long long)i * DMODEL];
    __shared__ float pooled[DMODEL];
    pooled[t] = s * (1.f / (float)SEQ);
    __syncthreads();
    if (t < 16) {
        float acc = cb[t];
        for (int d = 0; d < DMODEL; d++) acc = fmaf(pooled[d], cw[d * 16 + t], acc);
        out[b * 16 + t] = acc;
    }
}

// ---------------- host driver ----------------
extern "C" void kernel_launch(void* const* d_in, const int* in_sizes, int n_in,
                              void* d_out, int out_size)
{
    const float* x      = (const float*)d_in[0];
    const float* pos    = (const float*)d_in[1];
    const float* enc_w1 = (const float*)d_in[2];
    const float* enc_b1 = (const float*)d_in[3];
    const float* enc_w2 = (const float*)d_in[4];
    const float* enc_b2 = (const float*)d_in[5];
    const float* enc_g  = (const float*)d_in[6];
    const float* enc_bb = (const float*)d_in[7];
    const float* wq     = (const float*)d_in[8];
    const float* bq     = (const float*)d_in[9];
    const float* wk     = (const float*)d_in[10];
    const float* bk     = (const float*)d_in[11];
    const float* wv     = (const float*)d_in[12];
    const float* bv     = (const float*)d_in[13];
    const float* wo     = (const float*)d_in[14];
    const float* bo     = (const float*)d_in[15];
    const float* ln1_g  = (const float*)d_in[16];
    const float* ln1_b  = (const float*)d_in[17];
    const float* w1     = (const float*)d_in[18];
    const float* b1     = (const float*)d_in[19];
    const float* w2     = (const float*)d_in[20];
    const float* b2     = (const float*)d_in[21];
    const float* ln2_g  = (const float*)d_in[22];
    const float* ln2_b  = (const float*)d_in[23];
    const float* omega  = (const float*)d_in[24];
    const float* cls_w  = (const float*)d_in[25];
    const float* cls_b  = (const float*)d_in[26];

    float *p_h, *p_v, *p_ks, *p_kp, *p_z, *p_bqkv;
    __half *p_h16, *p_t016, *p_qkv16, *p_ffn16, *p_attn16, *p_Qf, *p_Kf, *p_kv;
    __half *p_wqkvT, *p_w1T, *p_w2T, *p_woT, *p_ew2T;
    cudaGetSymbolAddress((void**)&p_h,    g_h);
    cudaGetSymbolAddress((void**)&p_v,    g_v);
    cudaGetSymbolAddress((void**)&p_Qf,   g_Qf);
    cudaGetSymbolAddress((void**)&p_Kf,   g_Kf);
    cudaGetSymbolAddress((void**)&p_kv,   g_kv);
    cudaGetSymbolAddress((void**)&p_ks,   g_ks);
    cudaGetSymbolAddress((void**)&p_kp,   g_kp);
    cudaGetSymbolAddress((void**)&p_z,    g_z);
    cudaGetSymbolAddress((void**)&p_bqkv, g_bqkv);
    cudaGetSymbolAddress((void**)&p_h16,  g_h16);
    cudaGetSymbolAddress((void**)&p_t016, g_t016);
    cudaGetSymbolAddress((void**)&p_qkv16,g_qkv16);
    cudaGetSymbolAddress((void**)&p_ffn16,g_ffn16);
    cudaGetSymbolAddress((void**)&p_attn16,g_attn16);
    cudaGetSymbolAddress((void**)&p_wqkvT,g_wqkvT);
    cudaGetSymbolAddress((void**)&p_w1T,  g_w1T);
    cudaGetSymbolAddress((void**)&p_w2T,  g_w2T);
    cudaGetSymbolAddress((void**)&p_woT,  g_woT);
    cudaGetSymbolAddress((void**)&p_ew2T, g_ew2T);

    // smem sizes
    const int SM_H    = 2 * 2 * 128 * 72 * 2;                   // 73728 (BK=64, NS=2)
    const int SM_KV   = 3 * 2 * 32 * 72 * 2;                    // 27648
    const int SM_ATTN = 3 * (128 * 40 + 32 * 72) * 2;           // 44544
    cudaFuncSetAttribute(hgemm<0>, cudaFuncAttributeMaxDynamicSharedMemorySize, SM_H);
    cudaFuncSetAttribute(hgemm<1>, cudaFuncAttributeMaxDynamicSharedMemorySize, SM_H);
    cudaFuncSetAttribute(kv_gemm,  cudaFuncAttributeMaxDynamicSharedMemorySize, SM_KV);
    cudaFuncSetAttribute(attn_gemm,cudaFuncAttributeMaxDynamicSharedMemorySize, SM_ATTN);

    // ---- weight prep: transpose+convert ----
    transpose_h<<<dim3(16,16,4), 256>>>(wq, p_wqkvT,            DMODEL, DMODEL, 512*512, (long long)QKVW*DMODEL);
    transpose_h<<<dim3(16,16,4), 256>>>(wk, p_wqkvT + 512*512,  DMODEL, DMODEL, 512*512, (long long)QKVW*DMODEL);
    transpose_h<<<dim3(16,16,4), 256>>>(wv, p_wqkvT + 1024*512, DMODEL, DMODEL, 512*512, (long long)QKVW*DMODEL);
    transpose_h<<<dim3(32,16,4), 256>>>(w1, p_w1T, DMODEL, FFNH, (long long)512*1024, (long long)FFNH*DMODEL);
    transpose_h<<<dim3(16,32,4), 256>>>(w2, p_w2T, FFNH, DMODEL, (long long)1024*512, (long long)DMODEL*FFNH);
    transpose_h<<<dim3(16,16,4), 256>>>(wo, p_woT, DMODEL, DMODEL, 512*512, 512*512);
    transpose_h<<<dim3(16,8,1),  256>>>(enc_w2, p_ew2T, 256, DMODEL, 0, 0);
    prep_bias_kernel<<<(NLAYERS*QKVW + 255)/256, 256>>>(bq, bk, bv, p_bqkv);

    auto dense = [&](const __half* A, const __half* Bt, const float* bias,
                     void* C, int M, int Nn, int K, int relu, int outh) {
        dim3 grid(Nn / 128, M / 128, 1);
        if (outh) hgemm<1><<<grid, 256, SM_H>>>(A, Bt, bias, C, M, Nn, K, relu);
        else      hgemm<0><<<grid, 256, SM_H>>>(A, Bt, bias, C, M, Nn, K, relu);
    };

    // ---- encoder ----
    enc1_kernel<<<NTOK, 256>>>(x, pos, enc_w1, enc_b1, p_t016);
    dense(p_t016, p_ew2T, enc_b2, p_v, NTOK, DMODEL, 256, 0, 0);
    ln_kernel<<<NTOK, 512>>>(p_h, p_h16, nullptr, p_v, enc_g, enc_bb);

    for (int l = 0; l < NLAYERS; l++) {
        const __half* WqkvT = p_wqkvT + (long long)l * QKVW * DMODEL;
        const float*  Bqkv  = p_bqkv + l * QKVW;
        const __half* WoT   = p_woT + (long long)l * DMODEL * DMODEL;
        const float*  Bo    = bo + l * DMODEL;
        const __half* W1T   = p_w1T + (long long)l * FFNH * DMODEL;
        const float*  B1    = b1 + l * FFNH;
        const __half* W2T   = p_w2T + (long long)l * DMODEL * FFNH;
        const float*  B2    = b2 + l * DMODEL;
        const float*  Om    = omega + (long long)l * HD * 128;

        // merged QKV projection (half out)
        dense(p_h16, WqkvT, Bqkv, p_qkv16, NTOK, QKVW, DMODEL, 0, 1);

        // FAVOR(K); ksum from half Kf; FAVOR(Q) + fused z
        favor_kernel<<<dim3(NTOK/4, NH), 128>>>(p_qkv16, Om, p_Kf, nullptr, nullptr, 512);
        ksum1_kernel<<<dim3(BATCH*NH, 8), 256>>>(p_Kf, p_kp);
        ksum2_kernel<<<BATCH*NH, 256>>>(p_kp, p_ks);
        favor_kernel<<<dim3(NTOK/4, NH), 128>>>(p_qkv16, Om, p_Qf, p_z, p_ks, 0);

        // kv[f][d] = sum_s Kf[s][f] v[s][d]   (fp16)
        kv_gemm<<<dim3(1, NF/64, BATCH*NH), 256, SM_KV>>>(p_Kf, p_qkv16 + 1024, p_kv);

        // attn = z * Qf @ kv  (fp16)
        attn_gemm<<<dim3(1, SEQ/128, BATCH*NH), 256, SM_ATTN>>>(p_Qf, p_kv, p_z, p_attn16);

        // output projection + residual LN
        dense(p_attn16, WoT, Bo, p_v, NTOK, DMODEL, DMODEL, 0, 0);
        ln_kernel<<<NTOK, 512>>>(p_h, p_h16, p_h, p_v, ln1_g + l*DMODEL, ln1_b + l*DMODEL);

        // FFN + residual LN
        dense(p_h16, W1T, B1, p_ffn16, NTOK, FFNH, DMODEL, 1, 1);
        dense(p_ffn16, W2T, B2, p_v, NTOK, DMODEL, FFNH, 0, 0);
        ln_kernel<<<NTOK, 512>>>(p_h, p_h16, p_h, p_v, ln2_g + l*DMODEL, ln2_b + l*DMODEL);
    }

    pool_cls_kernel<<<BATCH, 512>>>(p_h, cls_w, cls_b, (float*)d_out);
}

// round 13
// speedup vs baseline: 7.2335x; 1.2657x over previous
#include <cuda_runtime.h>
#include <cuda_fp16.h>
#include <math.h>

#define BATCH 16
#define SEQ 1024
#define NTOK (BATCH*SEQ)
#define DMODEL 512
#define NH 8
#define HD 64
#define NF 256
#define NLAYERS 4
#define FFNH 1024
#define QKVW 1536

// ---------------- scratch ----------------
__device__ float  g_h   [NTOK*DMODEL];
__device__ __half g_h16 [NTOK*DMODEL];
__device__ __half g_t016[NTOK*256];
__device__ __half g_qkv16[NTOK*QKVW];
__device__ __half g_ffn16[NTOK*FFNH];
__device__ __half g_attn16[NTOK*DMODEL];
__device__ float  g_v   [NTOK*DMODEL];
__device__ __half g_Qf  [BATCH*NH*SEQ*NF];
__device__ __half g_Kf  [BATCH*NH*SEQ*NF];
__device__ __half g_kv  [BATCH*NH*NF*HD];
__device__ float  g_ks  [BATCH*NH*NF];
__device__ float  g_kp  [BATCH*NH*8*NF];
__device__ float  g_z   [BATCH*NH*SEQ];
__device__ __half g_wqkvT[NLAYERS*QKVW*DMODEL];
__device__ float  g_bqkv [NLAYERS*QKVW];
__device__ __half g_w1T  [NLAYERS*FFNH*DMODEL];
__device__ __half g_w2T  [NLAYERS*DMODEL*FFNH];
__device__ __half g_woT  [NLAYERS*DMODEL*DMODEL];
__device__ __half g_ew2T [DMODEL*256];
__device__ __half g_om16 [NLAYERS*HD*128];

__device__ __forceinline__ void mma_f16(float* d, const unsigned* a, const unsigned* b) {
    asm volatile(
        "mma.sync.aligned.m16n8k16.row.col.f32.f16.f16.f32 "
        "{%0,%1,%2,%3},{%4,%5,%6,%7},{%8,%9},{%0,%1,%2,%3};\n"
        : "+f"(d[0]), "+f"(d[1]), "+f"(d[2]), "+f"(d[3])
        : "r"(a[0]), "r"(a[1]), "r"(a[2]), "r"(a[3]),
          "r"(b[0]), "r"(b[1]));
}

__device__ __forceinline__ void ldsm_x4(unsigned& r0, unsigned& r1,
                                        unsigned& r2, unsigned& r3, unsigned addr) {
    asm volatile("ldmatrix.sync.aligned.m8n8.x4.shared.b16 {%0,%1,%2,%3}, [%4];"
        : "=r"(r0), "=r"(r1), "=r"(r2), "=r"(r3) : "r"(addr));
}
__device__ __forceinline__ void ldsm_x4t(unsigned& r0, unsigned& r1,
                                         unsigned& r2, unsigned& r3, unsigned addr) {
    asm volatile("ldmatrix.sync.aligned.m8n8.x4.trans.shared.b16 {%0,%1,%2,%3}, [%4];"
        : "=r"(r0), "=r"(r1), "=r"(r2), "=r"(r3) : "r"(addr));
}

__device__ __forceinline__ void cpa16(void* dst, const void* src) {
    unsigned s = (unsigned)__cvta_generic_to_shared(dst);
    asm volatile("cp.async.ca.shared.global [%0], [%1], 16;\n" :: "r"(s), "l"(src));
}
#define CP_COMMIT  asm volatile("cp.async.commit_group;\n")

// ================= fp16 dense GEMM: C = A[M][K] @ B^T (B stored [N][K]) =================
template<int OUTH>
__global__ void __launch_bounds__(256, 2) hgemm(
    const __half* __restrict__ A, const __half* __restrict__ B,
    const float* __restrict__ bias, void* __restrict__ Cout,
    int M, int N, int K, int relu)
{
    constexpr int BM = 128, BN = 128, BK = 64, NS = 2;
    constexpr int PITCH = BK + 8;
    constexpr int TSZ = BM * PITCH;

    extern __shared__ __half hsm[];
    unsigned sb = (unsigned)__cvta_generic_to_shared(hsm);

    int m0 = blockIdx.y * BM;
    int n0 = blockIdx.x * BN;
    int tid = threadIdx.x;
    int warp = tid >> 5, lane = tid & 31;
    int wy = warp & 1, wx = warp >> 1;
    int wm = wy * 64, wn = wx * 32;
    int lrow = lane & 15, lk = lane >> 4;

    float acc[4][4][4];
#pragma unroll
    for (int i = 0; i < 4; i++)
#pragma unroll
        for (int j = 0; j < 4; j++)
#pragma unroll
            for (int c = 0; c < 4; c++) acc[i][j][c] = 0.f;

    auto loadT = [&](__half* S, const __half* G, int row0, int ld, int kt) {
#pragma unroll
        for (int i = 0; i < 4; i++) {
            int e = tid + i * 256;
            int row = e >> 3, q = (e & 7) * 8;
            cpa16(&S[row * PITCH + q], G + (long long)(row0 + row) * ld + kt + q);
        }
    };

    int T = K / BK;
    loadT(hsm, A, m0, K, 0);
    loadT(hsm + NS * TSZ, B, n0, K, 0);
    CP_COMMIT;

    int st = 0;
    for (int t = 0; t < T; t++) {
        if (t + 1 < T) {
            loadT(hsm + (st ^ 1) * TSZ, A, m0, K, (t + 1) * BK);
            loadT(hsm + (NS + (st ^ 1)) * TSZ, B, n0, K, (t + 1) * BK);
            CP_COMMIT;
            asm volatile("cp.async.wait_group 1;\n");
        } else {
            asm volatile("cp.async.wait_group 0;\n");
        }
        __syncthreads();

        unsigned sA = sb + st * (TSZ * 2);
        unsigned sB = sb + (NS + st) * (TSZ * 2);
        unsigned aB = sA + (wm + lrow) * (PITCH * 2) + lk * 16;
        unsigned bB = sB + (wn + lrow) * (PITCH * 2) + lk * 16;

#pragma unroll
        for (int ks = 0; ks < 4; ks++) {
            unsigned kb = ks * 32;
            unsigned a[4][4], b0q[4], b1q[4];
#pragma unroll
            for (int i = 0; i < 4; i++)
                ldsm_x4(a[i][0], a[i][1], a[i][2], a[i][3],
                        aB + i * (16 * PITCH * 2) + kb);
            ldsm_x4(b0q[0], b0q[1], b0q[2], b0q[3], bB + kb);
            ldsm_x4(b1q[0], b1q[1], b1q[2], b1q[3], bB + 16 * (PITCH * 2) + kb);
            unsigned bfr[4][2] = {
                {b0q[0], b0q[2]}, {b0q[1], b0q[3]},
                {b1q[0], b1q[2]}, {b1q[1], b1q[3]}};
#pragma unroll
            for (int i = 0; i < 4; i++)
#pragma unroll
                for (int j = 0; j < 4; j++)
                    mma_f16(acc[i][j], a[i], bfr[j]);
        }
        __syncthreads();
        st ^= 1;
    }

#pragma unroll
    for (int i = 0; i < 4; i++) {
        int mA = m0 + wm + i * 16 + (lane >> 2);
        int mB = mA + 8;
#pragma unroll
        for (int j = 0; j < 4; j++) {
            int n = n0 + wn + j * 8 + (lane & 3) * 2;
            float b0 = bias ? bias[n] : 0.f;
            float b1 = bias ? bias[n + 1] : 0.f;
            float v00 = acc[i][j][0] + b0, v01 = acc[i][j][1] + b1;
            float v10 = acc[i][j][2] + b0, v11 = acc[i][j][3] + b1;
            if (relu) {
                v00 = fmaxf(v00, 0.f); v01 = fmaxf(v01, 0.f);
                v10 = fmaxf(v10, 0.f); v11 = fmaxf(v11, 0.f);
            }
            if (OUTH) {
                __half* C = (__half*)Cout;
                __half2 h0; h0.x = __float2half(v00); h0.y = __float2half(v01);
                __half2 h1; h1.x = __float2half(v10); h1.y = __float2half(v11);
                *(__half2*)(C + (long long)mA * N + n) = h0;
                *(__half2*)(C + (long long)mB * N + n) = h1;
            } else {
                float* C = (float*)Cout;
                *(float2*)(C + (long long)mA * N + n) = make_float2(v00, v01);
                *(float2*)(C + (long long)mB * N + n) = make_float2(v10, v11);
            }
        }
    }
}

// ================= kv GEMM: kv[f][d] = sum_s Kf[s][f] * v[s][d] =================
__global__ void __launch_bounds__(256, 2) kv_gemm(
    const __half* __restrict__ Kf, const __half* __restrict__ V,
    __half* __restrict__ KV)
{
    constexpr int BK = 32, NS = 3;
    constexpr int PITCH = 72;
    constexpr int TSZ = BK * PITCH;

    extern __shared__ __half hsm[];
    unsigned sb = (unsigned)__cvta_generic_to_shared(hsm);

    int bh = blockIdx.z;
    int b = bh >> 3, h = bh & 7;
    const __half* Ap = Kf + (long long)bh * SEQ * NF;
    const __half* Vp = V + (long long)b * SEQ * QKVW + h * HD;
    __half* Cp = KV + (long long)bh * NF * HD;

    int m0 = blockIdx.y * 64;
    int tid = threadIdx.x;
    int warp = tid >> 5, lane = tid & 31;
    int wm = (warp & 1) * 32, wn = (warp >> 1) * 16;
    int trow = (lane & 7) + ((lane >> 4) << 3);
    int tcol = ((lane >> 3) & 1) << 3;

    float acc[2][2][4];
#pragma unroll
    for (int i = 0; i < 2; i++)
#pragma unroll
        for (int j = 0; j < 2; j++)
#pragma unroll
            for (int c = 0; c < 4; c++) acc[i][j][c] = 0.f;

    auto loadA = [&](__half* S, int kt) {
        int kk = tid >> 3, q = (tid & 7) * 8;
        cpa16(&S[kk * PITCH + q], Ap + (long long)(kt + kk) * NF + m0 + q);
    };
    auto loadB = [&](__half* S, int kt) {
        int kk = tid >> 3, q = (tid & 7) * 8;
        cpa16(&S[kk * PITCH + q], Vp + (long long)(kt + kk) * QKVW + q);
    };

    int T = SEQ / BK;
#pragma unroll
    for (int s = 0; s < NS - 1; s++) {
        loadA(hsm + s * TSZ, s * BK);
        loadB(hsm + (NS + s) * TSZ, s * BK);
        CP_COMMIT;
    }

    int st = 0, ps = NS - 1;
    for (int t = 0; t < T; t++) {
        asm volatile("cp.async.wait_group %0;\n" :: "n"(NS - 2));
        __syncthreads();
        int pf = t + NS - 1;
        if (pf < T) {
            loadA(hsm + ps * TSZ, pf * BK);
            loadB(hsm + (NS + ps) * TSZ, pf * BK);
        }
        CP_COMMIT;

        unsigned sA = sb + st * (TSZ * 2);
        unsigned sB = sb + (NS + st) * (TSZ * 2);
#pragma unroll
        for (int ks = 0; ks < 2; ks++) {
            int kr = ks * 16 + trow;
            unsigned a[2][4], bq[4];
#pragma unroll
            for (int i = 0; i < 2; i++)
                ldsm_x4t(a[i][0], a[i][1], a[i][2], a[i][3],
                         sA + (kr * PITCH + wm + i * 16 + tcol) * 2);
            ldsm_x4t(bq[0], bq[1], bq[2], bq[3],
                     sB + (kr * PITCH + wn + tcol) * 2);
            unsigned bfr[2][2] = {{bq[0], bq[2]}, {bq[1], bq[3]}};
#pragma unroll
            for (int i = 0; i < 2; i++)
#pragma unroll
                for (int j = 0; j < 2; j++)
                    mma_f16(acc[i][j], a[i], bfr[j]);
        }
        st = (st + 1 == NS) ? 0 : st + 1;
        ps = (ps + 1 == NS) ? 0 : ps + 1;
    }

#pragma unroll
    for (int i = 0; i < 2; i++) {
        int mA = m0 + wm + i * 16 + (lane >> 2);
        int mB = mA + 8;
#pragma unroll
        for (int j = 0; j < 2; j++) {
            int n = wn + j * 8 + (lane & 3) * 2;
            __half2 h0, h1;
            h0.x = __float2half(acc[i][j][0]); h0.y = __float2half(acc[i][j][1]);
            h1.x = __float2half(acc[i][j][2]); h1.y = __float2half(acc[i][j][3]);
            *(__half2*)(Cp + mA * HD + n) = h0;
            *(__half2*)(Cp + mB * HD + n) = h1;
        }
    }
}

// ================= attn GEMM: O[s][h*64+d] = z[s] * Qf[s][:] @ kv[:][d] =================
__global__ void __launch_bounds__(256, 2) attn_gemm(
    const __half* __restrict__ Qf, const __half* __restrict__ KV,
    const float* __restrict__ z, __half* __restrict__ O)
{
    constexpr int BK = 32, NS = 3;
    constexpr int APITCH = 40;
    constexpr int BPITCH = 72;
    constexpr int ATSZ = 128 * APITCH;
    constexpr int BTSZ = BK * BPITCH;

    extern __shared__ __half hsm[];
    unsigned sb = (unsigned)__cvta_generic_to_shared(hsm);
    __half* Bs0 = hsm + NS * ATSZ;

    int bh = blockIdx.z;
    int b = bh >> 3, h = bh & 7;
    int m0 = blockIdx.y * 128;
    const __half* Ap = Qf + (long long)bh * SEQ * NF;
    const __half* Bp = KV + (long long)bh * NF * HD;
    __half* Op = O + (long long)b * SEQ * DMODEL + h * HD;
    const float* zp = z + (long long)bh * SEQ;

    int tid = threadIdx.x;
    int warp = tid >> 5, lane = tid & 31;
    int wm = (warp & 1) * 64, wn = (warp >> 1) * 16;
    int lrow = lane & 15, lk = lane >> 4;
    int trow = (lane & 7) + ((lane >> 4) << 3);
    int tcol = ((lane >> 3) & 1) << 3;

    float acc[4][2][4];
#pragma unroll
    for (int i = 0; i < 4; i++)
#pragma unroll
        for (int j = 0; j < 2; j++)
#pragma unroll
            for (int c = 0; c < 4; c++) acc[i][j][c] = 0.f;

    auto loadA = [&](__half* S, int kt) {
#pragma unroll
        for (int i = 0; i < 2; i++) {
            int e = tid + i * 256;
            int row = e >> 2, q = (e & 3) * 8;
            cpa16(&S[row * APITCH + q], Ap + (long long)(m0 + row) * NF + kt + q);
        }
    };
    auto loadB = [&](__half* S, int kt) {
        int kk = tid >> 3, q = (tid & 7) * 8;
        cpa16(&S[kk * BPITCH + q], Bp + (long long)(kt + kk) * HD + q);
    };

    int T = NF / BK;
#pragma unroll
    for (int s = 0; s < NS - 1; s++) {
        loadA(hsm + s * ATSZ, s * BK);
        loadB(Bs0 + s * BTSZ, s * BK);
        CP_COMMIT;
    }

    int st = 0, ps = NS - 1;
    for (int t = 0; t < T; t++) {
        asm volatile("cp.async.wait_group %0;\n" :: "n"(NS - 2));
        __syncthreads();
        int pf = t + NS - 1;
        if (pf < T) {
            loadA(hsm + ps * ATSZ, pf * BK);
            loadB(Bs0 + ps * BTSZ, pf * BK);
        }
        CP_COMMIT;

        unsigned sA = sb + st * (ATSZ * 2);
        unsigned sB = sb + (NS * ATSZ + st * BTSZ) * 2;
        unsigned aB = sA + (wm + lrow) * (APITCH * 2) + lk * 16;
#pragma unroll
        for (int ks = 0; ks < 2; ks++) {
            unsigned kb = ks * 32;
            int kr = ks * 16 + trow;
            unsigned a[4][4], bq[4];
#pragma unroll
            for (int i = 0; i < 4; i++)
                ldsm_x4(a[i][0], a[i][1], a[i][2], a[i][3],
                        aB + i * (16 * APITCH * 2) + kb);
            ldsm_x4t(bq[0], bq[1], bq[2], bq[3],
                     sB + (kr * BPITCH + wn + tcol) * 2);
            unsigned bfr[2][2] = {{bq[0], bq[2]}, {bq[1], bq[3]}};
#pragma unroll
            for (int i = 0; i < 4; i++)
#pragma unroll
                for (int j = 0; j < 2; j++)
                    mma_f16(acc[i][j], a[i], bfr[j]);
        }
        st = (st + 1 == NS) ? 0 : st + 1;
        ps = (ps + 1 == NS) ? 0 : ps + 1;
    }

#pragma unroll
    for (int i = 0; i < 4; i++) {
        int mA = m0 + wm + i * 16 + (lane >> 2);
        int mB = mA + 8;
        float rsA = zp[mA], rsB = zp[mB];
#pragma unroll
        for (int j = 0; j < 2; j++) {
            int n = wn + j * 8 + (lane & 3) * 2;
            __half2 h0, h1;
            h0.x = __float2half(acc[i][j][0] * rsA);
            h0.y = __float2half(acc[i][j][1] * rsA);
            h1.x = __float2half(acc[i][j][2] * rsB);
            h1.y = __float2half(acc[i][j][3] * rsB);
            *(__half2*)(Op + (long long)mA * DMODEL + n) = h0;
            *(__half2*)(Op + (long long)mB * DMODEL + n) = h1;
        }
    }
}

// ================= FAVOR via tensor cores: u = q_slice @ omega, then exp =================
// block: 64 rows x 1 head, 128 threads (4 warps, 2x2 grid).
__global__ void __launch_bounds__(128) favor_mma_kernel(
    const __half* __restrict__ qkv, const __half* __restrict__ om16,
    __half* __restrict__ outF, int colOff)
{
    constexpr int APITCH = 72, BPITCH = 136;
    __shared__ __half qa[64 * APITCH];
    __shared__ __half ob[64 * BPITCH];
    __shared__ float hvs[64];

    int r0 = blockIdx.x * 64;
    int h = blockIdx.y;
    int tid = threadIdx.x, warp = tid >> 5, lane = tid & 31;

    const __half* qp = qkv + (long long)r0 * QKVW + colOff + h * HD;
#pragma unroll
    for (int i = 0; i < 4; i++) {
        int e = tid + i * 128;
        int row = e >> 3, q = (e & 7) * 8;
        cpa16(&qa[row * APITCH + q], qp + (long long)row * QKVW + q);
    }
#pragma unroll
    for (int i = 0; i < 8; i++) {
        int e = tid + i * 128;
        int row = e >> 4, q = (e & 15) * 8;
        cpa16(&ob[row * BPITCH + q], om16 + row * 128 + q);
    }
    CP_COMMIT;
    asm volatile("cp.async.wait_group 0;\n");
    __syncthreads();

    // row norms: 2 threads per row
    {
        int row = tid >> 1, hs = tid & 1;
        float s = 0.f;
#pragma unroll
        for (int d = 0; d < 32; d++) {
            float v = __half2float(qa[row * APITCH + hs * 32 + d]);
            s = fmaf(v, v, s);
        }
        s += __shfl_xor_sync(0xffffffffu, s, 1);
        if (!hs) hvs[row] = s * 0.5f * 0.125f;   // 0.5 * s^2 * ||q||^2, s^2 = 8^-1... (64^-0.5)
    }
    __syncthreads();

    unsigned sbq = (unsigned)__cvta_generic_to_shared(qa);
    unsigned sbo = (unsigned)__cvta_generic_to_shared(ob);

    int wm = (warp & 1) * 32;
    int wn = (warp >> 1) * 64;
    int lrow = lane & 15, lk = lane >> 4;
    int trow = (lane & 7) + ((lane >> 4) << 3);
    int tcol = ((lane >> 3) & 1) << 3;

    float acc[2][8][4];
#pragma unroll
    for (int i = 0; i < 2; i++)
#pragma unroll
        for (int j = 0; j < 8; j++)
#pragma unroll
            for (int c = 0; c < 4; c++) acc[i][j][c] = 0.f;

    unsigned aB = sbq + (wm + lrow) * (APITCH * 2) + lk * 16;
#pragma unroll
    for (int ks = 0; ks < 4; ks++) {
        unsigned kb = ks * 32;
        int kr = ks * 16 + trow;
        unsigned a[2][4];
#pragma unroll
        for (int i = 0; i < 2; i++)
            ldsm_x4(a[i][0], a[i][1], a[i][2], a[i][3],
                    aB + i * (16 * APITCH * 2) + kb);
#pragma unroll
        for (int jj = 0; jj < 4; jj++) {
            unsigned bq[4];
            ldsm_x4t(bq[0], bq[1], bq[2], bq[3],
                     sbo + (kr * BPITCH + wn + jj * 16 + tcol) * 2);
            unsigned bfr[2][2] = {{bq[0], bq[2]}, {bq[1], bq[3]}};
#pragma unroll
            for (int i = 0; i < 2; i++)
#pragma unroll
                for (int j2 = 0; j2 < 2; j2++)
                    mma_f16(acc[i][jj * 2 + j2], a[i], bfr[j2]);
        }
    }

    int bh = (r0 >> 10) * NH + h;
    long long obase = ((long long)bh * SEQ + (r0 & 1023)) * NF;
    const float sc = 0.3535533905932738f;   // 64^-0.25
#pragma unroll
    for (int i = 0; i < 2; i++) {
        int lr = wm + i * 16 + (lane >> 2);
        float hvA = hvs[lr], hvB = hvs[lr + 8];
        long long oA = obase + (long long)lr * NF;
        long long oB = obase + (long long)(lr + 8) * NF;
#pragma unroll
        for (int j = 0; j < 8; j++) {
            int f = wn + j * 8 + (lane & 3) * 2;
            float u0 = acc[i][j][0] * sc, u1 = acc[i][j][1] * sc;
            float u2 = acc[i][j][2] * sc, u3 = acc[i][j][3] * sc;
            __half2 p0, p1, q0, q1;
            p0.x = __float2half(__expf( u0 - hvA) * 0.0625f);
            p0.y = __float2half(__expf( u1 - hvA) * 0.0625f);
            q0.x = __float2half(__expf(-u0 - hvA) * 0.0625f);
            q0.y = __float2half(__expf(-u1 - hvA) * 0.0625f);
            p1.x = __float2half(__expf( u2 - hvB) * 0.0625f);
            p1.y = __float2half(__expf( u3 - hvB) * 0.0625f);
            q1.x = __float2half(__expf(-u2 - hvB) * 0.0625f);
            q1.y = __float2half(__expf(-u3 - hvB) * 0.0625f);
            *(__half2*)(outF + oA + f)       = p0;
            *(__half2*)(outF + oA + 128 + f) = q0;
            *(__half2*)(outF + oB + f)       = p1;
            *(__half2*)(outF + oB + 128 + f) = q1;
        }
    }
}

// ---------------- z = 1/(Qf . ks + eps), Qf half ----------------
__global__ void __launch_bounds__(256) z_kernel(
    const __half* __restrict__ Qf, const float* __restrict__ ks,
    float* __restrict__ z)
{
    int bh = blockIdx.x;
    int s  = blockIdx.y * 8 + (threadIdx.x >> 5);
    int lane = threadIdx.x & 31;
    __shared__ float kss[NF];
    kss[threadIdx.x] = ks[bh * NF + threadIdx.x];
    __syncthreads();
    const __half* q = Qf + ((long long)bh * SEQ + s) * NF;
    float acc = 0.f;
#pragma unroll
    for (int i = lane; i < NF; i += 32) acc = fmaf(__half2float(q[i]), kss[i], acc);
#pragma unroll
    for (int o = 16; o; o >>= 1) acc += __shfl_xor_sync(0xffffffffu, acc, o);
    if (!lane) z[bh * SEQ + s] = 1.f / (acc + 1e-6f);
}

// ---------------- prep kernels ----------------
__global__ void __launch_bounds__(256) transpose_h(
    const float* __restrict__ in, __half* __restrict__ out, int K, int N,
    long long inL, long long outL)
{
    __shared__ float tile[32][33];
    const float* ip = in + blockIdx.z * inL;
    __half* op = out + blockIdx.z * outL;
    int n0 = blockIdx.x * 32, k0 = blockIdx.y * 32;
    int tx = threadIdx.x & 31, ty = threadIdx.x >> 5;
#pragma unroll
    for (int r = 0; r < 4; r++)
        tile[ty + r * 8][tx] = ip[(long long)(k0 + ty + r * 8) * N + n0 + tx];
    __syncthreads();
#pragma unroll
    for (int r = 0; r < 4; r++)
        op[(long long)(n0 + ty + r * 8) * K + k0 + tx] = __float2half(tile[tx][ty + r * 8]);
}

__global__ void __launch_bounds__(256) prep_bias_kernel(
    const float* __restrict__ bq, const float* __restrict__ bk,
    const float* __restrict__ bv, float* __restrict__ bqkv)
{
    int idx = blockIdx.x * 256 + threadIdx.x;
    if (idx < NLAYERS * QKVW) {
        int l = idx / QKVW, c = idx % QKVW;
        const float* src = c < 512 ? bq : (c < 1024 ? bk : bv);
        bqkv[idx] = src[l * DMODEL + (c & 511)];
    }
}

__global__ void __launch_bounds__(256) om_conv_kernel(
    const float* __restrict__ om, __half* __restrict__ om16)
{
    int idx = blockIdx.x * 256 + threadIdx.x;     // NLAYERS*64*128
    om16[idx] = __float2half(om[idx]);
}

// ---------------- encoder first layer ----------------
__global__ void __launch_bounds__(256) enc1_kernel(
    const float* __restrict__ x, const float* __restrict__ pos,
    const float* __restrict__ w, const float* __restrict__ b,
    __half* __restrict__ out)
{
    int idx = blockIdx.x * 256 + threadIdx.x;
    int row = idx >> 8, col = idx & 255;
    const float* xr = x + row * 3;
    const float* pr = pos + row * 3;
    float a = b[col];
#pragma unroll
    for (int d = 0; d < 3; d++) a = fmaf(xr[d], w[d * 256 + col], a);
#pragma unroll
    for (int d = 0; d < 3; d++) a = fmaf(pr[d], w[(3 + d) * 256 + col], a);
    out[idx] = __float2half(fmaxf(a, 0.f));
}

// ---------------- LayerNorm: writes fp32 + half ----------------
__global__ void __launch_bounds__(512) ln_kernel(
    float* __restrict__ out, __half* __restrict__ out16,
    const float* __restrict__ resid, const float* __restrict__ y,
    const float* __restrict__ g, const float* __restrict__ b)
{
    int row = blockIdx.x, t = threadIdx.x;
    long long base = (long long)row * 512;
    float v = y[base + t];
    if (resid) v += resid[base + t];
    float s = v, s2 = v * v;
#pragma unroll
    for (int o = 16; o; o >>= 1) {
        s  += __shfl_xor_sync(0xffffffffu, s,  o);
        s2 += __shfl_xor_sync(0xffffffffu, s2, o);
    }
    __shared__ float rs[16], rs2[16];
    int w = t >> 5, lane = t & 31;
    if (!lane) { rs[w] = s; rs2[w] = s2; }
    __syncthreads();
    if (t < 32) {
        float a  = (t < 16) ? rs[t]  : 0.f;
        float a2 = (t < 16) ? rs2[t] : 0.f;
#pragma unroll
        for (int o = 8; o; o >>= 1) {
            a  += __shfl_xor_sync(0xffffffffu, a,  o);
            a2 += __shfl_xor_sync(0xffffffffu, a2, o);
        }
        if (!t) { rs[0] = a; rs2[0] = a2; }
    }
    __syncthreads();
    float mean = rs[0] * (1.f / 512.f);
    float var  = rs2[0] * (1.f / 512.f) - mean * mean;
    float r = (v - mean) * rsqrtf(var + 1e-5f) * g[t] + b[t];
    out[base + t] = r;
    out16[base + t] = __float2half(r);
}

// ---------------- ksum: read half Kf, 2-stage ----------------
__global__ void __launch_bounds__(256) ksum1_kernel(
    const __half* __restrict__ Kf, float* __restrict__ part)
{
    int bh = blockIdx.x, ch = blockIdx.y, f = threadIdx.x;
    const __half* base = Kf + ((long long)bh * SEQ + ch * 128) * NF + f;
    float s = 0.f;
#pragma unroll 8
    for (int i = 0; i < 128; i++) s += __half2float(base[(long long)i * NF]);
    part[(bh * 8 + ch) * NF + f] = s;
}
__global__ void __launch_bounds__(256) ksum2_kernel(
    const float* __restrict__ part, float* __restrict__ ks)
{
    int bh = blockIdx.x, f = threadIdx.x;
    float s = 0.f;
#pragma unroll
    for (int c = 0; c < 8; c++) s += part[(bh * 8 + c) * NF + f];
    ks[bh * NF + f] = s;
}

// ---------------- mean pool + classifier ----------------
__global__ void __launch_bounds__(512) pool_cls_kernel(
    const float* __restrict__ h, const float* __restrict__ cw,
    const float* __restrict__ cb, float* __restrict__ out)
{
    int b = blockIdx.x, t = threadIdx.x;
    const float* base = h + (long long)b * SEQ * DMODEL + t;
    float s = 0.f;
#pragma unroll 8
    for (int i = 0; i < SEQ; i++) s += base[(long long)i * DMODEL];
    __shared__ float pooled[DMODEL];
    pooled[t] = s * (1.f / (float)SEQ);
    __syncthreads();
    if (t < 16) {
        float acc = cb[t];
        for (int d = 0; d < DMODEL; d++) acc = fmaf(pooled[d], cw[d * 16 + t], acc);
        out[b * 16 + t] = acc;
    }
}

// ---------------- host driver ----------------
extern "C" void kernel_launch(void* const* d_in, const int* in_sizes, int n_in,
                              void* d_out, int out_size)
{
    const float* x      = (const float*)d_in[0];
    const float* pos    = (const float*)d_in[1];
    const float* enc_w1 = (const float*)d_in[2];
    const float* enc_b1 = (const float*)d_in[3];
    const float* enc_w2 = (const float*)d_in[4];
    const float* enc_b2 = (const float*)d_in[5];
    const float* enc_g  = (const float*)d_in[6];
    const float* enc_bb = (const float*)d_in[7];
    const float* wq     = (const float*)d_in[8];
    const float* bq     = (const float*)d_in[9];
    const float* wk     = (const float*)d_in[10];
    const float* bk     = (const float*)d_in[11];
    const float* wv     = (const float*)d_in[12];
    const float* bv     = (const float*)d_in[13];
    const float* wo     = (const float*)d_in[14];
    const float* bo     = (const float*)d_in[15];
    const float* ln1_g  = (const float*)d_in[16];
    const float* ln1_b  = (const float*)d_in[17];
    const float* w1     = (const float*)d_in[18];
    const float* b1     = (const float*)d_in[19];
    const float* w2     = (const float*)d_in[20];
    const float* b2     = (const float*)d_in[21];
    const float* ln2_g  = (const float*)d_in[22];
    const float* ln2_b  = (const float*)d_in[23];
    const float* omega  = (const float*)d_in[24];
    const float* cls_w  = (const float*)d_in[25];
    const float* cls_b  = (const float*)d_in[26];

    float *p_h, *p_v, *p_ks, *p_kp, *p_z, *p_bqkv;
    __half *p_h16, *p_t016, *p_qkv16, *p_ffn16, *p_attn16, *p_Qf, *p_Kf, *p_kv, *p_om16;
    __half *p_wqkvT, *p_w1T, *p_w2T, *p_woT, *p_ew2T;
    cudaGetSymbolAddress((void**)&p_h,    g_h);
    cudaGetSymbolAddress((void**)&p_v,    g_v);
    cudaGetSymbolAddress((void**)&p_Qf,   g_Qf);
    cudaGetSymbolAddress((void**)&p_Kf,   g_Kf);
    cudaGetSymbolAddress((void**)&p_kv,   g_kv);
    cudaGetSymbolAddress((void**)&p_ks,   g_ks);
    cudaGetSymbolAddress((void**)&p_kp,   g_kp);
    cudaGetSymbolAddress((void**)&p_z,    g_z);
    cudaGetSymbolAddress((void**)&p_bqkv, g_bqkv);
    cudaGetSymbolAddress((void**)&p_h16,  g_h16);
    cudaGetSymbolAddress((void**)&p_t016, g_t016);
    cudaGetSymbolAddress((void**)&p_qkv16,g_qkv16);
    cudaGetSymbolAddress((void**)&p_ffn16,g_ffn16);
    cudaGetSymbolAddress((void**)&p_attn16,g_attn16);
    cudaGetSymbolAddress((void**)&p_om16, g_om16);
    cudaGetSymbolAddress((void**)&p_wqkvT,g_wqkvT);
    cudaGetSymbolAddress((void**)&p_w1T,  g_w1T);
    cudaGetSymbolAddress((void**)&p_w2T,  g_w2T);
    cudaGetSymbolAddress((void**)&p_woT,  g_woT);
    cudaGetSymbolAddress((void**)&p_ew2T, g_ew2T);

    const int SM_H    = 2 * 2 * 128 * 72 * 2;
    const int SM_KV   = 3 * 2 * 32 * 72 * 2;
    const int SM_ATTN = 3 * (128 * 40 + 32 * 72) * 2;
    cudaFuncSetAttribute(hgemm<0>, cudaFuncAttributeMaxDynamicSharedMemorySize, SM_H);
    cudaFuncSetAttribute(hgemm<1>, cudaFuncAttributeMaxDynamicSharedMemorySize, SM_H);
    cudaFuncSetAttribute(kv_gemm,  cudaFuncAttributeMaxDynamicSharedMemorySize, SM_KV);
    cudaFuncSetAttribute(attn_gemm,cudaFuncAttributeMaxDynamicSharedMemorySize, SM_ATTN);

    // ---- weight prep ----
    transpose_h<<<dim3(16,16,4), 256>>>(wq, p_wqkvT,            DMODEL, DMODEL, 512*512, (long long)QKVW*DMODEL);
    transpose_h<<<dim3(16,16,4), 256>>>(wk, p_wqkvT + 512*512,  DMODEL, DMODEL, 512*512, (long long)QKVW*DMODEL);
    transpose_h<<<dim3(16,16,4), 256>>>(wv, p_wqkvT + 1024*512, DMODEL, DMODEL, 512*512, (long long)QKVW*DMODEL);
    transpose_h<<<dim3(32,16,4), 256>>>(w1, p_w1T, DMODEL, FFNH, (long long)512*1024, (long long)FFNH*DMODEL);
    transpose_h<<<dim3(16,32,4), 256>>>(w2, p_w2T, FFNH, DMODEL, (long long)1024*512, (long long)DMODEL*FFNH);
    transpose_h<<<dim3(16,16,4), 256>>>(wo, p_woT, DMODEL, DMODEL, 512*512, 512*512);
    transpose_h<<<dim3(16,8,1),  256>>>(enc_w2, p_ew2T, 256, DMODEL, 0, 0);
    prep_bias_kernel<<<(NLAYERS*QKVW + 255)/256, 256>>>(bq, bk, bv, p_bqkv);
    om_conv_kernel<<<(NLAYERS*HD*128 + 255)/256, 256>>>(omega, p_om16);

    auto dense = [&](const __half* A, const __half* Bt, const float* bias,
                     void* C, int M, int Nn, int K, int relu, int outh) {
        dim3 grid(Nn / 128, M / 128, 1);
        if (outh) hgemm<1><<<grid, 256, SM_H>>>(A, Bt, bias, C, M, Nn, K, relu);
        else      hgemm<0><<<grid, 256, SM_H>>>(A, Bt, bias, C, M, Nn, K, relu);
    };

    // ---- encoder ----
    enc1_kernel<<<NTOK, 256>>>(x, pos, enc_w1, enc_b1, p_t016);
    dense(p_t016, p_ew2T, enc_b2, p_v, NTOK, DMODEL, 256, 0, 0);
    ln_kernel<<<NTOK, 512>>>(p_h, p_h16, nullptr, p_v, enc_g, enc_bb);

    for (int l = 0; l < NLAYERS; l++) {
        const __half* WqkvT = p_wqkvT + (long long)l * QKVW * DMODEL;
        const float*  Bqkv  = p_bqkv + l * QKVW;
        const __half* WoT   = p_woT + (long long)l * DMODEL * DMODEL;
        const float*  Bo    = bo + l * DMODEL;
        const __half* W1T   = p_w1T + (long long)l * FFNH * DMODEL;
        const float*  B1    = b1 + l * FFNH;
        const __half* W2T   = p_w2T + (long long)l * DMODEL * FFNH;
        const float*  B2    = b2 + l * DMODEL;
        const __half* Om16  = p_om16 + (long long)l * HD * 128;

        // merged QKV projection (half out)
        dense(p_h16, WqkvT, Bqkv, p_qkv16, NTOK, QKVW, DMODEL, 0, 1);

        // FAVOR(K) via tensor cores; ksum; FAVOR(Q); z
        favor_mma_kernel<<<dim3(NTOK/64, NH), 128>>>(p_qkv16, Om16, p_Kf, 512);
        ksum1_kernel<<<dim3(BATCH*NH, 8), 256>>>(p_Kf, p_kp);
        ksum2_kernel<<<BATCH*NH, 256>>>(p_kp, p_ks);
        favor_mma_kernel<<<dim3(NTOK/64, NH), 128>>>(p_qkv16, Om16, p_Qf, 0);
        z_kernel<<<dim3(BATCH*NH, SEQ/8), 256>>>(p_Qf, p_ks, p_z);

        // kv / attn (fp16 tensor)
        kv_gemm<<<dim3(1, NF/64, BATCH*NH), 256, SM_KV>>>(p_Kf, p_qkv16 + 1024, p_kv);
        attn_gemm<<<dim3(1, SEQ/128, BATCH*NH), 256, SM_ATTN>>>(p_Qf, p_kv, p_z, p_attn16);

        // output projection + residual LN
        dense(p_attn16, WoT, Bo, p_v, NTOK, DMODEL, DMODEL, 0, 0);
        ln_kernel<<<NTOK, 512>>>(p_h, p_h16, p_h, p_v, ln1_g + l*DMODEL, ln1_b + l*DMODEL);

        // FFN + residual LN
        dense(p_h16, W1T, B1, p_ffn16, NTOK, FFNH, DMODEL, 1, 1);
        dense(p_ffn16, W2T, B2, p_v, NTOK, DMODEL, FFNH, 0, 0);
        ln_kernel<<<NTOK, 512>>>(p_h, p_h16, p_h, p_v, ln2_g + l*DMODEL, ln2_b + l*DMODEL);
    }

    pool_cls_kernel<<<BATCH, 512>>>(p_h, cls_w, cls_b, (float*)d_out);
}

// round 15
// speedup vs baseline: 7.9896x; 1.1045x over previous
#include <cuda_runtime.h>
#include <cuda_fp16.h>
#include <math.h>

#define BATCH 16
#define SEQ 1024
#define NTOK (BATCH*SEQ)
#define DMODEL 512
#define NH 8
#define HD 64
#define NF 256
#define NLAYERS 4
#define FFNH 1024
#define QKVW 1536

// ---------------- scratch ----------------
__device__ __half g_h16 [NTOK*DMODEL];
__device__ __half g_t016[NTOK*256];
__device__ __half g_qkv16[NTOK*QKVW];
__device__ __half g_ffn16[NTOK*FFNH];
__device__ __half g_attn16[NTOK*DMODEL];
__device__ __half g_v16 [NTOK*DMODEL];
__device__ __half g_Qf  [BATCH*NH*SEQ*NF];
__device__ __half g_Kf  [BATCH*NH*SEQ*NF];
__device__ __half g_kv  [BATCH*NH*NF*HD];
__device__ float  g_ks  [BATCH*NH*NF];
__device__ float  g_kp  [BATCH*NH*8*NF];
__device__ float  g_z   [BATCH*NH*SEQ];
__device__ __half g_wqkvT[NLAYERS*QKVW*DMODEL];
__device__ float  g_bqkv [NLAYERS*QKVW];
__device__ __half g_w1T  [NLAYERS*FFNH*DMODEL];
__device__ __half g_w2T  [NLAYERS*DMODEL*FFNH];
__device__ __half g_woT  [NLAYERS*DMODEL*DMODEL];
__device__ __half g_ew2T [DMODEL*256];
__device__ __half g_om16 [NLAYERS*HD*128];

__device__ __forceinline__ void mma_f16(float* d, const unsigned* a, const unsigned* b) {
    asm volatile(
        "mma.sync.aligned.m16n8k16.row.col.f32.f16.f16.f32 "
        "{%0,%1,%2,%3},{%4,%5,%6,%7},{%8,%9},{%0,%1,%2,%3};\n"
        : "+f"(d[0]), "+f"(d[1]), "+f"(d[2]), "+f"(d[3])
        : "r"(a[0]), "r"(a[1]), "r"(a[2]), "r"(a[3]),
          "r"(b[0]), "r"(b[1]));
}

__device__ __forceinline__ void ldsm_x4(unsigned& r0, unsigned& r1,
                                        unsigned& r2, unsigned& r3, unsigned addr) {
    asm volatile("ldmatrix.sync.aligned.m8n8.x4.shared.b16 {%0,%1,%2,%3}, [%4];"
        : "=r"(r0), "=r"(r1), "=r"(r2), "=r"(r3) : "r"(addr));
}
__device__ __forceinline__ void ldsm_x4t(unsigned& r0, unsigned& r1,
                                         unsigned& r2, unsigned& r3, unsigned addr) {
    asm volatile("ldmatrix.sync.aligned.m8n8.x4.trans.shared.b16 {%0,%1,%2,%3}, [%4];"
        : "=r"(r0), "=r"(r1), "=r"(r2), "=r"(r3) : "r"(addr));
}

__device__ __forceinline__ void cpa16(void* dst, const void* src) {
    unsigned s = (unsigned)__cvta_generic_to_shared(dst);
    asm volatile("cp.async.ca.shared.global [%0], [%1], 16;\n" :: "r"(s), "l"(src));
}
#define CP_COMMIT  asm volatile("cp.async.commit_group;\n")

// ================= fp16 dense GEMM: C = A[M][K] @ B^T (B stored [N][K]) =================
template<int OUTH>
__global__ void __launch_bounds__(256, 2) hgemm(
    const __half* __restrict__ A, const __half* __restrict__ B,
    const float* __restrict__ bias, void* __restrict__ Cout,
    int M, int N, int K, int relu)
{
    constexpr int BM = 128, BN = 128, BK = 64, NS = 2;
    constexpr int PITCH = BK + 8;
    constexpr int TSZ = BM * PITCH;

    extern __shared__ __half hsm[];
    unsigned sb = (unsigned)__cvta_generic_to_shared(hsm);

    int m0 = blockIdx.y * BM;
    int n0 = blockIdx.x * BN;
    int tid = threadIdx.x;
    int warp = tid >> 5, lane = tid & 31;
    int wy = warp & 1, wx = warp >> 1;
    int wm = wy * 64, wn = wx * 32;
    int lrow = lane & 15, lk = lane >> 4;

    float acc[4][4][4];
#pragma unroll
    for (int i = 0; i < 4; i++)
#pragma unroll
        for (int j = 0; j < 4; j++)
#pragma unroll
            for (int c = 0; c < 4; c++) acc[i][j][c] = 0.f;

    auto loadT = [&](__half* S, const __half* G, int row0, int ld, int kt) {
#pragma unroll
        for (int i = 0; i < 4; i++) {
            int e = tid + i * 256;
            int row = e >> 3, q = (e & 7) * 8;
            cpa16(&S[row * PITCH + q], G + (long long)(row0 + row) * ld + kt + q);
        }
    };

    int T = K / BK;
    loadT(hsm, A, m0, K, 0);
    loadT(hsm + NS * TSZ, B, n0, K, 0);
    CP_COMMIT;

    int st = 0;
    for (int t = 0; t < T; t++) {
        if (t + 1 < T) {
            loadT(hsm + (st ^ 1) * TSZ, A, m0, K, (t + 1) * BK);
            loadT(hsm + (NS + (st ^ 1)) * TSZ, B, n0, K, (t + 1) * BK);
            CP_COMMIT;
            asm volatile("cp.async.wait_group 1;\n");
        } else {
            asm volatile("cp.async.wait_group 0;\n");
        }
        __syncthreads();

        unsigned sA = sb + st * (TSZ * 2);
        unsigned sB = sb + (NS + st) * (TSZ * 2);
        unsigned aB = sA + (wm + lrow) * (PITCH * 2) + lk * 16;
        unsigned bB = sB + (wn + lrow) * (PITCH * 2) + lk * 16;

#pragma unroll
        for (int ks = 0; ks < 4; ks++) {
            unsigned kb = ks * 32;
            unsigned a[4][4], b0q[4], b1q[4];
#pragma unroll
            for (int i = 0; i < 4; i++)
                ldsm_x4(a[i][0], a[i][1], a[i][2], a[i][3],
                        aB + i * (16 * PITCH * 2) + kb);
            ldsm_x4(b0q[0], b0q[1], b0q[2], b0q[3], bB + kb);
            ldsm_x4(b1q[0], b1q[1], b1q[2], b1q[3], bB + 16 * (PITCH * 2) + kb);
            unsigned bfr[4][2] = {
                {b0q[0], b0q[2]}, {b0q[1], b0q[3]},
                {b1q[0], b1q[2]}, {b1q[1], b1q[3]}};
#pragma unroll
            for (int i = 0; i < 4; i++)
#pragma unroll
                for (int j = 0; j < 4; j++)
                    mma_f16(acc[i][j], a[i], bfr[j]);
        }
        __syncthreads();
        st ^= 1;
    }

#pragma unroll
    for (int i = 0; i < 4; i++) {
        int mA = m0 + wm + i * 16 + (lane >> 2);
        int mB = mA + 8;
#pragma unroll
        for (int j = 0; j < 4; j++) {
            int n = n0 + wn + j * 8 + (lane & 3) * 2;
            float b0 = bias ? bias[n] : 0.f;
            float b1 = bias ? bias[n + 1] : 0.f;
            float v00 = acc[i][j][0] + b0, v01 = acc[i][j][1] + b1;
            float v10 = acc[i][j][2] + b0, v11 = acc[i][j][3] + b1;
            if (relu) {
                v00 = fmaxf(v00, 0.f); v01 = fmaxf(v01, 0.f);
                v10 = fmaxf(v10, 0.f); v11 = fmaxf(v11, 0.f);
            }
            if (OUTH) {
                __half* C = (__half*)Cout;
                __half2 h0; h0.x = __float2half(v00); h0.y = __float2half(v01);
                __half2 h1; h1.x = __float2half(v10); h1.y = __float2half(v11);
                *(__half2*)(C + (long long)mA * N + n) = h0;
                *(__half2*)(C + (long long)mB * N + n) = h1;
            } else {
                float* C = (float*)Cout;
                *(float2*)(C + (long long)mA * N + n) = make_float2(v00, v01);
                *(float2*)(C + (long long)mB * N + n) = make_float2(v10, v11);
            }
        }
    }
}

// ================= kv GEMM: kv[f][d] = sum_s Kf[s][f] * v[s][d] =================
__global__ void __launch_bounds__(256, 2) kv_gemm(
    const __half* __restrict__ Kf, const __half* __restrict__ V,
    __half* __restrict__ KV)
{
    constexpr int BK = 32, NS = 3;
    constexpr int PITCH = 72;
    constexpr int TSZ = BK * PITCH;

    extern __shared__ __half hsm[];
    unsigned sb = (unsigned)__cvta_generic_to_shared(hsm);

    int bh = blockIdx.z;
    int b = bh >> 3, h = bh & 7;
    const __half* Ap = Kf + (long long)bh * SEQ * NF;
    const __half* Vp = V + (long long)b * SEQ * QKVW + h * HD;
    __half* Cp = KV + (long long)bh * NF * HD;

    int m0 = blockIdx.y * 64;
    int tid = threadIdx.x;
    int warp = tid >> 5, lane = tid & 31;
    int wm = (warp & 1) * 32, wn = (warp >> 1) * 16;
    int trow = (lane & 7) + ((lane >> 4) << 3);
    int tcol = ((lane >> 3) & 1) << 3;

    float acc[2][2][4];
#pragma unroll
    for (int i = 0; i < 2; i++)
#pragma unroll
        for (int j = 0; j < 2; j++)
#pragma unroll
            for (int c = 0; c < 4; c++) acc[i][j][c] = 0.f;

    auto loadA = [&](__half* S, int kt) {
        int kk = tid >> 3, q = (tid & 7) * 8;
        cpa16(&S[kk * PITCH + q], Ap + (long long)(kt + kk) * NF + m0 + q);
    };
    auto loadB = [&](__half* S, int kt) {
        int kk = tid >> 3, q = (tid & 7) * 8;
        cpa16(&S[kk * PITCH + q], Vp + (long long)(kt + kk) * QKVW + q);
    };

    int T = SEQ / BK;
#pragma unroll
    for (int s = 0; s < NS - 1; s++) {
        loadA(hsm + s * TSZ, s * BK);
        loadB(hsm + (NS + s) * TSZ, s * BK);
        CP_COMMIT;
    }

    int st = 0, ps = NS - 1;
    for (int t = 0; t < T; t++) {
        asm volatile("cp.async.wait_group %0;\n" :: "n"(NS - 2));
        __syncthreads();
        int pf = t + NS - 1;
        if (pf < T) {
            loadA(hsm + ps * TSZ, pf * BK);
            loadB(hsm + (NS + ps) * TSZ, pf * BK);
        }
        CP_COMMIT;

        unsigned sA = sb + st * (TSZ * 2);
        unsigned sB = sb + (NS + st) * (TSZ * 2);
#pragma unroll
        for (int ks = 0; ks < 2; ks++) {
            int kr = ks * 16 + trow;
            unsigned a[2][4], bq[4];
#pragma unroll
            for (int i = 0; i < 2; i++)
                ldsm_x4t(a[i][0], a[i][1], a[i][2], a[i][3],
                         sA + (kr * PITCH + wm + i * 16 + tcol) * 2);
            ldsm_x4t(bq[0], bq[1], bq[2], bq[3],
                     sB + (kr * PITCH + wn + tcol) * 2);
            unsigned bfr[2][2] = {{bq[0], bq[2]}, {bq[1], bq[3]}};
#pragma unroll
            for (int i = 0; i < 2; i++)
#pragma unroll
                for (int j = 0; j < 2; j++)
                    mma_f16(acc[i][j], a[i], bfr[j]);
        }
        st = (st + 1 == NS) ? 0 : st + 1;
        ps = (ps + 1 == NS) ? 0 : ps + 1;
    }

#pragma unroll
    for (int i = 0; i < 2; i++) {
        int mA = m0 + wm + i * 16 + (lane >> 2);
        int mB = mA + 8;
#pragma unroll
        for (int j = 0; j < 2; j++) {
            int n = wn + j * 8 + (lane & 3) * 2;
            __half2 h0, h1;
            h0.x = __float2half(acc[i][j][0]); h0.y = __float2half(acc[i][j][1]);
            h1.x = __float2half(acc[i][j][2]); h1.y = __float2half(acc[i][j][3]);
            *(__half2*)(Cp + mA * HD + n) = h0;
            *(__half2*)(Cp + mB * HD + n) = h1;
        }
    }
}

// ================= attn GEMM: O[s][h*64+d] = z[s] * Qf[s][:] @ kv[:][d] =================
__global__ void __launch_bounds__(256, 2) attn_gemm(
    const __half* __restrict__ Qf, const __half* __restrict__ KV,
    const float* __restrict__ z, __half* __restrict__ O)
{
    constexpr int BK = 32, NS = 3;
    constexpr int APITCH = 40;
    constexpr int BPITCH = 72;
    constexpr int ATSZ = 128 * APITCH;
    constexpr int BTSZ = BK * BPITCH;

    extern __shared__ __half hsm[];
    unsigned sb = (unsigned)__cvta_generic_to_shared(hsm);
    __half* Bs0 = hsm + NS * ATSZ;

    int bh = blockIdx.z;
    int b = bh >> 3, h = bh & 7;
    int m0 = blockIdx.y * 128;
    const __half* Ap = Qf + (long long)bh * SEQ * NF;
    const __half* Bp = KV + (long long)bh * NF * HD;
    __half* Op = O + (long long)b * SEQ * DMODEL + h * HD;
    const float* zp = z + (long long)bh * SEQ;

    int tid = threadIdx.x;
    int warp = tid >> 5, lane = tid & 31;
    int wm = (warp & 1) * 64, wn = (warp >> 1) * 16;
    int lrow = lane & 15, lk = lane >> 4;
    int trow = (lane & 7) + ((lane >> 4) << 3);
    int tcol = ((lane >> 3) & 1) << 3;

    float acc[4][2][4];
#pragma unroll
    for (int i = 0; i < 4; i++)
#pragma unroll
        for (int j = 0; j < 2; j++)
#pragma unroll
            for (int c = 0; c < 4; c++) acc[i][j][c] = 0.f;

    auto loadA = [&](__half* S, int kt) {
#pragma unroll
        for (int i = 0; i < 2; i++) {
            int e = tid + i * 256;
            int row = e >> 2, q = (e & 3) * 8;
            cpa16(&S[row * APITCH + q], Ap + (long long)(m0 + row) * NF + kt + q);
        }
    };
    auto loadB = [&](__half* S, int kt) {
        int kk = tid >> 3, q = (tid & 7) * 8;
        cpa16(&S[kk * BPITCH + q], Bp + (long long)(kt + kk) * HD + q);
    };

    int T = NF / BK;
#pragma unroll
    for (int s = 0; s < NS - 1; s++) {
        loadA(hsm + s * ATSZ, s * BK);
        loadB(Bs0 + s * BTSZ, s * BK);
        CP_COMMIT;
    }

    int st = 0, ps = NS - 1;
    for (int t = 0; t < T; t++) {
        asm volatile("cp.async.wait_group %0;\n" :: "n"(NS - 2));
        __syncthreads();
        int pf = t + NS - 1;
        if (pf < T) {
            loadA(hsm + ps * ATSZ, pf * BK);
            loadB(Bs0 + ps * BTSZ, pf * BK);
        }
        CP_COMMIT;

        unsigned sA = sb + st * (ATSZ * 2);
        unsigned sB = sb + (NS * ATSZ + st * BTSZ) * 2;
        unsigned aB = sA + (wm + lrow) * (APITCH * 2) + lk * 16;
#pragma unroll
        for (int ks = 0; ks < 2; ks++) {
            unsigned kb = ks * 32;
            int kr = ks * 16 + trow;
            unsigned a[4][4], bq[4];
#pragma unroll
            for (int i = 0; i < 4; i++)
                ldsm_x4(a[i][0], a[i][1], a[i][2], a[i][3],
                        aB + i * (16 * APITCH * 2) + kb);
            ldsm_x4t(bq[0], bq[1], bq[2], bq[3],
                     sB + (kr * BPITCH + wn + tcol) * 2);
            unsigned bfr[2][2] = {{bq[0], bq[2]}, {bq[1], bq[3]}};
#pragma unroll
            for (int i = 0; i < 4; i++)
#pragma unroll
                for (int j = 0; j < 2; j++)
                    mma_f16(acc[i][j], a[i], bfr[j]);
        }
        st = (st + 1 == NS) ? 0 : st + 1;
        ps = (ps + 1 == NS) ? 0 : ps + 1;
    }

#pragma unroll
    for (int i = 0; i < 4; i++) {
        int mA = m0 + wm + i * 16 + (lane >> 2);
        int mB = mA + 8;
        float rsA = zp[mA], rsB = zp[mB];
#pragma unroll
        for (int j = 0; j < 2; j++) {
            int n = wn + j * 8 + (lane & 3) * 2;
            __half2 h0, h1;
            h0.x = __float2half(acc[i][j][0] * rsA);
            h0.y = __float2half(acc[i][j][1] * rsA);
            h1.x = __float2half(acc[i][j][2] * rsB);
            h1.y = __float2half(acc[i][j][3] * rsB);
            *(__half2*)(Op + (long long)mA * DMODEL + n) = h0;
            *(__half2*)(Op + (long long)mB * DMODEL + n) = h1;
        }
    }
}

// ================= FAVOR via tensor cores =================
__global__ void __launch_bounds__(128) favor_mma_kernel(
    const __half* __restrict__ qkv, const __half* __restrict__ om16,
    __half* __restrict__ outF, int colOff)
{
    constexpr int APITCH = 72, BPITCH = 136;
    __shared__ __half qa[64 * APITCH];
    __shared__ __half ob[64 * BPITCH];
    __shared__ float hvs[64];

    int r0 = blockIdx.x * 64;
    int h = blockIdx.y;
    int tid = threadIdx.x, warp = tid >> 5, lane = tid & 31;

    const __half* qp = qkv + (long long)r0 * QKVW + colOff + h * HD;
#pragma unroll
    for (int i = 0; i < 4; i++) {
        int e = tid + i * 128;
        int row = e >> 3, q = (e & 7) * 8;
        cpa16(&qa[row * APITCH + q], qp + (long long)row * QKVW + q);
    }
#pragma unroll
    for (int i = 0; i < 8; i++) {
        int e = tid + i * 128;
        int row = e >> 4, q = (e & 15) * 8;
        cpa16(&ob[row * BPITCH + q], om16 + row * 128 + q);
    }
    CP_COMMIT;
    asm volatile("cp.async.wait_group 0;\n");
    __syncthreads();

    {
        int row = tid >> 1, hs = tid & 1;
        float s = 0.f;
#pragma unroll
        for (int d = 0; d < 32; d++) {
            float v = __half2float(qa[row * APITCH + hs * 32 + d]);
            s = fmaf(v, v, s);
        }
        s += __shfl_xor_sync(0xffffffffu, s, 1);
        if (!hs) hvs[row] = s * 0.5f * 0.125f;
    }
    __syncthreads();

    unsigned sbq = (unsigned)__cvta_generic_to_shared(qa);
    unsigned sbo = (unsigned)__cvta_generic_to_shared(ob);

    int wm = (warp & 1) * 32;
    int wn = (warp >> 1) * 64;
    int lrow = lane & 15, lk = lane >> 4;
    int trow = (lane & 7) + ((lane >> 4) << 3);
    int tcol = ((lane >> 3) & 1) << 3;

    float acc[2][8][4];
#pragma unroll
    for (int i = 0; i < 2; i++)
#pragma unroll
        for (int j = 0; j < 8; j++)
#pragma unroll
            for (int c = 0; c < 4; c++) acc[i][j][c] = 0.f;

    unsigned aB = sbq + (wm + lrow) * (APITCH * 2) + lk * 16;
#pragma unroll
    for (int ks = 0; ks < 4; ks++) {
        unsigned kb = ks * 32;
        int kr = ks * 16 + trow;
        unsigned a[2][4];
#pragma unroll
        for (int i = 0; i < 2; i++)
            ldsm_x4(a[i][0], a[i][1], a[i][2], a[i][3],
                    aB + i * (16 * APITCH * 2) + kb);
#pragma unroll
        for (int jj = 0; jj < 4; jj++) {
            unsigned bq[4];
            ldsm_x4t(bq[0], bq[1], bq[2], bq[3],
                     sbo + (kr * BPITCH + wn + jj * 16 + tcol) * 2);
            unsigned bfr[2][2] = {{bq[0], bq[2]}, {bq[1], bq[3]}};
#pragma unroll
            for (int i = 0; i < 2; i++)
#pragma unroll
                for (int j2 = 0; j2 < 2; j2++)
                    mma_f16(acc[i][jj * 2 + j2], a[i], bfr[j2]);
        }
    }

    int bh = (r0 >> 10) * NH + h;
    long long obase = ((long long)bh * SEQ + (r0 & 1023)) * NF;
    const float sc = 0.3535533905932738f;
#pragma unroll
    for (int i = 0; i < 2; i++) {
        int lr = wm + i * 16 + (lane >> 2);
        float hvA = hvs[lr], hvB = hvs[lr + 8];
        long long oA = obase + (long long)lr * NF;
        long long oB = obase + (long long)(lr + 8) * NF;
#pragma unroll
        for (int j = 0; j < 8; j++) {
            int f = wn + j * 8 + (lane & 3) * 2;
            float u0 = acc[i][j][0] * sc, u1 = acc[i][j][1] * sc;
            float u2 = acc[i][j][2] * sc, u3 = acc[i][j][3] * sc;
            __half2 p0, p1, q0, q1;
            p0.x = __float2half(__expf( u0 - hvA) * 0.0625f);
            p0.y = __float2half(__expf( u1 - hvA) * 0.0625f);
            q0.x = __float2half(__expf(-u0 - hvA) * 0.0625f);
            q0.y = __float2half(__expf(-u1 - hvA) * 0.0625f);
            p1.x = __float2half(__expf( u2 - hvB) * 0.0625f);
            p1.y = __float2half(__expf( u3 - hvB) * 0.0625f);
            q1.x = __float2half(__expf(-u2 - hvB) * 0.0625f);
            q1.y = __float2half(__expf(-u3 - hvB) * 0.0625f);
            *(__half2*)(outF + oA + f)       = p0;
            *(__half2*)(outF + oA + 128 + f) = q0;
            *(__half2*)(outF + oB + f)       = p1;
            *(__half2*)(outF + oB + 128 + f) = q1;
        }
    }
}

// ---------------- z = 1/(Qf . ks + eps) ----------------
__global__ void __launch_bounds__(256) z_kernel(
    const __half* __restrict__ Qf, const float* __restrict__ ks,
    float* __restrict__ z)
{
    int bh = blockIdx.x;
    int s  = blockIdx.y * 8 + (threadIdx.x >> 5);
    int lane = threadIdx.x & 31;
    __shared__ float kss[NF];
    kss[threadIdx.x] = ks[bh * NF + threadIdx.x];
    __syncthreads();
    const __half* q = Qf + ((long long)bh * SEQ + s) * NF;
    float acc = 0.f;
#pragma unroll
    for (int i = lane; i < NF; i += 32) acc = fmaf(__half2float(q[i]), kss[i], acc);
#pragma unroll
    for (int o = 16; o; o >>= 1) acc += __shfl_xor_sync(0xffffffffu, acc, o);
    if (!lane) z[bh * SEQ + s] = 1.f / (acc + 1e-6f);
}

// ---------------- merged prep: all transposes + bias + omega, one kernel ----------------
__device__ __forceinline__ void tr32(const float* ip, __half* op, int K, int N,
                                     int tx, int ty, int tid, float (*tile)[33])
{
    int n0 = tx * 32, k0 = ty * 32;
    int lx = tid & 31, ly = tid >> 5;
#pragma unroll
    for (int r = 0; r < 4; r++)
        tile[ly + r * 8][lx] = ip[(long long)(k0 + ly + r * 8) * N + n0 + lx];
    __syncthreads();
#pragma unroll
    for (int r = 0; r < 4; r++)
        op[(long long)(n0 + ly + r * 8) * K + k0 + lx] = __float2half(tile[lx][ly + r * 8]);
}

__global__ void __launch_bounds__(256) prep_all(
    const float* __restrict__ wq, const float* __restrict__ wk, const float* __restrict__ wv,
    const float* __restrict__ w1, const float* __restrict__ w2, const float* __restrict__ wo,
    const float* __restrict__ ew2,
    const float* __restrict__ bq, const float* __restrict__ bk, const float* __restrict__ bv,
    const float* __restrict__ om,
    __half* __restrict__ wqkvT, __half* __restrict__ w1T, __half* __restrict__ w2T,
    __half* __restrict__ woT, __half* __restrict__ ew2T, __half* __restrict__ om16,
    float* __restrict__ bqkv)
{
    __shared__ float tile[32][33];
    int b = blockIdx.x, tid = threadIdx.x;
    if (b < 3072) {                    // wq/wk/wv: 1024 tiles each
        int which = b >> 10, t = b & 1023;
        int l = t >> 8, rem = t & 255;
        int tx = rem & 15, ty = rem >> 4;
        const float* src = which == 0 ? wq : (which == 1 ? wk : wv);
        tr32(src + (long long)l * 512 * 512,
             wqkvT + (long long)l * QKVW * DMODEL + which * 512 * 512,
             512, 512, tx, ty, tid, tile);
    } else if (b < 5120) {             // w1: [512][1024] -> [1024][512]
        int t = b - 3072;
        int l = t >> 9, rem = t & 511;
        int tx = rem & 31, ty = rem >> 5;
        tr32(w1 + (long long)l * 512 * 1024,
             w1T + (long long)l * FFNH * DMODEL, 512, 1024, tx, ty, tid, tile);
    } else if (b < 7168) {             // w2: [1024][512] -> [512][1024]
        int t = b - 5120;
        int l = t >> 9, rem = t & 511;
        int tx = rem & 15, ty = rem >> 4;
        tr32(w2 + (long long)l * 1024 * 512,
             w2T + (long long)l * DMODEL * FFNH, 1024, 512, tx, ty, tid, tile);
    } else if (b < 8192) {             // wo
        int t = b - 7168;
        int l = t >> 8, rem = t & 255;
        int tx = rem & 15, ty = rem >> 4;
        tr32(wo + (long long)l * 512 * 512,
             woT + (long long)l * 512 * 512, 512, 512, tx, ty, tid, tile);
    } else if (b < 8320) {             // ew2: [256][512] -> [512][256]
        int t = b - 8192;
        int tx = t & 15, ty = t >> 4;
        tr32(ew2, ew2T, 256, 512, tx, ty, tid, tile);
    } else if (b < 8344) {             // bias concat: 24*256 = 6144
        int idx = (b - 8320) * 256 + tid;
        if (idx < NLAYERS * QKVW) {
            int l = idx / QKVW, c = idx % QKVW;
            const float* src = c < 512 ? bq : (c < 1024 ? bk : bv);
            bqkv[idx] = src[l * DMODEL + (c & 511)];
        }
    } else {                           // omega: 128*256 = 32768
        int idx = (b - 8344) * 256 + tid;
        om16[idx] = __float2half(om[idx]);
    }
}

// ---------------- encoder first layer ----------------
__global__ void __launch_bounds__(256) enc1_kernel(
    const float* __restrict__ x, const float* __restrict__ pos,
    const float* __restrict__ w, const float* __restrict__ b,
    __half* __restrict__ out)
{
    int idx = blockIdx.x * 256 + threadIdx.x;
    int row = idx >> 8, col = idx & 255;
    const float* xr = x + row * 3;
    const float* pr = pos + row * 3;
    float a = b[col];
#pragma unroll
    for (int d = 0; d < 3; d++) a = fmaf(xr[d], w[d * 256 + col], a);
#pragma unroll
    for (int d = 0; d < 3; d++) a = fmaf(pr[d], w[(3 + d) * 256 + col], a);
    out[idx] = __float2half(fmaxf(a, 0.f));
}

// ---------------- LayerNorm: all-half I/O, 256 threads x half2 ----------------
__global__ void __launch_bounds__(256) ln_kernel(
    __half* __restrict__ out16, const __half* __restrict__ resid,
    const __half* __restrict__ y,
    const float* __restrict__ g, const float* __restrict__ b)
{
    int row = blockIdx.x, t = threadIdx.x;
    long long base = (long long)row * 256;          // half2 units
    float2 v = __half22float2(((const __half2*)y)[base + t]);
    if (resid) {
        float2 r = __half22float2(((const __half2*)resid)[base + t]);
        v.x += r.x; v.y += r.y;
    }
    float s = v.x + v.y;
    float s2 = v.x * v.x + v.y * v.y;
#pragma unroll
    for (int o = 16; o; o >>= 1) {
        s  += __shfl_xor_sync(0xffffffffu, s,  o);
        s2 += __shfl_xor_sync(0xffffffffu, s2, o);
    }
    __shared__ float rs[8], rs2[8];
    int w = t >> 5, lane = t & 31;
    if (!lane) { rs[w] = s; rs2[w] = s2; }
    __syncthreads();
    if (t < 32) {
        float a  = (t < 8) ? rs[t]  : 0.f;
        float a2 = (t < 8) ? rs2[t] : 0.f;
#pragma unroll
        for (int o = 4; o; o >>= 1) {
            a  += __shfl_xor_sync(0xffffffffu, a,  o);
            a2 += __shfl_xor_sync(0xffffffffu, a2, o);
        }
        if (!t) { rs[0] = a; rs2[0] = a2; }
    }
    __syncthreads();
    float mean = rs[0] * (1.f / 512.f);
    float var  = rs2[0] * (1.f / 512.f) - mean * mean;
    float rstd = rsqrtf(var + 1e-5f);
    float o0 = (v.x - mean) * rstd * g[t * 2]     + b[t * 2];
    float o1 = (v.y - mean) * rstd * g[t * 2 + 1] + b[t * 2 + 1];
    __half2 ho; ho.x = __float2half(o0); ho.y = __float2half(o1);
    ((__half2*)out16)[base + t] = ho;
}

// ---------------- ksum: read half Kf, 2-stage ----------------
__global__ void __launch_bounds__(256) ksum1_kernel(
    const __half* __restrict__ Kf, float* __restrict__ part)
{
    int bh = blockIdx.x, ch = blockIdx.y, f = threadIdx.x;
    const __half* base = Kf + ((long long)bh * SEQ + ch * 128) * NF + f;
    float s = 0.f;
#pragma unroll 8
    for (int i = 0; i < 128; i++) s += __half2float(base[(long long)i * NF]);
    part[(bh * 8 + ch) * NF + f] = s;
}
__global__ void __launch_bounds__(256) ksum2_kernel(
    const float* __restrict__ part, float* __restrict__ ks)
{
    int bh = blockIdx.x, f = threadIdx.x;
    float s = 0.f;
#pragma unroll
    for (int c = 0; c < 8; c++) s += part[(bh * 8 + c) * NF + f];
    ks[bh * NF + f] = s;
}

// ---------------- mean pool + classifier (half hidden) ----------------
__global__ void __launch_bounds__(512) pool_cls_kernel(
    const __half* __restrict__ h, const float* __restrict__ cw,
    const float* __restrict__ cb, float* __restrict__ out)
{
    int b = blockIdx.x, t = threadIdx.x;
    const __half* base = h + (long long)b * SEQ * DMODEL + t;
    float s = 0.f;
#pragma unroll 8
    for (int i = 0; i < SEQ; i++) s += __half2float(base[(long long)i * DMODEL]);
    __shared__ float pooled[DMODEL];
    pooled[t] = s * (1.f / (float)SEQ);
    __syncthreads();
    if (t < 16) {
        float acc = cb[t];
        for (int d = 0; d < DMODEL; d++) acc = fmaf(pooled[d], cw[d * 16 + t], acc);
        out[b * 16 + t] = acc;
    }
}

// ---------------- host driver ----------------
extern "C" void kernel_launch(void* const* d_in, const int* in_sizes, int n_in,
                              void* d_out, int out_size)
{
    const float* x      = (const float*)d_in[0];
    const float* pos    = (const float*)d_in[1];
    const float* enc_w1 = (const float*)d_in[2];
    const float* enc_b1 = (const float*)d_in[3];
    const float* enc_w2 = (const float*)d_in[4];
    const float* enc_b2 = (const float*)d_in[5];
    const float* enc_g  = (const float*)d_in[6];
    const float* enc_bb = (const float*)d_in[7];
    const float* wq     = (const float*)d_in[8];
    const float* bq     = (const float*)d_in[9];
    const float* wk     = (const float*)d_in[10];
    const float* bk     = (const float*)d_in[11];
    const float* wv     = (const float*)d_in[12];
    const float* bv     = (const float*)d_in[13];
    const float* wo     = (const float*)d_in[14];
    const float* bo     = (const float*)d_in[15];
    const float* ln1_g  = (const float*)d_in[16];
    const float* ln1_b  = (const float*)d_in[17];
    const float* w1     = (const float*)d_in[18];
    const float* b1     = (const float*)d_in[19];
    const float* w2     = (const float*)d_in[20];
    const float* b2     = (const float*)d_in[21];
    const float* ln2_g  = (const float*)d_in[22];
    const float* ln2_b  = (const float*)d_in[23];
    const float* omega  = (const float*)d_in[24];
    const float* cls_w  = (const float*)d_in[25];
    const float* cls_b  = (const float*)d_in[26];

    float *p_ks, *p_kp, *p_z, *p_bqkv;
    __half *p_h16, *p_t016, *p_qkv16, *p_ffn16, *p_attn16, *p_v16;
    __half *p_Qf, *p_Kf, *p_kv, *p_om16;
    __half *p_wqkvT, *p_w1T, *p_w2T, *p_woT, *p_ew2T;
    cudaGetSymbolAddress((void**)&p_Qf,   g_Qf);
    cudaGetSymbolAddress((void**)&p_Kf,   g_Kf);
    cudaGetSymbolAddress((void**)&p_kv,   g_kv);
    cudaGetSymbolAddress((void**)&p_ks,   g_ks);
    cudaGetSymbolAddress((void**)&p_kp,   g_kp);
    cudaGetSymbolAddress((void**)&p_z,    g_z);
    cudaGetSymbolAddress((void**)&p_bqkv, g_bqkv);
    cudaGetSymbolAddress((void**)&p_h16,  g_h16);
    cudaGetSymbolAddress((void**)&p_t016, g_t016);
    cudaGetSymbolAddress((void**)&p_qkv16,g_qkv16);
    cudaGetSymbolAddress((void**)&p_ffn16,g_ffn16);
    cudaGetSymbolAddress((void**)&p_attn16,g_attn16);
    cudaGetSymbolAddress((void**)&p_v16,  g_v16);
    cudaGetSymbolAddress((void**)&p_om16, g_om16);
    cudaGetSymbolAddress((void**)&p_wqkvT,g_wqkvT);
    cudaGetSymbolAddress((void**)&p_w1T,  g_w1T);
    cudaGetSymbolAddress((void**)&p_w2T,  g_w2T);
    cudaGetSymbolAddress((void**)&p_woT,  g_woT);
    cudaGetSymbolAddress((void**)&p_ew2T, g_ew2T);

    const int SM_H    = 2 * 2 * 128 * 72 * 2;
    const int SM_KV   = 3 * 2 * 32 * 72 * 2;
    const int SM_ATTN = 3 * (128 * 40 + 32 * 72) * 2;
    cudaFuncSetAttribute(hgemm<0>, cudaFuncAttributeMaxDynamicSharedMemorySize, SM_H);
    cudaFuncSetAttribute(hgemm<1>, cudaFuncAttributeMaxDynamicSharedMemorySize, SM_H);
    cudaFuncSetAttribute(kv_gemm,  cudaFuncAttributeMaxDynamicSharedMemorySize, SM_KV);
    cudaFuncSetAttribute(attn_gemm,cudaFuncAttributeMaxDynamicSharedMemorySize, SM_ATTN);

    // ---- single prep launch ----
    prep_all<<<8472, 256>>>(wq, wk, wv, w1, w2, wo, enc_w2, bq, bk, bv, omega,
                            p_wqkvT, p_w1T, p_w2T, p_woT, p_ew2T, p_om16, p_bqkv);

    auto dense = [&](const __half* A, const __half* Bt, const float* bias,
                     void* C, int M, int Nn, int K, int relu, int outh) {
        dim3 grid(Nn / 128, M / 128, 1);
        if (outh) hgemm<1><<<grid, 256, SM_H>>>(A, Bt, bias, C, M, Nn, K, relu);
        else      hgemm<0><<<grid, 256, SM_H>>>(A, Bt, bias, C, M, Nn, K, relu);
    };

    // ---- encoder ----
    enc1_kernel<<<NTOK, 256>>>(x, pos, enc_w1, enc_b1, p_t016);
    dense(p_t016, p_ew2T, enc_b2, p_v16, NTOK, DMODEL, 256, 0, 1);
    ln_kernel<<<NTOK, 256>>>(p_h16, nullptr, p_v16, enc_g, enc_bb);

    for (int l = 0; l < NLAYERS; l++) {
        const __half* WqkvT = p_wqkvT + (long long)l * QKVW * DMODEL;
        const float*  Bqkv  = p_bqkv + l * QKVW;
        const __half* WoT   = p_woT + (long long)l * DMODEL * DMODEL;
        const float*  Bo    = bo + l * DMODEL;
        const __half* W1T   = p_w1T + (long long)l * FFNH * DMODEL;
        const float*  B1    = b1 + l * FFNH;
        const __half* W2T   = p_w2T + (long long)l * DMODEL * FFNH;
        const float*  B2    = b2 + l * DMODEL;
        const __half* Om16  = p_om16 + (long long)l * HD * 128;

        // merged QKV projection (half out)
        dense(p_h16, WqkvT, Bqkv, p_qkv16, NTOK, QKVW, DMODEL, 0, 1);

        // FAVOR(K); ksum; FAVOR(Q); z
        favor_mma_kernel<<<dim3(NTOK/64, NH), 128>>>(p_qkv16, Om16, p_Kf, 512);
        ksum1_kernel<<<dim3(BATCH*NH, 8), 256>>>(p_Kf, p_kp);
        ksum2_kernel<<<BATCH*NH, 256>>>(p_kp, p_ks);
        favor_mma_kernel<<<dim3(NTOK/64, NH), 128>>>(p_qkv16, Om16, p_Qf, 0);
        z_kernel<<<dim3(BATCH*NH, SEQ/8), 256>>>(p_Qf, p_ks, p_z);

        // kv / attn (fp16 tensor)
        kv_gemm<<<dim3(1, NF/64, BATCH*NH), 256, SM_KV>>>(p_Kf, p_qkv16 + 1024, p_kv);
        attn_gemm<<<dim3(1, SEQ/128, BATCH*NH), 256, SM_ATTN>>>(p_Qf, p_kv, p_z, p_attn16);

        // output projection + residual LN (all-half)
        dense(p_attn16, WoT, Bo, p_v16, NTOK, DMODEL, DMODEL, 0, 1);
        ln_kernel<<<NTOK, 256>>>(p_h16, p_h16, p_v16, ln1_g + l*DMODEL, ln1_b + l*DMODEL);

        // FFN + residual LN
        dense(p_h16, W1T, B1, p_ffn16, NTOK, FFNH, DMODEL, 1, 1);
        dense(p_ffn16, W2T, B2, p_v16, NTOK, DMODEL, FFNH, 0, 1);
        ln_kernel<<<NTOK, 256>>>(p_h16, p_h16, p_v16, ln2_g + l*DMODEL, ln2_b + l*DMODEL);
    }

    pool_cls_kernel<<<BATCH, 512>>>(p_h16, cls_w, cls_b, (float*)d_out);
}

// round 16
// speedup vs baseline: 8.5002x; 1.0639x over previous
#include <cuda_runtime.h>
#include <cuda_fp16.h>
#include <math.h>

#define BATCH 16
#define SEQ 1024
#define NTOK (BATCH*SEQ)
#define DMODEL 512
#define NH 8
#define HD 64
#define NF 256
#define NLAYERS 4
#define FFNH 1024
#define QKVW 1536

// ---------------- scratch ----------------
__device__ __half g_h16 [NTOK*DMODEL];
__device__ __half g_t016[NTOK*256];
__device__ __half g_qkv16[NTOK*QKVW];
__device__ __half g_ffn16[NTOK*FFNH];
__device__ __half g_attn16[NTOK*DMODEL];
__device__ __half g_v16 [NTOK*DMODEL];
__device__ __half g_Qf  [BATCH*NH*SEQ*NF];
__device__ __half g_Kf  [BATCH*NH*SEQ*NF];
__device__ __half g_kv  [BATCH*NH*NF*HD];
__device__ float  g_ks  [BATCH*NH*NF];
__device__ float  g_kp  [BATCH*NH*8*NF];
__device__ float  g_z   [BATCH*NH*SEQ];
__device__ __half g_wqkvT[NLAYERS*QKVW*DMODEL];
__device__ float  g_bqkv [NLAYERS*QKVW];
__device__ __half g_w1T  [NLAYERS*FFNH*DMODEL];
__device__ __half g_w2T  [NLAYERS*DMODEL*FFNH];
__device__ __half g_woT  [NLAYERS*DMODEL*DMODEL];
__device__ __half g_ew2T [DMODEL*256];
__device__ __half g_om16 [NLAYERS*HD*128];

__device__ __forceinline__ void mma_f16(float* d, const unsigned* a, const unsigned* b) {
    asm volatile(
        "mma.sync.aligned.m16n8k16.row.col.f32.f16.f16.f32 "
        "{%0,%1,%2,%3},{%4,%5,%6,%7},{%8,%9},{%0,%1,%2,%3};\n"
        : "+f"(d[0]), "+f"(d[1]), "+f"(d[2]), "+f"(d[3])
        : "r"(a[0]), "r"(a[1]), "r"(a[2]), "r"(a[3]),
          "r"(b[0]), "r"(b[1]));
}

__device__ __forceinline__ void ldsm_x4(unsigned& r0, unsigned& r1,
                                        unsigned& r2, unsigned& r3, unsigned addr) {
    asm volatile("ldmatrix.sync.aligned.m8n8.x4.shared.b16 {%0,%1,%2,%3}, [%4];"
        : "=r"(r0), "=r"(r1), "=r"(r2), "=r"(r3) : "r"(addr));
}
__device__ __forceinline__ void ldsm_x4t(unsigned& r0, unsigned& r1,
                                         unsigned& r2, unsigned& r3, unsigned addr) {
    asm volatile("ldmatrix.sync.aligned.m8n8.x4.trans.shared.b16 {%0,%1,%2,%3}, [%4];"
        : "=r"(r0), "=r"(r1), "=r"(r2), "=r"(r3) : "r"(addr));
}

__device__ __forceinline__ void cpa16(void* dst, const void* src) {
    unsigned s = (unsigned)__cvta_generic_to_shared(dst);
    asm volatile("cp.async.ca.shared.global [%0], [%1], 16;\n" :: "r"(s), "l"(src));
}
#define CP_COMMIT  asm volatile("cp.async.commit_group;\n")

// ================= fp16 dense GEMM: C = A[M][K] @ B^T (B stored [N][K]) =================
template<int OUTH>
__global__ void __launch_bounds__(256, 2) hgemm(
    const __half* __restrict__ A, const __half* __restrict__ B,
    const float* __restrict__ bias, void* __restrict__ Cout,
    int M, int N, int K, int relu)
{
    constexpr int BM = 128, BN = 128, BK = 64, NS = 2;
    constexpr int PITCH = BK + 8;
    constexpr int TSZ = BM * PITCH;

    extern __shared__ __half hsm[];
    unsigned sb = (unsigned)__cvta_generic_to_shared(hsm);

    int m0 = blockIdx.y * BM;
    int n0 = blockIdx.x * BN;
    int tid = threadIdx.x;
    int warp = tid >> 5, lane = tid & 31;
    int wy = warp & 1, wx = warp >> 1;
    int wm = wy * 64, wn = wx * 32;
    int lrow = lane & 15, lk = lane >> 4;

    float acc[4][4][4];
#pragma unroll
    for (int i = 0; i < 4; i++)
#pragma unroll
        for (int j = 0; j < 4; j++)
#pragma unroll
            for (int c = 0; c < 4; c++) acc[i][j][c] = 0.f;

    auto loadT = [&](__half* S, const __half* G, int row0, int ld, int kt) {
#pragma unroll
        for (int i = 0; i < 4; i++) {
            int e = tid + i * 256;
            int row = e >> 3, q = (e & 7) * 8;
            cpa16(&S[row * PITCH + q], G + (long long)(row0 + row) * ld + kt + q);
        }
    };

    int T = K / BK;
    loadT(hsm, A, m0, K, 0);
    loadT(hsm + NS * TSZ, B, n0, K, 0);
    CP_COMMIT;

    int st = 0;
    for (int t = 0; t < T; t++) {
        if (t + 1 < T) {
            loadT(hsm + (st ^ 1) * TSZ, A, m0, K, (t + 1) * BK);
            loadT(hsm + (NS + (st ^ 1)) * TSZ, B, n0, K, (t + 1) * BK);
            CP_COMMIT;
            asm volatile("cp.async.wait_group 1;\n");
        } else {
            asm volatile("cp.async.wait_group 0;\n");
        }
        __syncthreads();

        unsigned sA = sb + st * (TSZ * 2);
        unsigned sB = sb + (NS + st) * (TSZ * 2);
        unsigned aB = sA + (wm + lrow) * (PITCH * 2) + lk * 16;
        unsigned bB = sB + (wn + lrow) * (PITCH * 2) + lk * 16;

#pragma unroll
        for (int ks = 0; ks < 4; ks++) {
            unsigned kb = ks * 32;
            unsigned a[4][4], b0q[4], b1q[4];
#pragma unroll
            for (int i = 0; i < 4; i++)
                ldsm_x4(a[i][0], a[i][1], a[i][2], a[i][3],
                        aB + i * (16 * PITCH * 2) + kb);
            ldsm_x4(b0q[0], b0q[1], b0q[2], b0q[3], bB + kb);
            ldsm_x4(b1q[0], b1q[1], b1q[2], b1q[3], bB + 16 * (PITCH * 2) + kb);
            unsigned bfr[4][2] = {
                {b0q[0], b0q[2]}, {b0q[1], b0q[3]},
                {b1q[0], b1q[2]}, {b1q[1], b1q[3]}};
#pragma unroll
            for (int i = 0; i < 4; i++)
#pragma unroll
                for (int j = 0; j < 4; j++)
                    mma_f16(acc[i][j], a[i], bfr[j]);
        }
        __syncthreads();
        st ^= 1;
    }

#pragma unroll
    for (int i = 0; i < 4; i++) {
        int mA = m0 + wm + i * 16 + (lane >> 2);
        int mB = mA + 8;
#pragma unroll
        for (int j = 0; j < 4; j++) {
            int n = n0 + wn + j * 8 + (lane & 3) * 2;
            float b0 = bias ? bias[n] : 0.f;
            float b1 = bias ? bias[n + 1] : 0.f;
            float v00 = acc[i][j][0] + b0, v01 = acc[i][j][1] + b1;
            float v10 = acc[i][j][2] + b0, v11 = acc[i][j][3] + b1;
            if (relu) {
                v00 = fmaxf(v00, 0.f); v01 = fmaxf(v01, 0.f);
                v10 = fmaxf(v10, 0.f); v11 = fmaxf(v11, 0.f);
            }
            if (OUTH) {
                __half* C = (__half*)Cout;
                __half2 h0; h0.x = __float2half(v00); h0.y = __float2half(v01);
                __half2 h1; h1.x = __float2half(v10); h1.y = __float2half(v11);
                *(__half2*)(C + (long long)mA * N + n) = h0;
                *(__half2*)(C + (long long)mB * N + n) = h1;
            } else {
                float* C = (float*)Cout;
                *(float2*)(C + (long long)mA * N + n) = make_float2(v00, v01);
                *(float2*)(C + (long long)mB * N + n) = make_float2(v10, v11);
            }
        }
    }
}

// ================= kv GEMM: kv[f][d] = sum_s Kf[s][f] * v[s][d] =================
__global__ void __launch_bounds__(256, 2) kv_gemm(
    const __half* __restrict__ Kf, const __half* __restrict__ V,
    __half* __restrict__ KV)
{
    constexpr int BK = 32, NS = 3;
    constexpr int PITCH = 72;
    constexpr int TSZ = BK * PITCH;

    extern __shared__ __half hsm[];
    unsigned sb = (unsigned)__cvta_generic_to_shared(hsm);

    int bh = blockIdx.z;
    int b = bh >> 3, h = bh & 7;
    const __half* Ap = Kf + (long long)bh * SEQ * NF;
    const __half* Vp = V + (long long)b * SEQ * QKVW + h * HD;
    __half* Cp = KV + (long long)bh * NF * HD;

    int m0 = blockIdx.y * 64;
    int tid = threadIdx.x;
    int warp = tid >> 5, lane = tid & 31;
    int wm = (warp & 1) * 32, wn = (warp >> 1) * 16;
    int trow = (lane & 7) + ((lane >> 4) << 3);
    int tcol = ((lane >> 3) & 1) << 3;

    float acc[2][2][4];
#pragma unroll
    for (int i = 0; i < 2; i++)
#pragma unroll
        for (int j = 0; j < 2; j++)
#pragma unroll
            for (int c = 0; c < 4; c++) acc[i][j][c] = 0.f;

    auto loadA = [&](__half* S, int kt) {
        int kk = tid >> 3, q = (tid & 7) * 8;
        cpa16(&S[kk * PITCH + q], Ap + (long long)(kt + kk) * NF + m0 + q);
    };
    auto loadB = [&](__half* S, int kt) {
        int kk = tid >> 3, q = (tid & 7) * 8;
        cpa16(&S[kk * PITCH + q], Vp + (long long)(kt + kk) * QKVW + q);
    };

    int T = SEQ / BK;
#pragma unroll
    for (int s = 0; s < NS - 1; s++) {
        loadA(hsm + s * TSZ, s * BK);
        loadB(hsm + (NS + s) * TSZ, s * BK);
        CP_COMMIT;
    }

    int st = 0, ps = NS - 1;
    for (int t = 0; t < T; t++) {
        asm volatile("cp.async.wait_group %0;\n" :: "n"(NS - 2));
        __syncthreads();
        int pf = t + NS - 1;
        if (pf < T) {
            loadA(hsm + ps * TSZ, pf * BK);
            loadB(hsm + (NS + ps) * TSZ, pf * BK);
        }
        CP_COMMIT;

        unsigned sA = sb + st * (TSZ * 2);
        unsigned sB = sb + (NS + st) * (TSZ * 2);
#pragma unroll
        for (int ks = 0; ks < 2; ks++) {
            int kr = ks * 16 + trow;
            unsigned a[2][4], bq[4];
#pragma unroll
            for (int i = 0; i < 2; i++)
                ldsm_x4t(a[i][0], a[i][1], a[i][2], a[i][3],
                         sA + (kr * PITCH + wm + i * 16 + tcol) * 2);
            ldsm_x4t(bq[0], bq[1], bq[2], bq[3],
                     sB + (kr * PITCH + wn + tcol) * 2);
            unsigned bfr[2][2] = {{bq[0], bq[2]}, {bq[1], bq[3]}};
#pragma unroll
            for (int i = 0; i < 2; i++)
#pragma unroll
                for (int j = 0; j < 2; j++)
                    mma_f16(acc[i][j], a[i], bfr[j]);
        }
        st = (st + 1 == NS) ? 0 : st + 1;
        ps = (ps + 1 == NS) ? 0 : ps + 1;
    }

#pragma unroll
    for (int i = 0; i < 2; i++) {
        int mA = m0 + wm + i * 16 + (lane >> 2);
        int mB = mA + 8;
#pragma unroll
        for (int j = 0; j < 2; j++) {
            int n = wn + j * 8 + (lane & 3) * 2;
            __half2 h0, h1;
            h0.x = __float2half(acc[i][j][0]); h0.y = __float2half(acc[i][j][1]);
            h1.x = __float2half(acc[i][j][2]); h1.y = __float2half(acc[i][j][3]);
            *(__half2*)(Cp + mA * HD + n) = h0;
            *(__half2*)(Cp + mB * HD + n) = h1;
        }
    }
}

// ================= attn GEMM: O[s][h*64+d] = z[s] * Qf[s][:] @ kv[:][d] =================
__global__ void __launch_bounds__(256, 2) attn_gemm(
    const __half* __restrict__ Qf, const __half* __restrict__ KV,
    const float* __restrict__ z, __half* __restrict__ O)
{
    constexpr int BK = 32, NS = 3;
    constexpr int APITCH = 40;
    constexpr int BPITCH = 72;
    constexpr int ATSZ = 128 * APITCH;
    constexpr int BTSZ = BK * BPITCH;

    extern __shared__ __half hsm[];
    unsigned sb = (unsigned)__cvta_generic_to_shared(hsm);
    __half* Bs0 = hsm + NS * ATSZ;

    int bh = blockIdx.z;
    int b = bh >> 3, h = bh & 7;
    int m0 = blockIdx.y * 128;
    const __half* Ap = Qf + (long long)bh * SEQ * NF;
    const __half* Bp = KV + (long long)bh * NF * HD;
    __half* Op = O + (long long)b * SEQ * DMODEL + h * HD;
    const float* zp = z + (long long)bh * SEQ;

    int tid = threadIdx.x;
    int warp = tid >> 5, lane = tid & 31;
    int wm = (warp & 1) * 64, wn = (warp >> 1) * 16;
    int lrow = lane & 15, lk = lane >> 4;
    int trow = (lane & 7) + ((lane >> 4) << 3);
    int tcol = ((lane >> 3) & 1) << 3;

    float acc[4][2][4];
#pragma unroll
    for (int i = 0; i < 4; i++)
#pragma unroll
        for (int j = 0; j < 2; j++)
#pragma unroll
            for (int c = 0; c < 4; c++) acc[i][j][c] = 0.f;

    auto loadA = [&](__half* S, int kt) {
#pragma unroll
        for (int i = 0; i < 2; i++) {
            int e = tid + i * 256;
            int row = e >> 2, q = (e & 3) * 8;
            cpa16(&S[row * APITCH + q], Ap + (long long)(m0 + row) * NF + kt + q);
        }
    };
    auto loadB = [&](__half* S, int kt) {
        int kk = tid >> 3, q = (tid & 7) * 8;
        cpa16(&S[kk * BPITCH + q], Bp + (long long)(kt + kk) * HD + q);
    };

    int T = NF / BK;
#pragma unroll
    for (int s = 0; s < NS - 1; s++) {
        loadA(hsm + s * ATSZ, s * BK);
        loadB(Bs0 + s * BTSZ, s * BK);
        CP_COMMIT;
    }

    int st = 0, ps = NS - 1;
    for (int t = 0; t < T; t++) {
        asm volatile("cp.async.wait_group %0;\n" :: "n"(NS - 2));
        __syncthreads();
        int pf = t + NS - 1;
        if (pf < T) {
            loadA(hsm + ps * ATSZ, pf * BK);
            loadB(Bs0 + ps * BTSZ, pf * BK);
        }
        CP_COMMIT;

        unsigned sA = sb + st * (ATSZ * 2);
        unsigned sB = sb + (NS * ATSZ + st * BTSZ) * 2;
        unsigned aB = sA + (wm + lrow) * (APITCH * 2) + lk * 16;
#pragma unroll
        for (int ks = 0; ks < 2; ks++) {
            unsigned kb = ks * 32;
            int kr = ks * 16 + trow;
            unsigned a[4][4], bq[4];
#pragma unroll
            for (int i = 0; i < 4; i++)
                ldsm_x4(a[i][0], a[i][1], a[i][2], a[i][3],
                        aB + i * (16 * APITCH * 2) + kb);
            ldsm_x4t(bq[0], bq[1], bq[2], bq[3],
                     sB + (kr * BPITCH + wn + tcol) * 2);
            unsigned bfr[2][2] = {{bq[0], bq[2]}, {bq[1], bq[3]}};
#pragma unroll
            for (int i = 0; i < 4; i++)
#pragma unroll
                for (int j = 0; j < 2; j++)
                    mma_f16(acc[i][j], a[i], bfr[j]);
        }
        st = (st + 1 == NS) ? 0 : st + 1;
        ps = (ps + 1 == NS) ? 0 : ps + 1;
    }

#pragma unroll
    for (int i = 0; i < 4; i++) {
        int mA = m0 + wm + i * 16 + (lane >> 2);
        int mB = mA + 8;
        float rsA = zp[mA], rsB = zp[mB];
#pragma unroll
        for (int j = 0; j < 2; j++) {
            int n = wn + j * 8 + (lane & 3) * 2;
            __half2 h0, h1;
            h0.x = __float2half(acc[i][j][0] * rsA);
            h0.y = __float2half(acc[i][j][1] * rsA);
            h1.x = __float2half(acc[i][j][2] * rsB);
            h1.y = __float2half(acc[i][j][3] * rsB);
            *(__half2*)(Op + (long long)mA * DMODEL + n) = h0;
            *(__half2*)(Op + (long long)mB * DMODEL + n) = h1;
        }
    }
}

// ================= FAVOR via tensor cores =================
__global__ void __launch_bounds__(128) favor_mma_kernel(
    const __half* __restrict__ qkv, const __half* __restrict__ om16,
    __half* __restrict__ outF, int colOff)
{
    constexpr int APITCH = 72, BPITCH = 136;
    __shared__ __half qa[64 * APITCH];
    __shared__ __half ob[64 * BPITCH];
    __shared__ float hvs[64];

    int r0 = blockIdx.x * 64;
    int h = blockIdx.y;
    int tid = threadIdx.x, warp = tid >> 5, lane = tid & 31;

    const __half* qp = qkv + (long long)r0 * QKVW + colOff + h * HD;
#pragma unroll
    for (int i = 0; i < 4; i++) {
        int e = tid + i * 128;
        int row = e >> 3, q = (e & 7) * 8;
        cpa16(&qa[row * APITCH + q], qp + (long long)row * QKVW + q);
    }
#pragma unroll
    for (int i = 0; i < 8; i++) {
        int e = tid + i * 128;
        int row = e >> 4, q = (e & 15) * 8;
        cpa16(&ob[row * BPITCH + q], om16 + row * 128 + q);
    }
    CP_COMMIT;
    asm volatile("cp.async.wait_group 0;\n");
    __syncthreads();

    {
        int row = tid >> 1, hs = tid & 1;
        float s = 0.f;
#pragma unroll
        for (int d = 0; d < 32; d++) {
            float v = __half2float(qa[row * APITCH + hs * 32 + d]);
            s = fmaf(v, v, s);
        }
        s += __shfl_xor_sync(0xffffffffu, s, 1);
        if (!hs) hvs[row] = s * 0.5f * 0.125f;
    }
    __syncthreads();

    unsigned sbq = (unsigned)__cvta_generic_to_shared(qa);
    unsigned sbo = (unsigned)__cvta_generic_to_shared(ob);

    int wm = (warp & 1) * 32;
    int wn = (warp >> 1) * 64;
    int lrow = lane & 15, lk = lane >> 4;
    int trow = (lane & 7) + ((lane >> 4) << 3);
    int tcol = ((lane >> 3) & 1) << 3;

    float acc[2][8][4];
#pragma unroll
    for (int i = 0; i < 2; i++)
#pragma unroll
        for (int j = 0; j < 8; j++)
#pragma unroll
            for (int c = 0; c < 4; c++) acc[i][j][c] = 0.f;

    unsigned aB = sbq + (wm + lrow) * (APITCH * 2) + lk * 16;
#pragma unroll
    for (int ks = 0; ks < 4; ks++) {
        unsigned kb = ks * 32;
        int kr = ks * 16 + trow;
        unsigned a[2][4];
#pragma unroll
        for (int i = 0; i < 2; i++)
            ldsm_x4(a[i][0], a[i][1], a[i][2], a[i][3],
                    aB + i * (16 * APITCH * 2) + kb);
#pragma unroll
        for (int jj = 0; jj < 4; jj++) {
            unsigned bq[4];
            ldsm_x4t(bq[0], bq[1], bq[2], bq[3],
                     sbo + (kr * BPITCH + wn + jj * 16 + tcol) * 2);
            unsigned bfr[2][2] = {{bq[0], bq[2]}, {bq[1], bq[3]}};
#pragma unroll
            for (int i = 0; i < 2; i++)
#pragma unroll
                for (int j2 = 0; j2 < 2; j2++)
                    mma_f16(acc[i][jj * 2 + j2], a[i], bfr[j2]);
        }
    }

    int bh = (r0 >> 10) * NH + h;
    long long obase = ((long long)bh * SEQ + (r0 & 1023)) * NF;
    const float sc = 0.3535533905932738f;
#pragma unroll
    for (int i = 0; i < 2; i++) {
        int lr = wm + i * 16 + (lane >> 2);
        float hvA = hvs[lr], hvB = hvs[lr + 8];
        long long oA = obase + (long long)lr * NF;
        long long oB = obase + (long long)(lr + 8) * NF;
#pragma unroll
        for (int j = 0; j < 8; j++) {
            int f = wn + j * 8 + (lane & 3) * 2;
            float u0 = acc[i][j][0] * sc, u1 = acc[i][j][1] * sc;
            float u2 = acc[i][j][2] * sc, u3 = acc[i][j][3] * sc;
            __half2 p0, p1, q0, q1;
            p0.x = __float2half(__expf( u0 - hvA) * 0.0625f);
            p0.y = __float2half(__expf( u1 - hvA) * 0.0625f);
            q0.x = __float2half(__expf(-u0 - hvA) * 0.0625f);
            q0.y = __float2half(__expf(-u1 - hvA) * 0.0625f);
            p1.x = __float2half(__expf( u2 - hvB) * 0.0625f);
            p1.y = __float2half(__expf( u3 - hvB) * 0.0625f);
            q1.x = __float2half(__expf(-u2 - hvB) * 0.0625f);
            q1.y = __float2half(__expf(-u3 - hvB) * 0.0625f);
            *(__half2*)(outF + oA + f)       = p0;
            *(__half2*)(outF + oA + 128 + f) = q0;
            *(__half2*)(outF + oB + f)       = p1;
            *(__half2*)(outF + oB + 128 + f) = q1;
        }
    }
}

// ---------------- z = 1/(Qf . ks + eps) ----------------
__global__ void __launch_bounds__(256) z_kernel(
    const __half* __restrict__ Qf, const float* __restrict__ ks,
    float* __restrict__ z)
{
    int bh = blockIdx.x;
    int s  = blockIdx.y * 8 + (threadIdx.x >> 5);
    int lane = threadIdx.x & 31;
    __shared__ float kss[NF];
    kss[threadIdx.x] = ks[bh * NF + threadIdx.x];
    __syncthreads();
    const __half* q = Qf + ((long long)bh * SEQ + s) * NF;
    float acc = 0.f;
#pragma unroll
    for (int i = lane; i < NF; i += 32) acc = fmaf(__half2float(q[i]), kss[i], acc);
#pragma unroll
    for (int o = 16; o; o >>= 1) acc += __shfl_xor_sync(0xffffffffu, acc, o);
    if (!lane) z[bh * SEQ + s] = 1.f / (acc + 1e-6f);
}

// ---------------- merged prep ----------------
__device__ __forceinline__ void tr32(const float* ip, __half* op, int K, int N,
                                     int tx, int ty, int tid, float (*tile)[33])
{
    int n0 = tx * 32, k0 = ty * 32;
    int lx = tid & 31, ly = tid >> 5;
#pragma unroll
    for (int r = 0; r < 4; r++)
        tile[ly + r * 8][lx] = ip[(long long)(k0 + ly + r * 8) * N + n0 + lx];
    __syncthreads();
#pragma unroll
    for (int r = 0; r < 4; r++)
        op[(long long)(n0 + ly + r * 8) * K + k0 + lx] = __float2half(tile[lx][ly + r * 8]);
}

__global__ void __launch_bounds__(256) prep_all(
    const float* __restrict__ wq, const float* __restrict__ wk, const float* __restrict__ wv,
    const float* __restrict__ w1, const float* __restrict__ w2, const float* __restrict__ wo,
    const float* __restrict__ ew2,
    const float* __restrict__ bq, const float* __restrict__ bk, const float* __restrict__ bv,
    const float* __restrict__ om,
    __half* __restrict__ wqkvT, __half* __restrict__ w1T, __half* __restrict__ w2T,
    __half* __restrict__ woT, __half* __restrict__ ew2T, __half* __restrict__ om16,
    float* __restrict__ bqkv)
{
    __shared__ float tile[32][33];
    int b = blockIdx.x, tid = threadIdx.x;
    if (b < 3072) {
        int which = b >> 10, t = b & 1023;
        int l = t >> 8, rem = t & 255;
        int tx = rem & 15, ty = rem >> 4;
        const float* src = which == 0 ? wq : (which == 1 ? wk : wv);
        tr32(src + (long long)l * 512 * 512,
             wqkvT + (long long)l * QKVW * DMODEL + which * 512 * 512,
             512, 512, tx, ty, tid, tile);
    } else if (b < 5120) {
        int t = b - 3072;
        int l = t >> 9, rem = t & 511;
        int tx = rem & 31, ty = rem >> 5;
        tr32(w1 + (long long)l * 512 * 1024,
             w1T + (long long)l * FFNH * DMODEL, 512, 1024, tx, ty, tid, tile);
    } else if (b < 7168) {
        int t = b - 5120;
        int l = t >> 9, rem = t & 511;
        int tx = rem & 15, ty = rem >> 4;
        tr32(w2 + (long long)l * 1024 * 512,
             w2T + (long long)l * DMODEL * FFNH, 1024, 512, tx, ty, tid, tile);
    } else if (b < 8192) {
        int t = b - 7168;
        int l = t >> 8, rem = t & 255;
        int tx = rem & 15, ty = rem >> 4;
        tr32(wo + (long long)l * 512 * 512,
             woT + (long long)l * 512 * 512, 512, 512, tx, ty, tid, tile);
    } else if (b < 8320) {
        int t = b - 8192;
        int tx = t & 15, ty = t >> 4;
        tr32(ew2, ew2T, 256, 512, tx, ty, tid, tile);
    } else if (b < 8344) {
        int idx = (b - 8320) * 256 + tid;
        if (idx < NLAYERS * QKVW) {
            int l = idx / QKVW, c = idx % QKVW;
            const float* src = c < 512 ? bq : (c < 1024 ? bk : bv);
            bqkv[idx] = src[l * DMODEL + (c & 511)];
        }
    } else {
        int idx = (b - 8344) * 256 + tid;
        om16[idx] = __float2half(om[idx]);
    }
}

// ---------------- encoder first layer ----------------
__global__ void __launch_bounds__(256) enc1_kernel(
    const float* __restrict__ x, const float* __restrict__ pos,
    const float* __restrict__ w, const float* __restrict__ b,
    __half* __restrict__ out)
{
    int idx = blockIdx.x * 256 + threadIdx.x;
    int row = idx >> 8, col = idx & 255;
    const float* xr = x + row * 3;
    const float* pr = pos + row * 3;
    float a = b[col];
#pragma unroll
    for (int d = 0; d < 3; d++) a = fmaf(xr[d], w[d * 256 + col], a);
#pragma unroll
    for (int d = 0; d < 3; d++) a = fmaf(pr[d], w[(3 + d) * 256 + col], a);
    out[idx] = __float2half(fmaxf(a, 0.f));
}

// ---------------- LayerNorm: warp-per-row, all-half I/O ----------------
__global__ void __launch_bounds__(256) ln_kernel(
    __half* __restrict__ out16, const __half* __restrict__ resid,
    const __half* __restrict__ y,
    const float* __restrict__ g, const float* __restrict__ b)
{
    int w = threadIdx.x >> 5, lane = threadIdx.x & 31;
    long long row = (long long)blockIdx.x * 8 + w;
    const __half2* yp = (const __half2*)y + row * 256;
    const __half2* rp = resid ? (const __half2*)resid + row * 256 : nullptr;
    float2 v[8];
    float s = 0.f, s2 = 0.f;
#pragma unroll
    for (int i = 0; i < 8; i++) {
        float2 t = __half22float2(yp[lane + i * 32]);
        if (rp) {
            float2 r = __half22float2(rp[lane + i * 32]);
            t.x += r.x; t.y += r.y;
        }
        v[i] = t;
        s += t.x + t.y;
        s2 += t.x * t.x + t.y * t.y;
    }
#pragma unroll
    for (int o = 16; o; o >>= 1) {
        s  += __shfl_xor_sync(0xffffffffu, s,  o);
        s2 += __shfl_xor_sync(0xffffffffu, s2, o);
    }
    float mean = s * (1.f / 512.f);
    float var  = s2 * (1.f / 512.f) - mean * mean;
    float rstd = rsqrtf(var + 1e-5f);
    __half2* op = (__half2*)out16 + row * 256;
#pragma unroll
    for (int i = 0; i < 8; i++) {
        int c = (lane + i * 32) * 2;
        float o0 = (v[i].x - mean) * rstd * g[c]     + b[c];
        float o1 = (v[i].y - mean) * rstd * g[c + 1] + b[c + 1];
        __half2 ho; ho.x = __float2half(o0); ho.y = __float2half(o1);
        op[lane + i * 32] = ho;
    }
}

// ---------------- ksum: read half Kf, 2-stage ----------------
__global__ void __launch_bounds__(256) ksum1_kernel(
    const __half* __restrict__ Kf, float* __restrict__ part)
{
    int bh = blockIdx.x, ch = blockIdx.y, f = threadIdx.x;
    const __half* base = Kf + ((long long)bh * SEQ + ch * 128) * NF + f;
    float s = 0.f;
#pragma unroll 8
    for (int i = 0; i < 128; i++) s += __half2float(base[(long long)i * NF]);
    part[(bh * 8 + ch) * NF + f] = s;
}
__global__ void __launch_bounds__(256) ksum2_kernel(
    const float* __restrict__ part, float* __restrict__ ks)
{
    int bh = blockIdx.x, f = threadIdx.x;
    float s = 0.f;
#pragma unroll
    for (int c = 0; c < 8; c++) s += part[(bh * 8 + c) * NF + f];
    ks[bh * NF + f] = s;
}

// ---------------- pool stage1: partial sums over 128-row chunks ----------------
__global__ void __launch_bounds__(512) pool1_kernel(
    const __half* __restrict__ h, float* __restrict__ part)
{
    int b = blockIdx.x >> 3, c = blockIdx.x & 7, t = threadIdx.x;
    const __half* base = h + ((long long)b * SEQ + c * 128) * DMODEL + t;
    float s = 0.f;
#pragma unroll 8
    for (int i = 0; i < 128; i++) s += __half2float(base[(long long)i * DMODEL]);
    part[(b * 8 + c) * DMODEL + t] = s;
}
// ---------------- pool stage2 + classifier ----------------
__global__ void __launch_bounds__(512) pool2_kernel(
    const float* __restrict__ part, const float* __restrict__ cw,
    const float* __restrict__ cb, float* __restrict__ out)
{
    int b = blockIdx.x, t = threadIdx.x;
    float s = 0.f;
#pragma unroll
    for (int c = 0; c < 8; c++) s += part[(b * 8 + c) * DMODEL + t];
    __shared__ float pooled[DMODEL];
    pooled[t] = s * (1.f / (float)SEQ);
    __syncthreads();
    if (t < 16) {
        float acc = cb[t];
        for (int d = 0; d < DMODEL; d++) acc = fmaf(pooled[d], cw[d * 16 + t], acc);
        out[b * 16 + t] = acc;
    }
}

// ---------------- host driver ----------------
extern "C" void kernel_launch(void* const* d_in, const int* in_sizes, int n_in,
                              void* d_out, int out_size)
{
    const float* x      = (const float*)d_in[0];
    const float* pos    = (const float*)d_in[1];
    const float* enc_w1 = (const float*)d_in[2];
    const float* enc_b1 = (const float*)d_in[3];
    const float* enc_w2 = (const float*)d_in[4];
    const float* enc_b2 = (const float*)d_in[5];
    const float* enc_g  = (const float*)d_in[6];
    const float* enc_bb = (const float*)d_in[7];
    const float* wq     = (const float*)d_in[8];
    const float* bq     = (const float*)d_in[9];
    const float* wk     = (const float*)d_in[10];
    const float* bk     = (const float*)d_in[11];
    const float* wv     = (const float*)d_in[12];
    const float* bv     = (const float*)d_in[13];
    const float* wo     = (const float*)d_in[14];
    const float* bo     = (const float*)d_in[15];
    const float* ln1_g  = (const float*)d_in[16];
    const float* ln1_b  = (const float*)d_in[17];
    const float* w1     = (const float*)d_in[18];
    const float* b1     = (const float*)d_in[19];
    const float* w2     = (const float*)d_in[20];
    const float* b2     = (const float*)d_in[21];
    const float* ln2_g  = (const float*)d_in[22];
    const float* ln2_b  = (const float*)d_in[23];
    const float* omega  = (const float*)d_in[24];
    const float* cls_w  = (const float*)d_in[25];
    const float* cls_b  = (const float*)d_in[26];

    float *p_ks, *p_kp, *p_z, *p_bqkv;
    __half *p_h16, *p_t016, *p_qkv16, *p_ffn16, *p_attn16, *p_v16;
    __half *p_Qf, *p_Kf, *p_kv, *p_om16;
    __half *p_wqkvT, *p_w1T, *p_w2T, *p_woT, *p_ew2T;
    cudaGetSymbolAddress((void**)&p_Qf,   g_Qf);
    cudaGetSymbolAddress((void**)&p_Kf,   g_Kf);
    cudaGetSymbolAddress((void**)&p_kv,   g_kv);
    cudaGetSymbolAddress((void**)&p_ks,   g_ks);
    cudaGetSymbolAddress((void**)&p_kp,   g_kp);
    cudaGetSymbolAddress((void**)&p_z,    g_z);
    cudaGetSymbolAddress((void**)&p_bqkv, g_bqkv);
    cudaGetSymbolAddress((void**)&p_h16,  g_h16);
    cudaGetSymbolAddress((void**)&p_t016, g_t016);
    cudaGetSymbolAddress((void**)&p_qkv16,g_qkv16);
    cudaGetSymbolAddress((void**)&p_ffn16,g_ffn16);
    cudaGetSymbolAddress((void**)&p_attn16,g_attn16);
    cudaGetSymbolAddress((void**)&p_v16,  g_v16);
    cudaGetSymbolAddress((void**)&p_om16, g_om16);
    cudaGetSymbolAddress((void**)&p_wqkvT,g_wqkvT);
    cudaGetSymbolAddress((void**)&p_w1T,  g_w1T);
    cudaGetSymbolAddress((void**)&p_w2T,  g_w2T);
    cudaGetSymbolAddress((void**)&p_woT,  g_woT);
    cudaGetSymbolAddress((void**)&p_ew2T, g_ew2T);

    const int SM_H    = 2 * 2 * 128 * 72 * 2;
    const int SM_KV   = 3 * 2 * 32 * 72 * 2;
    const int SM_ATTN = 3 * (128 * 40 + 32 * 72) * 2;
    cudaFuncSetAttribute(hgemm<0>, cudaFuncAttributeMaxDynamicSharedMemorySize, SM_H);
    cudaFuncSetAttribute(hgemm<1>, cudaFuncAttributeMaxDynamicSharedMemorySize, SM_H);
    cudaFuncSetAttribute(kv_gemm,  cudaFuncAttributeMaxDynamicSharedMemorySize, SM_KV);
    cudaFuncSetAttribute(attn_gemm,cudaFuncAttributeMaxDynamicSharedMemorySize, SM_ATTN);

    // ---- single prep launch ----
    prep_all<<<8472, 256>>>(wq, wk, wv, w1, w2, wo, enc_w2, bq, bk, bv, omega,
                            p_wqkvT, p_w1T, p_w2T, p_woT, p_ew2T, p_om16, p_bqkv);

    auto dense = [&](const __half* A, const __half* Bt, const float* bias,
                     void* C, int M, int Nn, int K, int relu, int outh) {
        dim3 grid(Nn / 128, M / 128, 1);
        if (outh) hgemm<1><<<grid, 256, SM_H>>>(A, Bt, bias, C, M, Nn, K, relu);
        else      hgemm<0><<<grid, 256, SM_H>>>(A, Bt, bias, C, M, Nn, K, relu);
    };

    // ---- encoder ----
    enc1_kernel<<<NTOK, 256>>>(x, pos, enc_w1, enc_b1, p_t016);
    dense(p_t016, p_ew2T, enc_b2, p_v16, NTOK, DMODEL, 256, 0, 1);
    ln_kernel<<<NTOK / 8, 256>>>(p_h16, nullptr, p_v16, enc_g, enc_bb);

    for (int l = 0; l < NLAYERS; l++) {
        const __half* WqkvT = p_wqkvT + (long long)l * QKVW * DMODEL;
        const float*  Bqkv  = p_bqkv + l * QKVW;
        const __half* WoT   = p_woT + (long long)l * DMODEL * DMODEL;
        const float*  Bo    = bo + l * DMODEL;
        const __half* W1T   = p_w1T + (long long)l * FFNH * DMODEL;
        const float*  B1    = b1 + l * FFNH;
        const __half* W2T   = p_w2T + (long long)l * DMODEL * FFNH;
        const float*  B2    = b2 + l * DMODEL;
        const __half* Om16  = p_om16 + (long long)l * HD * 128;

        // merged QKV projection (half out)
        dense(p_h16, WqkvT, Bqkv, p_qkv16, NTOK, QKVW, DMODEL, 0, 1);

        // FAVOR(K); ksum; FAVOR(Q); z
        favor_mma_kernel<<<dim3(NTOK/64, NH), 128>>>(p_qkv16, Om16, p_Kf, 512);
        ksum1_kernel<<<dim3(BATCH*NH, 8), 256>>>(p_Kf, p_kp);
        ksum2_kernel<<<BATCH*NH, 256>>>(p_kp, p_ks);
        favor_mma_kernel<<<dim3(NTOK/64, NH), 128>>>(p_qkv16, Om16, p_Qf, 0);
        z_kernel<<<dim3(BATCH*NH, SEQ/8), 256>>>(p_Qf, p_ks, p_z);

        // kv / attn (fp16 tensor)
        kv_gemm<<<dim3(1, NF/64, BATCH*NH), 256, SM_KV>>>(p_Kf, p_qkv16 + 1024, p_kv);
        attn_gemm<<<dim3(1, SEQ/128, BATCH*NH), 256, SM_ATTN>>>(p_Qf, p_kv, p_z, p_attn16);

        // output projection + residual LN (all-half)
        dense(p_attn16, WoT, Bo, p_v16, NTOK, DMODEL, DMODEL, 0, 1);
        ln_kernel<<<NTOK / 8, 256>>>(p_h16, p_h16, p_v16, ln1_g + l*DMODEL, ln1_b + l*DMODEL);

        // FFN + residual LN
        dense(p_h16, W1T, B1, p_ffn16, NTOK, FFNH, DMODEL, 1, 1);
        dense(p_ffn16, W2T, B2, p_v16, NTOK, DMODEL, FFNH, 0, 1);
        ln_kernel<<<NTOK / 8, 256>>>(p_h16, p_h16, p_v16, ln2_g + l*DMODEL, ln2_b + l*DMODEL);
    }

    pool1_kernel<<<BATCH * 8, 512>>>(p_h16, p_kp);
    pool2_kernel<<<BATCH, 512>>>(p_kp, cls_w, cls_b, (float*)d_out);
}

// round 17
// speedup vs baseline: 8.6555x; 1.0183x over previous
#include <cuda_runtime.h>
#include <cuda_fp16.h>
#include <math.h>

#define BATCH 16
#define SEQ 1024
#define NTOK (BATCH*SEQ)
#define DMODEL 512
#define NH 8
#define HD 64
#define NF 256
#define NLAYERS 4
#define FFNH 1024
#define QKVW 1536

// ---------------- scratch ----------------
__device__ __half g_h16 [NTOK*DMODEL];
__device__ __half g_t016[NTOK*256];
__device__ __half g_qkv16[NTOK*QKVW];
__device__ __half g_ffn16[NTOK*FFNH];
__device__ __half g_attn16[NTOK*DMODEL];
__device__ __half g_v16 [NTOK*DMODEL];
__device__ __half g_Qf  [BATCH*NH*SEQ*NF];
__device__ __half g_Kf  [BATCH*NH*SEQ*NF];
__device__ __half g_kv  [BATCH*NH*NF*HD];
__device__ float  g_ks  [BATCH*NH*NF];
__device__ float  g_kp  [BATCH*NH*8*NF];
__device__ float  g_z   [BATCH*NH*SEQ];
__device__ __half g_wqkvT[NLAYERS*QKVW*DMODEL];
__device__ float  g_bqkv [NLAYERS*QKVW];
__device__ __half g_w1T  [NLAYERS*FFNH*DMODEL];
__device__ __half g_w2T  [NLAYERS*DMODEL*FFNH];
__device__ __half g_woT  [NLAYERS*DMODEL*DMODEL];
__device__ __half g_ew2T [DMODEL*256];
__device__ __half g_om16 [NLAYERS*HD*128];

__device__ __forceinline__ void mma_f16(float* d, const unsigned* a, const unsigned* b) {
    asm volatile(
        "mma.sync.aligned.m16n8k16.row.col.f32.f16.f16.f32 "
        "{%0,%1,%2,%3},{%4,%5,%6,%7},{%8,%9},{%0,%1,%2,%3};\n"
        : "+f"(d[0]), "+f"(d[1]), "+f"(d[2]), "+f"(d[3])
        : "r"(a[0]), "r"(a[1]), "r"(a[2]), "r"(a[3]),
          "r"(b[0]), "r"(b[1]));
}

__device__ __forceinline__ void ldsm_x4(unsigned& r0, unsigned& r1,
                                        unsigned& r2, unsigned& r3, unsigned addr) {
    asm volatile("ldmatrix.sync.aligned.m8n8.x4.shared.b16 {%0,%1,%2,%3}, [%4];"
        : "=r"(r0), "=r"(r1), "=r"(r2), "=r"(r3) : "r"(addr));
}
__device__ __forceinline__ void ldsm_x4t(unsigned& r0, unsigned& r1,
                                         unsigned& r2, unsigned& r3, unsigned addr) {
    asm volatile("ldmatrix.sync.aligned.m8n8.x4.trans.shared.b16 {%0,%1,%2,%3}, [%4];"
        : "=r"(r0), "=r"(r1), "=r"(r2), "=r"(r3) : "r"(addr));
}

__device__ __forceinline__ void cpa16(void* dst, const void* src) {
    unsigned s = (unsigned)__cvta_generic_to_shared(dst);
    asm volatile("cp.async.ca.shared.global [%0], [%1], 16;\n" :: "r"(s), "l"(src));
}
#define CP_COMMIT  asm volatile("cp.async.commit_group;\n")

// ================= fp16 dense GEMM: C = A[M][K] @ B^T (B stored [N][K]) =================
template<int OUTH>
__global__ void __launch_bounds__(256, 2) hgemm(
    const __half* __restrict__ A, const __half* __restrict__ B,
    const float* __restrict__ bias, void* __restrict__ Cout,
    int M, int N, int K, int relu)
{
    constexpr int BM = 128, BN = 128, BK = 64, NS = 2;
    constexpr int PITCH = BK + 8;
    constexpr int TSZ = BM * PITCH;

    extern __shared__ __half hsm[];
    unsigned sb = (unsigned)__cvta_generic_to_shared(hsm);

    int m0 = blockIdx.y * BM;
    int n0 = blockIdx.x * BN;
    int tid = threadIdx.x;
    int warp = tid >> 5, lane = tid & 31;
    int wy = warp & 1, wx = warp >> 1;
    int wm = wy * 64, wn = wx * 32;
    int lrow = lane & 15, lk = lane >> 4;

    float acc[4][4][4];
#pragma unroll
    for (int i = 0; i < 4; i++)
#pragma unroll
        for (int j = 0; j < 4; j++)
#pragma unroll
            for (int c = 0; c < 4; c++) acc[i][j][c] = 0.f;

    auto loadT = [&](__half* S, const __half* G, int row0, int ld, int kt) {
#pragma unroll
        for (int i = 0; i < 4; i++) {
            int e = tid + i * 256;
            int row = e >> 3, q = (e & 7) * 8;
            cpa16(&S[row * PITCH + q], G + (long long)(row0 + row) * ld + kt + q);
        }
    };

    int T = K / BK;
    loadT(hsm, A, m0, K, 0);
    loadT(hsm + NS * TSZ, B, n0, K, 0);
    CP_COMMIT;

    int st = 0;
    for (int t = 0; t < T; t++) {
        if (t + 1 < T) {
            loadT(hsm + (st ^ 1) * TSZ, A, m0, K, (t + 1) * BK);
            loadT(hsm + (NS + (st ^ 1)) * TSZ, B, n0, K, (t + 1) * BK);
            CP_COMMIT;
            asm volatile("cp.async.wait_group 1;\n");
        } else {
            asm volatile("cp.async.wait_group 0;\n");
        }
        __syncthreads();

        unsigned sA = sb + st * (TSZ * 2);
        unsigned sB = sb + (NS + st) * (TSZ * 2);
        unsigned aB = sA + (wm + lrow) * (PITCH * 2) + lk * 16;
        unsigned bB = sB + (wn + lrow) * (PITCH * 2) + lk * 16;

#pragma unroll
        for (int ks = 0; ks < 4; ks++) {
            unsigned kb = ks * 32;
            unsigned a[4][4], b0q[4], b1q[4];
#pragma unroll
            for (int i = 0; i < 4; i++)
                ldsm_x4(a[i][0], a[i][1], a[i][2], a[i][3],
                        aB + i * (16 * PITCH * 2) + kb);
            ldsm_x4(b0q[0], b0q[1], b0q[2], b0q[3], bB + kb);
            ldsm_x4(b1q[0], b1q[1], b1q[2], b1q[3], bB + 16 * (PITCH * 2) + kb);
            unsigned bfr[4][2] = {
                {b0q[0], b0q[2]}, {b0q[1], b0q[3]},
                {b1q[0], b1q[2]}, {b1q[1], b1q[3]}};
#pragma unroll
            for (int i = 0; i < 4; i++)
#pragma unroll
                for (int j = 0; j < 4; j++)
                    mma_f16(acc[i][j], a[i], bfr[j]);
        }
        __syncthreads();
        st ^= 1;
    }

#pragma unroll
    for (int i = 0; i < 4; i++) {
        int mA = m0 + wm + i * 16 + (lane >> 2);
        int mB = mA + 8;
#pragma unroll
        for (int j = 0; j < 4; j++) {
            int n = n0 + wn + j * 8 + (lane & 3) * 2;
            float b0 = bias ? bias[n] : 0.f;
            float b1 = bias ? bias[n + 1] : 0.f;
            float v00 = acc[i][j][0] + b0, v01 = acc[i][j][1] + b1;
            float v10 = acc[i][j][2] + b0, v11 = acc[i][j][3] + b1;
            if (relu) {
                v00 = fmaxf(v00, 0.f); v01 = fmaxf(v01, 0.f);
                v10 = fmaxf(v10, 0.f); v11 = fmaxf(v11, 0.f);
            }
            if (OUTH) {
                __half* C = (__half*)Cout;
                __half2 h0; h0.x = __float2half(v00); h0.y = __float2half(v01);
                __half2 h1; h1.x = __float2half(v10); h1.y = __float2half(v11);
                *(__half2*)(C + (long long)mA * N + n) = h0;
                *(__half2*)(C + (long long)mB * N + n) = h1;
            } else {
                float* C = (float*)Cout;
                *(float2*)(C + (long long)mA * N + n) = make_float2(v00, v01);
                *(float2*)(C + (long long)mB * N + n) = make_float2(v10, v11);
            }
        }
    }
}

// ================= kv GEMM + fused ksum: kv[f][d] = sum_s Kf[s][f]*v[s][d]; ks[f]=sum_s Kf[s][f] =================
__global__ void __launch_bounds__(256, 2) kv_gemm(
    const __half* __restrict__ Kf, const __half* __restrict__ V,
    __half* __restrict__ KV, float* __restrict__ ksOut)
{
    constexpr int BK = 32, NS = 3;
    constexpr int PITCH = 72;
    constexpr int TSZ = BK * PITCH;

    extern __shared__ __half hsm[];
    unsigned sb = (unsigned)__cvta_generic_to_shared(hsm);
    __shared__ float kspart[4][64];

    int bh = blockIdx.z;
    int b = bh >> 3, h = bh & 7;
    const __half* Ap = Kf + (long long)bh * SEQ * NF;
    const __half* Vp = V + (long long)b * SEQ * QKVW + h * HD;
    __half* Cp = KV + (long long)bh * NF * HD;

    int m0 = blockIdx.y * 64;
    int tid = threadIdx.x;
    int warp = tid >> 5, lane = tid & 31;
    int wm = (warp & 1) * 32, wn = (warp >> 1) * 16;
    int trow = (lane & 7) + ((lane >> 4) << 3);
    int tcol = ((lane >> 3) & 1) << 3;

    float acc[2][2][4];
#pragma unroll
    for (int i = 0; i < 2; i++)
#pragma unroll
        for (int j = 0; j < 2; j++)
#pragma unroll
            for (int c = 0; c < 4; c++) acc[i][j][c] = 0.f;
    float ksacc = 0.f;
    int kcol = tid & 63, krg = tid >> 6;

    auto loadA = [&](__half* S, int kt) {
        int kk = tid >> 3, q = (tid & 7) * 8;
        cpa16(&S[kk * PITCH + q], Ap + (long long)(kt + kk) * NF + m0 + q);
    };
    auto loadB = [&](__half* S, int kt) {
        int kk = tid >> 3, q = (tid & 7) * 8;
        cpa16(&S[kk * PITCH + q], Vp + (long long)(kt + kk) * QKVW + q);
    };

    int T = SEQ / BK;
#pragma unroll
    for (int s = 0; s < NS - 1; s++) {
        loadA(hsm + s * TSZ, s * BK);
        loadB(hsm + (NS + s) * TSZ, s * BK);
        CP_COMMIT;
    }

    int st = 0, ps = NS - 1;
    for (int t = 0; t < T; t++) {
        asm volatile("cp.async.wait_group %0;\n" :: "n"(NS - 2));
        __syncthreads();
        int pf = t + NS - 1;
        if (pf < T) {
            loadA(hsm + ps * TSZ, pf * BK);
            loadB(hsm + (NS + ps) * TSZ, pf * BK);
        }
        CP_COMMIT;

        // fused ksum: column sums of the resident A tile
        {
            const __half* At = hsm + st * TSZ;
#pragma unroll
            for (int rr = 0; rr < 8; rr++)
                ksacc += __half2float(At[(krg * 8 + rr) * PITCH + kcol]);
        }

        unsigned sA = sb + st * (TSZ * 2);
        unsigned sB = sb + (NS + st) * (TSZ * 2);
#pragma unroll
        for (int ks = 0; ks < 2; ks++) {
            int kr = ks * 16 + trow;
            unsigned a[2][4], bq[4];
#pragma unroll
            for (int i = 0; i < 2; i++)
                ldsm_x4t(a[i][0], a[i][1], a[i][2], a[i][3],
                         sA + (kr * PITCH + wm + i * 16 + tcol) * 2);
            ldsm_x4t(bq[0], bq[1], bq[2], bq[3],
                     sB + (kr * PITCH + wn + tcol) * 2);
            unsigned bfr[2][2] = {{bq[0], bq[2]}, {bq[1], bq[3]}};
#pragma unroll
            for (int i = 0; i < 2; i++)
#pragma unroll
                for (int j = 0; j < 2; j++)
                    mma_f16(acc[i][j], a[i], bfr[j]);
        }
        st = (st + 1 == NS) ? 0 : st + 1;
        ps = (ps + 1 == NS) ? 0 : ps + 1;
    }

    kspart[krg][kcol] = ksacc;

#pragma unroll
    for (int i = 0; i < 2; i++) {
        int mA = m0 + wm + i * 16 + (lane >> 2);
        int mB = mA + 8;
#pragma unroll
        for (int j = 0; j < 2; j++) {
            int n = wn + j * 8 + (lane & 3) * 2;
            __half2 h0, h1;
            h0.x = __float2half(acc[i][j][0]); h0.y = __float2half(acc[i][j][1]);
            h1.x = __float2half(acc[i][j][2]); h1.y = __float2half(acc[i][j][3]);
            *(__half2*)(Cp + mA * HD + n) = h0;
            *(__half2*)(Cp + mB * HD + n) = h1;
        }
    }
    __syncthreads();
    if (tid < 64)
        ksOut[bh * NF + m0 + tid] =
            kspart[0][tid] + kspart[1][tid] + kspart[2][tid] + kspart[3][tid];
}

// ================= attn GEMM: O[s][h*64+d] = z[s] * Qf[s][:] @ kv[:][d] =================
__global__ void __launch_bounds__(256, 2) attn_gemm(
    const __half* __restrict__ Qf, const __half* __restrict__ KV,
    const float* __restrict__ z, __half* __restrict__ O)
{
    constexpr int BK = 32, NS = 3;
    constexpr int APITCH = 40;
    constexpr int BPITCH = 72;
    constexpr int ATSZ = 128 * APITCH;
    constexpr int BTSZ = BK * BPITCH;

    extern __shared__ __half hsm[];
    unsigned sb = (unsigned)__cvta_generic_to_shared(hsm);
    __half* Bs0 = hsm + NS * ATSZ;

    int bh = blockIdx.z;
    int b = bh >> 3, h = bh & 7;
    int m0 = blockIdx.y * 128;
    const __half* Ap = Qf + (long long)bh * SEQ * NF;
    const __half* Bp = KV + (long long)bh * NF * HD;
    __half* Op = O + (long long)b * SEQ * DMODEL + h * HD;
    const float* zp = z + (long long)bh * SEQ;

    int tid = threadIdx.x;
    int warp = tid >> 5, lane = tid & 31;
    int wm = (warp & 1) * 64, wn = (warp >> 1) * 16;
    int lrow = lane & 15, lk = lane >> 4;
    int trow = (lane & 7) + ((lane >> 4) << 3);
    int tcol = ((lane >> 3) & 1) << 3;

    float acc[4][2][4];
#pragma unroll
    for (int i = 0; i < 4; i++)
#pragma unroll
        for (int j = 0; j < 2; j++)
#pragma unroll
            for (int c = 0; c < 4; c++) acc[i][j][c] = 0.f;

    auto loadA = [&](__half* S, int kt) {
#pragma unroll
        for (int i = 0; i < 2; i++) {
            int e = tid + i * 256;
            int row = e >> 2, q = (e & 3) * 8;
            cpa16(&S[row * APITCH + q], Ap + (long long)(m0 + row) * NF + kt + q);
        }
    };
    auto loadB = [&](__half* S, int kt) {
        int kk = tid >> 3, q = (tid & 7) * 8;
        cpa16(&S[kk * BPITCH + q], Bp + (long long)(kt + kk) * HD + q);
    };

    int T = NF / BK;
#pragma unroll
    for (int s = 0; s < NS - 1; s++) {
        loadA(hsm + s * ATSZ, s * BK);
        loadB(Bs0 + s * BTSZ, s * BK);
        CP_COMMIT;
    }

    int st = 0, ps = NS - 1;
    for (int t = 0; t < T; t++) {
        asm volatile("cp.async.wait_group %0;\n" :: "n"(NS - 2));
        __syncthreads();
        int pf = t + NS - 1;
        if (pf < T) {
            loadA(hsm + ps * ATSZ, pf * BK);
            loadB(Bs0 + ps * BTSZ, pf * BK);
        }
        CP_COMMIT;

        unsigned sA = sb + st * (ATSZ * 2);
        unsigned sB = sb + (NS * ATSZ + st * BTSZ) * 2;
        unsigned aB = sA + (wm + lrow) * (APITCH * 2) + lk * 16;
#pragma unroll
        for (int ks = 0; ks < 2; ks++) {
            unsigned kb = ks * 32;
            int kr = ks * 16 + trow;
            unsigned a[4][4], bq[4];
#pragma unroll
            for (int i = 0; i < 4; i++)
                ldsm_x4(a[i][0], a[i][1], a[i][2], a[i][3],
                        aB + i * (16 * APITCH * 2) + kb);
            ldsm_x4t(bq[0], bq[1], bq[2], bq[3],
                     sB + (kr * BPITCH + wn + tcol) * 2);
            unsigned bfr[2][2] = {{bq[0], bq[2]}, {bq[1], bq[3]}};
#pragma unroll
            for (int i = 0; i < 4; i++)
#pragma unroll
                for (int j = 0; j < 2; j++)
                    mma_f16(acc[i][j], a[i], bfr[j]);
        }
        st = (st + 1 == NS) ? 0 : st + 1;
        ps = (ps + 1 == NS) ? 0 : ps + 1;
    }

#pragma unroll
    for (int i = 0; i < 4; i++) {
        int mA = m0 + wm + i * 16 + (lane >> 2);
        int mB = mA + 8;
        float rsA = zp[mA], rsB = zp[mB];
#pragma unroll
        for (int j = 0; j < 2; j++) {
            int n = wn + j * 8 + (lane & 3) * 2;
            __half2 h0, h1;
            h0.x = __float2half(acc[i][j][0] * rsA);
            h0.y = __float2half(acc[i][j][1] * rsA);
            h1.x = __float2half(acc[i][j][2] * rsB);
            h1.y = __float2half(acc[i][j][3] * rsB);
            *(__half2*)(Op + (long long)mA * DMODEL + n) = h0;
            *(__half2*)(Op + (long long)mB * DMODEL + n) = h1;
        }
    }
}

// ================= FAVOR via tensor cores, optional fused z =================
__global__ void __launch_bounds__(128) favor_mma_kernel(
    const __half* __restrict__ qkv, const __half* __restrict__ om16,
    __half* __restrict__ outF, float* __restrict__ zOut,
    const float* __restrict__ ksIn, int colOff)
{
    constexpr int APITCH = 72, BPITCH = 136;
    __shared__ __half qa[64 * APITCH];
    __shared__ __half ob[64 * BPITCH];
    __shared__ float hvs[64];
    __shared__ float ksS[NF];
    __shared__ float zpart[64][2];

    int r0 = blockIdx.x * 64;
    int h = blockIdx.y;
    int tid = threadIdx.x, warp = tid >> 5, lane = tid & 31;
    int bh = (r0 >> 10) * NH + h;

    const __half* qp = qkv + (long long)r0 * QKVW + colOff + h * HD;
#pragma unroll
    for (int i = 0; i < 4; i++) {
        int e = tid + i * 128;
        int row = e >> 3, q = (e & 7) * 8;
        cpa16(&qa[row * APITCH + q], qp + (long long)row * QKVW + q);
    }
#pragma unroll
    for (int i = 0; i < 8; i++) {
        int e = tid + i * 128;
        int row = e >> 4, q = (e & 15) * 8;
        cpa16(&ob[row * BPITCH + q], om16 + row * 128 + q);
    }
    CP_COMMIT;
    if (zOut) {
        ksS[tid]       = ksIn[bh * NF + tid];
        ksS[tid + 128] = ksIn[bh * NF + tid + 128];
    }
    asm volatile("cp.async.wait_group 0;\n");
    __syncthreads();

    {
        int row = tid >> 1, hs = tid & 1;
        float s = 0.f;
#pragma unroll
        for (int d = 0; d < 32; d++) {
            float v = __half2float(qa[row * APITCH + hs * 32 + d]);
            s = fmaf(v, v, s);
        }
        s += __shfl_xor_sync(0xffffffffu, s, 1);
        if (!hs) hvs[row] = s * 0.5f * 0.125f;
    }
    __syncthreads();

    unsigned sbq = (unsigned)__cvta_generic_to_shared(qa);
    unsigned sbo = (unsigned)__cvta_generic_to_shared(ob);

    int wm = (warp & 1) * 32;
    int wn = (warp >> 1) * 64;
    int lrow = lane & 15, lk = lane >> 4;
    int trow = (lane & 7) + ((lane >> 4) << 3);
    int tcol = ((lane >> 3) & 1) << 3;

    float acc[2][8][4];
#pragma unroll
    for (int i = 0; i < 2; i++)
#pragma unroll
        for (int j = 0; j < 8; j++)
#pragma unroll
            for (int c = 0; c < 4; c++) acc[i][j][c] = 0.f;

    unsigned aB = sbq + (wm + lrow) * (APITCH * 2) + lk * 16;
#pragma unroll
    for (int ks = 0; ks < 4; ks++) {
        unsigned kb = ks * 32;
        int kr = ks * 16 + trow;
        unsigned a[2][4];
#pragma unroll
        for (int i = 0; i < 2; i++)
            ldsm_x4(a[i][0], a[i][1], a[i][2], a[i][3],
                    aB + i * (16 * APITCH * 2) + kb);
#pragma unroll
        for (int jj = 0; jj < 4; jj++) {
            unsigned bq[4];
            ldsm_x4t(bq[0], bq[1], bq[2], bq[3],
                     sbo + (kr * BPITCH + wn + jj * 16 + tcol) * 2);
            unsigned bfr[2][2] = {{bq[0], bq[2]}, {bq[1], bq[3]}};
#pragma unroll
            for (int i = 0; i < 2; i++)
#pragma unroll
                for (int j2 = 0; j2 < 2; j2++)
                    mma_f16(acc[i][jj * 2 + j2], a[i], bfr[j2]);
        }
    }

    long long obase = ((long long)bh * SEQ + (r0 & 1023)) * NF;
    const float sc = 0.3535533905932738f;
    float zpacc[4] = {0.f, 0.f, 0.f, 0.f};
#pragma unroll
    for (int i = 0; i < 2; i++) {
        int lr = wm + i * 16 + (lane >> 2);
        float hvA = hvs[lr], hvB = hvs[lr + 8];
        long long oA = obase + (long long)lr * NF;
        long long oB = obase + (long long)(lr + 8) * NF;
#pragma unroll
        for (int j = 0; j < 8; j++) {
            int f = wn + j * 8 + (lane & 3) * 2;
            float u0 = acc[i][j][0] * sc, u1 = acc[i][j][1] * sc;
            float u2 = acc[i][j][2] * sc, u3 = acc[i][j][3] * sc;
            float ea0 = __expf( u0 - hvA) * 0.0625f;
            float ea1 = __expf( u1 - hvA) * 0.0625f;
            float ma0 = __expf(-u0 - hvA) * 0.0625f;
            float ma1 = __expf(-u1 - hvA) * 0.0625f;
            float eb0 = __expf( u2 - hvB) * 0.0625f;
            float eb1 = __expf( u3 - hvB) * 0.0625f;
            float mb0 = __expf(-u2 - hvB) * 0.0625f;
            float mb1 = __expf(-u3 - hvB) * 0.0625f;
            if (zOut) {
                float k0 = ksS[f], k1 = ksS[f + 1];
                float k2 = ksS[f + 128], k3 = ksS[f + 129];
                zpacc[i * 2]     += ea0 * k0 + ea1 * k1 + ma0 * k2 + ma1 * k3;
                zpacc[i * 2 + 1] += eb0 * k0 + eb1 * k1 + mb0 * k2 + mb1 * k3;
            }
            __half2 p0, p1, q0, q1;
            p0.x = __float2half(ea0); p0.y = __float2half(ea1);
            q0.x = __float2half(ma0); q0.y = __float2half(ma1);
            p1.x = __float2half(eb0); p1.y = __float2half(eb1);
            q1.x = __float2half(mb0); q1.y = __float2half(mb1);
            *(__half2*)(outF + oA + f)       = p0;
            *(__half2*)(outF + oA + 128 + f) = q0;
            *(__half2*)(outF + oB + f)       = p1;
            *(__half2*)(outF + oB + 128 + f) = q1;
        }
    }
    if (zOut) {
#pragma unroll
        for (int o = 1; o <= 2; o <<= 1)
#pragma unroll
            for (int k = 0; k < 4; k++)
                zpacc[k] += __shfl_xor_sync(0xffffffffu, zpacc[k], o);
        if ((lane & 3) == 0) {
            int rb = wm + (lane >> 2);
            int hw = warp >> 1;
            zpart[rb][hw]      = zpacc[0];
            zpart[rb + 8][hw]  = zpacc[1];
            zpart[rb + 16][hw] = zpacc[2];
            zpart[rb + 24][hw] = zpacc[3];
        }
        __syncthreads();
        if (tid < 64)
            zOut[(long long)bh * SEQ + (r0 & 1023) + tid] =
                1.f / (zpart[tid][0] + zpart[tid][1] + 1e-6f);
    }
}

// ---------------- merged prep ----------------
__device__ __forceinline__ void tr32(const float* ip, __half* op, int K, int N,
                                     int tx, int ty, int tid, float (*tile)[33])
{
    int n0 = tx * 32, k0 = ty * 32;
    int lx = tid & 31, ly = tid >> 5;
#pragma unroll
    for (int r = 0; r < 4; r++)
        tile[ly + r * 8][lx] = ip[(long long)(k0 + ly + r * 8) * N + n0 + lx];
    __syncthreads();
#pragma unroll
    for (int r = 0; r < 4; r++)
        op[(long long)(n0 + ly + r * 8) * K + k0 + lx] = __float2half(tile[lx][ly + r * 8]);
}

__global__ void __launch_bounds__(256) prep_all(
    const float* __restrict__ wq, const float* __restrict__ wk, const float* __restrict__ wv,
    const float* __restrict__ w1, const float* __restrict__ w2, const float* __restrict__ wo,
    const float* __restrict__ ew2,
    const float* __restrict__ bq, const float* __restrict__ bk, const float* __restrict__ bv,
    const float* __restrict__ om,
    __half* __restrict__ wqkvT, __half* __restrict__ w1T, __half* __restrict__ w2T,
    __half* __restrict__ woT, __half* __restrict__ ew2T, __half* __restrict__ om16,
    float* __restrict__ bqkv)
{
    __shared__ float tile[32][33];
    int b = blockIdx.x, tid = threadIdx.x;
    if (b < 3072) {
        int which = b >> 10, t = b & 1023;
        int l = t >> 8, rem = t & 255;
        int tx = rem & 15, ty = rem >> 4;
        const float* src = which == 0 ? wq : (which == 1 ? wk : wv);
        tr32(src + (long long)l * 512 * 512,
             wqkvT + (long long)l * QKVW * DMODEL + which * 512 * 512,
             512, 512, tx, ty, tid, tile);
    } else if (b < 5120) {
        int t = b - 3072;
        int l = t >> 9, rem = t & 511;
        int tx = rem & 31, ty = rem >> 5;
        tr32(w1 + (long long)l * 512 * 1024,
             w1T + (long long)l * FFNH * DMODEL, 512, 1024, tx, ty, tid, tile);
    } else if (b < 7168) {
        int t = b - 5120;
        int l = t >> 9, rem = t & 511;
        int tx = rem & 15, ty = rem >> 4;
        tr32(w2 + (long long)l * 1024 * 512,
             w2T + (long long)l * DMODEL * FFNH, 1024, 512, tx, ty, tid, tile);
    } else if (b < 8192) {
        int t = b - 7168;
        int l = t >> 8, rem = t & 255;
        int tx = rem & 15, ty = rem >> 4;
        tr32(wo + (long long)l * 512 * 512,
             woT + (long long)l * 512 * 512, 512, 512, tx, ty, tid, tile);
    } else if (b < 8320) {
        int t = b - 8192;
        int tx = t & 15, ty = t >> 4;
        tr32(ew2, ew2T, 256, 512, tx, ty, tid, tile);
    } else if (b < 8344) {
        int idx = (b - 8320) * 256 + tid;
        if (idx < NLAYERS * QKVW) {
            int l = idx / QKVW, c = idx % QKVW;
            const float* src = c < 512 ? bq : (c < 1024 ? bk : bv);
            bqkv[idx] = src[l * DMODEL + (c & 511)];
        }
    } else {
        int idx = (b - 8344) * 256 + tid;
        om16[idx] = __float2half(om[idx]);
    }
}

// ---------------- encoder first layer ----------------
__global__ void __launch_bounds__(256) enc1_kernel(
    const float* __restrict__ x, const float* __restrict__ pos,
    const float* __restrict__ w, const float* __restrict__ b,
    __half* __restrict__ out)
{
    int idx = blockIdx.x * 256 + threadIdx.x;
    int row = idx >> 8, col = idx & 255;
    const float* xr = x + row * 3;
    const float* pr = pos + row * 3;
    float a = b[col];
#pragma unroll
    for (int d = 0; d < 3; d++) a = fmaf(xr[d], w[d * 256 + col], a);
#pragma unroll
    for (int d = 0; d < 3; d++) a = fmaf(pr[d], w[(3 + d) * 256 + col], a);
    out[idx] = __float2half(fmaxf(a, 0.f));
}

// ---------------- LayerNorm: warp-per-row, uint4 I/O ----------------
__global__ void __launch_bounds__(256) ln_kernel(
    __half* __restrict__ out16, const __half* __restrict__ resid,
    const __half* __restrict__ y,
    const float* __restrict__ g, const float* __restrict__ b)
{
    int w = threadIdx.x >> 5, lane = threadIdx.x & 31;
    long long row = (long long)blockIdx.x * 8 + w;
    const uint4* yp = (const uint4*)(y + row * 512);
    const uint4* rp = resid ? (const uint4*)(resid + row * 512) : nullptr;
    uint4 u[2];
    float2 v[8];
    float s = 0.f, s2 = 0.f;
#pragma unroll
    for (int q = 0; q < 2; q++) {
        u[q] = yp[lane + q * 32];
        __half2* hp = (__half2*)&u[q];
        if (rp) {
            uint4 r = rp[lane + q * 32];
            __half2* hr = (__half2*)&r;
#pragma unroll
            for (int k = 0; k < 4; k++) {
                float2 t = __half22float2(hp[k]);
                float2 rr = __half22float2(hr[k]);
                t.x += rr.x; t.y += rr.y;
                v[q * 4 + k] = t;
            }
        } else {
#pragma unroll
            for (int k = 0; k < 4; k++) v[q * 4 + k] = __half22float2(hp[k]);
        }
    }
#pragma unroll
    for (int k = 0; k < 8; k++) {
        s += v[k].x + v[k].y;
        s2 += v[k].x * v[k].x + v[k].y * v[k].y;
    }
#pragma unroll
    for (int o = 16; o; o >>= 1) {
        s  += __shfl_xor_sync(0xffffffffu, s,  o);
        s2 += __shfl_xor_sync(0xffffffffu, s2, o);
    }
    float mean = s * (1.f / 512.f);
    float var  = s2 * (1.f / 512.f) - mean * mean;
    float rstd = rsqrtf(var + 1e-5f);
    uint4* op = (uint4*)(out16 + row * 512);
#pragma unroll
    for (int q = 0; q < 2; q++) {
        uint4 ou;
        __half2* ho = (__half2*)&ou;
#pragma unroll
        for (int k = 0; k < 4; k++) {
            int c = (lane + q * 32) * 8 + k * 2;
            float o0 = (v[q * 4 + k].x - mean) * rstd * g[c]     + b[c];
            float o1 = (v[q * 4 + k].y - mean) * rstd * g[c + 1] + b[c + 1];
            __half2 hh; hh.x = __float2half(o0); hh.y = __float2half(o1);
            ho[k] = hh;
        }
        op[lane + q * 32] = ou;
    }
}

// ---------------- pool stage1 + stage2 ----------------
__global__ void __launch_bounds__(512) pool1_kernel(
    const __half* __restrict__ h, float* __restrict__ part)
{
    int b = blockIdx.x >> 3, c = blockIdx.x & 7, t = threadIdx.x;
    const __half* base = h + ((long long)b * SEQ + c * 128) * DMODEL + t;
    float s = 0.f;
#pragma unroll 8
    for (int i = 0; i < 128; i++) s += __half2float(base[(long long)i * DMODEL]);
    part[(b * 8 + c) * DMODEL + t] = s;
}
__global__ void __launch_bounds__(512) pool2_kernel(
    const float* __restrict__ part, const float* __restrict__ cw,
    const float* __restrict__ cb, float* __restrict__ out)
{
    int b = blockIdx.x, t = threadIdx.x;
    float s = 0.f;
#pragma unroll
    for (int c = 0; c < 8; c++) s += part[(b * 8 + c) * DMODEL + t];
    __shared__ float pooled[DMODEL];
    pooled[t] = s * (1.f / (float)SEQ);
    __syncthreads();
    if (t < 16) {
        float acc = cb[t];
        for (int d = 0; d < DMODEL; d++) acc = fmaf(pooled[d], cw[d * 16 + t], acc);
        out[b * 16 + t] = acc;
    }
}

// ---------------- host driver ----------------
extern "C" void kernel_launch(void* const* d_in, const int* in_sizes, int n_in,
                              void* d_out, int out_size)
{
    const float* x      = (const float*)d_in[0];
    const float* pos    = (const float*)d_in[1];
    const float* enc_w1 = (const float*)d_in[2];
    const float* enc_b1 = (const float*)d_in[3];
    const float* enc_w2 = (const float*)d_in[4];
    const float* enc_b2 = (const float*)d_in[5];
    const float* enc_g  = (const float*)d_in[6];
    const float* enc_bb = (const float*)d_in[7];
    const float* wq     = (const float*)d_in[8];
    const float* bq     = (const float*)d_in[9];
    const float* wk     = (const float*)d_in[10];
    const float* bk     = (const float*)d_in[11];
    const float* wv     = (const float*)d_in[12];
    const float* bv     = (const float*)d_in[13];
    const float* wo     = (const float*)d_in[14];
    const float* bo     = (const float*)d_in[15];
    const float* ln1_g  = (const float*)d_in[16];
    const float* ln1_b  = (const float*)d_in[17];
    const float* w1     = (const float*)d_in[18];
    const float* b1     = (const float*)d_in[19];
    const float* w2     = (const float*)d_in[20];
    const float* b2     = (const float*)d_in[21];
    const float* ln2_g  = (const float*)d_in[22];
    const float* ln2_b  = (const float*)d_in[23];
    const float* omega  = (const float*)d_in[24];
    const float* cls_w  = (const float*)d_in[25];
    const float* cls_b  = (const float*)d_in[26];

    float *p_ks, *p_kp, *p_z, *p_bqkv;
    __half *p_h16, *p_t016, *p_qkv16, *p_ffn16, *p_attn16, *p_v16;
    __half *p_Qf, *p_Kf, *p_kv, *p_om16;
    __half *p_wqkvT, *p_w1T, *p_w2T, *p_woT, *p_ew2T;
    cudaGetSymbolAddress((void**)&p_Qf,   g_Qf);
    cudaGetSymbolAddress((void**)&p_Kf,   g_Kf);
    cudaGetSymbolAddress((void**)&p_kv,   g_kv);
    cudaGetSymbolAddress((void**)&p_ks,   g_ks);
    cudaGetSymbolAddress((void**)&p_kp,   g_kp);
    cudaGetSymbolAddress((void**)&p_z,    g_z);
    cudaGetSymbolAddress((void**)&p_bqkv, g_bqkv);
    cudaGetSymbolAddress((void**)&p_h16,  g_h16);
    cudaGetSymbolAddress((void**)&p_t016, g_t016);
    cudaGetSymbolAddress((void**)&p_qkv16,g_qkv16);
    cudaGetSymbolAddress((void**)&p_ffn16,g_ffn16);
    cudaGetSymbolAddress((void**)&p_attn16,g_attn16);
    cudaGetSymbolAddress((void**)&p_v16,  g_v16);
    cudaGetSymbolAddress((void**)&p_om16, g_om16);
    cudaGetSymbolAddress((void**)&p_wqkvT,g_wqkvT);
    cudaGetSymbolAddress((void**)&p_w1T,  g_w1T);
    cudaGetSymbolAddress((void**)&p_w2T,  g_w2T);
    cudaGetSymbolAddress((void**)&p_woT,  g_woT);
    cudaGetSymbolAddress((void**)&p_ew2T, g_ew2T);

    const int SM_H    = 2 * 2 * 128 * 72 * 2;
    const int SM_KV   = 3 * 2 * 32 * 72 * 2;
    const int SM_ATTN = 3 * (128 * 40 + 32 * 72) * 2;
    cudaFuncSetAttribute(hgemm<0>, cudaFuncAttributeMaxDynamicSharedMemorySize, SM_H);
    cudaFuncSetAttribute(hgemm<1>, cudaFuncAttributeMaxDynamicSharedMemorySize, SM_H);
    cudaFuncSetAttribute(kv_gemm,  cudaFuncAttributeMaxDynamicSharedMemorySize, SM_KV);
    cudaFuncSetAttribute(attn_gemm,cudaFuncAttributeMaxDynamicSharedMemorySize, SM_ATTN);

    // ---- single prep launch ----
    prep_all<<<8472, 256>>>(wq, wk, wv, w1, w2, wo, enc_w2, bq, bk, bv, omega,
                            p_wqkvT, p_w1T, p_w2T, p_woT, p_ew2T, p_om16, p_bqkv);

    auto dense = [&](const __half* A, const __half* Bt, const float* bias,
                     void* C, int M, int Nn, int K, int relu, int outh) {
        dim3 grid(Nn / 128, M / 128, 1);
        if (outh) hgemm<1><<<grid, 256, SM_H>>>(A, Bt, bias, C, M, Nn, K, relu);
        else      hgemm<0><<<grid, 256, SM_H>>>(A, Bt, bias, C, M, Nn, K, relu);
    };

    // ---- encoder ----
    enc1_kernel<<<NTOK, 256>>>(x, pos, enc_w1, enc_b1, p_t016);
    dense(p_t016, p_ew2T, enc_b2, p_v16, NTOK, DMODEL, 256, 0, 1);
    ln_kernel<<<NTOK / 8, 256>>>(p_h16, nullptr, p_v16, enc_g, enc_bb);

    for (int l = 0; l < NLAYERS; l++) {
        const __half* WqkvT = p_wqkvT + (long long)l * QKVW * DMODEL;
        const float*  Bqkv  = p_bqkv + l * QKVW;
        const __half* WoT   = p_woT + (long long)l * DMODEL * DMODEL;
        const float*  Bo    = bo + l * DMODEL;
        const __half* W1T   = p_w1T + (long long)l * FFNH * DMODEL;
        const float*  B1    = b1 + l * FFNH;
        const __half* W2T   = p_w2T + (long long)l * DMODEL * FFNH;
        const float*  B2    = b2 + l * DMODEL;
        const __half* Om16  = p_om16 + (long long)l * HD * 128;

        // merged QKV projection (half out)
        dense(p_h16, WqkvT, Bqkv, p_qkv16, NTOK, QKVW, DMODEL, 0, 1);

        // FAVOR(K); kv GEMM with fused ksum; FAVOR(Q) with fused z; attn
        favor_mma_kernel<<<dim3(NTOK/64, NH), 128>>>(p_qkv16, Om16, p_Kf, nullptr, nullptr, 512);
        kv_gemm<<<dim3(1, NF/64, BATCH*NH), 256, SM_KV>>>(p_Kf, p_qkv16 + 1024, p_kv, p_ks);
        favor_mma_kernel<<<dim3(NTOK/64, NH), 128>>>(p_qkv16, Om16, p_Qf, p_z, p_ks, 0);
        attn_gemm<<<dim3(1, SEQ/128, BATCH*NH), 256, SM_ATTN>>>(p_Qf, p_kv, p_z, p_attn16);

        // output projection + residual LN (all-half)
        dense(p_attn16, WoT, Bo, p_v16, NTOK, DMODEL, DMODEL, 0, 1);
        ln_kernel<<<NTOK / 8, 256>>>(p_h16, p_h16, p_v16, ln1_g + l*DMODEL, ln1_b + l*DMODEL);

        // FFN + residual LN
        dense(p_h16, W1T, B1, p_ffn16, NTOK, FFNH, DMODEL, 1, 1);
        dense(p_ffn16, W2T, B2, p_v16, NTOK, DMODEL, FFNH, 0, 1);
        ln_kernel<<<NTOK / 8, 256>>>(p_h16, p_h16, p_v16, ln2_g + l*DMODEL, ln2_b + l*DMODEL);
    }

    pool1_kernel<<<BATCH * 8, 512>>>(p_h16, p_kp);
    pool2_kernel<<<BATCH, 512>>>(p_kp, cls_w, cls_b, (float*)d_out);
}